// round 1
// baseline (speedup 1.0000x reference)
#include <cuda_runtime.h>
#include <math.h>

// ---------------- problem constants ----------------
#define B_      2
#define S_      2048
#define DMODEL  2048
#define NH      16
#define DH      128
#define NOPE    14          // non-rope heads
#define QPROJ   1024
#define KVPROJ  1365
#define KNOPE   1792        // 14*128
#define KVCOLS  3840        // DMODEL + KNOPE
#define BS      (B_*S_)     // 4096

// ---------------- device scratch (static, no dynamic alloc) ----------------
__device__ float g_cq [BS * QPROJ];                 // 16 MB
__device__ float g_qn [BS * KNOPE];                 // 29 MB
__device__ float g_qr [BS * 256];                   // 4 MB
__device__ float g_kv [BS * KVCOLS];                // 63 MB
__device__ float g_kr [BS * 256];                   // 4 MB
__device__ float g_q  [(size_t)B_*NH*S_*DH];        // 33.5 MB  (B,H,S,D)
__device__ float g_k  [(size_t)B_*NH*S_*DH];
__device__ float g_v  [(size_t)B_*NH*S_*DH];
__device__ float g_sc [(size_t)B_*NH*S_*S_];        // 536 MB scores/attn
__device__ float g_ao [(size_t)B_*NH*S_*DH];        // attn output (B,H,S,D)
__device__ float g_ao2[(size_t)BS*DMODEL];          // merged (B,S,H*D)

// ---------------- generic tiled SGEMM ----------------
// C[M,N] = A[M,K] @ B  (TB=false: B is K x N;  TB=true: B is N x K, i.e. A@B^T)
// flags bit0: causal block skip (only blocks with some col <= row needed)
// flags bit1: triangular A (attn): limit K to r0+BM (rest of A row is zero)
template<bool TB>
__global__ __launch_bounds__(256)
void sgemm_kernel(const float* __restrict__ A, const float* __restrict__ Bm,
                  float* __restrict__ C, int M, int N, int K,
                  size_t sA, size_t sB, size_t sC, int flags)
{
    constexpr int BM = 128, BN = 128, BK = 16;
    constexpr int PAD = 4;   // keeps 16B alignment for LDS.128 while reducing STS conflicts
    int z = blockIdx.z;
    A  += (size_t)z * sA;
    Bm += (size_t)z * sB;
    C  += (size_t)z * sC;

    int r0 = blockIdx.y * BM;
    int c0 = blockIdx.x * BN;
    if ((flags & 1) && c0 >= r0 + BM) return;          // fully-masked causal block
    int Keff = (flags & 2) ? min(K, r0 + BM) : K;      // triangular attn rows

    __shared__ float As[BK][BM + PAD];
    __shared__ float Bs[BK][BN + PAD];

    int tid = threadIdx.x;
    int tm = (tid >> 4) << 3;      // 0..120
    int tn = (tid & 15) << 3;      // 0..120

    float acc[8][8];
#pragma unroll
    for (int i = 0; i < 8; i++)
#pragma unroll
        for (int j = 0; j < 8; j++) acc[i][j] = 0.f;

    for (int k0 = 0; k0 < Keff; k0 += BK) {
        // load A tile (BM x BK), As stored transposed As[k][m]
#pragma unroll
        for (int i = 0; i < 8; i++) {
            int e  = tid + i * 256;       // 0..2047
            int m  = e >> 4;              // 0..127
            int kk = e & 15;
            int gr = r0 + m, gk = k0 + kk;
            As[kk][m] = (gr < M && gk < K) ? A[(size_t)gr * K + gk] : 0.f;
        }
        // load B tile (BK x BN) -> Bs[k][n]
#pragma unroll
        for (int i = 0; i < 8; i++) {
            int e = tid + i * 256;
            if (TB) {
                int n  = e >> 4;
                int kk = e & 15;
                int gn = c0 + n, gk = k0 + kk;
                Bs[kk][n] = (gn < N && gk < K) ? Bm[(size_t)gn * K + gk] : 0.f;
            } else {
                int kk = e >> 7;
                int n  = e & 127;
                int gk = k0 + kk, gn = c0 + n;
                Bs[kk][n] = (gk < K && gn < N) ? Bm[(size_t)gk * N + gn] : 0.f;
            }
        }
        __syncthreads();

#pragma unroll
        for (int kk = 0; kk < BK; kk++) {
            float a[8], b[8];
#pragma unroll
            for (int i = 0; i < 8; i++) a[i] = As[kk][tm + i];
#pragma unroll
            for (int j = 0; j < 8; j++) b[j] = Bs[kk][tn + j];
#pragma unroll
            for (int i = 0; i < 8; i++)
#pragma unroll
                for (int j = 0; j < 8; j++)
                    acc[i][j] += a[i] * b[j];
        }
        __syncthreads();
    }

#pragma unroll
    for (int i = 0; i < 8; i++) {
        int gr = r0 + tm + i;
        if (gr >= M) continue;
#pragma unroll
        for (int j = 0; j < 8; j++) {
            int gc = c0 + tn + j;
            if (gc < N) C[(size_t)gr * N + gc] = acc[i][j];
        }
    }
}

// ---------------- LayerNorm (in-place, biased variance, eps=1e-5) ----------------
__global__ __launch_bounds__(256)
void layernorm_kernel(float* __restrict__ X, const float* __restrict__ w,
                      const float* __restrict__ b, int n)
{
    float* p = X + (size_t)blockIdx.x * n;
    float s = 0.f, s2 = 0.f;
    for (int j = threadIdx.x; j < n; j += 256) {
        float v = p[j];
        s += v; s2 += v * v;
    }
    __shared__ float sh[20];
#pragma unroll
    for (int o = 16; o; o >>= 1) {
        s  += __shfl_down_sync(0xffffffffu, s,  o);
        s2 += __shfl_down_sync(0xffffffffu, s2, o);
    }
    int wd = threadIdx.x >> 5, ln = threadIdx.x & 31;
    if (!ln) { sh[wd] = s; sh[wd + 8] = s2; }
    __syncthreads();
    if (threadIdx.x == 0) {
        float ts = 0.f, ts2 = 0.f;
        for (int i = 0; i < 8; i++) { ts += sh[i]; ts2 += sh[i + 8]; }
        float mean = ts / n;
        float var  = fmaxf(ts2 / n - mean * mean, 0.f);
        sh[16] = mean;
        sh[17] = rsqrtf(var + 1e-5f);
    }
    __syncthreads();
    float mean = sh[16], rstd = sh[17];
    for (int j = threadIdx.x; j < n; j += 256)
        p[j] = (p[j] - mean) * rstd * w[j] + b[j];
}

// ---------------- causal softmax (in-place on scores, applies 1/sqrt(DH)) ----------------
__global__ __launch_bounds__(256)
void softmax_kernel(float* __restrict__ Sc)
{
    size_t row = blockIdx.x;             // (b*NH+h)*S_ + i
    int i = (int)(row & (S_ - 1));
    float* p = Sc + row * S_;
    const float scale = 0.08838834764831845f;   // 1/sqrt(128)

    __shared__ float sh[12];
    float m = -1e30f;
    for (int j = threadIdx.x; j <= i; j += 256) m = fmaxf(m, p[j]);
#pragma unroll
    for (int o = 16; o; o >>= 1) m = fmaxf(m, __shfl_down_sync(0xffffffffu, m, o));
    int wd = threadIdx.x >> 5, ln = threadIdx.x & 31;
    if (!ln) sh[wd] = m;
    __syncthreads();
    if (threadIdx.x == 0) {
        float mm = sh[0];
        for (int q = 1; q < 8; q++) mm = fmaxf(mm, sh[q]);
        sh[8] = mm;
    }
    __syncthreads();
    m = sh[8] * scale;

    float sum = 0.f;
    for (int j = threadIdx.x; j <= i; j += 256) {
        float e = __expf(p[j] * scale - m);
        p[j] = e;
        sum += e;
    }
#pragma unroll
    for (int o = 16; o; o >>= 1) sum += __shfl_down_sync(0xffffffffu, sum, o);
    if (!ln) sh[wd] = sum;
    __syncthreads();
    if (threadIdx.x == 0) {
        float ts = 0.f;
        for (int q = 0; q < 8; q++) ts += sh[q];
        sh[9] = 1.f / ts;
    }
    __syncthreads();
    float inv = sh[9];
    for (int j = threadIdx.x; j <= i; j += 256) p[j] *= inv;
    for (int j = i + 1 + threadIdx.x; j < S_; j += 256) p[j] = 0.f;
}

// ---------------- RoPE + head gather into (B,H,S,D) ----------------
__device__ __forceinline__ float rope_val(const float* __restrict__ base, int d, int s)
{
    int dd = d & 63;
    float freq = 1.0f / powf(10000.0f, (float)dd * (1.0f / 64.0f));
    float ang = (float)s * freq;
    float sn, cs;
    sincosf(ang, &sn, &cs);
    float x = base[d];
    return (d < 64) ? x * cs - base[d + 64] * sn
                    : x * cs + base[d - 64] * sn;
}

__global__ __launch_bounds__(256)
void build_qkv(const float* __restrict__ qn, const float* __restrict__ qr,
               const float* __restrict__ kv, const float* __restrict__ kr,
               float* __restrict__ q, float* __restrict__ k, float* __restrict__ v)
{
    int idx = blockIdx.x * blockDim.x + threadIdx.x;
    if (idx >= B_ * NH * S_ * DH) return;
    int d = idx & (DH - 1);
    int t = idx >> 7;
    int s = t & (S_ - 1); t >>= 11;
    int h = t & 15;
    int b = t >> 4;
    size_t row = (size_t)(b * S_ + s);

    v[idx] = kv[row * KVCOLS + KNOPE + h * DH + d];

    float qv, kvv;
    if (h < NOPE) {
        qv  = qn[row * KNOPE + h * DH + d];
        kvv = kv[row * KVCOLS + h * DH + d];
    } else {
        qv  = rope_val(qr + row * 256 + (h - NOPE) * DH, d, s);
        kvv = rope_val(kr + row * 256 + (h - NOPE) * DH, d, s);
    }
    q[idx] = qv;
    k[idx] = kvv;
}

// ---------------- (B,H,S,D) -> (B,S,H*D) merge ----------------
__global__ __launch_bounds__(256)
void permute_ao(const float* __restrict__ ao, float* __restrict__ ao2)
{
    int idx = blockIdx.x * blockDim.x + threadIdx.x;
    if (idx >= B_ * NH * S_ * DH) return;
    int d = idx & (DH - 1);
    int t = idx >> 7;
    int s = t & (S_ - 1); t >>= 11;
    int h = t & 15;
    int b = t >> 4;
    ao2[(size_t)(b * S_ + s) * DMODEL + h * DH + d] = ao[idx];
}

// ---------------- launch ----------------
extern "C" void kernel_launch(void* const* d_in, const int* in_sizes, int n_in,
                              void* d_out, int out_size)
{
    const float* x     = (const float*)d_in[0];
    const float* W_dq  = (const float*)d_in[1];
    const float* W_uq  = (const float*)d_in[2];
    const float* W_qr  = (const float*)d_in[3];
    const float* W_dkv = (const float*)d_in[4];
    const float* W_ukv = (const float*)d_in[5];
    const float* W_kr  = (const float*)d_in[6];
    const float* W_o   = (const float*)d_in[7];
    const float* q_w   = (const float*)d_in[8];
    const float* q_b   = (const float*)d_in[9];
    const float* kv_w  = (const float*)d_in[10];
    const float* kv_b  = (const float*)d_in[11];

    float* out = (float*)d_out;
    float* ckv = out + (size_t)BS * DMODEL;   // second output region

    float *cq, *qn, *qr, *kv, *kr, *q, *k, *v, *sc, *ao, *ao2;
    cudaGetSymbolAddress((void**)&cq,  g_cq);
    cudaGetSymbolAddress((void**)&qn,  g_qn);
    cudaGetSymbolAddress((void**)&qr,  g_qr);
    cudaGetSymbolAddress((void**)&kv,  g_kv);
    cudaGetSymbolAddress((void**)&kr,  g_kr);
    cudaGetSymbolAddress((void**)&q,   g_q);
    cudaGetSymbolAddress((void**)&k,   g_k);
    cudaGetSymbolAddress((void**)&v,   g_v);
    cudaGetSymbolAddress((void**)&sc,  g_sc);
    cudaGetSymbolAddress((void**)&ao,  g_ao);
    cudaGetSymbolAddress((void**)&ao2, g_ao2);

    // --- Q path ---
    sgemm_kernel<false><<<dim3(QPROJ/128, BS/128), 256>>>(x, W_dq, cq, BS, QPROJ, DMODEL, 0, 0, 0, 0);
    layernorm_kernel<<<BS, 256>>>(cq, q_w, q_b, QPROJ);
    sgemm_kernel<false><<<dim3(KNOPE/128, BS/128), 256>>>(cq, W_uq, qn, BS, KNOPE, QPROJ, 0, 0, 0, 0);
    sgemm_kernel<false><<<dim3(2, BS/128), 256>>>(cq, W_qr, qr, BS, 256, QPROJ, 0, 0, 0, 0);

    // --- KV path (ckv written straight into output region) ---
    sgemm_kernel<false><<<dim3((KVPROJ + 127)/128, BS/128), 256>>>(x, W_dkv, ckv, BS, KVPROJ, DMODEL, 0, 0, 0, 0);
    layernorm_kernel<<<BS, 256>>>(ckv, kv_w, kv_b, KVPROJ);
    sgemm_kernel<false><<<dim3(KVCOLS/128, BS/128), 256>>>(ckv, W_ukv, kv, BS, KVCOLS, KVPROJ, 0, 0, 0, 0);
    sgemm_kernel<false><<<dim3(2, BS/128), 256>>>(x, W_kr, kr, BS, 256, DMODEL, 0, 0, 0, 0);

    // --- gather heads + RoPE ---
    int nel = B_ * NH * S_ * DH;
    build_qkv<<<(nel + 255)/256, 256>>>(qn, qr, kv, kr, q, k, v);

    // --- attention: scores = q @ k^T (batched over 32 (b,h)), causal skip ---
    sgemm_kernel<true><<<dim3(S_/128, S_/128, B_*NH), 256>>>(
        q, k, sc, S_, S_, DH,
        (size_t)S_*DH, (size_t)S_*DH, (size_t)S_*S_, /*flags=*/1);

    softmax_kernel<<<B_*NH*S_, 256>>>(sc);

    // --- out = attn @ v (triangular A limits K) ---
    sgemm_kernel<false><<<dim3(1, S_/128, B_*NH), 256>>>(
        sc, v, ao, S_, DH, S_,
        (size_t)S_*S_, (size_t)S_*DH, (size_t)S_*DH, /*flags=*/2);

    permute_ao<<<(nel + 255)/256, 256>>>(ao, ao2);

    // --- final projection: out = ao2 @ W_o^T ---
    sgemm_kernel<true><<<dim3(DMODEL/128, BS/128), 256>>>(
        ao2, W_o, out, BS, DMODEL, DMODEL, 0, 0, 0, 0);
}

// round 3
// speedup vs baseline: 3.8396x; 3.8396x over previous
#include <cuda_runtime.h>
#include <cuda_bf16.h>
#include <cstdint>
#include <math.h>

// ---------------- problem constants ----------------
#define B_      2
#define S_      2048
#define DMODEL  2048
#define NH      16
#define DH      128
#define NOPE    14
#define QPROJ   1024
#define KVPROJ  1365
#define KVPAD   1408          // round_up_64(1365)
#define KNOPE   1792
#define KVCOLS  3840
#define BS      (B_*S_)       // 4096
#define NZ      (B_*NH)       // 32

typedef __nv_bfloat16 bf16;

// ---------------- device scratch ----------------
__device__ bf16 g_xhi[(size_t)BS*DMODEL],   g_xlo[(size_t)BS*DMODEL];
__device__ bf16 g_wdqh[(size_t)QPROJ*DMODEL],  g_wdql[(size_t)QPROJ*DMODEL];
__device__ bf16 g_wuqh[(size_t)KNOPE*QPROJ],   g_wuql[(size_t)KNOPE*QPROJ];
__device__ bf16 g_wqrh[(size_t)256*QPROJ],     g_wqrl[(size_t)256*QPROJ];
__device__ bf16 g_wdkvh[(size_t)KVPAD*DMODEL], g_wdkvl[(size_t)KVPAD*DMODEL];
__device__ bf16 g_wukvh[(size_t)KVCOLS*KVPAD], g_wukvl[(size_t)KVCOLS*KVPAD];
__device__ bf16 g_wkrh[(size_t)256*DMODEL],    g_wkrl[(size_t)256*DMODEL];
__device__ bf16 g_woh[(size_t)DMODEL*DMODEL],  g_wol[(size_t)DMODEL*DMODEL];
__device__ float g_cq[(size_t)BS*QPROJ];
__device__ bf16 g_cqh[(size_t)BS*QPROJ],    g_cql[(size_t)BS*QPROJ];
__device__ bf16 g_ckvh[(size_t)BS*KVPAD],   g_ckvl[(size_t)BS*KVPAD];
__device__ float g_qn[(size_t)BS*KNOPE];
__device__ float g_qrf[(size_t)BS*256];
__device__ float g_kvf[(size_t)BS*KVCOLS];
__device__ float g_krf[(size_t)BS*256];
__device__ bf16 g_qh[(size_t)NZ*S_*DH], g_ql[(size_t)NZ*S_*DH];
__device__ bf16 g_kh[(size_t)NZ*S_*DH], g_kl[(size_t)NZ*S_*DH];
__device__ bf16 g_vth[(size_t)NZ*DH*S_], g_vtl[(size_t)NZ*DH*S_];
__device__ float g_sc[(size_t)NZ*S_*S_];
__device__ bf16 g_ph[(size_t)NZ*S_*S_], g_pl[(size_t)NZ*S_*S_];
__device__ float g_ao[(size_t)NZ*S_*DH];
__device__ bf16 g_aoh[(size_t)BS*DMODEL], g_aol[(size_t)BS*DMODEL];

// ---------------- helpers ----------------
__device__ __forceinline__ uint32_t smem_u32(const void* p) {
    uint32_t a;
    asm("{ .reg .u64 t; cvta.to.shared.u64 t, %1; cvt.u32.u64 %0, t; }" : "=r"(a) : "l"(p));
    return a;
}
__device__ __forceinline__ void cp16(uint32_t saddr, const void* g) {
    asm volatile("cp.async.cg.shared.global [%0], [%1], 16;" :: "r"(saddr), "l"(g) : "memory");
}
__device__ __forceinline__ void cp_commit() {
    asm volatile("cp.async.commit_group;" ::: "memory");
}
template<int N> __device__ __forceinline__ void cp_wait() {
    asm volatile("cp.async.wait_group %0;" :: "n"(N) : "memory");
}
__device__ __forceinline__ void ldm_x4(uint32_t addr, uint32_t* r) {
    asm volatile("ldmatrix.sync.aligned.m8n8.x4.shared.b16 {%0,%1,%2,%3}, [%4];"
        : "=r"(r[0]), "=r"(r[1]), "=r"(r[2]), "=r"(r[3]) : "r"(addr));
}
__device__ __forceinline__ void mma16816(float* d, const uint32_t* a, const uint32_t* b) {
    asm volatile("mma.sync.aligned.m16n8k16.row.col.f32.bf16.bf16.f32 "
        "{%0,%1,%2,%3}, {%4,%5,%6,%7}, {%8,%9}, {%0,%1,%2,%3};"
        : "+f"(d[0]), "+f"(d[1]), "+f"(d[2]), "+f"(d[3])
        : "r"(a[0]), "r"(a[1]), "r"(a[2]), "r"(a[3]), "r"(b[0]), "r"(b[1]));
}
__device__ __forceinline__ void split2(float v, bf16& h, bf16& l) {
    h = __float2bfloat16(v);
    l = __float2bfloat16(v - __bfloat162float(h));
}

// ---------------- HMMA NT GEMM: C[M,N] = A[M,K] @ B[N,K]^T ----------------
// A,B as bf16 hi/lo pairs. Kpad multiple of 32, padded regions zero-filled.
// flags bit0: causal block skip. bit1: triangular A (K limited to r0+128).
#define STAGE 32768
#define SMEM_GEMM (2*STAGE)

__global__ __launch_bounds__(256, 1)
void hmma_gemm(const bf16* __restrict__ Ahi, const bf16* __restrict__ Alo,
               const bf16* __restrict__ Bhi, const bf16* __restrict__ Blo,
               float* __restrict__ C,
               int N, int Kpad, int lda, int ldb, int ldc,
               size_t sA, size_t sB, size_t sC, int flags)
{
    extern __shared__ __align__(128) char smem[];
    int tid = threadIdx.x, lane = tid & 31, wid = tid >> 5;
    int z = blockIdx.z;
    int r0 = blockIdx.y * 128, c0 = blockIdx.x * 128;
    if ((flags & 1) && c0 >= r0 + 128) return;
    int Keff = (flags & 2) ? min(Kpad, r0 + 128) : Kpad;
    int tiles = Keff >> 5;

    const bf16* srcs[4];
    srcs[0] = Ahi + (size_t)z * sA + (size_t)r0 * lda;
    srcs[1] = Alo + (size_t)z * sA + (size_t)r0 * lda;
    srcs[2] = Bhi + (size_t)z * sB + (size_t)c0 * ldb;
    srcs[3] = Blo + (size_t)z * sB + (size_t)c0 * ldb;
    float* Cz = C + (size_t)z * sC;

    uint32_t sbase = smem_u32(smem);
    int wm = (wid >> 2) * 64, wn = (wid & 3) * 32;

    float acc[4][4][4];
#pragma unroll
    for (int i = 0; i < 4; i++)
#pragma unroll
        for (int j = 0; j < 4; j++)
#pragma unroll
            for (int v = 0; v < 4; v++) acc[i][j][v] = 0.f;

    auto load_stage = [&](int t) {
        int k0 = t << 5;
        uint32_t sb = sbase + (uint32_t)(t & 1) * STAGE;
#pragma unroll
        for (int tl = 0; tl < 4; tl++) {
            const bf16* src = srcs[tl] + k0;
            int ld = (tl < 2) ? lda : ldb;
            uint32_t toff = sb + tl * 8192;
#pragma unroll
            for (int q = 0; q < 2; q++) {
                int c = tid + q * 256;
                int row = c >> 2, ch = c & 3;
                const bf16* g = src + (size_t)row * ld + ch * 8;
                uint32_t sa = toff + row * 64 + (uint32_t)((ch ^ ((row >> 1) & 3)) << 4);
                cp16(sa, g);
            }
        }
        cp_commit();
    };

    auto compute_stage = [&](int s) {
        uint32_t sb = sbase + (uint32_t)s * STAGE;
#pragma unroll
        for (int kk = 0; kk < 32; kk += 16) {
            uint32_t bh[4][2], bl[4][2];
#pragma unroll
            for (int p = 0; p < 2; p++) {
                int rowB = wn + p * 16 + ((lane >> 4) << 3) + (lane & 7);
                int ch = (kk >> 3) + ((lane >> 3) & 1);
                uint32_t off = (uint32_t)rowB * 64 + (uint32_t)((ch ^ ((rowB >> 1) & 3)) << 4);
                uint32_t r[4];
                ldm_x4(sb + 16384 + off, r);
                bh[2 * p][0] = r[0]; bh[2 * p][1] = r[1];
                bh[2 * p + 1][0] = r[2]; bh[2 * p + 1][1] = r[3];
                ldm_x4(sb + 24576 + off, r);
                bl[2 * p][0] = r[0]; bl[2 * p][1] = r[1];
                bl[2 * p + 1][0] = r[2]; bl[2 * p + 1][1] = r[3];
            }
#pragma unroll
            for (int mt = 0; mt < 4; mt++) {
                int rowA = wm + mt * 16 + (lane & 15);
                int ch = (kk >> 3) + (lane >> 4);
                uint32_t off = (uint32_t)rowA * 64 + (uint32_t)((ch ^ ((rowA >> 1) & 3)) << 4);
                uint32_t ah[4], al[4];
                ldm_x4(sb + off, ah);
                ldm_x4(sb + 8192 + off, al);
#pragma unroll
                for (int nt = 0; nt < 4; nt++) {
                    mma16816(acc[mt][nt], ah, bh[nt]);
                    mma16816(acc[mt][nt], ah, bl[nt]);
                    mma16816(acc[mt][nt], al, bh[nt]);
                }
            }
        }
    };

    load_stage(0);
    for (int t = 0; t < tiles; t++) {
        if (t + 1 < tiles) { load_stage(t + 1); cp_wait<1>(); }
        else               { cp_wait<0>(); }
        __syncthreads();
        compute_stage(t & 1);
        __syncthreads();
    }

    // epilogue: fp32 store with N bounds check
#pragma unroll
    for (int mt = 0; mt < 4; mt++) {
#pragma unroll
        for (int nt = 0; nt < 4; nt++) {
            int r = r0 + wm + mt * 16 + (lane >> 2);
            int c = c0 + wn + nt * 8 + ((lane & 3) << 1);
            float* p0 = Cz + (size_t)r * ldc + c;
            float* p1 = p0 + 8 * ldc;
            if (c < N)     { p0[0] = acc[mt][nt][0]; p1[0] = acc[mt][nt][2]; }
            if (c + 1 < N) { p0[1] = acc[mt][nt][1]; p1[1] = acc[mt][nt][3]; }
        }
    }
}

// ---------------- elementwise kernels ----------------
__global__ __launch_bounds__(256)
void split_plain(const float* __restrict__ in, bf16* __restrict__ hi, bf16* __restrict__ lo,
                 int R, int C, int Cpad)
{
    size_t idx = (size_t)blockIdx.x * 256 + threadIdx.x;
    if (idx >= (size_t)R * Cpad) return;
    int c = (int)(idx % Cpad);
    size_t r = idx / Cpad;
    float v = (c < C) ? in[r * C + c] : 0.f;
    split2(v, hi[idx], lo[idx]);
}

__global__ __launch_bounds__(256)
void transpose_split(const float* __restrict__ in, bf16* __restrict__ hi, bf16* __restrict__ lo,
                     int K, int N, int Npad, int Kpad)
{
    __shared__ float t[32][33];
    int k0 = blockIdx.x * 32, n0 = blockIdx.y * 32;
    int tx = threadIdx.x, ty = threadIdx.y;
#pragma unroll
    for (int i = 0; i < 4; i++) {
        int k = k0 + ty + i * 8;
        float v = (k < K && n0 + tx < N) ? in[(size_t)k * N + n0 + tx] : 0.f;
        t[ty + i * 8][tx] = v;
    }
    __syncthreads();
#pragma unroll
    for (int i = 0; i < 4; i++) {
        int n = n0 + ty + i * 8, k = k0 + tx;
        if (n < Npad && k < Kpad) {
            size_t o = (size_t)n * Kpad + k;
            split2(t[tx][ty + i * 8], hi[o], lo[o]);
        }
    }
}

__global__ __launch_bounds__(256)
void layernorm_split(const float* __restrict__ X, float* __restrict__ outf,
                     bf16* __restrict__ hi, bf16* __restrict__ lo,
                     const float* __restrict__ w, const float* __restrict__ b,
                     int n, int npad)
{
    const float* p = X + (size_t)blockIdx.x * n;
    float s = 0.f, s2 = 0.f;
    for (int j = threadIdx.x; j < n; j += 256) {
        float v = p[j];
        s += v; s2 += v * v;
    }
    __shared__ float sh[20];
#pragma unroll
    for (int o = 16; o; o >>= 1) {
        s  += __shfl_down_sync(0xffffffffu, s,  o);
        s2 += __shfl_down_sync(0xffffffffu, s2, o);
    }
    int wd = threadIdx.x >> 5, ln = threadIdx.x & 31;
    if (!ln) { sh[wd] = s; sh[wd + 8] = s2; }
    __syncthreads();
    if (threadIdx.x == 0) {
        float ts = 0.f, ts2 = 0.f;
        for (int i = 0; i < 8; i++) { ts += sh[i]; ts2 += sh[i + 8]; }
        float mean = ts / n;
        float var = fmaxf(ts2 / n - mean * mean, 0.f);
        sh[16] = mean;
        sh[17] = rsqrtf(var + 1e-5f);
    }
    __syncthreads();
    float mean = sh[16], rstd = sh[17];
    float* of = outf ? outf + (size_t)blockIdx.x * n : nullptr;
    bf16* hh = hi + (size_t)blockIdx.x * npad;
    bf16* ll = lo + (size_t)blockIdx.x * npad;
    for (int j = threadIdx.x; j < npad; j += 256) {
        float v = 0.f;
        if (j < n) {
            v = (p[j] - mean) * rstd * w[j] + b[j];
            if (of) of[j] = v;
        }
        split2(v, hh[j], ll[j]);
    }
}

__global__ __launch_bounds__(256)
void softmax_split(const float* __restrict__ Sc, bf16* __restrict__ ph, bf16* __restrict__ pl)
{
    size_t rowi = blockIdx.x;
    int i = (int)(rowi & (S_ - 1));
    const float* p = Sc + rowi * S_;
    bf16* oh = ph + rowi * S_;
    bf16* ol = pl + rowi * S_;
    const float scale = 0.08838834764831845f;

    __shared__ float sh[12];
    float m = -1e30f;
    for (int j = threadIdx.x; j <= i; j += 256) m = fmaxf(m, p[j]);
#pragma unroll
    for (int o = 16; o; o >>= 1) m = fmaxf(m, __shfl_down_sync(0xffffffffu, m, o));
    int wd = threadIdx.x >> 5, ln = threadIdx.x & 31;
    if (!ln) sh[wd] = m;
    __syncthreads();
    if (threadIdx.x == 0) {
        float mm = sh[0];
        for (int q = 1; q < 8; q++) mm = fmaxf(mm, sh[q]);
        sh[8] = mm;
    }
    __syncthreads();
    m = sh[8] * scale;

    float sum = 0.f;
    for (int j = threadIdx.x; j <= i; j += 256) sum += __expf(p[j] * scale - m);
#pragma unroll
    for (int o = 16; o; o >>= 1) sum += __shfl_down_sync(0xffffffffu, sum, o);
    if (!ln) sh[wd] = sum;
    __syncthreads();
    if (threadIdx.x == 0) {
        float ts = 0.f;
        for (int q = 0; q < 8; q++) ts += sh[q];
        sh[9] = 1.f / ts;
    }
    __syncthreads();
    float inv = sh[9];
    for (int j = threadIdx.x; j <= i; j += 256) {
        float e = __expf(p[j] * scale - m) * inv;
        split2(e, oh[j], ol[j]);
    }
    int rowEnd = (i | 127) + 1;
    bf16 zero = __float2bfloat16(0.f);
    for (int j = i + 1 + threadIdx.x; j < rowEnd; j += 256) { oh[j] = zero; ol[j] = zero; }
}

__device__ __forceinline__ float rope_val(const float* __restrict__ base, int d, int s) {
    int dd = d & 63;
    float freq = 1.0f / powf(10000.0f, (float)dd * (1.0f / 64.0f));
    float ang = (float)s * freq;
    float sn, cs;
    sincosf(ang, &sn, &cs);
    float x = base[d];
    return (d < 64) ? x * cs - base[d + 64] * sn
                    : x * cs + base[d - 64] * sn;
}

__global__ __launch_bounds__(256)
void build_qk(const float* __restrict__ qn, const float* __restrict__ qr,
              const float* __restrict__ kv, const float* __restrict__ kr,
              bf16* __restrict__ qh, bf16* __restrict__ ql,
              bf16* __restrict__ kh, bf16* __restrict__ kl)
{
    size_t idx = (size_t)blockIdx.x * 256 + threadIdx.x;
    if (idx >= (size_t)NZ * S_ * DH) return;
    int d = (int)(idx & (DH - 1));
    size_t t = idx >> 7;
    int s = (int)(t & (S_ - 1)); t >>= 11;
    int h = (int)(t & 15);
    int b = (int)(t >> 4);
    size_t row = (size_t)(b * S_ + s);

    float qv, kvv;
    if (h < NOPE) {
        qv  = qn[row * KNOPE + h * DH + d];
        kvv = kv[row * KVCOLS + h * DH + d];
    } else {
        qv  = rope_val(qr + row * 256 + (h - NOPE) * DH, d, s);
        kvv = rope_val(kr + row * 256 + (h - NOPE) * DH, d, s);
    }
    split2(qv, qh[idx], ql[idx]);
    split2(kvv, kh[idx], kl[idx]);
}

__global__ void build_vt(const float* __restrict__ kvf, bf16* __restrict__ vth, bf16* __restrict__ vtl)
{
    __shared__ float t[32][33];
    int z = blockIdx.z, b = z >> 4, h = z & 15;
    int s0 = blockIdx.x * 32, d0 = blockIdx.y * 32;
    int tx = threadIdx.x, ty = threadIdx.y;
#pragma unroll
    for (int i = 0; i < 4; i++) {
        int s = s0 + ty + i * 8;
        t[ty + i * 8][tx] = kvf[(size_t)(b * S_ + s) * KVCOLS + KNOPE + h * DH + d0 + tx];
    }
    __syncthreads();
#pragma unroll
    for (int i = 0; i < 4; i++) {
        int d = d0 + ty + i * 8, s = s0 + tx;
        size_t o = ((size_t)z * DH + d) * S_ + s;
        split2(t[tx][ty + i * 8], vth[o], vtl[o]);
    }
}

__global__ __launch_bounds__(256)
void permute_split(const float* __restrict__ ao, bf16* __restrict__ hi, bf16* __restrict__ lo)
{
    size_t idx = (size_t)blockIdx.x * 256 + threadIdx.x;
    if (idx >= (size_t)NZ * S_ * DH) return;
    int d = (int)(idx & (DH - 1));
    size_t t = idx >> 7;
    int s = (int)(t & (S_ - 1)); t >>= 11;
    int h = (int)(t & 15);
    int b = (int)(t >> 4);
    size_t o = (size_t)(b * S_ + s) * DMODEL + h * DH + d;
    split2(ao[idx], hi[o], lo[o]);
}

// ---------------- launch ----------------
static inline void* sym(const void* s) { void* p; cudaGetSymbolAddress(&p, s); return p; }

extern "C" void kernel_launch(void* const* d_in, const int* in_sizes, int n_in,
                              void* d_out, int out_size)
{
    const float* x     = (const float*)d_in[0];
    const float* W_dq  = (const float*)d_in[1];
    const float* W_uq  = (const float*)d_in[2];
    const float* W_qr  = (const float*)d_in[3];
    const float* W_dkv = (const float*)d_in[4];
    const float* W_ukv = (const float*)d_in[5];
    const float* W_kr  = (const float*)d_in[6];
    const float* W_o   = (const float*)d_in[7];
    const float* q_w   = (const float*)d_in[8];
    const float* q_b   = (const float*)d_in[9];
    const float* kv_w  = (const float*)d_in[10];
    const float* kv_b  = (const float*)d_in[11];

    float* out = (float*)d_out;
    float* ckv = out + (size_t)BS * DMODEL;

    bf16 *xhi=(bf16*)sym(g_xhi), *xlo=(bf16*)sym(g_xlo);
    bf16 *wdqh=(bf16*)sym(g_wdqh), *wdql=(bf16*)sym(g_wdql);
    bf16 *wuqh=(bf16*)sym(g_wuqh), *wuql=(bf16*)sym(g_wuql);
    bf16 *wqrh=(bf16*)sym(g_wqrh), *wqrl=(bf16*)sym(g_wqrl);
    bf16 *wdkvh=(bf16*)sym(g_wdkvh), *wdkvl=(bf16*)sym(g_wdkvl);
    bf16 *wukvh=(bf16*)sym(g_wukvh), *wukvl=(bf16*)sym(g_wukvl);
    bf16 *wkrh=(bf16*)sym(g_wkrh), *wkrl=(bf16*)sym(g_wkrl);
    bf16 *woh=(bf16*)sym(g_woh), *wol=(bf16*)sym(g_wol);
    float *cq=(float*)sym(g_cq);
    bf16 *cqh=(bf16*)sym(g_cqh), *cql=(bf16*)sym(g_cql);
    bf16 *ckvh=(bf16*)sym(g_ckvh), *ckvl=(bf16*)sym(g_ckvl);
    float *qn=(float*)sym(g_qn), *qrf=(float*)sym(g_qrf);
    float *kvf=(float*)sym(g_kvf), *krf=(float*)sym(g_krf);
    bf16 *qh=(bf16*)sym(g_qh), *ql=(bf16*)sym(g_ql);
    bf16 *kh=(bf16*)sym(g_kh), *kl=(bf16*)sym(g_kl);
    bf16 *vth=(bf16*)sym(g_vth), *vtl=(bf16*)sym(g_vtl);
    float *sc=(float*)sym(g_sc);
    bf16 *ph=(bf16*)sym(g_ph), *pl=(bf16*)sym(g_pl);
    float *ao=(float*)sym(g_ao);
    bf16 *aoh=(bf16*)sym(g_aoh), *aol=(bf16*)sym(g_aol);

    cudaFuncSetAttribute(hmma_gemm, cudaFuncAttributeMaxDynamicSharedMemorySize, SMEM_GEMM);

    // --- input conversions ---
    split_plain<<<(unsigned)(((size_t)BS*DMODEL + 255)/256), 256>>>(x, xhi, xlo, BS, DMODEL, DMODEL);
    split_plain<<<(unsigned)(((size_t)DMODEL*DMODEL + 255)/256), 256>>>(W_o, woh, wol, DMODEL, DMODEL, DMODEL);
    transpose_split<<<dim3(DMODEL/32, QPROJ/32),  dim3(32,8)>>>(W_dq,  wdqh,  wdql,  DMODEL, QPROJ,  QPROJ,  DMODEL);
    transpose_split<<<dim3(QPROJ/32,  KNOPE/32),  dim3(32,8)>>>(W_uq,  wuqh,  wuql,  QPROJ,  KNOPE,  KNOPE,  QPROJ);
    transpose_split<<<dim3(QPROJ/32,  256/32),    dim3(32,8)>>>(W_qr,  wqrh,  wqrl,  QPROJ,  256,    256,    QPROJ);
    transpose_split<<<dim3(DMODEL/32, KVPAD/32),  dim3(32,8)>>>(W_dkv, wdkvh, wdkvl, DMODEL, KVPROJ, KVPAD,  DMODEL);
    transpose_split<<<dim3(KVPAD/32,  KVCOLS/32), dim3(32,8)>>>(W_ukv, wukvh, wukvl, KVPROJ, KVCOLS, KVCOLS, KVPAD);
    transpose_split<<<dim3(DMODEL/32, 256/32),    dim3(32,8)>>>(W_kr,  wkrh,  wkrl,  DMODEL, 256,    256,    DMODEL);

    // --- Q path ---
    hmma_gemm<<<dim3(QPROJ/128, BS/128), 256, SMEM_GEMM>>>(
        xhi, xlo, wdqh, wdql, cq, QPROJ, DMODEL, DMODEL, DMODEL, QPROJ, 0, 0, 0, 0);
    layernorm_split<<<BS, 256>>>(cq, nullptr, cqh, cql, q_w, q_b, QPROJ, QPROJ);
    hmma_gemm<<<dim3(KNOPE/128, BS/128), 256, SMEM_GEMM>>>(
        cqh, cql, wuqh, wuql, qn, KNOPE, QPROJ, QPROJ, QPROJ, KNOPE, 0, 0, 0, 0);
    hmma_gemm<<<dim3(2, BS/128), 256, SMEM_GEMM>>>(
        cqh, cql, wqrh, wqrl, qrf, 256, QPROJ, QPROJ, QPROJ, 256, 0, 0, 0, 0);

    // --- KV path ---
    hmma_gemm<<<dim3((KVPROJ+127)/128, BS/128), 256, SMEM_GEMM>>>(
        xhi, xlo, wdkvh, wdkvl, ckv, KVPROJ, DMODEL, DMODEL, DMODEL, KVPROJ, 0, 0, 0, 0);
    layernorm_split<<<BS, 256>>>(ckv, ckv, ckvh, ckvl, kv_w, kv_b, KVPROJ, KVPAD);
    hmma_gemm<<<dim3(KVCOLS/128, BS/128), 256, SMEM_GEMM>>>(
        ckvh, ckvl, wukvh, wukvl, kvf, KVCOLS, KVPAD, KVPAD, KVPAD, KVCOLS, 0, 0, 0, 0);
    hmma_gemm<<<dim3(2, BS/128), 256, SMEM_GEMM>>>(
        xhi, xlo, wkrh, wkrl, krf, 256, DMODEL, DMODEL, DMODEL, 256, 0, 0, 0, 0);

    // --- heads + RoPE ---
    size_t nel = (size_t)NZ * S_ * DH;
    build_qk<<<(unsigned)((nel + 255)/256), 256>>>(qn, qrf, kvf, krf, qh, ql, kh, kl);
    build_vt<<<dim3(S_/32, DH/32, NZ), dim3(32,8)>>>(kvf, vth, vtl);

    // --- attention scores (causal block skip) ---
    hmma_gemm<<<dim3(S_/128, S_/128, NZ), 256, SMEM_GEMM>>>(
        qh, ql, kh, kl, sc, S_, DH, DH, DH, S_,
        (size_t)S_*DH, (size_t)S_*DH, (size_t)S_*S_, 1);

    softmax_split<<<NZ*S_, 256>>>(sc, ph, pl);

    // --- out = P @ V (triangular K) ---
    hmma_gemm<<<dim3(1, S_/128, NZ), 256, SMEM_GEMM>>>(
        ph, pl, vth, vtl, ao, DH, S_, S_, S_, DH,
        (size_t)S_*S_, (size_t)DH*S_, (size_t)S_*DH, 2);

    permute_split<<<(unsigned)((nel + 255)/256), 256>>>(ao, aoh, aol);

    // --- final projection ---
    hmma_gemm<<<dim3(DMODEL/128, BS/128), 256, SMEM_GEMM>>>(
        aoh, aol, woh, wol, out, DMODEL, DMODEL, DMODEL, DMODEL, DMODEL, 0, 0, 0, 0);
}

// round 4
// speedup vs baseline: 4.4879x; 1.1689x over previous
#include <cuda_runtime.h>
#include <cuda_bf16.h>
#include <cstdint>
#include <math.h>

// ---------------- problem constants ----------------
#define B_      2
#define S_      2048
#define DMODEL  2048
#define NH      16
#define DH      128
#define NOPE    14
#define QPROJ   1024
#define KVPROJ  1365
#define KVPAD   1408
#define KNOPE   1792
#define KVCOLS  3840
#define BS      (B_*S_)
#define NZ      (B_*NH)

typedef __nv_bfloat16 bf16;

// ---------------- device scratch ----------------
__device__ bf16 g_xhi[(size_t)BS*DMODEL],   g_xlo[(size_t)BS*DMODEL];
__device__ bf16 g_wdqh[(size_t)QPROJ*DMODEL],  g_wdql[(size_t)QPROJ*DMODEL];
__device__ bf16 g_wuqh[(size_t)KNOPE*QPROJ],   g_wuql[(size_t)KNOPE*QPROJ];
__device__ bf16 g_wqrh[(size_t)256*QPROJ],     g_wqrl[(size_t)256*QPROJ];
__device__ bf16 g_wdkvh[(size_t)KVPAD*DMODEL], g_wdkvl[(size_t)KVPAD*DMODEL];
__device__ bf16 g_wukvh[(size_t)KVCOLS*KVPAD], g_wukvl[(size_t)KVCOLS*KVPAD];
__device__ bf16 g_wkrh[(size_t)256*DMODEL],    g_wkrl[(size_t)256*DMODEL];
__device__ bf16 g_woh[(size_t)DMODEL*DMODEL],  g_wol[(size_t)DMODEL*DMODEL];
__device__ float g_cq[(size_t)BS*QPROJ];
__device__ bf16 g_cqh[(size_t)BS*QPROJ],    g_cql[(size_t)BS*QPROJ];
__device__ bf16 g_ckvh[(size_t)BS*KVPAD],   g_ckvl[(size_t)BS*KVPAD];
__device__ float g_qn[(size_t)BS*KNOPE];
__device__ float g_qrf[(size_t)BS*256];
__device__ float g_kvf[(size_t)BS*KVCOLS];
__device__ float g_krf[(size_t)BS*256];
__device__ bf16 g_qh[(size_t)NZ*S_*DH], g_ql[(size_t)NZ*S_*DH];
__device__ bf16 g_kh[(size_t)NZ*S_*DH], g_kl[(size_t)NZ*S_*DH];
__device__ bf16 g_vth[(size_t)NZ*DH*S_], g_vtl[(size_t)NZ*DH*S_];
__device__ bf16 g_aoh[(size_t)BS*DMODEL], g_aol[(size_t)BS*DMODEL];

// ---------------- helpers ----------------
__device__ __forceinline__ uint32_t smem_u32(const void* p) {
    uint32_t a;
    asm("{ .reg .u64 t; cvta.to.shared.u64 t, %1; cvt.u32.u64 %0, t; }" : "=r"(a) : "l"(p));
    return a;
}
__device__ __forceinline__ void cp16(uint32_t saddr, const void* g) {
    asm volatile("cp.async.cg.shared.global [%0], [%1], 16;" :: "r"(saddr), "l"(g) : "memory");
}
__device__ __forceinline__ void cp_commit() {
    asm volatile("cp.async.commit_group;" ::: "memory");
}
template<int N> __device__ __forceinline__ void cp_wait() {
    asm volatile("cp.async.wait_group %0;" :: "n"(N) : "memory");
}
__device__ __forceinline__ void ldm_x4(uint32_t addr, uint32_t* r) {
    asm volatile("ldmatrix.sync.aligned.m8n8.x4.shared.b16 {%0,%1,%2,%3}, [%4];"
        : "=r"(r[0]), "=r"(r[1]), "=r"(r[2]), "=r"(r[3]) : "r"(addr));
}
__device__ __forceinline__ void mma16816(float* d, const uint32_t* a, const uint32_t* b) {
    asm volatile("mma.sync.aligned.m16n8k16.row.col.f32.bf16.bf16.f32 "
        "{%0,%1,%2,%3}, {%4,%5,%6,%7}, {%8,%9}, {%0,%1,%2,%3};"
        : "+f"(d[0]), "+f"(d[1]), "+f"(d[2]), "+f"(d[3])
        : "r"(a[0]), "r"(a[1]), "r"(a[2]), "r"(a[3]), "r"(b[0]), "r"(b[1]));
}
__device__ __forceinline__ void split2(float v, bf16& h, bf16& l) {
    h = __float2bfloat16(v);
    l = __float2bfloat16(v - __bfloat162float(h));
}
__device__ __forceinline__ uint32_t pack_bf2(float a, float b) {
    __nv_bfloat162 t = __floats2bfloat162_rn(a, b);
    return *(uint32_t*)&t;
}

// ---------------- HMMA NT GEMM (projections): C = A @ B^T ----------------
#define STAGE 32768
#define SMEM_GEMM (2*STAGE)

__global__ __launch_bounds__(256, 1)
void hmma_gemm(const bf16* __restrict__ Ahi, const bf16* __restrict__ Alo,
               const bf16* __restrict__ Bhi, const bf16* __restrict__ Blo,
               float* __restrict__ C,
               int N, int Kpad, int lda, int ldb, int ldc)
{
    extern __shared__ __align__(128) char smem[];
    int tid = threadIdx.x, lane = tid & 31, wid = tid >> 5;
    int r0 = blockIdx.y * 128, c0 = blockIdx.x * 128;
    int tiles = Kpad >> 5;

    const bf16* srcs[4];
    srcs[0] = Ahi + (size_t)r0 * lda;
    srcs[1] = Alo + (size_t)r0 * lda;
    srcs[2] = Bhi + (size_t)c0 * ldb;
    srcs[3] = Blo + (size_t)c0 * ldb;

    uint32_t sbase = smem_u32(smem);
    int wm = (wid >> 2) * 64, wn = (wid & 3) * 32;

    float acc[4][4][4];
#pragma unroll
    for (int i = 0; i < 4; i++)
#pragma unroll
        for (int j = 0; j < 4; j++)
#pragma unroll
            for (int v = 0; v < 4; v++) acc[i][j][v] = 0.f;

    auto load_stage = [&](int t) {
        int k0 = t << 5;
        uint32_t sb = sbase + (uint32_t)(t & 1) * STAGE;
#pragma unroll
        for (int tl = 0; tl < 4; tl++) {
            const bf16* src = srcs[tl] + k0;
            int ld = (tl < 2) ? lda : ldb;
            uint32_t toff = sb + tl * 8192;
#pragma unroll
            for (int q = 0; q < 2; q++) {
                int c = tid + q * 256;
                int row = c >> 2, ch = c & 3;
                cp16(toff + row * 64 + (uint32_t)((ch ^ ((row >> 1) & 3)) << 4),
                     src + (size_t)row * ld + ch * 8);
            }
        }
        cp_commit();
    };

    auto compute_stage = [&](int s) {
        uint32_t sb = sbase + (uint32_t)s * STAGE;
#pragma unroll
        for (int kk = 0; kk < 32; kk += 16) {
            uint32_t bh[4][2], bl[4][2];
#pragma unroll
            for (int p = 0; p < 2; p++) {
                int rowB = wn + p * 16 + ((lane >> 4) << 3) + (lane & 7);
                int ch = (kk >> 3) + ((lane >> 3) & 1);
                uint32_t off = (uint32_t)rowB * 64 + (uint32_t)((ch ^ ((rowB >> 1) & 3)) << 4);
                uint32_t r[4];
                ldm_x4(sb + 16384 + off, r);
                bh[2 * p][0] = r[0]; bh[2 * p][1] = r[1];
                bh[2 * p + 1][0] = r[2]; bh[2 * p + 1][1] = r[3];
                ldm_x4(sb + 24576 + off, r);
                bl[2 * p][0] = r[0]; bl[2 * p][1] = r[1];
                bl[2 * p + 1][0] = r[2]; bl[2 * p + 1][1] = r[3];
            }
#pragma unroll
            for (int mt = 0; mt < 4; mt++) {
                int rowA = wm + mt * 16 + (lane & 15);
                int ch = (kk >> 3) + (lane >> 4);
                uint32_t off = (uint32_t)rowA * 64 + (uint32_t)((ch ^ ((rowA >> 1) & 3)) << 4);
                uint32_t ah[4], al[4];
                ldm_x4(sb + off, ah);
                ldm_x4(sb + 8192 + off, al);
#pragma unroll
                for (int nt = 0; nt < 4; nt++) {
                    mma16816(acc[mt][nt], ah, bh[nt]);
                    mma16816(acc[mt][nt], ah, bl[nt]);
                    mma16816(acc[mt][nt], al, bh[nt]);
                }
            }
        }
    };

    load_stage(0);
    for (int t = 0; t < tiles; t++) {
        if (t + 1 < tiles) { load_stage(t + 1); cp_wait<1>(); }
        else               { cp_wait<0>(); }
        __syncthreads();
        compute_stage(t & 1);
        __syncthreads();
    }

#pragma unroll
    for (int mt = 0; mt < 4; mt++) {
#pragma unroll
        for (int nt = 0; nt < 4; nt++) {
            int r = r0 + wm + mt * 16 + (lane >> 2);
            int c = c0 + wn + nt * 8 + ((lane & 3) << 1);
            float* p0 = C + (size_t)r * ldc + c;
            float* p1 = p0 + 8 * ldc;
            if (c < N)     { p0[0] = acc[mt][nt][0]; p1[0] = acc[mt][nt][2]; }
            if (c + 1 < N) { p0[1] = acc[mt][nt][1]; p1[1] = acc[mt][nt][3]; }
        }
    }
}

// ---------------- fused flash attention ----------------
// grid (S_/128, NZ); CTA = 128 q-rows of head z; 8 warps x 16 rows.
// Q kept in registers; K/V tiles (64 keys) double-buffered in smem.
// Writes output directly to (B,S,H*DH) bf16 hi/lo.
#define FQB 65536                  // Q staging: hi 32K + lo 32K
#define FST 65536                  // stage: Khi 16K, Klo 16K, Vthi 16K, Vtlo 16K
#define SMEM_FLASH (FQB + 2*FST)   // 192 KB

__global__ __launch_bounds__(256, 1)
void flash_attn(const bf16* __restrict__ qh_, const bf16* __restrict__ ql_,
                const bf16* __restrict__ kh_, const bf16* __restrict__ kl_,
                const bf16* __restrict__ vth_, const bf16* __restrict__ vtl_,
                bf16* __restrict__ aoh, bf16* __restrict__ aol)
{
    extern __shared__ __align__(128) char smem[];
    int tid = threadIdx.x, lane = tid & 31, wid = tid >> 5;
    int z = blockIdx.y, bb = z >> 4, hh = z & 15;
    int r0 = ((int)gridDim.x - 1 - (int)blockIdx.x) * 128;   // big blocks first

    const bf16* qhz = qh_ + (size_t)z * S_ * DH + (size_t)r0 * DH;
    const bf16* qlz = ql_ + (size_t)z * S_ * DH + (size_t)r0 * DH;
    const bf16* khz = kh_ + (size_t)z * S_ * DH;
    const bf16* klz = kl_ + (size_t)z * S_ * DH;
    const bf16* vthz = vth_ + (size_t)z * DH * S_;
    const bf16* vtlz = vtl_ + (size_t)z * DH * S_;

    uint32_t sb = smem_u32(smem);

    // stage Q (128 x 128 bf16, hi+lo), 256B rows, 16 chunks, xor-swizzled
#pragma unroll
    for (int q = 0; q < 8; q++) {
        int idx = tid + q * 256;
        int row = idx >> 4, ch = idx & 15;
        uint32_t off = (uint32_t)row * 256 + (uint32_t)((ch ^ (row & 7)) << 4);
        cp16(sb + off,         qhz + (size_t)row * DH + ch * 8);
        cp16(sb + 32768 + off, qlz + (size_t)row * DH + ch * 8);
    }
    cp_commit();

    int ntiles = (r0 >> 6) + 2;
    int diag = r0 >> 6;

    auto load_stage = [&](int jt) {
        uint32_t st = sb + FQB + (uint32_t)(jt & 1) * FST;
        int s0 = jt * 64;
#pragma unroll
        for (int q = 0; q < 4; q++) {            // K: 64 rows x 16 chunks
            int idx = tid + q * 256;
            int row = idx >> 4, ch = idx & 15;
            uint32_t off = (uint32_t)row * 256 + (uint32_t)((ch ^ (row & 7)) << 4);
            cp16(st + off,         khz + (size_t)(s0 + row) * DH + ch * 8);
            cp16(st + 16384 + off, klz + (size_t)(s0 + row) * DH + ch * 8);
        }
#pragma unroll
        for (int q = 0; q < 4; q++) {            // Vt: 128 rows x 8 chunks
            int idx = tid + q * 256;
            int row = idx >> 3, ch = idx & 7;
            uint32_t off = (uint32_t)row * 128 + (uint32_t)((ch ^ (row & 7)) << 4);
            cp16(st + 32768 + off, vthz + (size_t)row * S_ + s0 + ch * 8);
            cp16(st + 49152 + off, vtlz + (size_t)row * S_ + s0 + ch * 8);
        }
        cp_commit();
    };

    load_stage(0);
    cp_wait<1>();          // Q complete
    __syncthreads();

    // Q fragments (held across whole loop)
    int wrow = wid * 16;
    uint32_t qah[8][4], qal[8][4];
#pragma unroll
    for (int kf = 0; kf < 8; kf++) {
        int row = wrow + (lane & 15);
        int ch = kf * 2 + (lane >> 4);
        uint32_t off = (uint32_t)row * 256 + (uint32_t)((ch ^ (row & 7)) << 4);
        ldm_x4(sb + off, qah[kf]);
        ldm_x4(sb + 32768 + off, qal[kf]);
    }

    float of[16][4];
#pragma unroll
    for (int i = 0; i < 16; i++)
#pragma unroll
        for (int v = 0; v < 4; v++) of[i][v] = 0.f;
    float m0 = -1e30f, m1 = -1e30f, l0 = 0.f, l1 = 0.f;
    const float CEXP = 0.08838834764831845f * 1.4426950408889634f;  // scale*log2(e)

    int rowa = r0 + wrow + (lane >> 2);

    for (int jt = 0; jt < ntiles; jt++) {
        if (jt + 1 < ntiles) { load_stage(jt + 1); cp_wait<1>(); }
        else                 { cp_wait<0>(); }
        __syncthreads();
        uint32_t st = sb + FQB + (uint32_t)(jt & 1) * FST;

        // ---- S = Q @ K^T (16 x 64 per warp) ----
        float sf[8][4];
#pragma unroll
        for (int nf = 0; nf < 8; nf++)
#pragma unroll
            for (int v = 0; v < 4; v++) sf[nf][v] = 0.f;

#pragma unroll
        for (int kf = 0; kf < 8; kf++) {
            uint32_t bh[8][2], bl[8][2];
#pragma unroll
            for (int p = 0; p < 4; p++) {
                int rowB = p * 16 + ((lane >> 4) << 3) + (lane & 7);
                int ch = kf * 2 + ((lane >> 3) & 1);
                uint32_t off = (uint32_t)rowB * 256 + (uint32_t)((ch ^ (rowB & 7)) << 4);
                uint32_t r4[4];
                ldm_x4(st + off, r4);
                bh[2 * p][0] = r4[0]; bh[2 * p][1] = r4[1];
                bh[2 * p + 1][0] = r4[2]; bh[2 * p + 1][1] = r4[3];
                ldm_x4(st + 16384 + off, r4);
                bl[2 * p][0] = r4[0]; bl[2 * p][1] = r4[1];
                bl[2 * p + 1][0] = r4[2]; bl[2 * p + 1][1] = r4[3];
            }
#pragma unroll
            for (int nf = 0; nf < 8; nf++) {
                mma16816(sf[nf], qah[kf], bh[nf]);
                mma16816(sf[nf], qah[kf], bl[nf]);
                mma16816(sf[nf], qal[kf], bh[nf]);
            }
        }

        // ---- causal mask on diagonal tiles ----
        if (jt >= diag) {
            int colb = jt * 64 + 2 * (lane & 3);
#pragma unroll
            for (int nf = 0; nf < 8; nf++) {
                int c = colb + nf * 8;
                if (c > rowa)     sf[nf][0] = -1e30f;
                if (c + 1 > rowa) sf[nf][1] = -1e30f;
                if (c > rowa + 8)     sf[nf][2] = -1e30f;
                if (c + 1 > rowa + 8) sf[nf][3] = -1e30f;
            }
        }

        // ---- online softmax ----
        float tm0 = -1e30f, tm1 = -1e30f;
#pragma unroll
        for (int nf = 0; nf < 8; nf++) {
            tm0 = fmaxf(tm0, fmaxf(sf[nf][0], sf[nf][1]));
            tm1 = fmaxf(tm1, fmaxf(sf[nf][2], sf[nf][3]));
        }
        tm0 = fmaxf(tm0, __shfl_xor_sync(0xffffffffu, tm0, 1));
        tm0 = fmaxf(tm0, __shfl_xor_sync(0xffffffffu, tm0, 2));
        tm1 = fmaxf(tm1, __shfl_xor_sync(0xffffffffu, tm1, 1));
        tm1 = fmaxf(tm1, __shfl_xor_sync(0xffffffffu, tm1, 2));
        float mn0 = fmaxf(m0, tm0), mn1 = fmaxf(m1, tm1);
        float al0 = exp2f((m0 - mn0) * CEXP), al1 = exp2f((m1 - mn1) * CEXP);
        m0 = mn0; m1 = mn1;

        uint32_t pah[4][4], pal[4][4];
        float rs0 = 0.f, rs1 = 0.f;
#pragma unroll
        for (int nf = 0; nf < 8; nf++) {
            float e0 = exp2f((sf[nf][0] - m0) * CEXP);
            float e1 = exp2f((sf[nf][1] - m0) * CEXP);
            float e2 = exp2f((sf[nf][2] - m1) * CEXP);
            float e3 = exp2f((sf[nf][3] - m1) * CEXP);
            rs0 += e0 + e1; rs1 += e2 + e3;
            float h0 = __bfloat162float(__float2bfloat16(e0));
            float h1 = __bfloat162float(__float2bfloat16(e1));
            float h2 = __bfloat162float(__float2bfloat16(e2));
            float h3 = __bfloat162float(__float2bfloat16(e3));
            int kf2 = nf >> 1, s = (nf & 1) * 2;
            pah[kf2][s]     = pack_bf2(h0, h1);
            pah[kf2][s + 1] = pack_bf2(h2, h3);
            pal[kf2][s]     = pack_bf2(e0 - h0, e1 - h1);
            pal[kf2][s + 1] = pack_bf2(e2 - h2, e3 - h3);
        }
        l0 = l0 * al0 + rs0;
        l1 = l1 * al1 + rs1;

#pragma unroll
        for (int i = 0; i < 16; i++) {
            of[i][0] *= al0; of[i][1] *= al0;
            of[i][2] *= al1; of[i][3] *= al1;
        }

        // ---- O += P @ V ----
#pragma unroll
        for (int kf2 = 0; kf2 < 4; kf2++) {
#pragma unroll
            for (int p2 = 0; p2 < 8; p2++) {
                int rowB = p2 * 16 + ((lane >> 4) << 3) + (lane & 7);
                int ch = kf2 * 2 + ((lane >> 3) & 1);
                uint32_t off = (uint32_t)rowB * 128 + (uint32_t)((ch ^ (rowB & 7)) << 4);
                uint32_t rh[4], rl[4];
                ldm_x4(st + 32768 + off, rh);
                ldm_x4(st + 49152 + off, rl);
                uint32_t bh0[2] = {rh[0], rh[1]}, bh1[2] = {rh[2], rh[3]};
                uint32_t bl0[2] = {rl[0], rl[1]}, bl1[2] = {rl[2], rl[3]};
                mma16816(of[2 * p2],     pah[kf2], bh0);
                mma16816(of[2 * p2],     pah[kf2], bl0);
                mma16816(of[2 * p2],     pal[kf2], bh0);
                mma16816(of[2 * p2 + 1], pah[kf2], bh1);
                mma16816(of[2 * p2 + 1], pah[kf2], bl1);
                mma16816(of[2 * p2 + 1], pal[kf2], bh1);
            }
        }
        __syncthreads();
    }

    // full row sums across the 4 threads per row
    l0 += __shfl_xor_sync(0xffffffffu, l0, 1);
    l0 += __shfl_xor_sync(0xffffffffu, l0, 2);
    l1 += __shfl_xor_sync(0xffffffffu, l1, 1);
    l1 += __shfl_xor_sync(0xffffffffu, l1, 2);
    float inv0 = 1.f / l0, inv1 = 1.f / l1;

    size_t ga = ((size_t)(bb * S_) + rowa) * DMODEL + hh * DH;
    size_t gb = ga + (size_t)8 * DMODEL;
#pragma unroll
    for (int i = 0; i < 16; i++) {
        int d = i * 8 + 2 * (lane & 3);
        float v0 = of[i][0] * inv0, v1 = of[i][1] * inv0;
        float v2 = of[i][2] * inv1, v3 = of[i][3] * inv1;
        float h0 = __bfloat162float(__float2bfloat16(v0));
        float h1 = __bfloat162float(__float2bfloat16(v1));
        float h2 = __bfloat162float(__float2bfloat16(v2));
        float h3 = __bfloat162float(__float2bfloat16(v3));
        *(uint32_t*)(aoh + ga + d) = pack_bf2(h0, h1);
        *(uint32_t*)(aoh + gb + d) = pack_bf2(h2, h3);
        *(uint32_t*)(aol + ga + d) = pack_bf2(v0 - h0, v1 - h1);
        *(uint32_t*)(aol + gb + d) = pack_bf2(v2 - h2, v3 - h3);
    }
}

// ---------------- elementwise kernels ----------------
__global__ __launch_bounds__(256)
void split_plain(const float* __restrict__ in, bf16* __restrict__ hi, bf16* __restrict__ lo,
                 int R, int C, int Cpad)
{
    size_t idx = (size_t)blockIdx.x * 256 + threadIdx.x;
    if (idx >= (size_t)R * Cpad) return;
    int c = (int)(idx % Cpad);
    size_t r = idx / Cpad;
    float v = (c < C) ? in[r * C + c] : 0.f;
    split2(v, hi[idx], lo[idx]);
}

__global__ __launch_bounds__(256)
void transpose_split(const float* __restrict__ in, bf16* __restrict__ hi, bf16* __restrict__ lo,
                     int K, int N, int Npad, int Kpad)
{
    __shared__ float t[32][33];
    int k0 = blockIdx.x * 32, n0 = blockIdx.y * 32;
    int tx = threadIdx.x, ty = threadIdx.y;
#pragma unroll
    for (int i = 0; i < 4; i++) {
        int k = k0 + ty + i * 8;
        float v = (k < K && n0 + tx < N) ? in[(size_t)k * N + n0 + tx] : 0.f;
        t[ty + i * 8][tx] = v;
    }
    __syncthreads();
#pragma unroll
    for (int i = 0; i < 4; i++) {
        int n = n0 + ty + i * 8, k = k0 + tx;
        if (n < Npad && k < Kpad) {
            size_t o = (size_t)n * Kpad + k;
            split2(t[tx][ty + i * 8], hi[o], lo[o]);
        }
    }
}

__global__ __launch_bounds__(256)
void layernorm_split(const float* __restrict__ X, float* __restrict__ outf,
                     bf16* __restrict__ hi, bf16* __restrict__ lo,
                     const float* __restrict__ w, const float* __restrict__ b,
                     int n, int npad)
{
    const float* p = X + (size_t)blockIdx.x * n;
    float s = 0.f, s2 = 0.f;
    for (int j = threadIdx.x; j < n; j += 256) {
        float v = p[j];
        s += v; s2 += v * v;
    }
    __shared__ float sh[20];
#pragma unroll
    for (int o = 16; o; o >>= 1) {
        s  += __shfl_down_sync(0xffffffffu, s,  o);
        s2 += __shfl_down_sync(0xffffffffu, s2, o);
    }
    int wd = threadIdx.x >> 5, ln = threadIdx.x & 31;
    if (!ln) { sh[wd] = s; sh[wd + 8] = s2; }
    __syncthreads();
    if (threadIdx.x == 0) {
        float ts = 0.f, ts2 = 0.f;
        for (int i = 0; i < 8; i++) { ts += sh[i]; ts2 += sh[i + 8]; }
        float mean = ts / n;
        float var = fmaxf(ts2 / n - mean * mean, 0.f);
        sh[16] = mean;
        sh[17] = rsqrtf(var + 1e-5f);
    }
    __syncthreads();
    float mean = sh[16], rstd = sh[17];
    float* of = outf ? outf + (size_t)blockIdx.x * n : nullptr;
    bf16* hh = hi + (size_t)blockIdx.x * npad;
    bf16* ll = lo + (size_t)blockIdx.x * npad;
    for (int j = threadIdx.x; j < npad; j += 256) {
        float v = 0.f;
        if (j < n) {
            v = (p[j] - mean) * rstd * w[j] + b[j];
            if (of) of[j] = v;
        }
        split2(v, hh[j], ll[j]);
    }
}

__device__ __forceinline__ float rope_val(const float* __restrict__ base, int d, int s) {
    int dd = d & 63;
    float freq = 1.0f / powf(10000.0f, (float)dd * (1.0f / 64.0f));
    float ang = (float)s * freq;
    float sn, cs;
    sincosf(ang, &sn, &cs);
    float x = base[d];
    return (d < 64) ? x * cs - base[d + 64] * sn
                    : x * cs + base[d - 64] * sn;
}

__global__ __launch_bounds__(256)
void build_qk(const float* __restrict__ qn, const float* __restrict__ qr,
              const float* __restrict__ kv, const float* __restrict__ kr,
              bf16* __restrict__ qh, bf16* __restrict__ ql,
              bf16* __restrict__ kh, bf16* __restrict__ kl)
{
    size_t idx = (size_t)blockIdx.x * 256 + threadIdx.x;
    if (idx >= (size_t)NZ * S_ * DH) return;
    int d = (int)(idx & (DH - 1));
    size_t t = idx >> 7;
    int s = (int)(t & (S_ - 1)); t >>= 11;
    int h = (int)(t & 15);
    int b = (int)(t >> 4);
    size_t row = (size_t)(b * S_ + s);

    float qv, kvv;
    if (h < NOPE) {
        qv  = qn[row * KNOPE + h * DH + d];
        kvv = kv[row * KVCOLS + h * DH + d];
    } else {
        qv  = rope_val(qr + row * 256 + (h - NOPE) * DH, d, s);
        kvv = rope_val(kr + row * 256 + (h - NOPE) * DH, d, s);
    }
    split2(qv, qh[idx], ql[idx]);
    split2(kvv, kh[idx], kl[idx]);
}

__global__ void build_vt(const float* __restrict__ kvf, bf16* __restrict__ vth, bf16* __restrict__ vtl)
{
    __shared__ float t[32][33];
    int z = blockIdx.z, b = z >> 4, h = z & 15;
    int s0 = blockIdx.x * 32, d0 = blockIdx.y * 32;
    int tx = threadIdx.x, ty = threadIdx.y;
#pragma unroll
    for (int i = 0; i < 4; i++) {
        int s = s0 + ty + i * 8;
        t[ty + i * 8][tx] = kvf[(size_t)(b * S_ + s) * KVCOLS + KNOPE + h * DH + d0 + tx];
    }
    __syncthreads();
#pragma unroll
    for (int i = 0; i < 4; i++) {
        int d = d0 + ty + i * 8, s = s0 + tx;
        size_t o = ((size_t)z * DH + d) * S_ + s;
        split2(t[tx][ty + i * 8], vth[o], vtl[o]);
    }
}

// ---------------- launch ----------------
static inline void* sym(const void* s) { void* p; cudaGetSymbolAddress(&p, s); return p; }

extern "C" void kernel_launch(void* const* d_in, const int* in_sizes, int n_in,
                              void* d_out, int out_size)
{
    const float* x     = (const float*)d_in[0];
    const float* W_dq  = (const float*)d_in[1];
    const float* W_uq  = (const float*)d_in[2];
    const float* W_qr  = (const float*)d_in[3];
    const float* W_dkv = (const float*)d_in[4];
    const float* W_ukv = (const float*)d_in[5];
    const float* W_kr  = (const float*)d_in[6];
    const float* W_o   = (const float*)d_in[7];
    const float* q_w   = (const float*)d_in[8];
    const float* q_b   = (const float*)d_in[9];
    const float* kv_w  = (const float*)d_in[10];
    const float* kv_b  = (const float*)d_in[11];

    float* out = (float*)d_out;
    float* ckv = out + (size_t)BS * DMODEL;

    bf16 *xhi=(bf16*)sym(g_xhi), *xlo=(bf16*)sym(g_xlo);
    bf16 *wdqh=(bf16*)sym(g_wdqh), *wdql=(bf16*)sym(g_wdql);
    bf16 *wuqh=(bf16*)sym(g_wuqh), *wuql=(bf16*)sym(g_wuql);
    bf16 *wqrh=(bf16*)sym(g_wqrh), *wqrl=(bf16*)sym(g_wqrl);
    bf16 *wdkvh=(bf16*)sym(g_wdkvh), *wdkvl=(bf16*)sym(g_wdkvl);
    bf16 *wukvh=(bf16*)sym(g_wukvh), *wukvl=(bf16*)sym(g_wukvl);
    bf16 *wkrh=(bf16*)sym(g_wkrh), *wkrl=(bf16*)sym(g_wkrl);
    bf16 *woh=(bf16*)sym(g_woh), *wol=(bf16*)sym(g_wol);
    float *cq=(float*)sym(g_cq);
    bf16 *cqh=(bf16*)sym(g_cqh), *cql=(bf16*)sym(g_cql);
    bf16 *ckvh=(bf16*)sym(g_ckvh), *ckvl=(bf16*)sym(g_ckvl);
    float *qn=(float*)sym(g_qn), *qrf=(float*)sym(g_qrf);
    float *kvf=(float*)sym(g_kvf), *krf=(float*)sym(g_krf);
    bf16 *qh=(bf16*)sym(g_qh), *ql=(bf16*)sym(g_ql);
    bf16 *kh=(bf16*)sym(g_kh), *kl=(bf16*)sym(g_kl);
    bf16 *vth=(bf16*)sym(g_vth), *vtl=(bf16*)sym(g_vtl);
    bf16 *aoh=(bf16*)sym(g_aoh), *aol=(bf16*)sym(g_aol);

    cudaFuncSetAttribute(hmma_gemm, cudaFuncAttributeMaxDynamicSharedMemorySize, SMEM_GEMM);
    cudaFuncSetAttribute(flash_attn, cudaFuncAttributeMaxDynamicSharedMemorySize, SMEM_FLASH);

    // --- input conversions ---
    split_plain<<<(unsigned)(((size_t)BS*DMODEL + 255)/256), 256>>>(x, xhi, xlo, BS, DMODEL, DMODEL);
    split_plain<<<(unsigned)(((size_t)DMODEL*DMODEL + 255)/256), 256>>>(W_o, woh, wol, DMODEL, DMODEL, DMODEL);
    transpose_split<<<dim3(DMODEL/32, QPROJ/32),  dim3(32,8)>>>(W_dq,  wdqh,  wdql,  DMODEL, QPROJ,  QPROJ,  DMODEL);
    transpose_split<<<dim3(QPROJ/32,  KNOPE/32),  dim3(32,8)>>>(W_uq,  wuqh,  wuql,  QPROJ,  KNOPE,  KNOPE,  QPROJ);
    transpose_split<<<dim3(QPROJ/32,  256/32),    dim3(32,8)>>>(W_qr,  wqrh,  wqrl,  QPROJ,  256,    256,    QPROJ);
    transpose_split<<<dim3(DMODEL/32, KVPAD/32),  dim3(32,8)>>>(W_dkv, wdkvh, wdkvl, DMODEL, KVPROJ, KVPAD,  DMODEL);
    transpose_split<<<dim3(KVPAD/32,  KVCOLS/32), dim3(32,8)>>>(W_ukv, wukvh, wukvl, KVPROJ, KVCOLS, KVCOLS, KVPAD);
    transpose_split<<<dim3(DMODEL/32, 256/32),    dim3(32,8)>>>(W_kr,  wkrh,  wkrl,  DMODEL, 256,    256,    DMODEL);

    // --- Q path ---
    hmma_gemm<<<dim3(QPROJ/128, BS/128), 256, SMEM_GEMM>>>(
        xhi, xlo, wdqh, wdql, cq, QPROJ, DMODEL, DMODEL, DMODEL, QPROJ);
    layernorm_split<<<BS, 256>>>(cq, nullptr, cqh, cql, q_w, q_b, QPROJ, QPROJ);
    hmma_gemm<<<dim3(KNOPE/128, BS/128), 256, SMEM_GEMM>>>(
        cqh, cql, wuqh, wuql, qn, KNOPE, QPROJ, QPROJ, QPROJ, KNOPE);
    hmma_gemm<<<dim3(2, BS/128), 256, SMEM_GEMM>>>(
        cqh, cql, wqrh, wqrl, qrf, 256, QPROJ, QPROJ, QPROJ, 256);

    // --- KV path ---
    hmma_gemm<<<dim3((KVPROJ+127)/128, BS/128), 256, SMEM_GEMM>>>(
        xhi, xlo, wdkvh, wdkvl, ckv, KVPROJ, DMODEL, DMODEL, DMODEL, KVPROJ);
    layernorm_split<<<BS, 256>>>(ckv, ckv, ckvh, ckvl, kv_w, kv_b, KVPROJ, KVPAD);
    hmma_gemm<<<dim3(KVCOLS/128, BS/128), 256, SMEM_GEMM>>>(
        ckvh, ckvl, wukvh, wukvl, kvf, KVCOLS, KVPAD, KVPAD, KVPAD, KVCOLS);
    hmma_gemm<<<dim3(2, BS/128), 256, SMEM_GEMM>>>(
        xhi, xlo, wkrh, wkrl, krf, 256, DMODEL, DMODEL, DMODEL, 256);

    // --- heads + RoPE ---
    size_t nel = (size_t)NZ * S_ * DH;
    build_qk<<<(unsigned)((nel + 255)/256), 256>>>(qn, qrf, kvf, krf, qh, ql, kh, kl);
    build_vt<<<dim3(S_/32, DH/32, NZ), dim3(32,8)>>>(kvf, vth, vtl);

    // --- fused flash attention (writes permuted bf16 hi/lo directly) ---
    flash_attn<<<dim3(S_/128, NZ), 256, SMEM_FLASH>>>(qh, ql, kh, kl, vth, vtl, aoh, aol);

    // --- final projection ---
    hmma_gemm<<<dim3(DMODEL/128, BS/128), 256, SMEM_GEMM>>>(
        aoh, aol, woh, wol, out, DMODEL, DMODEL, DMODEL, DMODEL, DMODEL);
}

// round 5
// speedup vs baseline: 4.6096x; 1.0271x over previous
#include <cuda_runtime.h>
#include <cuda_bf16.h>
#include <cstdint>
#include <math.h>

// ---------------- problem constants ----------------
#define B_      2
#define S_      2048
#define DMODEL  2048
#define NH      16
#define DH      128
#define NOPE    14
#define QPROJ   1024
#define KVPROJ  1365
#define KVPAD   1408
#define KNOPE   1792
#define KVCOLS  3840
#define BS      (B_*S_)
#define NZ      (B_*NH)
#define N1      2688          // fused x-proj: 1024 dq | 1408 dkv | 256 kr
#define N2      2048          // fused cq-proj: 1792 uq | 256 qr

typedef __nv_bfloat16 bf16;

// ---------------- device scratch ----------------
__device__ bf16 g_xhi[(size_t)BS*DMODEL],   g_xlo[(size_t)BS*DMODEL];
__device__ bf16 g_w1h[(size_t)N1*DMODEL],   g_w1l[(size_t)N1*DMODEL];
__device__ bf16 g_w2h[(size_t)N2*QPROJ],    g_w2l[(size_t)N2*QPROJ];
__device__ bf16 g_wukvh[(size_t)KVCOLS*KVPAD], g_wukvl[(size_t)KVCOLS*KVPAD];
__device__ bf16 g_woh[(size_t)DMODEL*DMODEL],  g_wol[(size_t)DMODEL*DMODEL];
__device__ float g_p1[(size_t)BS*N1];
__device__ float g_p2[(size_t)BS*N2];
__device__ bf16 g_cqh[(size_t)BS*QPROJ],    g_cql[(size_t)BS*QPROJ];
__device__ bf16 g_ckvh[(size_t)BS*KVPAD],   g_ckvl[(size_t)BS*KVPAD];
__device__ float g_kvf[(size_t)BS*KVCOLS];
__device__ bf16 g_qh[(size_t)NZ*S_*DH], g_ql[(size_t)NZ*S_*DH];
__device__ bf16 g_kh[(size_t)NZ*S_*DH], g_kl[(size_t)NZ*S_*DH];
__device__ bf16 g_vth[(size_t)NZ*DH*S_], g_vtl[(size_t)NZ*DH*S_];
__device__ bf16 g_aoh[(size_t)BS*DMODEL], g_aol[(size_t)BS*DMODEL];

// ---------------- helpers ----------------
__device__ __forceinline__ uint32_t smem_u32(const void* p) {
    uint32_t a;
    asm("{ .reg .u64 t; cvta.to.shared.u64 t, %1; cvt.u32.u64 %0, t; }" : "=r"(a) : "l"(p));
    return a;
}
__device__ __forceinline__ void cp16(uint32_t saddr, const void* g) {
    asm volatile("cp.async.cg.shared.global [%0], [%1], 16;" :: "r"(saddr), "l"(g) : "memory");
}
__device__ __forceinline__ void cp_commit() {
    asm volatile("cp.async.commit_group;" ::: "memory");
}
template<int N> __device__ __forceinline__ void cp_wait() {
    asm volatile("cp.async.wait_group %0;" :: "n"(N) : "memory");
}
__device__ __forceinline__ void ldm_x4(uint32_t addr, uint32_t* r) {
    asm volatile("ldmatrix.sync.aligned.m8n8.x4.shared.b16 {%0,%1,%2,%3}, [%4];"
        : "=r"(r[0]), "=r"(r[1]), "=r"(r[2]), "=r"(r[3]) : "r"(addr));
}
__device__ __forceinline__ void mma16816(float* d, const uint32_t* a, const uint32_t* b) {
    asm volatile("mma.sync.aligned.m16n8k16.row.col.f32.bf16.bf16.f32 "
        "{%0,%1,%2,%3}, {%4,%5,%6,%7}, {%8,%9}, {%0,%1,%2,%3};"
        : "+f"(d[0]), "+f"(d[1]), "+f"(d[2]), "+f"(d[3])
        : "r"(a[0]), "r"(a[1]), "r"(a[2]), "r"(a[3]), "r"(b[0]), "r"(b[1]));
}
__device__ __forceinline__ void split2(float v, bf16& h, bf16& l) {
    h = __float2bfloat16(v);
    l = __float2bfloat16(v - __bfloat162float(h));
}
__device__ __forceinline__ uint32_t pack_bf2(float a, float b) {
    __nv_bfloat162 t = __floats2bfloat162_rn(a, b);
    return *(uint32_t*)&t;
}

// ---------------- HMMA NT GEMM: C = A @ B^T, 3-stage pipeline ----------------
#define STAGE 32768
#define SMEM_GEMM (3*STAGE)

__global__ __launch_bounds__(256, 1)
void hmma_gemm(const bf16* __restrict__ Ahi, const bf16* __restrict__ Alo,
               const bf16* __restrict__ Bhi, const bf16* __restrict__ Blo,
               float* __restrict__ C,
               int N, int Kpad, int lda, int ldb, int ldc)
{
    extern __shared__ __align__(128) char smem[];
    int tid = threadIdx.x, lane = tid & 31, wid = tid >> 5;
    int r0 = blockIdx.y * 128, c0 = blockIdx.x * 128;
    int tiles = Kpad >> 5;

    const bf16* srcs[4];
    srcs[0] = Ahi + (size_t)r0 * lda;
    srcs[1] = Alo + (size_t)r0 * lda;
    srcs[2] = Bhi + (size_t)c0 * ldb;
    srcs[3] = Blo + (size_t)c0 * ldb;

    uint32_t sbase = smem_u32(smem);
    int wm = (wid >> 2) * 64, wn = (wid & 3) * 32;

    float acc[4][4][4];
#pragma unroll
    for (int i = 0; i < 4; i++)
#pragma unroll
        for (int j = 0; j < 4; j++)
#pragma unroll
            for (int v = 0; v < 4; v++) acc[i][j][v] = 0.f;

    auto load_stage = [&](int t) {
        int k0 = t << 5;
        uint32_t sb = sbase + (uint32_t)(t % 3) * STAGE;
#pragma unroll
        for (int tl = 0; tl < 4; tl++) {
            const bf16* src = srcs[tl] + k0;
            int ld = (tl < 2) ? lda : ldb;
            uint32_t toff = sb + tl * 8192;
#pragma unroll
            for (int q = 0; q < 2; q++) {
                int c = tid + q * 256;
                int row = c >> 2, ch = c & 3;
                cp16(toff + row * 64 + (uint32_t)((ch ^ ((row >> 1) & 3)) << 4),
                     src + (size_t)row * ld + ch * 8);
            }
        }
        cp_commit();
    };

    auto compute_stage = [&](int t) {
        uint32_t sb = sbase + (uint32_t)(t % 3) * STAGE;
#pragma unroll
        for (int kk = 0; kk < 32; kk += 16) {
            uint32_t bh[4][2], bl[4][2];
#pragma unroll
            for (int p = 0; p < 2; p++) {
                int rowB = wn + p * 16 + ((lane >> 4) << 3) + (lane & 7);
                int ch = (kk >> 3) + ((lane >> 3) & 1);
                uint32_t off = (uint32_t)rowB * 64 + (uint32_t)((ch ^ ((rowB >> 1) & 3)) << 4);
                uint32_t r[4];
                ldm_x4(sb + 16384 + off, r);
                bh[2 * p][0] = r[0]; bh[2 * p][1] = r[1];
                bh[2 * p + 1][0] = r[2]; bh[2 * p + 1][1] = r[3];
                ldm_x4(sb + 24576 + off, r);
                bl[2 * p][0] = r[0]; bl[2 * p][1] = r[1];
                bl[2 * p + 1][0] = r[2]; bl[2 * p + 1][1] = r[3];
            }
#pragma unroll
            for (int mt = 0; mt < 4; mt++) {
                int rowA = wm + mt * 16 + (lane & 15);
                int ch = (kk >> 3) + (lane >> 4);
                uint32_t off = (uint32_t)rowA * 64 + (uint32_t)((ch ^ ((rowA >> 1) & 3)) << 4);
                uint32_t ah[4], al[4];
                ldm_x4(sb + off, ah);
                ldm_x4(sb + 8192 + off, al);
#pragma unroll
                for (int nt = 0; nt < 4; nt++) {
                    mma16816(acc[mt][nt], ah, bh[nt]);
                    mma16816(acc[mt][nt], ah, bl[nt]);
                    mma16816(acc[mt][nt], al, bh[nt]);
                }
            }
        }
    };

    load_stage(0);
    if (tiles > 1) load_stage(1);
    for (int t = 0; t < tiles; t++) {
        if (t + 1 < tiles) cp_wait<1>(); else cp_wait<0>();
        __syncthreads();
        if (t + 2 < tiles) load_stage(t + 2);
        compute_stage(t);
    }

#pragma unroll
    for (int mt = 0; mt < 4; mt++) {
#pragma unroll
        for (int nt = 0; nt < 4; nt++) {
            int r = r0 + wm + mt * 16 + (lane >> 2);
            int c = c0 + wn + nt * 8 + ((lane & 3) << 1);
            float* p0 = C + (size_t)r * ldc + c;
            float* p1 = p0 + 8 * ldc;
            if (c < N)     { p0[0] = acc[mt][nt][0]; p1[0] = acc[mt][nt][2]; }
            if (c + 1 < N) { p0[1] = acc[mt][nt][1]; p1[1] = acc[mt][nt][3]; }
        }
    }
}

// ---------------- fused flash attention (3-stage, Q buffer recycled) ----------------
#define FST 65536                  // stage: Khi 16K, Klo 16K, Vthi 16K, Vtlo 16K
#define SMEM_FLASH (3*FST)         // 192 KB; buf0 initially holds Q hi/lo

__global__ __launch_bounds__(256, 1)
void flash_attn(const bf16* __restrict__ qh_, const bf16* __restrict__ ql_,
                const bf16* __restrict__ kh_, const bf16* __restrict__ kl_,
                const bf16* __restrict__ vth_, const bf16* __restrict__ vtl_,
                bf16* __restrict__ aoh, bf16* __restrict__ aol)
{
    extern __shared__ __align__(128) char smem[];
    int tid = threadIdx.x, lane = tid & 31, wid = tid >> 5;
    int z = blockIdx.y, bb = z >> 4, hh = z & 15;
    int r0 = ((int)gridDim.x - 1 - (int)blockIdx.x) * 128;   // big blocks first

    const bf16* qhz = qh_ + (size_t)z * S_ * DH + (size_t)r0 * DH;
    const bf16* qlz = ql_ + (size_t)z * S_ * DH + (size_t)r0 * DH;
    const bf16* khz = kh_ + (size_t)z * S_ * DH;
    const bf16* klz = kl_ + (size_t)z * S_ * DH;
    const bf16* vthz = vth_ + (size_t)z * DH * S_;
    const bf16* vtlz = vtl_ + (size_t)z * DH * S_;

    uint32_t sb = smem_u32(smem);

    // stage Q (128 x 128 bf16, hi+lo) into buffer 0
#pragma unroll
    for (int q = 0; q < 8; q++) {
        int idx = tid + q * 256;
        int row = idx >> 4, ch = idx & 15;
        uint32_t off = (uint32_t)row * 256 + (uint32_t)((ch ^ (row & 7)) << 4);
        cp16(sb + off,         qhz + (size_t)row * DH + ch * 8);
        cp16(sb + 32768 + off, qlz + (size_t)row * DH + ch * 8);
    }
    cp_commit();

    int ntiles = (r0 >> 6) + 2;
    int diag = r0 >> 6;

    // stage t lives in buffer (t+1)%3
    auto load_stage = [&](int jt) {
        uint32_t st = sb + (uint32_t)((jt + 1) % 3) * FST;
        int s0 = jt * 64;
#pragma unroll
        for (int q = 0; q < 4; q++) {            // K: 64 rows x 16 chunks
            int idx = tid + q * 256;
            int row = idx >> 4, ch = idx & 15;
            uint32_t off = (uint32_t)row * 256 + (uint32_t)((ch ^ (row & 7)) << 4);
            cp16(st + off,         khz + (size_t)(s0 + row) * DH + ch * 8);
            cp16(st + 16384 + off, klz + (size_t)(s0 + row) * DH + ch * 8);
        }
#pragma unroll
        for (int q = 0; q < 4; q++) {            // Vt: 128 rows x 8 chunks
            int idx = tid + q * 256;
            int row = idx >> 3, ch = idx & 7;
            uint32_t off = (uint32_t)row * 128 + (uint32_t)((ch ^ (row & 7)) << 4);
            cp16(st + 32768 + off, vthz + (size_t)row * S_ + s0 + ch * 8);
            cp16(st + 49152 + off, vtlz + (size_t)row * S_ + s0 + ch * 8);
        }
        cp_commit();
    };

    load_stage(0);          // buf1
    load_stage(1);          // buf2
    cp_wait<2>();           // Q complete
    __syncthreads();

    // Q fragments (held across whole loop); after this buf0 is reusable
    int wrow = wid * 16;
    uint32_t qah[8][4], qal[8][4];
#pragma unroll
    for (int kf = 0; kf < 8; kf++) {
        int row = wrow + (lane & 15);
        int ch = kf * 2 + (lane >> 4);
        uint32_t off = (uint32_t)row * 256 + (uint32_t)((ch ^ (row & 7)) << 4);
        ldm_x4(sb + off, qah[kf]);
        ldm_x4(sb + 32768 + off, qal[kf]);
    }

    float of[16][4];
#pragma unroll
    for (int i = 0; i < 16; i++)
#pragma unroll
        for (int v = 0; v < 4; v++) of[i][v] = 0.f;
    float m0 = -1e30f, m1 = -1e30f, l0 = 0.f, l1 = 0.f;
    const float CEXP = 0.08838834764831845f * 1.4426950408889634f;

    int rowa = r0 + wrow + (lane >> 2);

    for (int jt = 0; jt < ntiles; jt++) {
        if (jt + 1 < ntiles) cp_wait<1>(); else cp_wait<0>();
        __syncthreads();
        if (jt + 2 < ntiles) load_stage(jt + 2);
        uint32_t st = sb + (uint32_t)((jt + 1) % 3) * FST;

        // ---- S = Q @ K^T (16 x 64 per warp) ----
        float sf[8][4];
#pragma unroll
        for (int nf = 0; nf < 8; nf++)
#pragma unroll
            for (int v = 0; v < 4; v++) sf[nf][v] = 0.f;

#pragma unroll
        for (int kf = 0; kf < 8; kf++) {
            uint32_t bh[8][2], bl[8][2];
#pragma unroll
            for (int p = 0; p < 4; p++) {
                int rowB = p * 16 + ((lane >> 4) << 3) + (lane & 7);
                int ch = kf * 2 + ((lane >> 3) & 1);
                uint32_t off = (uint32_t)rowB * 256 + (uint32_t)((ch ^ (rowB & 7)) << 4);
                uint32_t r4[4];
                ldm_x4(st + off, r4);
                bh[2 * p][0] = r4[0]; bh[2 * p][1] = r4[1];
                bh[2 * p + 1][0] = r4[2]; bh[2 * p + 1][1] = r4[3];
                ldm_x4(st + 16384 + off, r4);
                bl[2 * p][0] = r4[0]; bl[2 * p][1] = r4[1];
                bl[2 * p + 1][0] = r4[2]; bl[2 * p + 1][1] = r4[3];
            }
#pragma unroll
            for (int nf = 0; nf < 8; nf++) {
                mma16816(sf[nf], qah[kf], bh[nf]);
                mma16816(sf[nf], qah[kf], bl[nf]);
                mma16816(sf[nf], qal[kf], bh[nf]);
            }
        }

        // ---- causal mask on diagonal tiles ----
        if (jt >= diag) {
            int colb = jt * 64 + 2 * (lane & 3);
#pragma unroll
            for (int nf = 0; nf < 8; nf++) {
                int c = colb + nf * 8;
                if (c > rowa)     sf[nf][0] = -1e30f;
                if (c + 1 > rowa) sf[nf][1] = -1e30f;
                if (c > rowa + 8)     sf[nf][2] = -1e30f;
                if (c + 1 > rowa + 8) sf[nf][3] = -1e30f;
            }
        }

        // ---- online softmax ----
        float tm0 = -1e30f, tm1 = -1e30f;
#pragma unroll
        for (int nf = 0; nf < 8; nf++) {
            tm0 = fmaxf(tm0, fmaxf(sf[nf][0], sf[nf][1]));
            tm1 = fmaxf(tm1, fmaxf(sf[nf][2], sf[nf][3]));
        }
        tm0 = fmaxf(tm0, __shfl_xor_sync(0xffffffffu, tm0, 1));
        tm0 = fmaxf(tm0, __shfl_xor_sync(0xffffffffu, tm0, 2));
        tm1 = fmaxf(tm1, __shfl_xor_sync(0xffffffffu, tm1, 1));
        tm1 = fmaxf(tm1, __shfl_xor_sync(0xffffffffu, tm1, 2));
        float mn0 = fmaxf(m0, tm0), mn1 = fmaxf(m1, tm1);
        float al0 = exp2f((m0 - mn0) * CEXP), al1 = exp2f((m1 - mn1) * CEXP);
        m0 = mn0; m1 = mn1;

        uint32_t pah[4][4], pal[4][4];
        float rs0 = 0.f, rs1 = 0.f;
#pragma unroll
        for (int nf = 0; nf < 8; nf++) {
            float e0 = exp2f((sf[nf][0] - m0) * CEXP);
            float e1 = exp2f((sf[nf][1] - m0) * CEXP);
            float e2 = exp2f((sf[nf][2] - m1) * CEXP);
            float e3 = exp2f((sf[nf][3] - m1) * CEXP);
            rs0 += e0 + e1; rs1 += e2 + e3;
            float h0 = __bfloat162float(__float2bfloat16(e0));
            float h1 = __bfloat162float(__float2bfloat16(e1));
            float h2 = __bfloat162float(__float2bfloat16(e2));
            float h3 = __bfloat162float(__float2bfloat16(e3));
            int kf2 = nf >> 1, s = (nf & 1) * 2;
            pah[kf2][s]     = pack_bf2(h0, h1);
            pah[kf2][s + 1] = pack_bf2(h2, h3);
            pal[kf2][s]     = pack_bf2(e0 - h0, e1 - h1);
            pal[kf2][s + 1] = pack_bf2(e2 - h2, e3 - h3);
        }
        l0 = l0 * al0 + rs0;
        l1 = l1 * al1 + rs1;

#pragma unroll
        for (int i = 0; i < 16; i++) {
            of[i][0] *= al0; of[i][1] *= al0;
            of[i][2] *= al1; of[i][3] *= al1;
        }

        // ---- O += P @ V ----
#pragma unroll
        for (int kf2 = 0; kf2 < 4; kf2++) {
#pragma unroll
            for (int p2 = 0; p2 < 8; p2++) {
                int rowB = p2 * 16 + ((lane >> 4) << 3) + (lane & 7);
                int ch = kf2 * 2 + ((lane >> 3) & 1);
                uint32_t off = (uint32_t)rowB * 128 + (uint32_t)((ch ^ (rowB & 7)) << 4);
                uint32_t rh[4], rl[4];
                ldm_x4(st + 32768 + off, rh);
                ldm_x4(st + 49152 + off, rl);
                uint32_t bh0[2] = {rh[0], rh[1]}, bh1[2] = {rh[2], rh[3]};
                uint32_t bl0[2] = {rl[0], rl[1]}, bl1[2] = {rl[2], rl[3]};
                mma16816(of[2 * p2],     pah[kf2], bh0);
                mma16816(of[2 * p2],     pah[kf2], bl0);
                mma16816(of[2 * p2],     pal[kf2], bh0);
                mma16816(of[2 * p2 + 1], pah[kf2], bh1);
                mma16816(of[2 * p2 + 1], pah[kf2], bl1);
                mma16816(of[2 * p2 + 1], pal[kf2], bh1);
            }
        }
    }

    l0 += __shfl_xor_sync(0xffffffffu, l0, 1);
    l0 += __shfl_xor_sync(0xffffffffu, l0, 2);
    l1 += __shfl_xor_sync(0xffffffffu, l1, 1);
    l1 += __shfl_xor_sync(0xffffffffu, l1, 2);
    float inv0 = 1.f / l0, inv1 = 1.f / l1;

    size_t ga = ((size_t)(bb * S_) + rowa) * DMODEL + hh * DH;
    size_t gb = ga + (size_t)8 * DMODEL;
#pragma unroll
    for (int i = 0; i < 16; i++) {
        int d = i * 8 + 2 * (lane & 3);
        float v0 = of[i][0] * inv0, v1 = of[i][1] * inv0;
        float v2 = of[i][2] * inv1, v3 = of[i][3] * inv1;
        float h0 = __bfloat162float(__float2bfloat16(v0));
        float h1 = __bfloat162float(__float2bfloat16(v1));
        float h2 = __bfloat162float(__float2bfloat16(v2));
        float h3 = __bfloat162float(__float2bfloat16(v3));
        *(uint32_t*)(aoh + ga + d) = pack_bf2(h0, h1);
        *(uint32_t*)(aoh + gb + d) = pack_bf2(h2, h3);
        *(uint32_t*)(aol + ga + d) = pack_bf2(v0 - h0, v1 - h1);
        *(uint32_t*)(aol + gb + d) = pack_bf2(v2 - h2, v3 - h3);
    }
}

// ---------------- elementwise kernels ----------------
__global__ __launch_bounds__(256)
void split_plain(const float* __restrict__ in, bf16* __restrict__ hi, bf16* __restrict__ lo,
                 int R, int C, int Cpad)
{
    size_t idx = (size_t)blockIdx.x * 256 + threadIdx.x;
    if (idx >= (size_t)R * Cpad) return;
    int c = (int)(idx % Cpad);
    size_t r = idx / Cpad;
    float v = (c < C) ? in[r * C + c] : 0.f;
    split2(v, hi[idx], lo[idx]);
}

// fp32 in[K,N] -> bf16 hi/lo out[(n+rowOff), k] with ld=Kpad; zero-pads section
__global__ __launch_bounds__(256)
void transpose_split(const float* __restrict__ in, bf16* __restrict__ hi, bf16* __restrict__ lo,
                     int K, int N, int Npad, int Kpad, int rowOff)
{
    __shared__ float t[32][33];
    int k0 = blockIdx.x * 32, n0 = blockIdx.y * 32;
    int tx = threadIdx.x, ty = threadIdx.y;
#pragma unroll
    for (int i = 0; i < 4; i++) {
        int k = k0 + ty + i * 8;
        float v = (k < K && n0 + tx < N) ? in[(size_t)k * N + n0 + tx] : 0.f;
        t[ty + i * 8][tx] = v;
    }
    __syncthreads();
#pragma unroll
    for (int i = 0; i < 4; i++) {
        int n = n0 + ty + i * 8, k = k0 + tx;
        if (n < Npad && k < Kpad) {
            size_t o = (size_t)(n + rowOff) * Kpad + k;
            split2(t[tx][ty + i * 8], hi[o], lo[o]);
        }
    }
}

// LayerNorm over strided input section; fp32 out (own stride) optional; bf16 hi/lo out
__global__ __launch_bounds__(256)
void layernorm_split(const float* __restrict__ X, int xld,
                     float* __restrict__ outf, int ofld,
                     bf16* __restrict__ hi, bf16* __restrict__ lo,
                     const float* __restrict__ w, const float* __restrict__ b,
                     int n, int npad)
{
    const float* p = X + (size_t)blockIdx.x * xld;
    float s = 0.f, s2 = 0.f;
    for (int j = threadIdx.x; j < n; j += 256) {
        float v = p[j];
        s += v; s2 += v * v;
    }
    __shared__ float sh[20];
#pragma unroll
    for (int o = 16; o; o >>= 1) {
        s  += __shfl_down_sync(0xffffffffu, s,  o);
        s2 += __shfl_down_sync(0xffffffffu, s2, o);
    }
    int wd = threadIdx.x >> 5, ln = threadIdx.x & 31;
    if (!ln) { sh[wd] = s; sh[wd + 8] = s2; }
    __syncthreads();
    if (threadIdx.x == 0) {
        float ts = 0.f, ts2 = 0.f;
        for (int i = 0; i < 8; i++) { ts += sh[i]; ts2 += sh[i + 8]; }
        float mean = ts / n;
        float var = fmaxf(ts2 / n - mean * mean, 0.f);
        sh[16] = mean;
        sh[17] = rsqrtf(var + 1e-5f);
    }
    __syncthreads();
    float mean = sh[16], rstd = sh[17];
    float* of = outf ? outf + (size_t)blockIdx.x * ofld : nullptr;
    bf16* hh = hi + (size_t)blockIdx.x * npad;
    bf16* ll = lo + (size_t)blockIdx.x * npad;
    for (int j = threadIdx.x; j < npad; j += 256) {
        float v = 0.f;
        if (j < n) {
            v = (p[j] - mean) * rstd * w[j] + b[j];
            if (of) of[j] = v;
        }
        split2(v, hh[j], ll[j]);
    }
}

__device__ __forceinline__ float rope_val(const float* __restrict__ base, int d, int s) {
    int dd = d & 63;
    float freq = 1.0f / powf(10000.0f, (float)dd * (1.0f / 64.0f));
    float ang = (float)s * freq;
    float sn, cs;
    sincosf(ang, &sn, &cs);
    float x = base[d];
    return (d < 64) ? x * cs - base[d + 64] * sn
                    : x * cs + base[d - 64] * sn;
}

// gather heads + RoPE from fused projection buffers
__global__ __launch_bounds__(256)
void build_qk(const float* __restrict__ p2, const float* __restrict__ kvf,
              const float* __restrict__ p1,
              bf16* __restrict__ qh, bf16* __restrict__ ql,
              bf16* __restrict__ kh, bf16* __restrict__ kl)
{
    size_t idx = (size_t)blockIdx.x * 256 + threadIdx.x;
    if (idx >= (size_t)NZ * S_ * DH) return;
    int d = (int)(idx & (DH - 1));
    size_t t = idx >> 7;
    int s = (int)(t & (S_ - 1)); t >>= 11;
    int h = (int)(t & 15);
    int b = (int)(t >> 4);
    size_t row = (size_t)(b * S_ + s);

    float qv, kvv;
    if (h < NOPE) {
        qv  = p2[row * N2 + h * DH + d];
        kvv = kvf[row * KVCOLS + h * DH + d];
    } else {
        qv  = rope_val(p2 + row * N2 + KNOPE + (h - NOPE) * DH, d, s);
        kvv = rope_val(p1 + row * N1 + 2432 + (h - NOPE) * DH, d, s);
    }
    split2(qv, qh[idx], ql[idx]);
    split2(kvv, kh[idx], kl[idx]);
}

__global__ void build_vt(const float* __restrict__ kvf, bf16* __restrict__ vth, bf16* __restrict__ vtl)
{
    __shared__ float t[32][33];
    int z = blockIdx.z, b = z >> 4, h = z & 15;
    int s0 = blockIdx.x * 32, d0 = blockIdx.y * 32;
    int tx = threadIdx.x, ty = threadIdx.y;
#pragma unroll
    for (int i = 0; i < 4; i++) {
        int s = s0 + ty + i * 8;
        t[ty + i * 8][tx] = kvf[(size_t)(b * S_ + s) * KVCOLS + KNOPE + h * DH + d0 + tx];
    }
    __syncthreads();
#pragma unroll
    for (int i = 0; i < 4; i++) {
        int d = d0 + ty + i * 8, s = s0 + tx;
        size_t o = ((size_t)z * DH + d) * S_ + s;
        split2(t[tx][ty + i * 8], vth[o], vtl[o]);
    }
}

// ---------------- launch ----------------
static inline void* sym(const void* s) { void* p; cudaGetSymbolAddress(&p, s); return p; }

extern "C" void kernel_launch(void* const* d_in, const int* in_sizes, int n_in,
                              void* d_out, int out_size)
{
    const float* x     = (const float*)d_in[0];
    const float* W_dq  = (const float*)d_in[1];
    const float* W_uq  = (const float*)d_in[2];
    const float* W_qr  = (const float*)d_in[3];
    const float* W_dkv = (const float*)d_in[4];
    const float* W_ukv = (const float*)d_in[5];
    const float* W_kr  = (const float*)d_in[6];
    const float* W_o   = (const float*)d_in[7];
    const float* q_w   = (const float*)d_in[8];
    const float* q_b   = (const float*)d_in[9];
    const float* kv_w  = (const float*)d_in[10];
    const float* kv_b  = (const float*)d_in[11];

    float* out = (float*)d_out;
    float* ckv = out + (size_t)BS * DMODEL;

    bf16 *xhi=(bf16*)sym(g_xhi), *xlo=(bf16*)sym(g_xlo);
    bf16 *w1h=(bf16*)sym(g_w1h), *w1l=(bf16*)sym(g_w1l);
    bf16 *w2h=(bf16*)sym(g_w2h), *w2l=(bf16*)sym(g_w2l);
    bf16 *wukvh=(bf16*)sym(g_wukvh), *wukvl=(bf16*)sym(g_wukvl);
    bf16 *woh=(bf16*)sym(g_woh), *wol=(bf16*)sym(g_wol);
    float *p1=(float*)sym(g_p1), *p2=(float*)sym(g_p2);
    bf16 *cqh=(bf16*)sym(g_cqh), *cql=(bf16*)sym(g_cql);
    bf16 *ckvh=(bf16*)sym(g_ckvh), *ckvl=(bf16*)sym(g_ckvl);
    float *kvf=(float*)sym(g_kvf);
    bf16 *qh=(bf16*)sym(g_qh), *ql=(bf16*)sym(g_ql);
    bf16 *kh=(bf16*)sym(g_kh), *kl=(bf16*)sym(g_kl);
    bf16 *vth=(bf16*)sym(g_vth), *vtl=(bf16*)sym(g_vtl);
    bf16 *aoh=(bf16*)sym(g_aoh), *aol=(bf16*)sym(g_aol);

    cudaFuncSetAttribute(hmma_gemm, cudaFuncAttributeMaxDynamicSharedMemorySize, SMEM_GEMM);
    cudaFuncSetAttribute(flash_attn, cudaFuncAttributeMaxDynamicSharedMemorySize, SMEM_FLASH);

    // --- input conversions ---
    split_plain<<<(unsigned)(((size_t)BS*DMODEL + 255)/256), 256>>>(x, xhi, xlo, BS, DMODEL, DMODEL);
    split_plain<<<(unsigned)(((size_t)DMODEL*DMODEL + 255)/256), 256>>>(W_o, woh, wol, DMODEL, DMODEL, DMODEL);
    // fused W1 = [W_dq^T ; W_dkv^T(pad 1408) ; W_kr^T], ld = 2048
    transpose_split<<<dim3(DMODEL/32, QPROJ/32),  dim3(32,8)>>>(W_dq,  w1h, w1l, DMODEL, QPROJ,  QPROJ,  DMODEL, 0);
    transpose_split<<<dim3(DMODEL/32, KVPAD/32),  dim3(32,8)>>>(W_dkv, w1h, w1l, DMODEL, KVPROJ, KVPAD,  DMODEL, QPROJ);
    transpose_split<<<dim3(DMODEL/32, 256/32),    dim3(32,8)>>>(W_kr,  w1h, w1l, DMODEL, 256,    256,    DMODEL, QPROJ + KVPAD);
    // fused W2 = [W_uq^T ; W_qr^T], ld = 1024
    transpose_split<<<dim3(QPROJ/32,  KNOPE/32),  dim3(32,8)>>>(W_uq,  w2h, w2l, QPROJ,  KNOPE,  KNOPE,  QPROJ, 0);
    transpose_split<<<dim3(QPROJ/32,  256/32),    dim3(32,8)>>>(W_qr,  w2h, w2l, QPROJ,  256,    256,    QPROJ, KNOPE);
    // ukv
    transpose_split<<<dim3(KVPAD/32,  KVCOLS/32), dim3(32,8)>>>(W_ukv, wukvh, wukvl, KVPROJ, KVCOLS, KVCOLS, KVPAD, 0);

    // --- fused projection 1: p1 = x @ [W_dq | W_dkv | W_kr] ---
    hmma_gemm<<<dim3(N1/128, BS/128), 256, SMEM_GEMM>>>(
        xhi, xlo, w1h, w1l, p1, N1, DMODEL, DMODEL, DMODEL, N1);

    // --- LayerNorms (strided sections of p1) ---
    layernorm_split<<<BS, 256>>>(p1, N1, nullptr, 0, cqh, cql, q_w, q_b, QPROJ, QPROJ);
    layernorm_split<<<BS, 256>>>(p1 + QPROJ, N1, ckv, KVPROJ, ckvh, ckvl, kv_w, kv_b, KVPROJ, KVPAD);

    // --- fused projection 2: p2 = cq @ [W_uq | W_qr] ---
    hmma_gemm<<<dim3(N2/128, BS/128), 256, SMEM_GEMM>>>(
        cqh, cql, w2h, w2l, p2, N2, QPROJ, QPROJ, QPROJ, N2);

    // --- KV decompress ---
    hmma_gemm<<<dim3(KVCOLS/128, BS/128), 256, SMEM_GEMM>>>(
        ckvh, ckvl, wukvh, wukvl, kvf, KVCOLS, KVPAD, KVPAD, KVPAD, KVCOLS);

    // --- heads + RoPE ---
    size_t nel = (size_t)NZ * S_ * DH;
    build_qk<<<(unsigned)((nel + 255)/256), 256>>>(p2, kvf, p1, qh, ql, kh, kl);
    build_vt<<<dim3(S_/32, DH/32, NZ), dim3(32,8)>>>(kvf, vth, vtl);

    // --- fused flash attention ---
    flash_attn<<<dim3(S_/128, NZ), 256, SMEM_FLASH>>>(qh, ql, kh, kl, vth, vtl, aoh, aol);

    // --- final projection ---
    hmma_gemm<<<dim3(DMODEL/128, BS/128), 256, SMEM_GEMM>>>(
        aoh, aol, woh, wol, out, DMODEL, DMODEL, DMODEL, DMODEL, DMODEL);
}

// round 6
// speedup vs baseline: 4.8143x; 1.0444x over previous
#include <cuda_runtime.h>
#include <cuda_bf16.h>
#include <cstdint>
#include <math.h>

// ---------------- problem constants ----------------
#define B_      2
#define S_      2048
#define DMODEL  2048
#define NH      16
#define DH      128
#define NOPE    14
#define QPROJ   1024
#define KVPROJ  1365
#define KVPAD   1408
#define KNOPE   1792
#define KVCOLS  3840
#define KVLD    4096          // kv buffer row stride (3840 gemm + 256 rope-K)
#define BS      (B_*S_)
#define NZ      (B_*NH)
#define N1      2688          // fused x-proj: 1024 dq | 1408 dkv | 256 kr
#define N2      2048          // fused cq-proj: 1792 uq | 256 qr

typedef __nv_bfloat16 bf16;

// ---------------- device scratch ----------------
__device__ bf16 g_xhi[(size_t)BS*DMODEL],   g_xlo[(size_t)BS*DMODEL];
__device__ bf16 g_w1h[(size_t)N1*DMODEL],   g_w1l[(size_t)N1*DMODEL];
__device__ bf16 g_w2h[(size_t)N2*QPROJ],    g_w2l[(size_t)N2*QPROJ];
__device__ bf16 g_wukvh[(size_t)KVCOLS*KVPAD], g_wukvl[(size_t)KVCOLS*KVPAD];
__device__ bf16 g_woh[(size_t)DMODEL*DMODEL],  g_wol[(size_t)DMODEL*DMODEL];
__device__ float g_p1[(size_t)BS*N1];
__device__ bf16 g_cqh[(size_t)BS*QPROJ],    g_cql[(size_t)BS*QPROJ];
__device__ bf16 g_ckvh[(size_t)BS*KVPAD],   g_ckvl[(size_t)BS*KVPAD];
__device__ bf16 g_q2h[(size_t)BS*N2],       g_q2l[(size_t)BS*N2];
__device__ bf16 g_kvh[(size_t)BS*KVLD],     g_kvl[(size_t)BS*KVLD];
__device__ bf16 g_aoh[(size_t)BS*DMODEL],   g_aol[(size_t)BS*DMODEL];

// ---------------- helpers ----------------
__device__ __forceinline__ uint32_t smem_u32(const void* p) {
    uint32_t a;
    asm("{ .reg .u64 t; cvta.to.shared.u64 t, %1; cvt.u32.u64 %0, t; }" : "=r"(a) : "l"(p));
    return a;
}
__device__ __forceinline__ void cp16(uint32_t saddr, const void* g) {
    asm volatile("cp.async.cg.shared.global [%0], [%1], 16;" :: "r"(saddr), "l"(g) : "memory");
}
__device__ __forceinline__ void cp_commit() {
    asm volatile("cp.async.commit_group;" ::: "memory");
}
template<int N> __device__ __forceinline__ void cp_wait() {
    asm volatile("cp.async.wait_group %0;" :: "n"(N) : "memory");
}
__device__ __forceinline__ void ldm_x4(uint32_t addr, uint32_t* r) {
    asm volatile("ldmatrix.sync.aligned.m8n8.x4.shared.b16 {%0,%1,%2,%3}, [%4];"
        : "=r"(r[0]), "=r"(r[1]), "=r"(r[2]), "=r"(r[3]) : "r"(addr));
}
__device__ __forceinline__ void ldm_x4_t(uint32_t addr, uint32_t* r) {
    asm volatile("ldmatrix.sync.aligned.m8n8.x4.trans.shared.b16 {%0,%1,%2,%3}, [%4];"
        : "=r"(r[0]), "=r"(r[1]), "=r"(r[2]), "=r"(r[3]) : "r"(addr));
}
__device__ __forceinline__ void mma16816(float* d, const uint32_t* a, const uint32_t* b) {
    asm volatile("mma.sync.aligned.m16n8k16.row.col.f32.bf16.bf16.f32 "
        "{%0,%1,%2,%3}, {%4,%5,%6,%7}, {%8,%9}, {%0,%1,%2,%3};"
        : "+f"(d[0]), "+f"(d[1]), "+f"(d[2]), "+f"(d[3])
        : "r"(a[0]), "r"(a[1]), "r"(a[2]), "r"(a[3]), "r"(b[0]), "r"(b[1]));
}
__device__ __forceinline__ void split2(float v, bf16& h, bf16& l) {
    h = __float2bfloat16(v);
    l = __float2bfloat16(v - __bfloat162float(h));
}
__device__ __forceinline__ uint32_t pack_bf2(float a, float b) {
    __nv_bfloat162 t = __floats2bfloat162_rn(a, b);
    return *(uint32_t*)&t;
}

// ---------------- HMMA NT GEMM: C = A @ B^T, 3-stage pipeline ----------------
// Output: fp32 (Cf) OR split bf16 hi/lo (Ch/Cl), ldc stride.
#define STAGE 32768
#define SMEM_GEMM (3*STAGE)

__global__ __launch_bounds__(256, 1)
void hmma_gemm(const bf16* __restrict__ Ahi, const bf16* __restrict__ Alo,
               const bf16* __restrict__ Bhi, const bf16* __restrict__ Blo,
               float* __restrict__ Cf, bf16* __restrict__ Ch, bf16* __restrict__ Cl,
               int N, int Kpad, int lda, int ldb, int ldc)
{
    extern __shared__ __align__(128) char smem[];
    int tid = threadIdx.x, lane = tid & 31, wid = tid >> 5;
    int r0 = blockIdx.y * 128, c0 = blockIdx.x * 128;
    int tiles = Kpad >> 5;

    const bf16* srcs[4];
    srcs[0] = Ahi + (size_t)r0 * lda;
    srcs[1] = Alo + (size_t)r0 * lda;
    srcs[2] = Bhi + (size_t)c0 * ldb;
    srcs[3] = Blo + (size_t)c0 * ldb;

    uint32_t sbase = smem_u32(smem);
    int wm = (wid >> 2) * 64, wn = (wid & 3) * 32;

    float acc[4][4][4];
#pragma unroll
    for (int i = 0; i < 4; i++)
#pragma unroll
        for (int j = 0; j < 4; j++)
#pragma unroll
            for (int v = 0; v < 4; v++) acc[i][j][v] = 0.f;

    auto load_stage = [&](int t) {
        int k0 = t << 5;
        uint32_t sb = sbase + (uint32_t)(t % 3) * STAGE;
#pragma unroll
        for (int tl = 0; tl < 4; tl++) {
            const bf16* src = srcs[tl] + k0;
            int ld = (tl < 2) ? lda : ldb;
            uint32_t toff = sb + tl * 8192;
#pragma unroll
            for (int q = 0; q < 2; q++) {
                int c = tid + q * 256;
                int row = c >> 2, ch = c & 3;
                cp16(toff + row * 64 + (uint32_t)((ch ^ ((row >> 1) & 3)) << 4),
                     src + (size_t)row * ld + ch * 8);
            }
        }
        cp_commit();
    };

    auto compute_stage = [&](int t) {
        uint32_t sb = sbase + (uint32_t)(t % 3) * STAGE;
#pragma unroll
        for (int kk = 0; kk < 32; kk += 16) {
            uint32_t bh[4][2], bl[4][2];
#pragma unroll
            for (int p = 0; p < 2; p++) {
                int rowB = wn + p * 16 + ((lane >> 4) << 3) + (lane & 7);
                int ch = (kk >> 3) + ((lane >> 3) & 1);
                uint32_t off = (uint32_t)rowB * 64 + (uint32_t)((ch ^ ((rowB >> 1) & 3)) << 4);
                uint32_t r[4];
                ldm_x4(sb + 16384 + off, r);
                bh[2 * p][0] = r[0]; bh[2 * p][1] = r[1];
                bh[2 * p + 1][0] = r[2]; bh[2 * p + 1][1] = r[3];
                ldm_x4(sb + 24576 + off, r);
                bl[2 * p][0] = r[0]; bl[2 * p][1] = r[1];
                bl[2 * p + 1][0] = r[2]; bl[2 * p + 1][1] = r[3];
            }
#pragma unroll
            for (int mt = 0; mt < 4; mt++) {
                int rowA = wm + mt * 16 + (lane & 15);
                int ch = (kk >> 3) + (lane >> 4);
                uint32_t off = (uint32_t)rowA * 64 + (uint32_t)((ch ^ ((rowA >> 1) & 3)) << 4);
                uint32_t ah[4], al[4];
                ldm_x4(sb + off, ah);
                ldm_x4(sb + 8192 + off, al);
#pragma unroll
                for (int nt = 0; nt < 4; nt++) {
                    mma16816(acc[mt][nt], ah, bh[nt]);
                    mma16816(acc[mt][nt], ah, bl[nt]);
                    mma16816(acc[mt][nt], al, bh[nt]);
                }
            }
        }
    };

    load_stage(0);
    if (tiles > 1) load_stage(1);
    for (int t = 0; t < tiles; t++) {
        if (t + 1 < tiles) cp_wait<1>(); else cp_wait<0>();
        __syncthreads();
        if (t + 2 < tiles) load_stage(t + 2);
        compute_stage(t);
    }

    if (Cf) {
#pragma unroll
        for (int mt = 0; mt < 4; mt++) {
#pragma unroll
            for (int nt = 0; nt < 4; nt++) {
                int r = r0 + wm + mt * 16 + (lane >> 2);
                int c = c0 + wn + nt * 8 + ((lane & 3) << 1);
                float* p0 = Cf + (size_t)r * ldc + c;
                float* p1 = p0 + 8 * ldc;
                p0[0] = acc[mt][nt][0]; p0[1] = acc[mt][nt][1];
                p1[0] = acc[mt][nt][2]; p1[1] = acc[mt][nt][3];
            }
        }
    } else {
#pragma unroll
        for (int mt = 0; mt < 4; mt++) {
#pragma unroll
            for (int nt = 0; nt < 4; nt++) {
                int r = r0 + wm + mt * 16 + (lane >> 2);
                int c = c0 + wn + nt * 8 + ((lane & 3) << 1);
                size_t o0 = (size_t)r * ldc + c;
                size_t o1 = o0 + (size_t)8 * ldc;
                float v0 = acc[mt][nt][0], v1 = acc[mt][nt][1];
                float v2 = acc[mt][nt][2], v3 = acc[mt][nt][3];
                float h0 = __bfloat162float(__float2bfloat16(v0));
                float h1 = __bfloat162float(__float2bfloat16(v1));
                float h2 = __bfloat162float(__float2bfloat16(v2));
                float h3 = __bfloat162float(__float2bfloat16(v3));
                *(uint32_t*)(Ch + o0) = pack_bf2(h0, h1);
                *(uint32_t*)(Ch + o1) = pack_bf2(h2, h3);
                *(uint32_t*)(Cl + o0) = pack_bf2(v0 - h0, v1 - h1);
                *(uint32_t*)(Cl + o1) = pack_bf2(v2 - h2, v3 - h3);
            }
        }
    }
}

// ---------------- fused flash attention ----------------
// Q from q2 (ld N2, col h*128); K from kv (ld KVLD, col h*128 or rope cols);
// V natural (s,d) from kv col 1792+h*128 via ldmatrix.trans.
#define FST 65536                  // stage: Khi 16K, Klo 16K, Vhi 16K, Vlo 16K
#define SMEM_FLASH (3*FST)

__global__ __launch_bounds__(256, 1)
void flash_attn(const bf16* __restrict__ q2h, const bf16* __restrict__ q2l,
                const bf16* __restrict__ kvh, const bf16* __restrict__ kvl,
                bf16* __restrict__ aoh, bf16* __restrict__ aol)
{
    extern __shared__ __align__(128) char smem[];
    int tid = threadIdx.x, lane = tid & 31, wid = tid >> 5;
    int z = blockIdx.y, bb = z >> 4, hh = z & 15;
    int r0 = ((int)gridDim.x - 1 - (int)blockIdx.x) * 128;   // big blocks first

    int kcol = (hh < NOPE) ? hh * DH : KVCOLS + (hh - NOPE) * DH;
    int vcol = KNOPE + hh * DH;

    const bf16* qhz = q2h + ((size_t)(bb * S_ + r0)) * N2 + hh * DH;
    const bf16* qlz = q2l + ((size_t)(bb * S_ + r0)) * N2 + hh * DH;
    const bf16* khz = kvh + (size_t)(bb * S_) * KVLD + kcol;
    const bf16* klz = kvl + (size_t)(bb * S_) * KVLD + kcol;
    const bf16* vhz = kvh + (size_t)(bb * S_) * KVLD + vcol;
    const bf16* vlz = kvl + (size_t)(bb * S_) * KVLD + vcol;

    uint32_t sb = smem_u32(smem);

    // stage Q (128 x 128 bf16, hi+lo) into buffer 0
#pragma unroll
    for (int q = 0; q < 8; q++) {
        int idx = tid + q * 256;
        int row = idx >> 4, ch = idx & 15;
        uint32_t off = (uint32_t)row * 256 + (uint32_t)((ch ^ (row & 7)) << 4);
        cp16(sb + off,         qhz + (size_t)row * N2 + ch * 8);
        cp16(sb + 32768 + off, qlz + (size_t)row * N2 + ch * 8);
    }
    cp_commit();

    int ntiles = (r0 >> 6) + 2;
    int diag = r0 >> 6;

    // stage t lives in buffer (t+1)%3; K and V both 64 rows x 128 cols
    auto load_stage = [&](int jt) {
        uint32_t st = sb + (uint32_t)((jt + 1) % 3) * FST;
        int s0 = jt * 64;
#pragma unroll
        for (int q = 0; q < 4; q++) {
            int idx = tid + q * 256;
            int row = idx >> 4, ch = idx & 15;
            uint32_t off = (uint32_t)row * 256 + (uint32_t)((ch ^ (row & 7)) << 4);
            size_t g = (size_t)(s0 + row) * KVLD + ch * 8;
            cp16(st + off,         khz + g);
            cp16(st + 16384 + off, klz + g);
        }
#pragma unroll
        for (int q = 0; q < 4; q++) {
            int idx = tid + q * 256;
            int row = idx >> 4, ch = idx & 15;
            uint32_t off = (uint32_t)row * 256 + (uint32_t)((ch ^ (row & 7)) << 4);
            size_t g = (size_t)(s0 + row) * KVLD + ch * 8;
            cp16(st + 32768 + off, vhz + g);
            cp16(st + 49152 + off, vlz + g);
        }
        cp_commit();
    };

    load_stage(0);
    load_stage(1);
    cp_wait<2>();           // Q complete
    __syncthreads();

    int wrow = wid * 16;
    uint32_t qah[8][4], qal[8][4];
#pragma unroll
    for (int kf = 0; kf < 8; kf++) {
        int row = wrow + (lane & 15);
        int ch = kf * 2 + (lane >> 4);
        uint32_t off = (uint32_t)row * 256 + (uint32_t)((ch ^ (row & 7)) << 4);
        ldm_x4(sb + off, qah[kf]);
        ldm_x4(sb + 32768 + off, qal[kf]);
    }

    float of[16][4];
#pragma unroll
    for (int i = 0; i < 16; i++)
#pragma unroll
        for (int v = 0; v < 4; v++) of[i][v] = 0.f;
    float m0 = -1e30f, m1 = -1e30f, l0 = 0.f, l1 = 0.f;
    const float CEXP = 0.08838834764831845f * 1.4426950408889634f;

    int rowa = r0 + wrow + (lane >> 2);

    for (int jt = 0; jt < ntiles; jt++) {
        if (jt + 1 < ntiles) cp_wait<1>(); else cp_wait<0>();
        __syncthreads();
        if (jt + 2 < ntiles) load_stage(jt + 2);
        uint32_t st = sb + (uint32_t)((jt + 1) % 3) * FST;

        // ---- S = Q @ K^T ----
        float sf[8][4];
#pragma unroll
        for (int nf = 0; nf < 8; nf++)
#pragma unroll
            for (int v = 0; v < 4; v++) sf[nf][v] = 0.f;

#pragma unroll
        for (int kf = 0; kf < 8; kf++) {
            uint32_t bh[8][2], bl[8][2];
#pragma unroll
            for (int p = 0; p < 4; p++) {
                int rowB = p * 16 + ((lane >> 4) << 3) + (lane & 7);
                int ch = kf * 2 + ((lane >> 3) & 1);
                uint32_t off = (uint32_t)rowB * 256 + (uint32_t)((ch ^ (rowB & 7)) << 4);
                uint32_t r4[4];
                ldm_x4(st + off, r4);
                bh[2 * p][0] = r4[0]; bh[2 * p][1] = r4[1];
                bh[2 * p + 1][0] = r4[2]; bh[2 * p + 1][1] = r4[3];
                ldm_x4(st + 16384 + off, r4);
                bl[2 * p][0] = r4[0]; bl[2 * p][1] = r4[1];
                bl[2 * p + 1][0] = r4[2]; bl[2 * p + 1][1] = r4[3];
            }
#pragma unroll
            for (int nf = 0; nf < 8; nf++) {
                mma16816(sf[nf], qah[kf], bh[nf]);
                mma16816(sf[nf], qah[kf], bl[nf]);
                mma16816(sf[nf], qal[kf], bh[nf]);
            }
        }

        // ---- causal mask on diagonal tiles ----
        if (jt >= diag) {
            int colb = jt * 64 + 2 * (lane & 3);
#pragma unroll
            for (int nf = 0; nf < 8; nf++) {
                int c = colb + nf * 8;
                if (c > rowa)     sf[nf][0] = -1e30f;
                if (c + 1 > rowa) sf[nf][1] = -1e30f;
                if (c > rowa + 8)     sf[nf][2] = -1e30f;
                if (c + 1 > rowa + 8) sf[nf][3] = -1e30f;
            }
        }

        // ---- online softmax ----
        float tm0 = -1e30f, tm1 = -1e30f;
#pragma unroll
        for (int nf = 0; nf < 8; nf++) {
            tm0 = fmaxf(tm0, fmaxf(sf[nf][0], sf[nf][1]));
            tm1 = fmaxf(tm1, fmaxf(sf[nf][2], sf[nf][3]));
        }
        tm0 = fmaxf(tm0, __shfl_xor_sync(0xffffffffu, tm0, 1));
        tm0 = fmaxf(tm0, __shfl_xor_sync(0xffffffffu, tm0, 2));
        tm1 = fmaxf(tm1, __shfl_xor_sync(0xffffffffu, tm1, 1));
        tm1 = fmaxf(tm1, __shfl_xor_sync(0xffffffffu, tm1, 2));
        float mn0 = fmaxf(m0, tm0), mn1 = fmaxf(m1, tm1);
        float al0 = exp2f((m0 - mn0) * CEXP), al1 = exp2f((m1 - mn1) * CEXP);
        m0 = mn0; m1 = mn1;

        uint32_t pah[4][4], pal[4][4];
        float rs0 = 0.f, rs1 = 0.f;
#pragma unroll
        for (int nf = 0; nf < 8; nf++) {
            float e0 = exp2f((sf[nf][0] - m0) * CEXP);
            float e1 = exp2f((sf[nf][1] - m0) * CEXP);
            float e2 = exp2f((sf[nf][2] - m1) * CEXP);
            float e3 = exp2f((sf[nf][3] - m1) * CEXP);
            rs0 += e0 + e1; rs1 += e2 + e3;
            float h0 = __bfloat162float(__float2bfloat16(e0));
            float h1 = __bfloat162float(__float2bfloat16(e1));
            float h2 = __bfloat162float(__float2bfloat16(e2));
            float h3 = __bfloat162float(__float2bfloat16(e3));
            int kf2 = nf >> 1, s = (nf & 1) * 2;
            pah[kf2][s]     = pack_bf2(h0, h1);
            pah[kf2][s + 1] = pack_bf2(h2, h3);
            pal[kf2][s]     = pack_bf2(e0 - h0, e1 - h1);
            pal[kf2][s + 1] = pack_bf2(e2 - h2, e3 - h3);
        }
        l0 = l0 * al0 + rs0;
        l1 = l1 * al1 + rs1;

#pragma unroll
        for (int i = 0; i < 16; i++) {
            of[i][0] *= al0; of[i][1] *= al0;
            of[i][2] *= al1; of[i][3] *= al1;
        }

        // ---- O += P @ V (V natural (s,d), ldmatrix.trans) ----
#pragma unroll
        for (int kf2 = 0; kf2 < 4; kf2++) {
#pragma unroll
            for (int nb = 0; nb < 8; nb++) {
                int row = kf2 * 16 + (lane & 15);
                int ch = nb * 2 + (lane >> 4);
                uint32_t off = (uint32_t)row * 256 + (uint32_t)((ch ^ (row & 7)) << 4);
                uint32_t rh[4], rl[4];
                ldm_x4_t(st + 32768 + off, rh);
                ldm_x4_t(st + 49152 + off, rl);
                uint32_t bh0[2] = {rh[0], rh[1]}, bh1[2] = {rh[2], rh[3]};
                uint32_t bl0[2] = {rl[0], rl[1]}, bl1[2] = {rl[2], rl[3]};
                mma16816(of[2 * nb],     pah[kf2], bh0);
                mma16816(of[2 * nb],     pah[kf2], bl0);
                mma16816(of[2 * nb],     pal[kf2], bh0);
                mma16816(of[2 * nb + 1], pah[kf2], bh1);
                mma16816(of[2 * nb + 1], pah[kf2], bl1);
                mma16816(of[2 * nb + 1], pal[kf2], bh1);
            }
        }
    }

    l0 += __shfl_xor_sync(0xffffffffu, l0, 1);
    l0 += __shfl_xor_sync(0xffffffffu, l0, 2);
    l1 += __shfl_xor_sync(0xffffffffu, l1, 1);
    l1 += __shfl_xor_sync(0xffffffffu, l1, 2);
    float inv0 = 1.f / l0, inv1 = 1.f / l1;

    size_t ga = ((size_t)(bb * S_) + rowa) * DMODEL + hh * DH;
    size_t gb = ga + (size_t)8 * DMODEL;
#pragma unroll
    for (int i = 0; i < 16; i++) {
        int d = i * 8 + 2 * (lane & 3);
        float v0 = of[i][0] * inv0, v1 = of[i][1] * inv0;
        float v2 = of[i][2] * inv1, v3 = of[i][3] * inv1;
        float h0 = __bfloat162float(__float2bfloat16(v0));
        float h1 = __bfloat162float(__float2bfloat16(v1));
        float h2 = __bfloat162float(__float2bfloat16(v2));
        float h3 = __bfloat162float(__float2bfloat16(v3));
        *(uint32_t*)(aoh + ga + d) = pack_bf2(h0, h1);
        *(uint32_t*)(aoh + gb + d) = pack_bf2(h2, h3);
        *(uint32_t*)(aol + ga + d) = pack_bf2(v0 - h0, v1 - h1);
        *(uint32_t*)(aol + gb + d) = pack_bf2(v2 - h2, v3 - h3);
    }
}

// ---------------- elementwise kernels ----------------
__global__ __launch_bounds__(256)
void split_plain(const float* __restrict__ in, bf16* __restrict__ hi, bf16* __restrict__ lo,
                 int R, int C, int Cpad)
{
    size_t idx = (size_t)blockIdx.x * 256 + threadIdx.x;
    if (idx >= (size_t)R * Cpad) return;
    int c = (int)(idx % Cpad);
    size_t r = idx / Cpad;
    float v = (c < C) ? in[r * C + c] : 0.f;
    split2(v, hi[idx], lo[idx]);
}

__global__ __launch_bounds__(256)
void transpose_split(const float* __restrict__ in, bf16* __restrict__ hi, bf16* __restrict__ lo,
                     int K, int N, int Npad, int Kpad, int rowOff)
{
    __shared__ float t[32][33];
    int k0 = blockIdx.x * 32, n0 = blockIdx.y * 32;
    int tx = threadIdx.x, ty = threadIdx.y;
#pragma unroll
    for (int i = 0; i < 4; i++) {
        int k = k0 + ty + i * 8;
        float v = (k < K && n0 + tx < N) ? in[(size_t)k * N + n0 + tx] : 0.f;
        t[ty + i * 8][tx] = v;
    }
    __syncthreads();
#pragma unroll
    for (int i = 0; i < 4; i++) {
        int n = n0 + ty + i * 8, k = k0 + tx;
        if (n < Npad && k < Kpad) {
            size_t o = (size_t)(n + rowOff) * Kpad + k;
            split2(t[tx][ty + i * 8], hi[o], lo[o]);
        }
    }
}

__global__ __launch_bounds__(256)
void layernorm_split(const float* __restrict__ X, int xld,
                     float* __restrict__ outf, int ofld,
                     bf16* __restrict__ hi, bf16* __restrict__ lo,
                     const float* __restrict__ w, const float* __restrict__ b,
                     int n, int npad)
{
    const float* p = X + (size_t)blockIdx.x * xld;
    float s = 0.f, s2 = 0.f;
    for (int j = threadIdx.x; j < n; j += 256) {
        float v = p[j];
        s += v; s2 += v * v;
    }
    __shared__ float sh[20];
#pragma unroll
    for (int o = 16; o; o >>= 1) {
        s  += __shfl_down_sync(0xffffffffu, s,  o);
        s2 += __shfl_down_sync(0xffffffffu, s2, o);
    }
    int wd = threadIdx.x >> 5, ln = threadIdx.x & 31;
    if (!ln) { sh[wd] = s; sh[wd + 8] = s2; }
    __syncthreads();
    if (threadIdx.x == 0) {
        float ts = 0.f, ts2 = 0.f;
        for (int i = 0; i < 8; i++) { ts += sh[i]; ts2 += sh[i + 8]; }
        float mean = ts / n;
        float var = fmaxf(ts2 / n - mean * mean, 0.f);
        sh[16] = mean;
        sh[17] = rsqrtf(var + 1e-5f);
    }
    __syncthreads();
    float mean = sh[16], rstd = sh[17];
    float* of = outf ? outf + (size_t)blockIdx.x * ofld : nullptr;
    bf16* hh = hi + (size_t)blockIdx.x * npad;
    bf16* ll = lo + (size_t)blockIdx.x * npad;
    for (int j = threadIdx.x; j < npad; j += 256) {
        float v = 0.f;
        if (j < n) {
            v = (p[j] - mean) * rstd * w[j] + b[j];
            if (of) of[j] = v;
        }
        split2(v, hh[j], ll[j]);
    }
}

// in-place RoPE on q2 hi/lo cols [KNOPE, KNOPE+256)
__global__ __launch_bounds__(256)
void rope_q(bf16* __restrict__ hi, bf16* __restrict__ lo)
{
    int idx = blockIdx.x * 256 + threadIdx.x;
    if (idx >= BS * 2 * 64) return;
    int dp = idx & 63;
    int h2 = (idx >> 6) & 1;
    int row = idx >> 7;
    int s = row & (S_ - 1);
    size_t base = (size_t)row * N2 + KNOPE + h2 * DH;
    float x1 = __bfloat162float(hi[base + dp]) + __bfloat162float(lo[base + dp]);
    float x2 = __bfloat162float(hi[base + dp + 64]) + __bfloat162float(lo[base + dp + 64]);
    float freq = 1.0f / powf(10000.0f, (float)dp * (1.0f / 64.0f));
    float sn, cs;
    sincosf((float)s * freq, &sn, &cs);
    float v1 = x1 * cs - x2 * sn;
    float v2 = x2 * cs + x1 * sn;
    split2(v1, hi[base + dp], lo[base + dp]);
    split2(v2, hi[base + dp + 64], lo[base + dp + 64]);
}

// RoPE K: read p1 fp32 cols [2432,2688), write kv hi/lo cols [3840,4096)
__global__ __launch_bounds__(256)
void rope_k(const float* __restrict__ p1, bf16* __restrict__ hi, bf16* __restrict__ lo)
{
    int idx = blockIdx.x * 256 + threadIdx.x;
    if (idx >= BS * 2 * 64) return;
    int dp = idx & 63;
    int h2 = (idx >> 6) & 1;
    int row = idx >> 7;
    int s = row & (S_ - 1);
    const float* src = p1 + (size_t)row * N1 + 2432 + h2 * DH;
    float x1 = src[dp], x2 = src[dp + 64];
    float freq = 1.0f / powf(10000.0f, (float)dp * (1.0f / 64.0f));
    float sn, cs;
    sincosf((float)s * freq, &sn, &cs);
    float v1 = x1 * cs - x2 * sn;
    float v2 = x2 * cs + x1 * sn;
    size_t base = (size_t)row * KVLD + KVCOLS + h2 * DH;
    split2(v1, hi[base + dp], lo[base + dp]);
    split2(v2, hi[base + dp + 64], lo[base + dp + 64]);
}

// ---------------- launch ----------------
static inline void* sym(const void* s) { void* p; cudaGetSymbolAddress(&p, s); return p; }

extern "C" void kernel_launch(void* const* d_in, const int* in_sizes, int n_in,
                              void* d_out, int out_size)
{
    const float* x     = (const float*)d_in[0];
    const float* W_dq  = (const float*)d_in[1];
    const float* W_uq  = (const float*)d_in[2];
    const float* W_qr  = (const float*)d_in[3];
    const float* W_dkv = (const float*)d_in[4];
    const float* W_ukv = (const float*)d_in[5];
    const float* W_kr  = (const float*)d_in[6];
    const float* W_o   = (const float*)d_in[7];
    const float* q_w   = (const float*)d_in[8];
    const float* q_b   = (const float*)d_in[9];
    const float* kv_w  = (const float*)d_in[10];
    const float* kv_b  = (const float*)d_in[11];

    float* out = (float*)d_out;
    float* ckv = out + (size_t)BS * DMODEL;

    bf16 *xhi=(bf16*)sym(g_xhi), *xlo=(bf16*)sym(g_xlo);
    bf16 *w1h=(bf16*)sym(g_w1h), *w1l=(bf16*)sym(g_w1l);
    bf16 *w2h=(bf16*)sym(g_w2h), *w2l=(bf16*)sym(g_w2l);
    bf16 *wukvh=(bf16*)sym(g_wukvh), *wukvl=(bf16*)sym(g_wukvl);
    bf16 *woh=(bf16*)sym(g_woh), *wol=(bf16*)sym(g_wol);
    float *p1=(float*)sym(g_p1);
    bf16 *cqh=(bf16*)sym(g_cqh), *cql=(bf16*)sym(g_cql);
    bf16 *ckvh=(bf16*)sym(g_ckvh), *ckvl=(bf16*)sym(g_ckvl);
    bf16 *q2h=(bf16*)sym(g_q2h), *q2l=(bf16*)sym(g_q2l);
    bf16 *kvh=(bf16*)sym(g_kvh), *kvl=(bf16*)sym(g_kvl);
    bf16 *aoh=(bf16*)sym(g_aoh), *aol=(bf16*)sym(g_aol);

    cudaFuncSetAttribute(hmma_gemm, cudaFuncAttributeMaxDynamicSharedMemorySize, SMEM_GEMM);
    cudaFuncSetAttribute(flash_attn, cudaFuncAttributeMaxDynamicSharedMemorySize, SMEM_FLASH);

    // --- input conversions ---
    split_plain<<<(unsigned)(((size_t)BS*DMODEL + 255)/256), 256>>>(x, xhi, xlo, BS, DMODEL, DMODEL);
    split_plain<<<(unsigned)(((size_t)DMODEL*DMODEL + 255)/256), 256>>>(W_o, woh, wol, DMODEL, DMODEL, DMODEL);
    transpose_split<<<dim3(DMODEL/32, QPROJ/32),  dim3(32,8)>>>(W_dq,  w1h, w1l, DMODEL, QPROJ,  QPROJ,  DMODEL, 0);
    transpose_split<<<dim3(DMODEL/32, KVPAD/32),  dim3(32,8)>>>(W_dkv, w1h, w1l, DMODEL, KVPROJ, KVPAD,  DMODEL, QPROJ);
    transpose_split<<<dim3(DMODEL/32, 256/32),    dim3(32,8)>>>(W_kr,  w1h, w1l, DMODEL, 256,    256,    DMODEL, QPROJ + KVPAD);
    transpose_split<<<dim3(QPROJ/32,  KNOPE/32),  dim3(32,8)>>>(W_uq,  w2h, w2l, QPROJ,  KNOPE,  KNOPE,  QPROJ, 0);
    transpose_split<<<dim3(QPROJ/32,  256/32),    dim3(32,8)>>>(W_qr,  w2h, w2l, QPROJ,  256,    256,    QPROJ, KNOPE);
    transpose_split<<<dim3(KVPAD/32,  KVCOLS/32), dim3(32,8)>>>(W_ukv, wukvh, wukvl, KVPROJ, KVCOLS, KVCOLS, KVPAD, 0);

    // --- fused projection 1: p1 = x @ [W_dq | W_dkv | W_kr] (fp32) ---
    hmma_gemm<<<dim3(N1/128, BS/128), 256, SMEM_GEMM>>>(
        xhi, xlo, w1h, w1l, p1, nullptr, nullptr, N1, DMODEL, DMODEL, DMODEL, N1);

    // --- LayerNorms ---
    layernorm_split<<<BS, 256>>>(p1, N1, nullptr, 0, cqh, cql, q_w, q_b, QPROJ, QPROJ);
    layernorm_split<<<BS, 256>>>(p1 + QPROJ, N1, ckv, KVPROJ, ckvh, ckvl, kv_w, kv_b, KVPROJ, KVPAD);

    // --- fused projection 2: q2 = cq @ [W_uq | W_qr]  (split bf16) ---
    hmma_gemm<<<dim3(N2/128, BS/128), 256, SMEM_GEMM>>>(
        cqh, cql, w2h, w2l, nullptr, q2h, q2l, N2, QPROJ, QPROJ, QPROJ, N2);

    // --- KV decompress: kv = ckv @ W_ukv  (split bf16, ld KVLD) ---
    hmma_gemm<<<dim3(KVCOLS/128, BS/128), 256, SMEM_GEMM>>>(
        ckvh, ckvl, wukvh, wukvl, nullptr, kvh, kvl, KVCOLS, KVPAD, KVPAD, KVPAD, KVLD);

    // --- RoPE on the 2 rope heads ---
    rope_q<<<(BS*2*64 + 255)/256, 256>>>(q2h, q2l);
    rope_k<<<(BS*2*64 + 255)/256, 256>>>(p1, kvh, kvl);

    // --- fused flash attention ---
    flash_attn<<<dim3(S_/128, NZ), 256, SMEM_FLASH>>>(q2h, q2l, kvh, kvl, aoh, aol);

    // --- final projection ---
    hmma_gemm<<<dim3(DMODEL/128, BS/128), 256, SMEM_GEMM>>>(
        aoh, aol, woh, wol, out, nullptr, nullptr, DMODEL, DMODEL, DMODEL, DMODEL, DMODEL);
}

// round 7
// speedup vs baseline: 5.5299x; 1.1486x over previous
#include <cuda_runtime.h>
#include <cuda_bf16.h>
#include <cstdint>
#include <math.h>

// ---------------- problem constants ----------------
#define B_      2
#define S_      2048
#define DMODEL  2048
#define NH      16
#define DH      128
#define NOPE    14
#define QPROJ   1024
#define KVPROJ  1365
#define KVPAD   1408
#define KNOPE   1792
#define KVCOLS  3840
#define KVLD    4096
#define BS      (B_*S_)
#define NZ      (B_*NH)
#define N1      2688
#define N2      2048

typedef __nv_bfloat16 bf16;

// ---------------- device scratch ----------------
__device__ bf16 g_xhi[(size_t)BS*DMODEL],   g_xlo[(size_t)BS*DMODEL];
__device__ bf16 g_w1h[(size_t)N1*DMODEL],   g_w1l[(size_t)N1*DMODEL];
__device__ bf16 g_w2h[(size_t)N2*QPROJ],    g_w2l[(size_t)N2*QPROJ];
__device__ bf16 g_wukvh[(size_t)KVCOLS*KVPAD], g_wukvl[(size_t)KVCOLS*KVPAD];
__device__ bf16 g_woh[(size_t)DMODEL*DMODEL],  g_wol[(size_t)DMODEL*DMODEL];
__device__ float g_p1[(size_t)BS*N1];
__device__ bf16 g_cqh[(size_t)BS*QPROJ],    g_cql[(size_t)BS*QPROJ];
__device__ bf16 g_ckvh[(size_t)BS*KVPAD],   g_ckvl[(size_t)BS*KVPAD];
__device__ bf16 g_q2h[(size_t)BS*N2],       g_q2l[(size_t)BS*N2];
__device__ bf16 g_kvh[(size_t)BS*KVLD],     g_kvl[(size_t)BS*KVLD];
__device__ bf16 g_aoh[(size_t)BS*DMODEL],   g_aol[(size_t)BS*DMODEL];

// ---------------- helpers ----------------
__device__ __forceinline__ uint32_t smem_u32(const void* p) {
    uint32_t a;
    asm("{ .reg .u64 t; cvta.to.shared.u64 t, %1; cvt.u32.u64 %0, t; }" : "=r"(a) : "l"(p));
    return a;
}
__device__ __forceinline__ void cp16(uint32_t saddr, const void* g) {
    asm volatile("cp.async.cg.shared.global [%0], [%1], 16;" :: "r"(saddr), "l"(g) : "memory");
}
__device__ __forceinline__ void cp_commit() {
    asm volatile("cp.async.commit_group;" ::: "memory");
}
template<int N> __device__ __forceinline__ void cp_wait() {
    asm volatile("cp.async.wait_group %0;" :: "n"(N) : "memory");
}
__device__ __forceinline__ void ldm_x4(uint32_t addr, uint32_t* r) {
    asm volatile("ldmatrix.sync.aligned.m8n8.x4.shared.b16 {%0,%1,%2,%3}, [%4];"
        : "=r"(r[0]), "=r"(r[1]), "=r"(r[2]), "=r"(r[3]) : "r"(addr));
}
__device__ __forceinline__ void ldm_x4_t(uint32_t addr, uint32_t* r) {
    asm volatile("ldmatrix.sync.aligned.m8n8.x4.trans.shared.b16 {%0,%1,%2,%3}, [%4];"
        : "=r"(r[0]), "=r"(r[1]), "=r"(r[2]), "=r"(r[3]) : "r"(addr));
}
__device__ __forceinline__ void mma16816(float* d, const uint32_t* a, const uint32_t* b) {
    asm volatile("mma.sync.aligned.m16n8k16.row.col.f32.bf16.bf16.f32 "
        "{%0,%1,%2,%3}, {%4,%5,%6,%7}, {%8,%9}, {%0,%1,%2,%3};"
        : "+f"(d[0]), "+f"(d[1]), "+f"(d[2]), "+f"(d[3])
        : "r"(a[0]), "r"(a[1]), "r"(a[2]), "r"(a[3]), "r"(b[0]), "r"(b[1]));
}
__device__ __forceinline__ void split2(float v, bf16& h, bf16& l) {
    h = __float2bfloat16(v);
    l = __float2bfloat16(v - __bfloat162float(h));
}
__device__ __forceinline__ uint32_t pack_bf2(float a, float b) {
    __nv_bfloat162 t = __floats2bfloat162_rn(a, b);
    return *(uint32_t*)&t;
}

// ---------------- GEMM core: C = A @ B^T, BK=64, 3-stage ----------------
#define STAGE 65536
#define SMEM_GEMM (3*STAGE)

__device__ __forceinline__ void gemm_core(
    const bf16* __restrict__ Ahi, const bf16* __restrict__ Alo,
    const bf16* __restrict__ Bhi, const bf16* __restrict__ Blo,
    float* __restrict__ Cf, bf16* __restrict__ Ch, bf16* __restrict__ Cl,
    int N, int Kpad, int lda, int ldb, int ldc,
    int r0, int c0, char* smem)
{
    int tid = threadIdx.x, lane = tid & 31, wid = tid >> 5;
    int tiles = Kpad >> 6;

    const bf16* Ah = Ahi + (size_t)r0 * lda;
    const bf16* Al = Alo + (size_t)r0 * lda;
    const bf16* Bh = Bhi + (size_t)c0 * ldb;
    const bf16* Bl = Blo + (size_t)c0 * ldb;

    uint32_t sbase = smem_u32(smem);
    int wm = (wid >> 2) * 64, wn = (wid & 3) * 32;

    float acc[4][4][4];
#pragma unroll
    for (int i = 0; i < 4; i++)
#pragma unroll
        for (int j = 0; j < 4; j++)
#pragma unroll
            for (int v = 0; v < 4; v++) acc[i][j][v] = 0.f;

    // stage layout: Ah 0, Al 16K, Bh 32K, Bl 48K; 128 rows x 128B, 8 chunks xor-swizzled
    auto load_stage = [&](int t) {
        int k0 = t << 6;
        uint32_t sb = sbase + (uint32_t)(t % 3) * STAGE;
#pragma unroll
        for (int q = 0; q < 4; q++) {
            int idx = tid + q * 256;
            int row = idx >> 3, ch = idx & 7;
            uint32_t off = (uint32_t)row * 128 + (uint32_t)((ch ^ (row & 7)) << 4);
            size_t ga = (size_t)row * lda + k0 + ch * 8;
            size_t gb = (size_t)row * ldb + k0 + ch * 8;
            cp16(sb + off,         Ah + ga);
            cp16(sb + 16384 + off, Al + ga);
            cp16(sb + 32768 + off, Bh + gb);
            cp16(sb + 49152 + off, Bl + gb);
        }
        cp_commit();
    };

    auto compute_stage = [&](int t) {
        uint32_t sb = sbase + (uint32_t)(t % 3) * STAGE;
#pragma unroll
        for (int kk = 0; kk < 64; kk += 16) {
            uint32_t bh[4][2], bl[4][2];
#pragma unroll
            for (int p = 0; p < 2; p++) {
                int rowB = wn + p * 16 + ((lane >> 4) << 3) + (lane & 7);
                int ch = (kk >> 3) + ((lane >> 3) & 1);
                uint32_t off = (uint32_t)rowB * 128 + (uint32_t)((ch ^ (rowB & 7)) << 4);
                uint32_t r[4];
                ldm_x4(sb + 32768 + off, r);
                bh[2 * p][0] = r[0]; bh[2 * p][1] = r[1];
                bh[2 * p + 1][0] = r[2]; bh[2 * p + 1][1] = r[3];
                ldm_x4(sb + 49152 + off, r);
                bl[2 * p][0] = r[0]; bl[2 * p][1] = r[1];
                bl[2 * p + 1][0] = r[2]; bl[2 * p + 1][1] = r[3];
            }
#pragma unroll
            for (int mt = 0; mt < 4; mt++) {
                int rowA = wm + mt * 16 + (lane & 15);
                int ch = (kk >> 3) + (lane >> 4);
                uint32_t off = (uint32_t)rowA * 128 + (uint32_t)((ch ^ (rowA & 7)) << 4);
                uint32_t ah[4], al[4];
                ldm_x4(sb + off, ah);
                ldm_x4(sb + 16384 + off, al);
#pragma unroll
                for (int nt = 0; nt < 4; nt++) {
                    mma16816(acc[mt][nt], ah, bh[nt]);
                    mma16816(acc[mt][nt], ah, bl[nt]);
                    mma16816(acc[mt][nt], al, bh[nt]);
                }
            }
        }
    };

    load_stage(0);
    if (tiles > 1) load_stage(1);
    for (int t = 0; t < tiles; t++) {
        if (t + 1 < tiles) cp_wait<1>(); else cp_wait<0>();
        __syncthreads();
        if (t + 2 < tiles) load_stage(t + 2);
        compute_stage(t);
        __syncthreads();
    }

    if (Cf) {
#pragma unroll
        for (int mt = 0; mt < 4; mt++) {
#pragma unroll
            for (int nt = 0; nt < 4; nt++) {
                int r = r0 + wm + mt * 16 + (lane >> 2);
                int c = c0 + wn + nt * 8 + ((lane & 3) << 1);
                float* p0 = Cf + (size_t)r * ldc + c;
                float* p1 = p0 + 8 * ldc;
                p0[0] = acc[mt][nt][0]; p0[1] = acc[mt][nt][1];
                p1[0] = acc[mt][nt][2]; p1[1] = acc[mt][nt][3];
            }
        }
    } else {
#pragma unroll
        for (int mt = 0; mt < 4; mt++) {
#pragma unroll
            for (int nt = 0; nt < 4; nt++) {
                int r = r0 + wm + mt * 16 + (lane >> 2);
                int c = c0 + wn + nt * 8 + ((lane & 3) << 1);
                size_t o0 = (size_t)r * ldc + c;
                size_t o1 = o0 + (size_t)8 * ldc;
                float v0 = acc[mt][nt][0], v1 = acc[mt][nt][1];
                float v2 = acc[mt][nt][2], v3 = acc[mt][nt][3];
                float h0 = __bfloat162float(__float2bfloat16(v0));
                float h1 = __bfloat162float(__float2bfloat16(v1));
                float h2 = __bfloat162float(__float2bfloat16(v2));
                float h3 = __bfloat162float(__float2bfloat16(v3));
                *(uint32_t*)(Ch + o0) = pack_bf2(h0, h1);
                *(uint32_t*)(Ch + o1) = pack_bf2(h2, h3);
                *(uint32_t*)(Cl + o0) = pack_bf2(v0 - h0, v1 - h1);
                *(uint32_t*)(Cl + o1) = pack_bf2(v2 - h2, v3 - h3);
            }
        }
    }
}

__global__ __launch_bounds__(256, 1)
void hmma_gemm(const bf16* __restrict__ Ahi, const bf16* __restrict__ Alo,
               const bf16* __restrict__ Bhi, const bf16* __restrict__ Blo,
               float* __restrict__ Cf, bf16* __restrict__ Ch, bf16* __restrict__ Cl,
               int N, int Kpad, int lda, int ldb, int ldc)
{
    extern __shared__ __align__(128) char smem[];
    gemm_core(Ahi, Alo, Bhi, Blo, Cf, Ch, Cl, N, Kpad, lda, ldb, ldc,
              blockIdx.y * 128, blockIdx.x * 128, smem);
}

// two independent GEMMs in one launch (flat grid): [0,split) -> GEMM1, rest -> GEMM2
__global__ __launch_bounds__(256, 1)
void hmma_gemm_dual(
    const bf16* A1h, const bf16* A1l, const bf16* B1h, const bf16* B1l,
    bf16* C1h, bf16* C1l, int n1, int k1, int la1, int lb1, int lc1, int gx1,
    const bf16* A2h, const bf16* A2l, const bf16* B2h, const bf16* B2l,
    bf16* C2h, bf16* C2l, int n2, int k2, int la2, int lb2, int lc2, int gx2,
    int split)
{
    extern __shared__ __align__(128) char smem[];
    int idx = blockIdx.x;
    if (idx < split) {
        int cx = idx % gx1, cy = idx / gx1;
        gemm_core(A1h, A1l, B1h, B1l, nullptr, C1h, C1l, n1, k1, la1, lb1, lc1,
                  cy * 128, cx * 128, smem);
    } else {
        idx -= split;
        int cx = idx % gx2, cy = idx / gx2;
        gemm_core(A2h, A2l, B2h, B2l, nullptr, C2h, C2l, n2, k2, la2, lb2, lc2,
                  cy * 128, cx * 128, smem);
    }
}

// ---------------- fused flash attention ----------------
#define FST 65536
#define SMEM_FLASH (3*FST)

__global__ __launch_bounds__(256, 1)
void flash_attn(const bf16* __restrict__ q2h, const bf16* __restrict__ q2l,
                const bf16* __restrict__ kvh, const bf16* __restrict__ kvl,
                bf16* __restrict__ aoh, bf16* __restrict__ aol)
{
    extern __shared__ __align__(128) char smem[];
    int tid = threadIdx.x, lane = tid & 31, wid = tid >> 5;
    int z = blockIdx.y, bb = z >> 4, hh = z & 15;
    int r0 = ((int)gridDim.x - 1 - (int)blockIdx.x) * 128;

    int kcol = (hh < NOPE) ? hh * DH : KVCOLS + (hh - NOPE) * DH;
    int vcol = KNOPE + hh * DH;

    const bf16* qhz = q2h + ((size_t)(bb * S_ + r0)) * N2 + hh * DH;
    const bf16* qlz = q2l + ((size_t)(bb * S_ + r0)) * N2 + hh * DH;
    const bf16* khz = kvh + (size_t)(bb * S_) * KVLD + kcol;
    const bf16* klz = kvl + (size_t)(bb * S_) * KVLD + kcol;
    const bf16* vhz = kvh + (size_t)(bb * S_) * KVLD + vcol;
    const bf16* vlz = kvl + (size_t)(bb * S_) * KVLD + vcol;

    uint32_t sb = smem_u32(smem);

#pragma unroll
    for (int q = 0; q < 8; q++) {
        int idx = tid + q * 256;
        int row = idx >> 4, ch = idx & 15;
        uint32_t off = (uint32_t)row * 256 + (uint32_t)((ch ^ (row & 7)) << 4);
        cp16(sb + off,         qhz + (size_t)row * N2 + ch * 8);
        cp16(sb + 32768 + off, qlz + (size_t)row * N2 + ch * 8);
    }
    cp_commit();

    int ntiles = (r0 >> 6) + 2;
    int diag = r0 >> 6;

    auto load_stage = [&](int jt) {
        uint32_t st = sb + (uint32_t)((jt + 1) % 3) * FST;
        int s0 = jt * 64;
#pragma unroll
        for (int q = 0; q < 4; q++) {
            int idx = tid + q * 256;
            int row = idx >> 4, ch = idx & 15;
            uint32_t off = (uint32_t)row * 256 + (uint32_t)((ch ^ (row & 7)) << 4);
            size_t g = (size_t)(s0 + row) * KVLD + ch * 8;
            cp16(st + off,         khz + g);
            cp16(st + 16384 + off, klz + g);
        }
#pragma unroll
        for (int q = 0; q < 4; q++) {
            int idx = tid + q * 256;
            int row = idx >> 4, ch = idx & 15;
            uint32_t off = (uint32_t)row * 256 + (uint32_t)((ch ^ (row & 7)) << 4);
            size_t g = (size_t)(s0 + row) * KVLD + ch * 8;
            cp16(st + 32768 + off, vhz + g);
            cp16(st + 49152 + off, vlz + g);
        }
        cp_commit();
    };

    load_stage(0);
    load_stage(1);
    cp_wait<2>();
    __syncthreads();

    int wrow = wid * 16;
    uint32_t qah[8][4], qal[8][4];
#pragma unroll
    for (int kf = 0; kf < 8; kf++) {
        int row = wrow + (lane & 15);
        int ch = kf * 2 + (lane >> 4);
        uint32_t off = (uint32_t)row * 256 + (uint32_t)((ch ^ (row & 7)) << 4);
        ldm_x4(sb + off, qah[kf]);
        ldm_x4(sb + 32768 + off, qal[kf]);
    }

    float of[16][4];
#pragma unroll
    for (int i = 0; i < 16; i++)
#pragma unroll
        for (int v = 0; v < 4; v++) of[i][v] = 0.f;
    float m0 = -1e30f, m1 = -1e30f, l0 = 0.f, l1 = 0.f;
    const float CEXP = 0.08838834764831845f * 1.4426950408889634f;

    int rowa = r0 + wrow + (lane >> 2);

    for (int jt = 0; jt < ntiles; jt++) {
        if (jt + 1 < ntiles) cp_wait<1>(); else cp_wait<0>();
        __syncthreads();
        if (jt + 2 < ntiles) load_stage(jt + 2);
        uint32_t st = sb + (uint32_t)((jt + 1) % 3) * FST;

        float sf[8][4];
#pragma unroll
        for (int nf = 0; nf < 8; nf++)
#pragma unroll
            for (int v = 0; v < 4; v++) sf[nf][v] = 0.f;

#pragma unroll
        for (int kf = 0; kf < 8; kf++) {
            uint32_t bh[8][2], bl[8][2];
#pragma unroll
            for (int p = 0; p < 4; p++) {
                int rowB = p * 16 + ((lane >> 4) << 3) + (lane & 7);
                int ch = kf * 2 + ((lane >> 3) & 1);
                uint32_t off = (uint32_t)rowB * 256 + (uint32_t)((ch ^ (rowB & 7)) << 4);
                uint32_t r4[4];
                ldm_x4(st + off, r4);
                bh[2 * p][0] = r4[0]; bh[2 * p][1] = r4[1];
                bh[2 * p + 1][0] = r4[2]; bh[2 * p + 1][1] = r4[3];
                ldm_x4(st + 16384 + off, r4);
                bl[2 * p][0] = r4[0]; bl[2 * p][1] = r4[1];
                bl[2 * p + 1][0] = r4[2]; bl[2 * p + 1][1] = r4[3];
            }
#pragma unroll
            for (int nf = 0; nf < 8; nf++) {
                mma16816(sf[nf], qah[kf], bh[nf]);
                mma16816(sf[nf], qah[kf], bl[nf]);
                mma16816(sf[nf], qal[kf], bh[nf]);
            }
        }

        if (jt >= diag) {
            int colb = jt * 64 + 2 * (lane & 3);
#pragma unroll
            for (int nf = 0; nf < 8; nf++) {
                int c = colb + nf * 8;
                if (c > rowa)     sf[nf][0] = -1e30f;
                if (c + 1 > rowa) sf[nf][1] = -1e30f;
                if (c > rowa + 8)     sf[nf][2] = -1e30f;
                if (c + 1 > rowa + 8) sf[nf][3] = -1e30f;
            }
        }

        float tm0 = -1e30f, tm1 = -1e30f;
#pragma unroll
        for (int nf = 0; nf < 8; nf++) {
            tm0 = fmaxf(tm0, fmaxf(sf[nf][0], sf[nf][1]));
            tm1 = fmaxf(tm1, fmaxf(sf[nf][2], sf[nf][3]));
        }
        tm0 = fmaxf(tm0, __shfl_xor_sync(0xffffffffu, tm0, 1));
        tm0 = fmaxf(tm0, __shfl_xor_sync(0xffffffffu, tm0, 2));
        tm1 = fmaxf(tm1, __shfl_xor_sync(0xffffffffu, tm1, 1));
        tm1 = fmaxf(tm1, __shfl_xor_sync(0xffffffffu, tm1, 2));
        float mn0 = fmaxf(m0, tm0), mn1 = fmaxf(m1, tm1);
        float al0 = exp2f((m0 - mn0) * CEXP), al1 = exp2f((m1 - mn1) * CEXP);
        m0 = mn0; m1 = mn1;

        uint32_t pah[4][4], pal[4][4];
        float rs0 = 0.f, rs1 = 0.f;
#pragma unroll
        for (int nf = 0; nf < 8; nf++) {
            float e0 = exp2f((sf[nf][0] - m0) * CEXP);
            float e1 = exp2f((sf[nf][1] - m0) * CEXP);
            float e2 = exp2f((sf[nf][2] - m1) * CEXP);
            float e3 = exp2f((sf[nf][3] - m1) * CEXP);
            rs0 += e0 + e1; rs1 += e2 + e3;
            float h0 = __bfloat162float(__float2bfloat16(e0));
            float h1 = __bfloat162float(__float2bfloat16(e1));
            float h2 = __bfloat162float(__float2bfloat16(e2));
            float h3 = __bfloat162float(__float2bfloat16(e3));
            int kf2 = nf >> 1, s = (nf & 1) * 2;
            pah[kf2][s]     = pack_bf2(h0, h1);
            pah[kf2][s + 1] = pack_bf2(h2, h3);
            pal[kf2][s]     = pack_bf2(e0 - h0, e1 - h1);
            pal[kf2][s + 1] = pack_bf2(e2 - h2, e3 - h3);
        }
        l0 = l0 * al0 + rs0;
        l1 = l1 * al1 + rs1;

#pragma unroll
        for (int i = 0; i < 16; i++) {
            of[i][0] *= al0; of[i][1] *= al0;
            of[i][2] *= al1; of[i][3] *= al1;
        }

#pragma unroll
        for (int kf2 = 0; kf2 < 4; kf2++) {
#pragma unroll
            for (int nb = 0; nb < 8; nb++) {
                int row = kf2 * 16 + (lane & 15);
                int ch = nb * 2 + (lane >> 4);
                uint32_t off = (uint32_t)row * 256 + (uint32_t)((ch ^ (row & 7)) << 4);
                uint32_t rh[4], rl[4];
                ldm_x4_t(st + 32768 + off, rh);
                ldm_x4_t(st + 49152 + off, rl);
                uint32_t bh0[2] = {rh[0], rh[1]}, bh1[2] = {rh[2], rh[3]};
                uint32_t bl0[2] = {rl[0], rl[1]}, bl1[2] = {rl[2], rl[3]};
                mma16816(of[2 * nb],     pah[kf2], bh0);
                mma16816(of[2 * nb],     pah[kf2], bl0);
                mma16816(of[2 * nb],     pal[kf2], bh0);
                mma16816(of[2 * nb + 1], pah[kf2], bh1);
                mma16816(of[2 * nb + 1], pah[kf2], bl1);
                mma16816(of[2 * nb + 1], pal[kf2], bh1);
            }
        }
    }

    l0 += __shfl_xor_sync(0xffffffffu, l0, 1);
    l0 += __shfl_xor_sync(0xffffffffu, l0, 2);
    l1 += __shfl_xor_sync(0xffffffffu, l1, 1);
    l1 += __shfl_xor_sync(0xffffffffu, l1, 2);
    float inv0 = 1.f / l0, inv1 = 1.f / l1;

    size_t ga = ((size_t)(bb * S_) + rowa) * DMODEL + hh * DH;
    size_t gb = ga + (size_t)8 * DMODEL;
#pragma unroll
    for (int i = 0; i < 16; i++) {
        int d = i * 8 + 2 * (lane & 3);
        float v0 = of[i][0] * inv0, v1 = of[i][1] * inv0;
        float v2 = of[i][2] * inv1, v3 = of[i][3] * inv1;
        float h0 = __bfloat162float(__float2bfloat16(v0));
        float h1 = __bfloat162float(__float2bfloat16(v1));
        float h2 = __bfloat162float(__float2bfloat16(v2));
        float h3 = __bfloat162float(__float2bfloat16(v3));
        *(uint32_t*)(aoh + ga + d) = pack_bf2(h0, h1);
        *(uint32_t*)(aoh + gb + d) = pack_bf2(h2, h3);
        *(uint32_t*)(aol + ga + d) = pack_bf2(v0 - h0, v1 - h1);
        *(uint32_t*)(aol + gb + d) = pack_bf2(v2 - h2, v3 - h3);
    }
}

// ---------------- elementwise kernels ----------------
// fp32 -> bf16 hi/lo, vectorized (n % 4 == 0, no padding)
__global__ __launch_bounds__(256)
void split_plain4(const float4* __restrict__ in, __nv_bfloat162* __restrict__ hi,
                  __nv_bfloat162* __restrict__ lo, size_t n4)
{
    size_t i = (size_t)blockIdx.x * 256 + threadIdx.x;
    if (i >= n4) return;
    float4 v = in[i];
    bf16 h0, l0_, h1, l1_, h2, l2_, h3, l3_;
    split2(v.x, h0, l0_); split2(v.y, h1, l1_);
    split2(v.z, h2, l2_); split2(v.w, h3, l3_);
    hi[i * 2]     = __nv_bfloat162(h0, h1);
    hi[i * 2 + 1] = __nv_bfloat162(h2, h3);
    lo[i * 2]     = __nv_bfloat162(l0_, l1_);
    lo[i * 2 + 1] = __nv_bfloat162(l2_, l3_);
}

__global__ __launch_bounds__(256)
void transpose_split(const float* __restrict__ in, bf16* __restrict__ hi, bf16* __restrict__ lo,
                     int K, int N, int Npad, int Kpad, int rowOff)
{
    __shared__ float t[32][33];
    int k0 = blockIdx.x * 32, n0 = blockIdx.y * 32;
    int tx = threadIdx.x, ty = threadIdx.y;
#pragma unroll
    for (int i = 0; i < 4; i++) {
        int k = k0 + ty + i * 8;
        float v = (k < K && n0 + tx < N) ? in[(size_t)k * N + n0 + tx] : 0.f;
        t[ty + i * 8][tx] = v;
    }
    __syncthreads();
#pragma unroll
    for (int i = 0; i < 4; i++) {
        int n = n0 + ty + i * 8, k = k0 + tx;
        if (n < Npad && k < Kpad) {
            size_t o = (size_t)(n + rowOff) * Kpad + k;
            split2(t[tx][ty + i * 8], hi[o], lo[o]);
        }
    }
}

__global__ __launch_bounds__(256)
void layernorm_split(const float* __restrict__ X, int xld,
                     float* __restrict__ outf, int ofld,
                     bf16* __restrict__ hi, bf16* __restrict__ lo,
                     const float* __restrict__ w, const float* __restrict__ b,
                     int n, int npad)
{
    const float* p = X + (size_t)blockIdx.x * xld;
    float s = 0.f, s2 = 0.f;
    for (int j = threadIdx.x; j < n; j += 256) {
        float v = p[j];
        s += v; s2 += v * v;
    }
    __shared__ float sh[20];
#pragma unroll
    for (int o = 16; o; o >>= 1) {
        s  += __shfl_down_sync(0xffffffffu, s,  o);
        s2 += __shfl_down_sync(0xffffffffu, s2, o);
    }
    int wd = threadIdx.x >> 5, ln = threadIdx.x & 31;
    if (!ln) { sh[wd] = s; sh[wd + 8] = s2; }
    __syncthreads();
    if (threadIdx.x == 0) {
        float ts = 0.f, ts2 = 0.f;
        for (int i = 0; i < 8; i++) { ts += sh[i]; ts2 += sh[i + 8]; }
        float mean = ts / n;
        float var = fmaxf(ts2 / n - mean * mean, 0.f);
        sh[16] = mean;
        sh[17] = rsqrtf(var + 1e-5f);
    }
    __syncthreads();
    float mean = sh[16], rstd = sh[17];
    float* of = outf ? outf + (size_t)blockIdx.x * ofld : nullptr;
    bf16* hh = hi + (size_t)blockIdx.x * npad;
    bf16* ll = lo + (size_t)blockIdx.x * npad;
    for (int j = threadIdx.x; j < npad; j += 256) {
        float v = 0.f;
        if (j < n) {
            v = (p[j] - mean) * rstd * w[j] + b[j];
            if (of) of[j] = v;
        }
        split2(v, hh[j], ll[j]);
    }
}

// merged RoPE: first half of indices -> Q (in-place on q2), second half -> K (p1 -> kv)
__global__ __launch_bounds__(256)
void rope_qk(bf16* __restrict__ q2h, bf16* __restrict__ q2l,
             const float* __restrict__ p1,
             bf16* __restrict__ kvh, bf16* __restrict__ kvl)
{
    int total = BS * 2 * 64;
    int idx = blockIdx.x * 256 + threadIdx.x;
    if (idx >= 2 * total) return;
    bool isK = idx >= total;
    if (isK) idx -= total;
    int dp = idx & 63;
    int h2 = (idx >> 6) & 1;
    int row = idx >> 7;
    int s = row & (S_ - 1);
    float freq = exp2f(-(float)dp * 0.20762050593046015f);   // 10000^(-dp/64)
    float sn, cs;
    sincosf((float)s * freq, &sn, &cs);

    if (!isK) {
        size_t base = (size_t)row * N2 + KNOPE + h2 * DH;
        float x1 = __bfloat162float(q2h[base + dp]) + __bfloat162float(q2l[base + dp]);
        float x2 = __bfloat162float(q2h[base + dp + 64]) + __bfloat162float(q2l[base + dp + 64]);
        float v1 = x1 * cs - x2 * sn;
        float v2 = x2 * cs + x1 * sn;
        split2(v1, q2h[base + dp], q2l[base + dp]);
        split2(v2, q2h[base + dp + 64], q2l[base + dp + 64]);
    } else {
        const float* src = p1 + (size_t)row * N1 + 2432 + h2 * DH;
        float x1 = src[dp], x2 = src[dp + 64];
        float v1 = x1 * cs - x2 * sn;
        float v2 = x2 * cs + x1 * sn;
        size_t base = (size_t)row * KVLD + KVCOLS + h2 * DH;
        split2(v1, kvh[base + dp], kvl[base + dp]);
        split2(v2, kvh[base + dp + 64], kvl[base + dp + 64]);
    }
}

// ---------------- launch ----------------
static inline void* sym(const void* s) { void* p; cudaGetSymbolAddress(&p, s); return p; }

extern "C" void kernel_launch(void* const* d_in, const int* in_sizes, int n_in,
                              void* d_out, int out_size)
{
    const float* x     = (const float*)d_in[0];
    const float* W_dq  = (const float*)d_in[1];
    const float* W_uq  = (const float*)d_in[2];
    const float* W_qr  = (const float*)d_in[3];
    const float* W_dkv = (const float*)d_in[4];
    const float* W_ukv = (const float*)d_in[5];
    const float* W_kr  = (const float*)d_in[6];
    const float* W_o   = (const float*)d_in[7];
    const float* q_w   = (const float*)d_in[8];
    const float* q_b   = (const float*)d_in[9];
    const float* kv_w  = (const float*)d_in[10];
    const float* kv_b  = (const float*)d_in[11];

    float* out = (float*)d_out;
    float* ckv = out + (size_t)BS * DMODEL;

    bf16 *xhi=(bf16*)sym(g_xhi), *xlo=(bf16*)sym(g_xlo);
    bf16 *w1h=(bf16*)sym(g_w1h), *w1l=(bf16*)sym(g_w1l);
    bf16 *w2h=(bf16*)sym(g_w2h), *w2l=(bf16*)sym(g_w2l);
    bf16 *wukvh=(bf16*)sym(g_wukvh), *wukvl=(bf16*)sym(g_wukvl);
    bf16 *woh=(bf16*)sym(g_woh), *wol=(bf16*)sym(g_wol);
    float *p1=(float*)sym(g_p1);
    bf16 *cqh=(bf16*)sym(g_cqh), *cql=(bf16*)sym(g_cql);
    bf16 *ckvh=(bf16*)sym(g_ckvh), *ckvl=(bf16*)sym(g_ckvl);
    bf16 *q2h=(bf16*)sym(g_q2h), *q2l=(bf16*)sym(g_q2l);
    bf16 *kvh=(bf16*)sym(g_kvh), *kvl=(bf16*)sym(g_kvl);
    bf16 *aoh=(bf16*)sym(g_aoh), *aol=(bf16*)sym(g_aol);

    cudaFuncSetAttribute(hmma_gemm, cudaFuncAttributeMaxDynamicSharedMemorySize, SMEM_GEMM);
    cudaFuncSetAttribute(hmma_gemm_dual, cudaFuncAttributeMaxDynamicSharedMemorySize, SMEM_GEMM);
    cudaFuncSetAttribute(flash_attn, cudaFuncAttributeMaxDynamicSharedMemorySize, SMEM_FLASH);

    // --- input conversions ---
    {
        size_t n4 = (size_t)BS * DMODEL / 4;
        split_plain4<<<(unsigned)((n4 + 255)/256), 256>>>(
            (const float4*)x, (__nv_bfloat162*)xhi, (__nv_bfloat162*)xlo, n4);
        size_t w4 = (size_t)DMODEL * DMODEL / 4;
        split_plain4<<<(unsigned)((w4 + 255)/256), 256>>>(
            (const float4*)W_o, (__nv_bfloat162*)woh, (__nv_bfloat162*)wol, w4);
    }
    transpose_split<<<dim3(DMODEL/32, QPROJ/32),  dim3(32,8)>>>(W_dq,  w1h, w1l, DMODEL, QPROJ,  QPROJ,  DMODEL, 0);
    transpose_split<<<dim3(DMODEL/32, KVPAD/32),  dim3(32,8)>>>(W_dkv, w1h, w1l, DMODEL, KVPROJ, KVPAD,  DMODEL, QPROJ);
    transpose_split<<<dim3(DMODEL/32, 256/32),    dim3(32,8)>>>(W_kr,  w1h, w1l, DMODEL, 256,    256,    DMODEL, QPROJ + KVPAD);
    transpose_split<<<dim3(QPROJ/32,  KNOPE/32),  dim3(32,8)>>>(W_uq,  w2h, w2l, QPROJ,  KNOPE,  KNOPE,  QPROJ, 0);
    transpose_split<<<dim3(QPROJ/32,  256/32),    dim3(32,8)>>>(W_qr,  w2h, w2l, QPROJ,  256,    256,    QPROJ, KNOPE);
    transpose_split<<<dim3(KVPAD/32,  KVCOLS/32), dim3(32,8)>>>(W_ukv, wukvh, wukvl, KVPROJ, KVCOLS, KVCOLS, KVPAD, 0);

    // --- fused projection 1: p1 = x @ [W_dq | W_dkv | W_kr] (fp32) ---
    hmma_gemm<<<dim3(N1/128, BS/128), 256, SMEM_GEMM>>>(
        xhi, xlo, w1h, w1l, p1, nullptr, nullptr, N1, DMODEL, DMODEL, DMODEL, N1);

    // --- LayerNorms ---
    layernorm_split<<<BS, 256>>>(p1, N1, nullptr, 0, cqh, cql, q_w, q_b, QPROJ, QPROJ);
    layernorm_split<<<BS, 256>>>(p1 + QPROJ, N1, ckv, KVPROJ, ckvh, ckvl, kv_w, kv_b, KVPROJ, KVPAD);

    // --- q2 = cq @ [W_uq | W_qr] AND kv = ckv @ W_ukv in ONE launch ---
    {
        int gx_ukv = KVCOLS / 128;      // 30
        int gx_q2  = N2 / 128;          // 16
        int blocks_ukv = gx_ukv * (BS / 128);   // 960
        int blocks_q2  = gx_q2  * (BS / 128);   // 512
        hmma_gemm_dual<<<blocks_ukv + blocks_q2, 256, SMEM_GEMM>>>(
            ckvh, ckvl, wukvh, wukvl, kvh, kvl,
            KVCOLS, KVPAD, KVPAD, KVPAD, KVLD, gx_ukv,
            cqh, cql, w2h, w2l, q2h, q2l,
            N2, QPROJ, QPROJ, QPROJ, N2, gx_q2,
            blocks_ukv);
    }

    // --- RoPE (merged q + k) ---
    rope_qk<<<(2*BS*2*64 + 255)/256, 256>>>(q2h, q2l, p1, kvh, kvl);

    // --- fused flash attention ---
    flash_attn<<<dim3(S_/128, NZ), 256, SMEM_FLASH>>>(q2h, q2l, kvh, kvl, aoh, aol);

    // --- final projection ---
    hmma_gemm<<<dim3(DMODEL/128, BS/128), 256, SMEM_GEMM>>>(
        aoh, aol, woh, wol, out, nullptr, nullptr, DMODEL, DMODEL, DMODEL, DMODEL, DMODEL);
}

// round 8
// speedup vs baseline: 5.6327x; 1.0186x over previous
#include <cuda_runtime.h>
#include <cuda_bf16.h>
#include <cstdint>
#include <math.h>

// ---------------- problem constants ----------------
#define B_      2
#define S_      2048
#define DMODEL  2048
#define NH      16
#define DH      128
#define NOPE    14
#define QPROJ   1024
#define KVPROJ  1365
#define KVPAD   1408
#define KNOPE   1792
#define KVCOLS  3840
#define KVLD    4096
#define BS      (B_*S_)
#define NZ      (B_*NH)
#define N1      2688
#define N2      2048

typedef __nv_bfloat16 bf16;

// ---------------- device scratch ----------------
__device__ bf16 g_xhi[(size_t)BS*DMODEL],   g_xlo[(size_t)BS*DMODEL];
__device__ bf16 g_w1h[(size_t)N1*DMODEL],   g_w1l[(size_t)N1*DMODEL];
__device__ bf16 g_w2h[(size_t)N2*QPROJ],    g_w2l[(size_t)N2*QPROJ];
__device__ bf16 g_wukvh[(size_t)KVCOLS*KVPAD], g_wukvl[(size_t)KVCOLS*KVPAD];
__device__ bf16 g_woh[(size_t)DMODEL*DMODEL],  g_wol[(size_t)DMODEL*DMODEL];
__device__ float g_p1[(size_t)BS*N1];
__device__ bf16 g_cqh[(size_t)BS*QPROJ],    g_cql[(size_t)BS*QPROJ];
__device__ bf16 g_ckvh[(size_t)BS*KVPAD],   g_ckvl[(size_t)BS*KVPAD];
__device__ bf16 g_q2h[(size_t)BS*N2],       g_q2l[(size_t)BS*N2];
__device__ bf16 g_kvh[(size_t)BS*KVLD],     g_kvl[(size_t)BS*KVLD];
__device__ bf16 g_aoh[(size_t)BS*DMODEL],   g_aol[(size_t)BS*DMODEL];

// ---------------- helpers ----------------
__device__ __forceinline__ uint32_t smem_u32(const void* p) {
    uint32_t a;
    asm("{ .reg .u64 t; cvta.to.shared.u64 t, %1; cvt.u32.u64 %0, t; }" : "=r"(a) : "l"(p));
    return a;
}
__device__ __forceinline__ void cp16(uint32_t saddr, const void* g) {
    asm volatile("cp.async.cg.shared.global [%0], [%1], 16;" :: "r"(saddr), "l"(g) : "memory");
}
__device__ __forceinline__ void cp_commit() {
    asm volatile("cp.async.commit_group;" ::: "memory");
}
template<int N> __device__ __forceinline__ void cp_wait() {
    asm volatile("cp.async.wait_group %0;" :: "n"(N) : "memory");
}
__device__ __forceinline__ void ldm_x4(uint32_t addr, uint32_t* r) {
    asm volatile("ldmatrix.sync.aligned.m8n8.x4.shared.b16 {%0,%1,%2,%3}, [%4];"
        : "=r"(r[0]), "=r"(r[1]), "=r"(r[2]), "=r"(r[3]) : "r"(addr));
}
__device__ __forceinline__ void ldm_x4_t(uint32_t addr, uint32_t* r) {
    asm volatile("ldmatrix.sync.aligned.m8n8.x4.trans.shared.b16 {%0,%1,%2,%3}, [%4];"
        : "=r"(r[0]), "=r"(r[1]), "=r"(r[2]), "=r"(r[3]) : "r"(addr));
}
__device__ __forceinline__ void mma16816(float* d, const uint32_t* a, const uint32_t* b) {
    asm volatile("mma.sync.aligned.m16n8k16.row.col.f32.bf16.bf16.f32 "
        "{%0,%1,%2,%3}, {%4,%5,%6,%7}, {%8,%9}, {%0,%1,%2,%3};"
        : "+f"(d[0]), "+f"(d[1]), "+f"(d[2]), "+f"(d[3])
        : "r"(a[0]), "r"(a[1]), "r"(a[2]), "r"(a[3]), "r"(b[0]), "r"(b[1]));
}
__device__ __forceinline__ void split2(float v, bf16& h, bf16& l) {
    h = __float2bfloat16(v);
    l = __float2bfloat16(v - __bfloat162float(h));
}
__device__ __forceinline__ uint32_t pack_bf2(float a, float b) {
    __nv_bfloat162 t = __floats2bfloat162_rn(a, b);
    return *(uint32_t*)&t;
}

// ---------------- prep device functions ----------------
// split 4096 float4s starting at base4 (16 per thread)
__device__ __forceinline__ void split_chunk(const float4* __restrict__ in,
                                            __nv_bfloat162* __restrict__ hi,
                                            __nv_bfloat162* __restrict__ lo,
                                            size_t base4, size_t n4)
{
#pragma unroll
    for (int q = 0; q < 16; q++) {
        size_t i = base4 + (size_t)q * 256 + threadIdx.x;
        if (i >= n4) return;
        float4 v = in[i];
        bf16 h0, l0_, h1, l1_, h2, l2_, h3, l3_;
        split2(v.x, h0, l0_); split2(v.y, h1, l1_);
        split2(v.z, h2, l2_); split2(v.w, h3, l3_);
        hi[i * 2]     = __nv_bfloat162(h0, h1);
        hi[i * 2 + 1] = __nv_bfloat162(h2, h3);
        lo[i * 2]     = __nv_bfloat162(l0_, l1_);
        lo[i * 2 + 1] = __nv_bfloat162(l2_, l3_);
    }
}

// transpose strip: one 32-row k-tile x up to 8 n-tiles of in[K,N] -> out[(n+rowOff)*Kpad + k]
__device__ __forceinline__ void tr_strip(const float* __restrict__ in,
                                         bf16* __restrict__ hi, bf16* __restrict__ lo,
                                         int K, int N, int Npad, int Kpad, int rowOff,
                                         int strip, int nStrips)
{
    __shared__ float t[32][33];
    int kTile = strip / nStrips;
    int nT0 = (strip % nStrips) * 8;
    int k0 = kTile * 32;
    int tx = threadIdx.x & 31, ty = threadIdx.x >> 5;   // 32 x 8
    for (int sub = 0; sub < 8; sub++) {
        int n0 = (nT0 + sub) * 32;
        if (n0 >= Npad) break;
        __syncthreads();
#pragma unroll
        for (int i = 0; i < 4; i++) {
            int k = k0 + ty + i * 8;
            float v = (k < K && n0 + tx < N) ? in[(size_t)k * N + n0 + tx] : 0.f;
            t[ty + i * 8][tx] = v;
        }
        __syncthreads();
#pragma unroll
        for (int i = 0; i < 4; i++) {
            int n = n0 + ty + i * 8, k = k0 + tx;
            if (n < Npad && k < Kpad) {
                size_t o = (size_t)(n + rowOff) * Kpad + k;
                split2(t[tx][ty + i * 8], hi[o], lo[o]);
            }
        }
    }
}

// ---------------- GEMM core: C = A @ B^T, BK=64, 3-stage ----------------
#define STAGE 65536
#define SMEM_GEMM (3*STAGE)

__device__ __forceinline__ void gemm_core(
    const bf16* __restrict__ Ahi, const bf16* __restrict__ Alo,
    const bf16* __restrict__ Bhi, const bf16* __restrict__ Blo,
    float* __restrict__ Cf, bf16* __restrict__ Ch, bf16* __restrict__ Cl,
    int N, int Kpad, int lda, int ldb, int ldc,
    int r0, int c0, char* smem)
{
    int tid = threadIdx.x, lane = tid & 31, wid = tid >> 5;
    int tiles = Kpad >> 6;

    const bf16* Ah = Ahi + (size_t)r0 * lda;
    const bf16* Al = Alo + (size_t)r0 * lda;
    const bf16* Bh = Bhi + (size_t)c0 * ldb;
    const bf16* Bl = Blo + (size_t)c0 * ldb;

    uint32_t sbase = smem_u32(smem);
    int wm = (wid >> 2) * 64, wn = (wid & 3) * 32;

    float acc[4][4][4];
#pragma unroll
    for (int i = 0; i < 4; i++)
#pragma unroll
        for (int j = 0; j < 4; j++)
#pragma unroll
            for (int v = 0; v < 4; v++) acc[i][j][v] = 0.f;

    auto load_stage = [&](int t) {
        int k0 = t << 6;
        uint32_t sb = sbase + (uint32_t)(t % 3) * STAGE;
#pragma unroll
        for (int q = 0; q < 4; q++) {
            int idx = tid + q * 256;
            int row = idx >> 3, ch = idx & 7;
            uint32_t off = (uint32_t)row * 128 + (uint32_t)((ch ^ (row & 7)) << 4);
            size_t ga = (size_t)row * lda + k0 + ch * 8;
            size_t gb = (size_t)row * ldb + k0 + ch * 8;
            cp16(sb + off,         Ah + ga);
            cp16(sb + 16384 + off, Al + ga);
            cp16(sb + 32768 + off, Bh + gb);
            cp16(sb + 49152 + off, Bl + gb);
        }
        cp_commit();
    };

    auto compute_stage = [&](int t) {
        uint32_t sb = sbase + (uint32_t)(t % 3) * STAGE;
#pragma unroll
        for (int kk = 0; kk < 64; kk += 16) {
            uint32_t bh[4][2], bl[4][2];
#pragma unroll
            for (int p = 0; p < 2; p++) {
                int rowB = wn + p * 16 + ((lane >> 4) << 3) + (lane & 7);
                int ch = (kk >> 3) + ((lane >> 3) & 1);
                uint32_t off = (uint32_t)rowB * 128 + (uint32_t)((ch ^ (rowB & 7)) << 4);
                uint32_t r[4];
                ldm_x4(sb + 32768 + off, r);
                bh[2 * p][0] = r[0]; bh[2 * p][1] = r[1];
                bh[2 * p + 1][0] = r[2]; bh[2 * p + 1][1] = r[3];
                ldm_x4(sb + 49152 + off, r);
                bl[2 * p][0] = r[0]; bl[2 * p][1] = r[1];
                bl[2 * p + 1][0] = r[2]; bl[2 * p + 1][1] = r[3];
            }
#pragma unroll
            for (int mt = 0; mt < 4; mt++) {
                int rowA = wm + mt * 16 + (lane & 15);
                int ch = (kk >> 3) + (lane >> 4);
                uint32_t off = (uint32_t)rowA * 128 + (uint32_t)((ch ^ (rowA & 7)) << 4);
                uint32_t ah[4], al[4];
                ldm_x4(sb + off, ah);
                ldm_x4(sb + 16384 + off, al);
#pragma unroll
                for (int nt = 0; nt < 4; nt++) {
                    mma16816(acc[mt][nt], ah, bh[nt]);
                    mma16816(acc[mt][nt], ah, bl[nt]);
                    mma16816(acc[mt][nt], al, bh[nt]);
                }
            }
        }
    };

    load_stage(0);
    if (tiles > 1) load_stage(1);
    for (int t = 0; t < tiles; t++) {
        if (t + 1 < tiles) cp_wait<1>(); else cp_wait<0>();
        __syncthreads();
        if (t + 2 < tiles) load_stage(t + 2);
        compute_stage(t);
    }

    if (Cf) {
#pragma unroll
        for (int mt = 0; mt < 4; mt++) {
#pragma unroll
            for (int nt = 0; nt < 4; nt++) {
                int r = r0 + wm + mt * 16 + (lane >> 2);
                int c = c0 + wn + nt * 8 + ((lane & 3) << 1);
                float* p0 = Cf + (size_t)r * ldc + c;
                float* p1 = p0 + 8 * ldc;
                p0[0] = acc[mt][nt][0]; p0[1] = acc[mt][nt][1];
                p1[0] = acc[mt][nt][2]; p1[1] = acc[mt][nt][3];
            }
        }
    } else {
#pragma unroll
        for (int mt = 0; mt < 4; mt++) {
#pragma unroll
            for (int nt = 0; nt < 4; nt++) {
                int r = r0 + wm + mt * 16 + (lane >> 2);
                int c = c0 + wn + nt * 8 + ((lane & 3) << 1);
                size_t o0 = (size_t)r * ldc + c;
                size_t o1 = o0 + (size_t)8 * ldc;
                float v0 = acc[mt][nt][0], v1 = acc[mt][nt][1];
                float v2 = acc[mt][nt][2], v3 = acc[mt][nt][3];
                float h0 = __bfloat162float(__float2bfloat16(v0));
                float h1 = __bfloat162float(__float2bfloat16(v1));
                float h2 = __bfloat162float(__float2bfloat16(v2));
                float h3 = __bfloat162float(__float2bfloat16(v3));
                *(uint32_t*)(Ch + o0) = pack_bf2(h0, h1);
                *(uint32_t*)(Ch + o1) = pack_bf2(h2, h3);
                *(uint32_t*)(Cl + o0) = pack_bf2(v0 - h0, v1 - h1);
                *(uint32_t*)(Cl + o1) = pack_bf2(v2 - h2, v3 - h3);
            }
        }
    }
}

// ---------------- prep1: x split + W1 transposes ----------------
// [0,512): x split | [512,768): W_dq | [768,1152): W_dkv | [1152,1216): W_kr
__global__ __launch_bounds__(256)
void prep1(const float* __restrict__ x,
           const float* __restrict__ W_dq, const float* __restrict__ W_dkv,
           const float* __restrict__ W_kr,
           bf16* __restrict__ xhi, bf16* __restrict__ xlo,
           bf16* __restrict__ w1h, bf16* __restrict__ w1l)
{
    int i = blockIdx.x;
    if (i < 512) {
        split_chunk((const float4*)x, (__nv_bfloat162*)xhi, (__nv_bfloat162*)xlo,
                    (size_t)i * 4096, (size_t)BS * DMODEL / 4);
    } else if (i < 768) {
        tr_strip(W_dq, w1h, w1l, DMODEL, QPROJ, QPROJ, DMODEL, 0, i - 512, 4);
    } else if (i < 1152) {
        tr_strip(W_dkv, w1h, w1l, DMODEL, KVPROJ, KVPAD, DMODEL, QPROJ, i - 768, 6);
    } else {
        tr_strip(W_kr, w1h, w1l, DMODEL, 256, 256, DMODEL, QPROJ + KVPAD, i - 1152, 1);
    }
}

// ---------------- p1 GEMM fused with prep2 (W_uq/W_qr/W_ukv transpose, W_o split) ---
// interleaved: i<1344: even->gemm(i/2), odd->prep(i/2); i>=1344 -> prep(672+i-1344)
__global__ __launch_bounds__(256, 1)
void gemm_p1_prep2(const bf16* __restrict__ xhi, const bf16* __restrict__ xlo,
                   const bf16* __restrict__ w1h, const bf16* __restrict__ w1l,
                   float* __restrict__ p1,
                   const float* __restrict__ W_uq, const float* __restrict__ W_qr,
                   const float* __restrict__ W_ukv, const float* __restrict__ W_o,
                   bf16* __restrict__ w2h, bf16* __restrict__ w2l,
                   bf16* __restrict__ wukvh, bf16* __restrict__ wukvl,
                   bf16* __restrict__ woh, bf16* __restrict__ wol)
{
    extern __shared__ __align__(128) char smem[];
    int i = blockIdx.x;
    bool isGemm;
    int sub;
    if (i < 1344) { isGemm = !(i & 1); sub = i >> 1; }
    else          { isGemm = false;    sub = 672 + (i - 1344); }

    if (isGemm) {
        int cx = sub % 21, cy = sub / 21;
        gemm_core(xhi, xlo, w1h, w1l, p1, nullptr, nullptr,
                  N1, DMODEL, DMODEL, DMODEL, N1, cy * 128, cx * 128, smem);
    } else {
        if (sub < 224) {
            tr_strip(W_uq, w2h, w2l, QPROJ, KNOPE, KNOPE, QPROJ, 0, sub, 7);
        } else if (sub < 256) {
            tr_strip(W_qr, w2h, w2l, QPROJ, 256, 256, QPROJ, KNOPE, sub - 224, 1);
        } else if (sub < 916) {
            tr_strip(W_ukv, wukvh, wukvl, KVPROJ, KVCOLS, KVCOLS, KVPAD, 0, sub - 256, 15);
        } else {
            split_chunk((const float4*)W_o, (__nv_bfloat162*)woh, (__nv_bfloat162*)wol,
                        (size_t)(sub - 916) * 4096, (size_t)DMODEL * DMODEL / 4);
        }
    }
}

__global__ __launch_bounds__(256, 1)
void hmma_gemm(const bf16* __restrict__ Ahi, const bf16* __restrict__ Alo,
               const bf16* __restrict__ Bhi, const bf16* __restrict__ Blo,
               float* __restrict__ Cf, bf16* __restrict__ Ch, bf16* __restrict__ Cl,
               int N, int Kpad, int lda, int ldb, int ldc)
{
    extern __shared__ __align__(128) char smem[];
    gemm_core(Ahi, Alo, Bhi, Blo, Cf, Ch, Cl, N, Kpad, lda, ldb, ldc,
              blockIdx.y * 128, blockIdx.x * 128, smem);
}

__global__ __launch_bounds__(256, 1)
void hmma_gemm_dual(
    const bf16* A1h, const bf16* A1l, const bf16* B1h, const bf16* B1l,
    bf16* C1h, bf16* C1l, int n1, int k1, int la1, int lb1, int lc1, int gx1,
    const bf16* A2h, const bf16* A2l, const bf16* B2h, const bf16* B2l,
    bf16* C2h, bf16* C2l, int n2, int k2, int la2, int lb2, int lc2, int gx2,
    int split)
{
    extern __shared__ __align__(128) char smem[];
    int idx = blockIdx.x;
    if (idx < split) {
        int cx = idx % gx1, cy = idx / gx1;
        gemm_core(A1h, A1l, B1h, B1l, nullptr, C1h, C1l, n1, k1, la1, lb1, lc1,
                  cy * 128, cx * 128, smem);
    } else {
        idx -= split;
        int cx = idx % gx2, cy = idx / gx2;
        gemm_core(A2h, A2l, B2h, B2l, nullptr, C2h, C2l, n2, k2, la2, lb2, lc2,
                  cy * 128, cx * 128, smem);
    }
}

// ---------------- fused flash attention ----------------
#define FST 65536
#define SMEM_FLASH (3*FST)

__global__ __launch_bounds__(256, 1)
void flash_attn(const bf16* __restrict__ q2h, const bf16* __restrict__ q2l,
                const bf16* __restrict__ kvh, const bf16* __restrict__ kvl,
                bf16* __restrict__ aoh, bf16* __restrict__ aol)
{
    extern __shared__ __align__(128) char smem[];
    int tid = threadIdx.x, lane = tid & 31, wid = tid >> 5;
    int z = blockIdx.y, bb = z >> 4, hh = z & 15;
    int r0 = ((int)gridDim.x - 1 - (int)blockIdx.x) * 128;

    int kcol = (hh < NOPE) ? hh * DH : KVCOLS + (hh - NOPE) * DH;
    int vcol = KNOPE + hh * DH;

    const bf16* qhz = q2h + ((size_t)(bb * S_ + r0)) * N2 + hh * DH;
    const bf16* qlz = q2l + ((size_t)(bb * S_ + r0)) * N2 + hh * DH;
    const bf16* khz = kvh + (size_t)(bb * S_) * KVLD + kcol;
    const bf16* klz = kvl + (size_t)(bb * S_) * KVLD + kcol;
    const bf16* vhz = kvh + (size_t)(bb * S_) * KVLD + vcol;
    const bf16* vlz = kvl + (size_t)(bb * S_) * KVLD + vcol;

    uint32_t sb = smem_u32(smem);

#pragma unroll
    for (int q = 0; q < 8; q++) {
        int idx = tid + q * 256;
        int row = idx >> 4, ch = idx & 15;
        uint32_t off = (uint32_t)row * 256 + (uint32_t)((ch ^ (row & 7)) << 4);
        cp16(sb + off,         qhz + (size_t)row * N2 + ch * 8);
        cp16(sb + 32768 + off, qlz + (size_t)row * N2 + ch * 8);
    }
    cp_commit();

    int ntiles = (r0 >> 6) + 2;
    int diag = r0 >> 6;

    auto load_stage = [&](int jt) {
        uint32_t st = sb + (uint32_t)((jt + 1) % 3) * FST;
        int s0 = jt * 64;
#pragma unroll
        for (int q = 0; q < 4; q++) {
            int idx = tid + q * 256;
            int row = idx >> 4, ch = idx & 15;
            uint32_t off = (uint32_t)row * 256 + (uint32_t)((ch ^ (row & 7)) << 4);
            size_t g = (size_t)(s0 + row) * KVLD + ch * 8;
            cp16(st + off,         khz + g);
            cp16(st + 16384 + off, klz + g);
        }
#pragma unroll
        for (int q = 0; q < 4; q++) {
            int idx = tid + q * 256;
            int row = idx >> 4, ch = idx & 15;
            uint32_t off = (uint32_t)row * 256 + (uint32_t)((ch ^ (row & 7)) << 4);
            size_t g = (size_t)(s0 + row) * KVLD + ch * 8;
            cp16(st + 32768 + off, vhz + g);
            cp16(st + 49152 + off, vlz + g);
        }
        cp_commit();
    };

    load_stage(0);
    load_stage(1);
    cp_wait<2>();
    __syncthreads();

    int wrow = wid * 16;
    uint32_t qah[8][4], qal[8][4];
#pragma unroll
    for (int kf = 0; kf < 8; kf++) {
        int row = wrow + (lane & 15);
        int ch = kf * 2 + (lane >> 4);
        uint32_t off = (uint32_t)row * 256 + (uint32_t)((ch ^ (row & 7)) << 4);
        ldm_x4(sb + off, qah[kf]);
        ldm_x4(sb + 32768 + off, qal[kf]);
    }

    float of[16][4];
#pragma unroll
    for (int i = 0; i < 16; i++)
#pragma unroll
        for (int v = 0; v < 4; v++) of[i][v] = 0.f;
    float m0 = -1e30f, m1 = -1e30f, l0 = 0.f, l1 = 0.f;
    const float CEXP = 0.08838834764831845f * 1.4426950408889634f;

    int rowa = r0 + wrow + (lane >> 2);

    for (int jt = 0; jt < ntiles; jt++) {
        if (jt + 1 < ntiles) cp_wait<1>(); else cp_wait<0>();
        __syncthreads();
        if (jt + 2 < ntiles) load_stage(jt + 2);
        uint32_t st = sb + (uint32_t)((jt + 1) % 3) * FST;

        float sf[8][4];
#pragma unroll
        for (int nf = 0; nf < 8; nf++)
#pragma unroll
            for (int v = 0; v < 4; v++) sf[nf][v] = 0.f;

#pragma unroll
        for (int kf = 0; kf < 8; kf++) {
            uint32_t bh[8][2], bl[8][2];
#pragma unroll
            for (int p = 0; p < 4; p++) {
                int rowB = p * 16 + ((lane >> 4) << 3) + (lane & 7);
                int ch = kf * 2 + ((lane >> 3) & 1);
                uint32_t off = (uint32_t)rowB * 256 + (uint32_t)((ch ^ (rowB & 7)) << 4);
                uint32_t r4[4];
                ldm_x4(st + off, r4);
                bh[2 * p][0] = r4[0]; bh[2 * p][1] = r4[1];
                bh[2 * p + 1][0] = r4[2]; bh[2 * p + 1][1] = r4[3];
                ldm_x4(st + 16384 + off, r4);
                bl[2 * p][0] = r4[0]; bl[2 * p][1] = r4[1];
                bl[2 * p + 1][0] = r4[2]; bl[2 * p + 1][1] = r4[3];
            }
#pragma unroll
            for (int nf = 0; nf < 8; nf++) {
                mma16816(sf[nf], qah[kf], bh[nf]);
                mma16816(sf[nf], qah[kf], bl[nf]);
                mma16816(sf[nf], qal[kf], bh[nf]);
            }
        }

        if (jt >= diag) {
            int colb = jt * 64 + 2 * (lane & 3);
#pragma unroll
            for (int nf = 0; nf < 8; nf++) {
                int c = colb + nf * 8;
                if (c > rowa)     sf[nf][0] = -1e30f;
                if (c + 1 > rowa) sf[nf][1] = -1e30f;
                if (c > rowa + 8)     sf[nf][2] = -1e30f;
                if (c + 1 > rowa + 8) sf[nf][3] = -1e30f;
            }
        }

        float tm0 = -1e30f, tm1 = -1e30f;
#pragma unroll
        for (int nf = 0; nf < 8; nf++) {
            tm0 = fmaxf(tm0, fmaxf(sf[nf][0], sf[nf][1]));
            tm1 = fmaxf(tm1, fmaxf(sf[nf][2], sf[nf][3]));
        }
        tm0 = fmaxf(tm0, __shfl_xor_sync(0xffffffffu, tm0, 1));
        tm0 = fmaxf(tm0, __shfl_xor_sync(0xffffffffu, tm0, 2));
        tm1 = fmaxf(tm1, __shfl_xor_sync(0xffffffffu, tm1, 1));
        tm1 = fmaxf(tm1, __shfl_xor_sync(0xffffffffu, tm1, 2));
        float mn0 = fmaxf(m0, tm0), mn1 = fmaxf(m1, tm1);
        float al0 = exp2f((m0 - mn0) * CEXP), al1 = exp2f((m1 - mn1) * CEXP);
        m0 = mn0; m1 = mn1;

        uint32_t pah[4][4], pal[4][4];
        float rs0 = 0.f, rs1 = 0.f;
#pragma unroll
        for (int nf = 0; nf < 8; nf++) {
            float e0 = exp2f((sf[nf][0] - m0) * CEXP);
            float e1 = exp2f((sf[nf][1] - m0) * CEXP);
            float e2 = exp2f((sf[nf][2] - m1) * CEXP);
            float e3 = exp2f((sf[nf][3] - m1) * CEXP);
            rs0 += e0 + e1; rs1 += e2 + e3;
            float h0 = __bfloat162float(__float2bfloat16(e0));
            float h1 = __bfloat162float(__float2bfloat16(e1));
            float h2 = __bfloat162float(__float2bfloat16(e2));
            float h3 = __bfloat162float(__float2bfloat16(e3));
            int kf2 = nf >> 1, s = (nf & 1) * 2;
            pah[kf2][s]     = pack_bf2(h0, h1);
            pah[kf2][s + 1] = pack_bf2(h2, h3);
            pal[kf2][s]     = pack_bf2(e0 - h0, e1 - h1);
            pal[kf2][s + 1] = pack_bf2(e2 - h2, e3 - h3);
        }
        l0 = l0 * al0 + rs0;
        l1 = l1 * al1 + rs1;

#pragma unroll
        for (int i = 0; i < 16; i++) {
            of[i][0] *= al0; of[i][1] *= al0;
            of[i][2] *= al1; of[i][3] *= al1;
        }

#pragma unroll
        for (int kf2 = 0; kf2 < 4; kf2++) {
#pragma unroll
            for (int nb = 0; nb < 8; nb++) {
                int row = kf2 * 16 + (lane & 15);
                int ch = nb * 2 + (lane >> 4);
                uint32_t off = (uint32_t)row * 256 + (uint32_t)((ch ^ (row & 7)) << 4);
                uint32_t rh[4], rl[4];
                ldm_x4_t(st + 32768 + off, rh);
                ldm_x4_t(st + 49152 + off, rl);
                uint32_t bh0[2] = {rh[0], rh[1]}, bh1[2] = {rh[2], rh[3]};
                uint32_t bl0[2] = {rl[0], rl[1]}, bl1[2] = {rl[2], rl[3]};
                mma16816(of[2 * nb],     pah[kf2], bh0);
                mma16816(of[2 * nb],     pah[kf2], bl0);
                mma16816(of[2 * nb],     pal[kf2], bh0);
                mma16816(of[2 * nb + 1], pah[kf2], bh1);
                mma16816(of[2 * nb + 1], pah[kf2], bl1);
                mma16816(of[2 * nb + 1], pal[kf2], bh1);
            }
        }
    }

    l0 += __shfl_xor_sync(0xffffffffu, l0, 1);
    l0 += __shfl_xor_sync(0xffffffffu, l0, 2);
    l1 += __shfl_xor_sync(0xffffffffu, l1, 1);
    l1 += __shfl_xor_sync(0xffffffffu, l1, 2);
    float inv0 = 1.f / l0, inv1 = 1.f / l1;

    size_t ga = ((size_t)(bb * S_) + rowa) * DMODEL + hh * DH;
    size_t gb = ga + (size_t)8 * DMODEL;
#pragma unroll
    for (int i = 0; i < 16; i++) {
        int d = i * 8 + 2 * (lane & 3);
        float v0 = of[i][0] * inv0, v1 = of[i][1] * inv0;
        float v2 = of[i][2] * inv1, v3 = of[i][3] * inv1;
        float h0 = __bfloat162float(__float2bfloat16(v0));
        float h1 = __bfloat162float(__float2bfloat16(v1));
        float h2 = __bfloat162float(__float2bfloat16(v2));
        float h3 = __bfloat162float(__float2bfloat16(v3));
        *(uint32_t*)(aoh + ga + d) = pack_bf2(h0, h1);
        *(uint32_t*)(aoh + gb + d) = pack_bf2(h2, h3);
        *(uint32_t*)(aol + ga + d) = pack_bf2(v0 - h0, v1 - h1);
        *(uint32_t*)(aol + gb + d) = pack_bf2(v2 - h2, v3 - h3);
    }
}

// ---------------- merged LayerNorm (y=0: q path, y=1: kv path) ----------------
__global__ __launch_bounds__(256)
void layernorm2(const float* __restrict__ p1,
                bf16* __restrict__ cqh, bf16* __restrict__ cql,
                float* __restrict__ ckv,
                bf16* __restrict__ ckvh, bf16* __restrict__ ckvl,
                const float* __restrict__ q_w, const float* __restrict__ q_b,
                const float* __restrict__ kv_w, const float* __restrict__ kv_b)
{
    bool isKV = blockIdx.y != 0;
    const float* p = p1 + (size_t)blockIdx.x * N1 + (isKV ? QPROJ : 0);
    int n = isKV ? KVPROJ : QPROJ;
    int npad = isKV ? KVPAD : QPROJ;
    const float* w = isKV ? kv_w : q_w;
    const float* b = isKV ? kv_b : q_b;
    bf16* hh = (isKV ? ckvh : cqh) + (size_t)blockIdx.x * npad;
    bf16* ll = (isKV ? ckvl : cql) + (size_t)blockIdx.x * npad;
    float* of = isKV ? ckv + (size_t)blockIdx.x * KVPROJ : nullptr;

    float s = 0.f, s2 = 0.f;
    for (int j = threadIdx.x; j < n; j += 256) {
        float v = p[j];
        s += v; s2 += v * v;
    }
    __shared__ float sh[20];
#pragma unroll
    for (int o = 16; o; o >>= 1) {
        s  += __shfl_down_sync(0xffffffffu, s,  o);
        s2 += __shfl_down_sync(0xffffffffu, s2, o);
    }
    int wd = threadIdx.x >> 5, ln = threadIdx.x & 31;
    if (!ln) { sh[wd] = s; sh[wd + 8] = s2; }
    __syncthreads();
    if (threadIdx.x == 0) {
        float ts = 0.f, ts2 = 0.f;
        for (int i = 0; i < 8; i++) { ts += sh[i]; ts2 += sh[i + 8]; }
        float mean = ts / n;
        float var = fmaxf(ts2 / n - mean * mean, 0.f);
        sh[16] = mean;
        sh[17] = rsqrtf(var + 1e-5f);
    }
    __syncthreads();
    float mean = sh[16], rstd = sh[17];
    for (int j = threadIdx.x; j < npad; j += 256) {
        float v = 0.f;
        if (j < n) {
            v = (p[j] - mean) * rstd * w[j] + b[j];
            if (of) of[j] = v;
        }
        split2(v, hh[j], ll[j]);
    }
}

// merged RoPE: first half -> Q (in-place on q2), second half -> K (p1 -> kv)
__global__ __launch_bounds__(256)
void rope_qk(bf16* __restrict__ q2h, bf16* __restrict__ q2l,
             const float* __restrict__ p1,
             bf16* __restrict__ kvh, bf16* __restrict__ kvl)
{
    int total = BS * 2 * 64;
    int idx = blockIdx.x * 256 + threadIdx.x;
    if (idx >= 2 * total) return;
    bool isK = idx >= total;
    if (isK) idx -= total;
    int dp = idx & 63;
    int h2 = (idx >> 6) & 1;
    int row = idx >> 7;
    int s = row & (S_ - 1);
    float freq = exp2f(-(float)dp * 0.20762050593046015f);
    float sn, cs;
    sincosf((float)s * freq, &sn, &cs);

    if (!isK) {
        size_t base = (size_t)row * N2 + KNOPE + h2 * DH;
        float x1 = __bfloat162float(q2h[base + dp]) + __bfloat162float(q2l[base + dp]);
        float x2 = __bfloat162float(q2h[base + dp + 64]) + __bfloat162float(q2l[base + dp + 64]);
        float v1 = x1 * cs - x2 * sn;
        float v2 = x2 * cs + x1 * sn;
        split2(v1, q2h[base + dp], q2l[base + dp]);
        split2(v2, q2h[base + dp + 64], q2l[base + dp + 64]);
    } else {
        const float* src = p1 + (size_t)row * N1 + 2432 + h2 * DH;
        float x1 = src[dp], x2 = src[dp + 64];
        float v1 = x1 * cs - x2 * sn;
        float v2 = x2 * cs + x1 * sn;
        size_t base = (size_t)row * KVLD + KVCOLS + h2 * DH;
        split2(v1, kvh[base + dp], kvl[base + dp]);
        split2(v2, kvh[base + dp + 64], kvl[base + dp + 64]);
    }
}

// ---------------- launch ----------------
static inline void* sym(const void* s) { void* p; cudaGetSymbolAddress(&p, s); return p; }

extern "C" void kernel_launch(void* const* d_in, const int* in_sizes, int n_in,
                              void* d_out, int out_size)
{
    const float* x     = (const float*)d_in[0];
    const float* W_dq  = (const float*)d_in[1];
    const float* W_uq  = (const float*)d_in[2];
    const float* W_qr  = (const float*)d_in[3];
    const float* W_dkv = (const float*)d_in[4];
    const float* W_ukv = (const float*)d_in[5];
    const float* W_kr  = (const float*)d_in[6];
    const float* W_o   = (const float*)d_in[7];
    const float* q_w   = (const float*)d_in[8];
    const float* q_b   = (const float*)d_in[9];
    const float* kv_w  = (const float*)d_in[10];
    const float* kv_b  = (const float*)d_in[11];

    float* out = (float*)d_out;
    float* ckv = out + (size_t)BS * DMODEL;

    bf16 *xhi=(bf16*)sym(g_xhi), *xlo=(bf16*)sym(g_xlo);
    bf16 *w1h=(bf16*)sym(g_w1h), *w1l=(bf16*)sym(g_w1l);
    bf16 *w2h=(bf16*)sym(g_w2h), *w2l=(bf16*)sym(g_w2l);
    bf16 *wukvh=(bf16*)sym(g_wukvh), *wukvl=(bf16*)sym(g_wukvl);
    bf16 *woh=(bf16*)sym(g_woh), *wol=(bf16*)sym(g_wol);
    float *p1=(float*)sym(g_p1);
    bf16 *cqh=(bf16*)sym(g_cqh), *cql=(bf16*)sym(g_cql);
    bf16 *ckvh=(bf16*)sym(g_ckvh), *ckvl=(bf16*)sym(g_ckvl);
    bf16 *q2h=(bf16*)sym(g_q2h), *q2l=(bf16*)sym(g_q2l);
    bf16 *kvh=(bf16*)sym(g_kvh), *kvl=(bf16*)sym(g_kvl);
    bf16 *aoh=(bf16*)sym(g_aoh), *aol=(bf16*)sym(g_aol);

    cudaFuncSetAttribute(hmma_gemm, cudaFuncAttributeMaxDynamicSharedMemorySize, SMEM_GEMM);
    cudaFuncSetAttribute(hmma_gemm_dual, cudaFuncAttributeMaxDynamicSharedMemorySize, SMEM_GEMM);
    cudaFuncSetAttribute(gemm_p1_prep2, cudaFuncAttributeMaxDynamicSharedMemorySize, SMEM_GEMM);
    cudaFuncSetAttribute(flash_attn, cudaFuncAttributeMaxDynamicSharedMemorySize, SMEM_FLASH);

    // 1. x split + W1 transposes
    prep1<<<1216, 256>>>(x, W_dq, W_dkv, W_kr, xhi, xlo, w1h, w1l);

    // 2. p1 = x @ W1 (fp32) fused with prep2 (W2/W_ukv transposes, W_o split)
    gemm_p1_prep2<<<1844, 256, SMEM_GEMM>>>(
        xhi, xlo, w1h, w1l, p1,
        W_uq, W_qr, W_ukv, W_o,
        w2h, w2l, wukvh, wukvl, woh, wol);

    // 3. LayerNorms (merged)
    layernorm2<<<dim3(BS, 2), 256>>>(p1, cqh, cql, ckv, ckvh, ckvl, q_w, q_b, kv_w, kv_b);

    // 4. q2 = cq @ W2 AND kv = ckv @ W_ukv in one launch
    {
        int gx_ukv = KVCOLS / 128;              // 30
        int gx_q2  = N2 / 128;                  // 16
        int blocks_ukv = gx_ukv * (BS / 128);   // 960
        int blocks_q2  = gx_q2  * (BS / 128);   // 512
        hmma_gemm_dual<<<blocks_ukv + blocks_q2, 256, SMEM_GEMM>>>(
            ckvh, ckvl, wukvh, wukvl, kvh, kvl,
            KVCOLS, KVPAD, KVPAD, KVPAD, KVLD, gx_ukv,
            cqh, cql, w2h, w2l, q2h, q2l,
            N2, QPROJ, QPROJ, QPROJ, N2, gx_q2,
            blocks_ukv);
    }

    // 5. RoPE
    rope_qk<<<(2*BS*2*64 + 255)/256, 256>>>(q2h, q2l, p1, kvh, kvl);

    // 6. flash attention
    flash_attn<<<dim3(S_/128, NZ), 256, SMEM_FLASH>>>(q2h, q2l, kvh, kvl, aoh, aol);

    // 7. final projection
    hmma_gemm<<<dim3(DMODEL/128, BS/128), 256, SMEM_GEMM>>>(
        aoh, aol, woh, wol, out, nullptr, nullptr, DMODEL, DMODEL, DMODEL, DMODEL, DMODEL);
}

// round 9
// speedup vs baseline: 5.6940x; 1.0109x over previous
#include <cuda_runtime.h>
#include <cuda_bf16.h>
#include <cstdint>
#include <math.h>

// ---------------- problem constants ----------------
#define B_      2
#define S_      2048
#define DMODEL  2048
#define NH      16
#define DH      128
#define NOPE    14
#define QPROJ   1024
#define KVPROJ  1365
#define KVPAD   1408
#define KNOPE   1792
#define KVCOLS  3840
#define KVLD    4096
#define BS      (B_*S_)
#define NZ      (B_*NH)
#define N1      2688
#define N2      2048

typedef __nv_bfloat16 bf16;

// ---------------- device scratch ----------------
__device__ bf16 g_xhi[(size_t)BS*DMODEL],   g_xlo[(size_t)BS*DMODEL];
__device__ bf16 g_w1h[(size_t)N1*DMODEL],   g_w1l[(size_t)N1*DMODEL];
__device__ bf16 g_w2h[(size_t)N2*QPROJ],    g_w2l[(size_t)N2*QPROJ];
__device__ bf16 g_wukvh[(size_t)KVCOLS*KVPAD], g_wukvl[(size_t)KVCOLS*KVPAD];
__device__ bf16 g_woh[(size_t)DMODEL*DMODEL],  g_wol[(size_t)DMODEL*DMODEL];
__device__ float g_p1[(size_t)BS*N1];
__device__ bf16 g_cqh[(size_t)BS*QPROJ],    g_cql[(size_t)BS*QPROJ];
__device__ bf16 g_ckvh[(size_t)BS*KVPAD],   g_ckvl[(size_t)BS*KVPAD];
__device__ bf16 g_q2h[(size_t)BS*N2],       g_q2l[(size_t)BS*N2];
__device__ bf16 g_kvh[(size_t)BS*KVLD],     g_kvl[(size_t)BS*KVLD];
__device__ bf16 g_aoh[(size_t)BS*DMODEL],   g_aol[(size_t)BS*DMODEL];

// ---------------- helpers ----------------
__device__ __forceinline__ uint32_t smem_u32(const void* p) {
    uint32_t a;
    asm("{ .reg .u64 t; cvta.to.shared.u64 t, %1; cvt.u32.u64 %0, t; }" : "=r"(a) : "l"(p));
    return a;
}
__device__ __forceinline__ void cp16(uint32_t saddr, const void* g) {
    asm volatile("cp.async.cg.shared.global [%0], [%1], 16;" :: "r"(saddr), "l"(g) : "memory");
}
__device__ __forceinline__ void cp_commit() {
    asm volatile("cp.async.commit_group;" ::: "memory");
}
template<int N> __device__ __forceinline__ void cp_wait() {
    asm volatile("cp.async.wait_group %0;" :: "n"(N) : "memory");
}
__device__ __forceinline__ void ldm_x4(uint32_t addr, uint32_t* r) {
    asm volatile("ldmatrix.sync.aligned.m8n8.x4.shared.b16 {%0,%1,%2,%3}, [%4];"
        : "=r"(r[0]), "=r"(r[1]), "=r"(r[2]), "=r"(r[3]) : "r"(addr));
}
__device__ __forceinline__ void ldm_x4_t(uint32_t addr, uint32_t* r) {
    asm volatile("ldmatrix.sync.aligned.m8n8.x4.trans.shared.b16 {%0,%1,%2,%3}, [%4];"
        : "=r"(r[0]), "=r"(r[1]), "=r"(r[2]), "=r"(r[3]) : "r"(addr));
}
__device__ __forceinline__ void mma16816(float* d, const uint32_t* a, const uint32_t* b) {
    asm volatile("mma.sync.aligned.m16n8k16.row.col.f32.bf16.bf16.f32 "
        "{%0,%1,%2,%3}, {%4,%5,%6,%7}, {%8,%9}, {%0,%1,%2,%3};"
        : "+f"(d[0]), "+f"(d[1]), "+f"(d[2]), "+f"(d[3])
        : "r"(a[0]), "r"(a[1]), "r"(a[2]), "r"(a[3]), "r"(b[0]), "r"(b[1]));
}
__device__ __forceinline__ void split2(float v, bf16& h, bf16& l) {
    h = __float2bfloat16(v);
    l = __float2bfloat16(v - __bfloat162float(h));
}
__device__ __forceinline__ uint32_t pack_bf2(float a, float b) {
    __nv_bfloat162 t = __floats2bfloat162_rn(a, b);
    return *(uint32_t*)&t;
}

// ---------------- prep device functions ----------------
__device__ __forceinline__ void split_chunk(const float4* __restrict__ in,
                                            __nv_bfloat162* __restrict__ hi,
                                            __nv_bfloat162* __restrict__ lo,
                                            size_t base4, size_t n4)
{
#pragma unroll
    for (int q = 0; q < 16; q++) {
        size_t i = base4 + (size_t)q * 256 + threadIdx.x;
        if (i >= n4) return;
        float4 v = in[i];
        bf16 h0, l0_, h1, l1_, h2, l2_, h3, l3_;
        split2(v.x, h0, l0_); split2(v.y, h1, l1_);
        split2(v.z, h2, l2_); split2(v.w, h3, l3_);
        hi[i * 2]     = __nv_bfloat162(h0, h1);
        hi[i * 2 + 1] = __nv_bfloat162(h2, h3);
        lo[i * 2]     = __nv_bfloat162(l0_, l1_);
        lo[i * 2 + 1] = __nv_bfloat162(l2_, l3_);
    }
}

__device__ __forceinline__ void tr_strip(const float* __restrict__ in,
                                         bf16* __restrict__ hi, bf16* __restrict__ lo,
                                         int K, int N, int Npad, int Kpad, int rowOff,
                                         int strip, int nStrips)
{
    __shared__ float t[32][33];
    int kTile = strip / nStrips;
    int nT0 = (strip % nStrips) * 8;
    int k0 = kTile * 32;
    int tx = threadIdx.x & 31, ty = threadIdx.x >> 5;
    for (int sub = 0; sub < 8; sub++) {
        int n0 = (nT0 + sub) * 32;
        if (n0 >= Npad) break;
        __syncthreads();
#pragma unroll
        for (int i = 0; i < 4; i++) {
            int k = k0 + ty + i * 8;
            float v = (k < K && n0 + tx < N) ? in[(size_t)k * N + n0 + tx] : 0.f;
            t[ty + i * 8][tx] = v;
        }
        __syncthreads();
#pragma unroll
        for (int i = 0; i < 4; i++) {
            int n = n0 + ty + i * 8, k = k0 + tx;
            if (n < Npad && k < Kpad) {
                size_t o = (size_t)(n + rowOff) * Kpad + k;
                split2(t[tx][ty + i * 8], hi[o], lo[o]);
            }
        }
    }
}

// ---------------- GEMM core: C = A @ B^T, BK=32, 3-stage, occupancy-2 ----------------
#define STAGE 32768
#define SMEM_GEMM (3*STAGE)

__device__ __forceinline__ void gemm_core(
    const bf16* __restrict__ Ahi, const bf16* __restrict__ Alo,
    const bf16* __restrict__ Bhi, const bf16* __restrict__ Blo,
    float* __restrict__ Cf, bf16* __restrict__ Ch, bf16* __restrict__ Cl,
    int N, int Kpad, int lda, int ldb, int ldc,
    int r0, int c0, char* smem)
{
    int tid = threadIdx.x, lane = tid & 31, wid = tid >> 5;
    int tiles = Kpad >> 5;

    const bf16* Ah = Ahi + (size_t)r0 * lda;
    const bf16* Al = Alo + (size_t)r0 * lda;
    const bf16* Bh = Bhi + (size_t)c0 * ldb;
    const bf16* Bl = Blo + (size_t)c0 * ldb;

    uint32_t sbase = smem_u32(smem);
    int wm = (wid >> 2) * 64, wn = (wid & 3) * 32;

    float acc[4][4][4];
#pragma unroll
    for (int i = 0; i < 4; i++)
#pragma unroll
        for (int j = 0; j < 4; j++)
#pragma unroll
            for (int v = 0; v < 4; v++) acc[i][j][v] = 0.f;

    // stage layout: Ah 0, Al 8K, Bh 16K, Bl 24K; 128 rows x 64B, 4 chunks, xor-swizzle
    auto load_stage = [&](int t) {
        int k0 = t << 5;
        uint32_t sb = sbase + (uint32_t)(t % 3) * STAGE;
#pragma unroll
        for (int q = 0; q < 2; q++) {
            int c = tid + q * 256;
            int row = c >> 2, ch = c & 3;
            uint32_t off = (uint32_t)row * 64 + (uint32_t)((ch ^ ((row >> 1) & 3)) << 4);
            size_t ga = (size_t)row * lda + k0 + ch * 8;
            size_t gb = (size_t)row * ldb + k0 + ch * 8;
            cp16(sb + off,         Ah + ga);
            cp16(sb + 8192 + off,  Al + ga);
            cp16(sb + 16384 + off, Bh + gb);
            cp16(sb + 24576 + off, Bl + gb);
        }
        cp_commit();
    };

    auto compute_stage = [&](int t) {
        uint32_t sb = sbase + (uint32_t)(t % 3) * STAGE;
#pragma unroll
        for (int kk = 0; kk < 32; kk += 16) {
            uint32_t bh[4][2], bl[4][2];
#pragma unroll
            for (int p = 0; p < 2; p++) {
                int rowB = wn + p * 16 + ((lane >> 4) << 3) + (lane & 7);
                int ch = (kk >> 3) + ((lane >> 3) & 1);
                uint32_t off = (uint32_t)rowB * 64 + (uint32_t)((ch ^ ((rowB >> 1) & 3)) << 4);
                uint32_t r[4];
                ldm_x4(sb + 16384 + off, r);
                bh[2 * p][0] = r[0]; bh[2 * p][1] = r[1];
                bh[2 * p + 1][0] = r[2]; bh[2 * p + 1][1] = r[3];
                ldm_x4(sb + 24576 + off, r);
                bl[2 * p][0] = r[0]; bl[2 * p][1] = r[1];
                bl[2 * p + 1][0] = r[2]; bl[2 * p + 1][1] = r[3];
            }
#pragma unroll
            for (int mt = 0; mt < 4; mt++) {
                int rowA = wm + mt * 16 + (lane & 15);
                int ch = (kk >> 3) + (lane >> 4);
                uint32_t off = (uint32_t)rowA * 64 + (uint32_t)((ch ^ ((rowA >> 1) & 3)) << 4);
                uint32_t ah[4], al[4];
                ldm_x4(sb + off, ah);
                ldm_x4(sb + 8192 + off, al);
#pragma unroll
                for (int nt = 0; nt < 4; nt++) {
                    mma16816(acc[mt][nt], ah, bh[nt]);
                    mma16816(acc[mt][nt], ah, bl[nt]);
                    mma16816(acc[mt][nt], al, bh[nt]);
                }
            }
        }
    };

    load_stage(0);
    if (tiles > 1) load_stage(1);
    for (int t = 0; t < tiles; t++) {
        if (t + 1 < tiles) cp_wait<1>(); else cp_wait<0>();
        __syncthreads();
        if (t + 2 < tiles) load_stage(t + 2);
        compute_stage(t);
    }

    if (Cf) {
#pragma unroll
        for (int mt = 0; mt < 4; mt++) {
#pragma unroll
            for (int nt = 0; nt < 4; nt++) {
                int r = r0 + wm + mt * 16 + (lane >> 2);
                int c = c0 + wn + nt * 8 + ((lane & 3) << 1);
                float* p0 = Cf + (size_t)r * ldc + c;
                float* p1 = p0 + 8 * ldc;
                p0[0] = acc[mt][nt][0]; p0[1] = acc[mt][nt][1];
                p1[0] = acc[mt][nt][2]; p1[1] = acc[mt][nt][3];
            }
        }
    } else {
#pragma unroll
        for (int mt = 0; mt < 4; mt++) {
#pragma unroll
            for (int nt = 0; nt < 4; nt++) {
                int r = r0 + wm + mt * 16 + (lane >> 2);
                int c = c0 + wn + nt * 8 + ((lane & 3) << 1);
                size_t o0 = (size_t)r * ldc + c;
                size_t o1 = o0 + (size_t)8 * ldc;
                float v0 = acc[mt][nt][0], v1 = acc[mt][nt][1];
                float v2 = acc[mt][nt][2], v3 = acc[mt][nt][3];
                float h0 = __bfloat162float(__float2bfloat16(v0));
                float h1 = __bfloat162float(__float2bfloat16(v1));
                float h2 = __bfloat162float(__float2bfloat16(v2));
                float h3 = __bfloat162float(__float2bfloat16(v3));
                *(uint32_t*)(Ch + o0) = pack_bf2(h0, h1);
                *(uint32_t*)(Ch + o1) = pack_bf2(h2, h3);
                *(uint32_t*)(Cl + o0) = pack_bf2(v0 - h0, v1 - h1);
                *(uint32_t*)(Cl + o1) = pack_bf2(v2 - h2, v3 - h3);
            }
        }
    }
}

// ---------------- prep1: x split + W1 transposes ----------------
__global__ __launch_bounds__(256)
void prep1(const float* __restrict__ x,
           const float* __restrict__ W_dq, const float* __restrict__ W_dkv,
           const float* __restrict__ W_kr,
           bf16* __restrict__ xhi, bf16* __restrict__ xlo,
           bf16* __restrict__ w1h, bf16* __restrict__ w1l)
{
    int i = blockIdx.x;
    if (i < 512) {
        split_chunk((const float4*)x, (__nv_bfloat162*)xhi, (__nv_bfloat162*)xlo,
                    (size_t)i * 4096, (size_t)BS * DMODEL / 4);
    } else if (i < 768) {
        tr_strip(W_dq, w1h, w1l, DMODEL, QPROJ, QPROJ, DMODEL, 0, i - 512, 4);
    } else if (i < 1152) {
        tr_strip(W_dkv, w1h, w1l, DMODEL, KVPROJ, KVPAD, DMODEL, QPROJ, i - 768, 6);
    } else {
        tr_strip(W_kr, w1h, w1l, DMODEL, 256, 256, DMODEL, QPROJ + KVPAD, i - 1152, 1);
    }
}

// ---------------- p1 GEMM fused with prep2 ----------------
__global__ __launch_bounds__(256, 2)
void gemm_p1_prep2(const bf16* __restrict__ xhi, const bf16* __restrict__ xlo,
                   const bf16* __restrict__ w1h, const bf16* __restrict__ w1l,
                   float* __restrict__ p1,
                   const float* __restrict__ W_uq, const float* __restrict__ W_qr,
                   const float* __restrict__ W_ukv, const float* __restrict__ W_o,
                   bf16* __restrict__ w2h, bf16* __restrict__ w2l,
                   bf16* __restrict__ wukvh, bf16* __restrict__ wukvl,
                   bf16* __restrict__ woh, bf16* __restrict__ wol)
{
    extern __shared__ __align__(128) char smem[];
    int i = blockIdx.x;
    bool isGemm;
    int sub;
    if (i < 1344) { isGemm = !(i & 1); sub = i >> 1; }
    else          { isGemm = false;    sub = 672 + (i - 1344); }

    if (isGemm) {
        int cx = sub % 21, cy = sub / 21;
        gemm_core(xhi, xlo, w1h, w1l, p1, nullptr, nullptr,
                  N1, DMODEL, DMODEL, DMODEL, N1, cy * 128, cx * 128, smem);
    } else {
        if (sub < 224) {
            tr_strip(W_uq, w2h, w2l, QPROJ, KNOPE, KNOPE, QPROJ, 0, sub, 7);
        } else if (sub < 256) {
            tr_strip(W_qr, w2h, w2l, QPROJ, 256, 256, QPROJ, KNOPE, sub - 224, 1);
        } else if (sub < 916) {
            tr_strip(W_ukv, wukvh, wukvl, KVPROJ, KVCOLS, KVCOLS, KVPAD, 0, sub - 256, 15);
        } else {
            split_chunk((const float4*)W_o, (__nv_bfloat162*)woh, (__nv_bfloat162*)wol,
                        (size_t)(sub - 916) * 4096, (size_t)DMODEL * DMODEL / 4);
        }
    }
}

__global__ __launch_bounds__(256, 2)
void hmma_gemm(const bf16* __restrict__ Ahi, const bf16* __restrict__ Alo,
               const bf16* __restrict__ Bhi, const bf16* __restrict__ Blo,
               float* __restrict__ Cf, bf16* __restrict__ Ch, bf16* __restrict__ Cl,
               int N, int Kpad, int lda, int ldb, int ldc)
{
    extern __shared__ __align__(128) char smem[];
    gemm_core(Ahi, Alo, Bhi, Blo, Cf, Ch, Cl, N, Kpad, lda, ldb, ldc,
              blockIdx.y * 128, blockIdx.x * 128, smem);
}

__global__ __launch_bounds__(256, 2)
void hmma_gemm_dual(
    const bf16* A1h, const bf16* A1l, const bf16* B1h, const bf16* B1l,
    bf16* C1h, bf16* C1l, int n1, int k1, int la1, int lb1, int lc1, int gx1,
    const bf16* A2h, const bf16* A2l, const bf16* B2h, const bf16* B2l,
    bf16* C2h, bf16* C2l, int n2, int k2, int la2, int lb2, int lc2, int gx2,
    int split)
{
    extern __shared__ __align__(128) char smem[];
    int idx = blockIdx.x;
    if (idx < split) {
        int cx = idx % gx1, cy = idx / gx1;
        gemm_core(A1h, A1l, B1h, B1l, nullptr, C1h, C1l, n1, k1, la1, lb1, lc1,
                  cy * 128, cx * 128, smem);
    } else {
        idx -= split;
        int cx = idx % gx2, cy = idx / gx2;
        gemm_core(A2h, A2l, B2h, B2l, nullptr, C2h, C2l, n2, k2, la2, lb2, lc2,
                  cy * 128, cx * 128, smem);
    }
}

// ---------------- fused flash attention (unchanged) ----------------
#define FST 65536
#define SMEM_FLASH (3*FST)

__global__ __launch_bounds__(256, 1)
void flash_attn(const bf16* __restrict__ q2h, const bf16* __restrict__ q2l,
                const bf16* __restrict__ kvh, const bf16* __restrict__ kvl,
                bf16* __restrict__ aoh, bf16* __restrict__ aol)
{
    extern __shared__ __align__(128) char smem[];
    int tid = threadIdx.x, lane = tid & 31, wid = tid >> 5;
    int z = blockIdx.y, bb = z >> 4, hh = z & 15;
    int r0 = ((int)gridDim.x - 1 - (int)blockIdx.x) * 128;

    int kcol = (hh < NOPE) ? hh * DH : KVCOLS + (hh - NOPE) * DH;
    int vcol = KNOPE + hh * DH;

    const bf16* qhz = q2h + ((size_t)(bb * S_ + r0)) * N2 + hh * DH;
    const bf16* qlz = q2l + ((size_t)(bb * S_ + r0)) * N2 + hh * DH;
    const bf16* khz = kvh + (size_t)(bb * S_) * KVLD + kcol;
    const bf16* klz = kvl + (size_t)(bb * S_) * KVLD + kcol;
    const bf16* vhz = kvh + (size_t)(bb * S_) * KVLD + vcol;
    const bf16* vlz = kvl + (size_t)(bb * S_) * KVLD + vcol;

    uint32_t sb = smem_u32(smem);

#pragma unroll
    for (int q = 0; q < 8; q++) {
        int idx = tid + q * 256;
        int row = idx >> 4, ch = idx & 15;
        uint32_t off = (uint32_t)row * 256 + (uint32_t)((ch ^ (row & 7)) << 4);
        cp16(sb + off,         qhz + (size_t)row * N2 + ch * 8);
        cp16(sb + 32768 + off, qlz + (size_t)row * N2 + ch * 8);
    }
    cp_commit();

    int ntiles = (r0 >> 6) + 2;
    int diag = r0 >> 6;

    auto load_stage = [&](int jt) {
        uint32_t st = sb + (uint32_t)((jt + 1) % 3) * FST;
        int s0 = jt * 64;
#pragma unroll
        for (int q = 0; q < 4; q++) {
            int idx = tid + q * 256;
            int row = idx >> 4, ch = idx & 15;
            uint32_t off = (uint32_t)row * 256 + (uint32_t)((ch ^ (row & 7)) << 4);
            size_t g = (size_t)(s0 + row) * KVLD + ch * 8;
            cp16(st + off,         khz + g);
            cp16(st + 16384 + off, klz + g);
        }
#pragma unroll
        for (int q = 0; q < 4; q++) {
            int idx = tid + q * 256;
            int row = idx >> 4, ch = idx & 15;
            uint32_t off = (uint32_t)row * 256 + (uint32_t)((ch ^ (row & 7)) << 4);
            size_t g = (size_t)(s0 + row) * KVLD + ch * 8;
            cp16(st + 32768 + off, vhz + g);
            cp16(st + 49152 + off, vlz + g);
        }
        cp_commit();
    };

    load_stage(0);
    load_stage(1);
    cp_wait<2>();
    __syncthreads();

    int wrow = wid * 16;
    uint32_t qah[8][4], qal[8][4];
#pragma unroll
    for (int kf = 0; kf < 8; kf++) {
        int row = wrow + (lane & 15);
        int ch = kf * 2 + (lane >> 4);
        uint32_t off = (uint32_t)row * 256 + (uint32_t)((ch ^ (row & 7)) << 4);
        ldm_x4(sb + off, qah[kf]);
        ldm_x4(sb + 32768 + off, qal[kf]);
    }

    float of[16][4];
#pragma unroll
    for (int i = 0; i < 16; i++)
#pragma unroll
        for (int v = 0; v < 4; v++) of[i][v] = 0.f;
    float m0 = -1e30f, m1 = -1e30f, l0 = 0.f, l1 = 0.f;
    const float CEXP = 0.08838834764831845f * 1.4426950408889634f;

    int rowa = r0 + wrow + (lane >> 2);

    for (int jt = 0; jt < ntiles; jt++) {
        if (jt + 1 < ntiles) cp_wait<1>(); else cp_wait<0>();
        __syncthreads();
        if (jt + 2 < ntiles) load_stage(jt + 2);
        uint32_t st = sb + (uint32_t)((jt + 1) % 3) * FST;

        float sf[8][4];
#pragma unroll
        for (int nf = 0; nf < 8; nf++)
#pragma unroll
            for (int v = 0; v < 4; v++) sf[nf][v] = 0.f;

#pragma unroll
        for (int kf = 0; kf < 8; kf++) {
            uint32_t bh[8][2], bl[8][2];
#pragma unroll
            for (int p = 0; p < 4; p++) {
                int rowB = p * 16 + ((lane >> 4) << 3) + (lane & 7);
                int ch = kf * 2 + ((lane >> 3) & 1);
                uint32_t off = (uint32_t)rowB * 256 + (uint32_t)((ch ^ (rowB & 7)) << 4);
                uint32_t r4[4];
                ldm_x4(st + off, r4);
                bh[2 * p][0] = r4[0]; bh[2 * p][1] = r4[1];
                bh[2 * p + 1][0] = r4[2]; bh[2 * p + 1][1] = r4[3];
                ldm_x4(st + 16384 + off, r4);
                bl[2 * p][0] = r4[0]; bl[2 * p][1] = r4[1];
                bl[2 * p + 1][0] = r4[2]; bl[2 * p + 1][1] = r4[3];
            }
#pragma unroll
            for (int nf = 0; nf < 8; nf++) {
                mma16816(sf[nf], qah[kf], bh[nf]);
                mma16816(sf[nf], qah[kf], bl[nf]);
                mma16816(sf[nf], qal[kf], bh[nf]);
            }
        }

        if (jt >= diag) {
            int colb = jt * 64 + 2 * (lane & 3);
#pragma unroll
            for (int nf = 0; nf < 8; nf++) {
                int c = colb + nf * 8;
                if (c > rowa)     sf[nf][0] = -1e30f;
                if (c + 1 > rowa) sf[nf][1] = -1e30f;
                if (c > rowa + 8)     sf[nf][2] = -1e30f;
                if (c + 1 > rowa + 8) sf[nf][3] = -1e30f;
            }
        }

        float tm0 = -1e30f, tm1 = -1e30f;
#pragma unroll
        for (int nf = 0; nf < 8; nf++) {
            tm0 = fmaxf(tm0, fmaxf(sf[nf][0], sf[nf][1]));
            tm1 = fmaxf(tm1, fmaxf(sf[nf][2], sf[nf][3]));
        }
        tm0 = fmaxf(tm0, __shfl_xor_sync(0xffffffffu, tm0, 1));
        tm0 = fmaxf(tm0, __shfl_xor_sync(0xffffffffu, tm0, 2));
        tm1 = fmaxf(tm1, __shfl_xor_sync(0xffffffffu, tm1, 1));
        tm1 = fmaxf(tm1, __shfl_xor_sync(0xffffffffu, tm1, 2));
        float mn0 = fmaxf(m0, tm0), mn1 = fmaxf(m1, tm1);
        float al0 = exp2f((m0 - mn0) * CEXP), al1 = exp2f((m1 - mn1) * CEXP);
        m0 = mn0; m1 = mn1;

        uint32_t pah[4][4], pal[4][4];
        float rs0 = 0.f, rs1 = 0.f;
#pragma unroll
        for (int nf = 0; nf < 8; nf++) {
            float e0 = exp2f((sf[nf][0] - m0) * CEXP);
            float e1 = exp2f((sf[nf][1] - m0) * CEXP);
            float e2 = exp2f((sf[nf][2] - m1) * CEXP);
            float e3 = exp2f((sf[nf][3] - m1) * CEXP);
            rs0 += e0 + e1; rs1 += e2 + e3;
            float h0 = __bfloat162float(__float2bfloat16(e0));
            float h1 = __bfloat162float(__float2bfloat16(e1));
            float h2 = __bfloat162float(__float2bfloat16(e2));
            float h3 = __bfloat162float(__float2bfloat16(e3));
            int kf2 = nf >> 1, s = (nf & 1) * 2;
            pah[kf2][s]     = pack_bf2(h0, h1);
            pah[kf2][s + 1] = pack_bf2(h2, h3);
            pal[kf2][s]     = pack_bf2(e0 - h0, e1 - h1);
            pal[kf2][s + 1] = pack_bf2(e2 - h2, e3 - h3);
        }
        l0 = l0 * al0 + rs0;
        l1 = l1 * al1 + rs1;

#pragma unroll
        for (int i = 0; i < 16; i++) {
            of[i][0] *= al0; of[i][1] *= al0;
            of[i][2] *= al1; of[i][3] *= al1;
        }

#pragma unroll
        for (int kf2 = 0; kf2 < 4; kf2++) {
#pragma unroll
            for (int nb = 0; nb < 8; nb++) {
                int row = kf2 * 16 + (lane & 15);
                int ch = nb * 2 + (lane >> 4);
                uint32_t off = (uint32_t)row * 256 + (uint32_t)((ch ^ (row & 7)) << 4);
                uint32_t rh[4], rl[4];
                ldm_x4_t(st + 32768 + off, rh);
                ldm_x4_t(st + 49152 + off, rl);
                uint32_t bh0[2] = {rh[0], rh[1]}, bh1[2] = {rh[2], rh[3]};
                uint32_t bl0[2] = {rl[0], rl[1]}, bl1[2] = {rl[2], rl[3]};
                mma16816(of[2 * nb],     pah[kf2], bh0);
                mma16816(of[2 * nb],     pah[kf2], bl0);
                mma16816(of[2 * nb],     pal[kf2], bh0);
                mma16816(of[2 * nb + 1], pah[kf2], bh1);
                mma16816(of[2 * nb + 1], pah[kf2], bl1);
                mma16816(of[2 * nb + 1], pal[kf2], bh1);
            }
        }
    }

    l0 += __shfl_xor_sync(0xffffffffu, l0, 1);
    l0 += __shfl_xor_sync(0xffffffffu, l0, 2);
    l1 += __shfl_xor_sync(0xffffffffu, l1, 1);
    l1 += __shfl_xor_sync(0xffffffffu, l1, 2);
    float inv0 = 1.f / l0, inv1 = 1.f / l1;

    size_t ga = ((size_t)(bb * S_) + rowa) * DMODEL + hh * DH;
    size_t gb = ga + (size_t)8 * DMODEL;
#pragma unroll
    for (int i = 0; i < 16; i++) {
        int d = i * 8 + 2 * (lane & 3);
        float v0 = of[i][0] * inv0, v1 = of[i][1] * inv0;
        float v2 = of[i][2] * inv1, v3 = of[i][3] * inv1;
        float h0 = __bfloat162float(__float2bfloat16(v0));
        float h1 = __bfloat162float(__float2bfloat16(v1));
        float h2 = __bfloat162float(__float2bfloat16(v2));
        float h3 = __bfloat162float(__float2bfloat16(v3));
        *(uint32_t*)(aoh + ga + d) = pack_bf2(h0, h1);
        *(uint32_t*)(aoh + gb + d) = pack_bf2(h2, h3);
        *(uint32_t*)(aol + ga + d) = pack_bf2(v0 - h0, v1 - h1);
        *(uint32_t*)(aol + gb + d) = pack_bf2(v2 - h2, v3 - h3);
    }
}

// ---------------- merged LayerNorm ----------------
__global__ __launch_bounds__(256)
void layernorm2(const float* __restrict__ p1,
                bf16* __restrict__ cqh, bf16* __restrict__ cql,
                float* __restrict__ ckv,
                bf16* __restrict__ ckvh, bf16* __restrict__ ckvl,
                const float* __restrict__ q_w, const float* __restrict__ q_b,
                const float* __restrict__ kv_w, const float* __restrict__ kv_b)
{
    bool isKV = blockIdx.y != 0;
    const float* p = p1 + (size_t)blockIdx.x * N1 + (isKV ? QPROJ : 0);
    int n = isKV ? KVPROJ : QPROJ;
    int npad = isKV ? KVPAD : QPROJ;
    const float* w = isKV ? kv_w : q_w;
    const float* b = isKV ? kv_b : q_b;
    bf16* hh = (isKV ? ckvh : cqh) + (size_t)blockIdx.x * npad;
    bf16* ll = (isKV ? ckvl : cql) + (size_t)blockIdx.x * npad;
    float* of = isKV ? ckv + (size_t)blockIdx.x * KVPROJ : nullptr;

    float s = 0.f, s2 = 0.f;
    for (int j = threadIdx.x; j < n; j += 256) {
        float v = p[j];
        s += v; s2 += v * v;
    }
    __shared__ float sh[20];
#pragma unroll
    for (int o = 16; o; o >>= 1) {
        s  += __shfl_down_sync(0xffffffffu, s,  o);
        s2 += __shfl_down_sync(0xffffffffu, s2, o);
    }
    int wd = threadIdx.x >> 5, ln = threadIdx.x & 31;
    if (!ln) { sh[wd] = s; sh[wd + 8] = s2; }
    __syncthreads();
    if (threadIdx.x == 0) {
        float ts = 0.f, ts2 = 0.f;
        for (int i = 0; i < 8; i++) { ts += sh[i]; ts2 += sh[i + 8]; }
        float mean = ts / n;
        float var = fmaxf(ts2 / n - mean * mean, 0.f);
        sh[16] = mean;
        sh[17] = rsqrtf(var + 1e-5f);
    }
    __syncthreads();
    float mean = sh[16], rstd = sh[17];
    for (int j = threadIdx.x; j < npad; j += 256) {
        float v = 0.f;
        if (j < n) {
            v = (p[j] - mean) * rstd * w[j] + b[j];
            if (of) of[j] = v;
        }
        split2(v, hh[j], ll[j]);
    }
}

// merged RoPE
__global__ __launch_bounds__(256)
void rope_qk(bf16* __restrict__ q2h, bf16* __restrict__ q2l,
             const float* __restrict__ p1,
             bf16* __restrict__ kvh, bf16* __restrict__ kvl)
{
    int total = BS * 2 * 64;
    int idx = blockIdx.x * 256 + threadIdx.x;
    if (idx >= 2 * total) return;
    bool isK = idx >= total;
    if (isK) idx -= total;
    int dp = idx & 63;
    int h2 = (idx >> 6) & 1;
    int row = idx >> 7;
    int s = row & (S_ - 1);
    float freq = exp2f(-(float)dp * 0.20762050593046015f);
    float sn, cs;
    sincosf((float)s * freq, &sn, &cs);

    if (!isK) {
        size_t base = (size_t)row * N2 + KNOPE + h2 * DH;
        float x1 = __bfloat162float(q2h[base + dp]) + __bfloat162float(q2l[base + dp]);
        float x2 = __bfloat162float(q2h[base + dp + 64]) + __bfloat162float(q2l[base + dp + 64]);
        float v1 = x1 * cs - x2 * sn;
        float v2 = x2 * cs + x1 * sn;
        split2(v1, q2h[base + dp], q2l[base + dp]);
        split2(v2, q2h[base + dp + 64], q2l[base + dp + 64]);
    } else {
        const float* src = p1 + (size_t)row * N1 + 2432 + h2 * DH;
        float x1 = src[dp], x2 = src[dp + 64];
        float v1 = x1 * cs - x2 * sn;
        float v2 = x2 * cs + x1 * sn;
        size_t base = (size_t)row * KVLD + KVCOLS + h2 * DH;
        split2(v1, kvh[base + dp], kvl[base + dp]);
        split2(v2, kvh[base + dp + 64], kvl[base + dp + 64]);
    }
}

// ---------------- launch ----------------
static inline void* sym(const void* s) { void* p; cudaGetSymbolAddress(&p, s); return p; }

extern "C" void kernel_launch(void* const* d_in, const int* in_sizes, int n_in,
                              void* d_out, int out_size)
{
    const float* x     = (const float*)d_in[0];
    const float* W_dq  = (const float*)d_in[1];
    const float* W_uq  = (const float*)d_in[2];
    const float* W_qr  = (const float*)d_in[3];
    const float* W_dkv = (const float*)d_in[4];
    const float* W_ukv = (const float*)d_in[5];
    const float* W_kr  = (const float*)d_in[6];
    const float* W_o   = (const float*)d_in[7];
    const float* q_w   = (const float*)d_in[8];
    const float* q_b   = (const float*)d_in[9];
    const float* kv_w  = (const float*)d_in[10];
    const float* kv_b  = (const float*)d_in[11];

    float* out = (float*)d_out;
    float* ckv = out + (size_t)BS * DMODEL;

    bf16 *xhi=(bf16*)sym(g_xhi), *xlo=(bf16*)sym(g_xlo);
    bf16 *w1h=(bf16*)sym(g_w1h), *w1l=(bf16*)sym(g_w1l);
    bf16 *w2h=(bf16*)sym(g_w2h), *w2l=(bf16*)sym(g_w2l);
    bf16 *wukvh=(bf16*)sym(g_wukvh), *wukvl=(bf16*)sym(g_wukvl);
    bf16 *woh=(bf16*)sym(g_woh), *wol=(bf16*)sym(g_wol);
    float *p1=(float*)sym(g_p1);
    bf16 *cqh=(bf16*)sym(g_cqh), *cql=(bf16*)sym(g_cql);
    bf16 *ckvh=(bf16*)sym(g_ckvh), *ckvl=(bf16*)sym(g_ckvl);
    bf16 *q2h=(bf16*)sym(g_q2h), *q2l=(bf16*)sym(g_q2l);
    bf16 *kvh=(bf16*)sym(g_kvh), *kvl=(bf16*)sym(g_kvl);
    bf16 *aoh=(bf16*)sym(g_aoh), *aol=(bf16*)sym(g_aol);

    cudaFuncSetAttribute(hmma_gemm, cudaFuncAttributeMaxDynamicSharedMemorySize, SMEM_GEMM);
    cudaFuncSetAttribute(hmma_gemm_dual, cudaFuncAttributeMaxDynamicSharedMemorySize, SMEM_GEMM);
    cudaFuncSetAttribute(gemm_p1_prep2, cudaFuncAttributeMaxDynamicSharedMemorySize, SMEM_GEMM);
    cudaFuncSetAttribute(flash_attn, cudaFuncAttributeMaxDynamicSharedMemorySize, SMEM_FLASH);

    // 1. x split + W1 transposes
    prep1<<<1216, 256>>>(x, W_dq, W_dkv, W_kr, xhi, xlo, w1h, w1l);

    // 2. p1 = x @ W1 (fp32) fused with prep2
    gemm_p1_prep2<<<1844, 256, SMEM_GEMM>>>(
        xhi, xlo, w1h, w1l, p1,
        W_uq, W_qr, W_ukv, W_o,
        w2h, w2l, wukvh, wukvl, woh, wol);

    // 3. LayerNorms (merged)
    layernorm2<<<dim3(BS, 2), 256>>>(p1, cqh, cql, ckv, ckvh, ckvl, q_w, q_b, kv_w, kv_b);

    // 4. q2 = cq @ W2 AND kv = ckv @ W_ukv in one launch
    {
        int gx_ukv = KVCOLS / 128;              // 30
        int gx_q2  = N2 / 128;                  // 16
        int blocks_ukv = gx_ukv * (BS / 128);   // 960
        int blocks_q2  = gx_q2  * (BS / 128);   // 512
        hmma_gemm_dual<<<blocks_ukv + blocks_q2, 256, SMEM_GEMM>>>(
            ckvh, ckvl, wukvh, wukvl, kvh, kvl,
            KVCOLS, KVPAD, KVPAD, KVPAD, KVLD, gx_ukv,
            cqh, cql, w2h, w2l, q2h, q2l,
            N2, QPROJ, QPROJ, QPROJ, N2, gx_q2,
            blocks_ukv);
    }

    // 5. RoPE
    rope_qk<<<(2*BS*2*64 + 255)/256, 256>>>(q2h, q2l, p1, kvh, kvl);

    // 6. flash attention
    flash_attn<<<dim3(S_/128, NZ), 256, SMEM_FLASH>>>(q2h, q2l, kvh, kvl, aoh, aol);

    // 7. final projection
    hmma_gemm<<<dim3(DMODEL/128, BS/128), 256, SMEM_GEMM>>>(
        aoh, aol, woh, wol, out, nullptr, nullptr, DMODEL, DMODEL, DMODEL, DMODEL, DMODEL);
}

// round 10
// speedup vs baseline: 7.7442x; 1.3601x over previous
#include <cuda_runtime.h>
#include <cuda_fp16.h>
#include <cstdint>
#include <math.h>

// ---------------- problem constants ----------------
#define B_      2
#define S_      2048
#define DMODEL  2048
#define NH      16
#define DH      128
#define NOPE    14
#define QPROJ   1024
#define KVPROJ  1365
#define KVPAD   1408
#define KNOPE   1792
#define KVCOLS  3840
#define KVLD    4096
#define BS      (B_*S_)
#define NZ      (B_*NH)
#define N1      2688
#define N2      2048

typedef __half h16;

// ---------------- device scratch ----------------
__device__ h16 g_xhi[(size_t)BS*DMODEL],   g_xlo[(size_t)BS*DMODEL];
__device__ h16 g_w1h[(size_t)N1*DMODEL];
__device__ h16 g_w2h[(size_t)N2*QPROJ];
__device__ h16 g_wukvh[(size_t)KVCOLS*KVPAD];
__device__ h16 g_woh[(size_t)DMODEL*DMODEL];
__device__ float g_p1[(size_t)BS*N1];
__device__ h16 g_cqh[(size_t)BS*QPROJ],    g_cql[(size_t)BS*QPROJ];
__device__ h16 g_ckvh[(size_t)BS*KVPAD],   g_ckvl[(size_t)BS*KVPAD];
__device__ h16 g_q2h[(size_t)BS*N2],       g_q2l[(size_t)BS*N2];
__device__ h16 g_kvh[(size_t)BS*KVLD];
__device__ h16 g_aoh[(size_t)BS*DMODEL],   g_aol[(size_t)BS*DMODEL];

// ---------------- helpers ----------------
__device__ __forceinline__ uint32_t smem_u32(const void* p) {
    uint32_t a;
    asm("{ .reg .u64 t; cvta.to.shared.u64 t, %1; cvt.u32.u64 %0, t; }" : "=r"(a) : "l"(p));
    return a;
}
__device__ __forceinline__ void cp16(uint32_t saddr, const void* g) {
    asm volatile("cp.async.cg.shared.global [%0], [%1], 16;" :: "r"(saddr), "l"(g) : "memory");
}
__device__ __forceinline__ void cp_commit() {
    asm volatile("cp.async.commit_group;" ::: "memory");
}
template<int N> __device__ __forceinline__ void cp_wait() {
    asm volatile("cp.async.wait_group %0;" :: "n"(N) : "memory");
}
__device__ __forceinline__ void ldm_x4(uint32_t addr, uint32_t* r) {
    asm volatile("ldmatrix.sync.aligned.m8n8.x4.shared.b16 {%0,%1,%2,%3}, [%4];"
        : "=r"(r[0]), "=r"(r[1]), "=r"(r[2]), "=r"(r[3]) : "r"(addr));
}
__device__ __forceinline__ void ldm_x4_t(uint32_t addr, uint32_t* r) {
    asm volatile("ldmatrix.sync.aligned.m8n8.x4.trans.shared.b16 {%0,%1,%2,%3}, [%4];"
        : "=r"(r[0]), "=r"(r[1]), "=r"(r[2]), "=r"(r[3]) : "r"(addr));
}
__device__ __forceinline__ void mma16816(float* d, const uint32_t* a, const uint32_t* b) {
    asm volatile("mma.sync.aligned.m16n8k16.row.col.f32.f16.f16.f32 "
        "{%0,%1,%2,%3}, {%4,%5,%6,%7}, {%8,%9}, {%0,%1,%2,%3};"
        : "+f"(d[0]), "+f"(d[1]), "+f"(d[2]), "+f"(d[3])
        : "r"(a[0]), "r"(a[1]), "r"(a[2]), "r"(a[3]), "r"(b[0]), "r"(b[1]));
}
__device__ __forceinline__ void split2(float v, h16& h, h16& l) {
    h = __float2half_rn(v);
    l = __float2half_rn(v - __half2float(h));
}
__device__ __forceinline__ uint32_t pack_h2(float a, float b) {
    __half2 t = __floats2half2_rn(a, b);
    return *(uint32_t*)&t;
}

// ---------------- prep device functions ----------------
// split: hi always, lo optional
__device__ __forceinline__ void split_chunk(const float4* __restrict__ in,
                                            __half2* __restrict__ hi,
                                            __half2* __restrict__ lo,
                                            size_t base4, size_t n4)
{
#pragma unroll
    for (int q = 0; q < 16; q++) {
        size_t i = base4 + (size_t)q * 256 + threadIdx.x;
        if (i >= n4) return;
        float4 v = in[i];
        h16 h0, l0_, h1, l1_, h2, l2_, h3, l3_;
        split2(v.x, h0, l0_); split2(v.y, h1, l1_);
        split2(v.z, h2, l2_); split2(v.w, h3, l3_);
        hi[i * 2]     = __halves2half2(h0, h1);
        hi[i * 2 + 1] = __halves2half2(h2, h3);
        if (lo) {
            lo[i * 2]     = __halves2half2(l0_, l1_);
            lo[i * 2 + 1] = __halves2half2(l2_, l3_);
        }
    }
}

// transpose strip (hi only — weights are B-side, rounded once)
__device__ __forceinline__ void tr_strip(const float* __restrict__ in,
                                         h16* __restrict__ hi,
                                         int K, int N, int Npad, int Kpad, int rowOff,
                                         int strip, int nStrips)
{
    __shared__ float t[32][33];
    int kTile = strip / nStrips;
    int nT0 = (strip % nStrips) * 8;
    int k0 = kTile * 32;
    int tx = threadIdx.x & 31, ty = threadIdx.x >> 5;
    for (int sub = 0; sub < 8; sub++) {
        int n0 = (nT0 + sub) * 32;
        if (n0 >= Npad) break;
        __syncthreads();
#pragma unroll
        for (int i = 0; i < 4; i++) {
            int k = k0 + ty + i * 8;
            float v = (k < K && n0 + tx < N) ? in[(size_t)k * N + n0 + tx] : 0.f;
            t[ty + i * 8][tx] = v;
        }
        __syncthreads();
#pragma unroll
        for (int i = 0; i < 4; i++) {
            int n = n0 + ty + i * 8, k = k0 + tx;
            if (n < Npad && k < Kpad)
                hi[(size_t)(n + rowOff) * Kpad + k] = __float2half_rn(t[tx][ty + i * 8]);
        }
    }
}

// ---------------- GEMM core: C = (Ah+Al) @ Bh^T, BK=32, 3-stage ----------------
#define STAGE 24576
#define SMEM_GEMM (3*STAGE)

__device__ __forceinline__ void gemm_core(
    const h16* __restrict__ Ahi, const h16* __restrict__ Alo,
    const h16* __restrict__ Bhi,
    float* __restrict__ Cf, h16* __restrict__ Ch, h16* __restrict__ Cl,
    int N, int Kpad, int lda, int ldb, int ldc,
    int r0, int c0, char* smem)
{
    int tid = threadIdx.x, lane = tid & 31, wid = tid >> 5;
    int tiles = Kpad >> 5;

    const h16* Ah = Ahi + (size_t)r0 * lda;
    const h16* Al = Alo + (size_t)r0 * lda;
    const h16* Bh = Bhi + (size_t)c0 * ldb;

    uint32_t sbase = smem_u32(smem);
    int wm = (wid >> 2) * 64, wn = (wid & 3) * 32;

    float acc[4][4][4];
#pragma unroll
    for (int i = 0; i < 4; i++)
#pragma unroll
        for (int j = 0; j < 4; j++)
#pragma unroll
            for (int v = 0; v < 4; v++) acc[i][j][v] = 0.f;

    // stage layout: Ah 0, Al 8K, Bh 16K; 128 rows x 64B, 4 chunks, xor-swizzle
    auto load_stage = [&](int t) {
        int k0 = t << 5;
        uint32_t sb = sbase + (uint32_t)(t % 3) * STAGE;
#pragma unroll
        for (int q = 0; q < 2; q++) {
            int c = tid + q * 256;
            int row = c >> 2, ch = c & 3;
            uint32_t off = (uint32_t)row * 64 + (uint32_t)((ch ^ ((row >> 1) & 3)) << 4);
            size_t ga = (size_t)row * lda + k0 + ch * 8;
            size_t gb = (size_t)row * ldb + k0 + ch * 8;
            cp16(sb + off,         Ah + ga);
            cp16(sb + 8192 + off,  Al + ga);
            cp16(sb + 16384 + off, Bh + gb);
        }
        cp_commit();
    };

    auto compute_stage = [&](int t) {
        uint32_t sb = sbase + (uint32_t)(t % 3) * STAGE;
#pragma unroll
        for (int kk = 0; kk < 32; kk += 16) {
            uint32_t bh[4][2];
#pragma unroll
            for (int p = 0; p < 2; p++) {
                int rowB = wn + p * 16 + ((lane >> 4) << 3) + (lane & 7);
                int ch = (kk >> 3) + ((lane >> 3) & 1);
                uint32_t off = (uint32_t)rowB * 64 + (uint32_t)((ch ^ ((rowB >> 1) & 3)) << 4);
                uint32_t r[4];
                ldm_x4(sb + 16384 + off, r);
                bh[2 * p][0] = r[0]; bh[2 * p][1] = r[1];
                bh[2 * p + 1][0] = r[2]; bh[2 * p + 1][1] = r[3];
            }
#pragma unroll
            for (int mt = 0; mt < 4; mt++) {
                int rowA = wm + mt * 16 + (lane & 15);
                int ch = (kk >> 3) + (lane >> 4);
                uint32_t off = (uint32_t)rowA * 64 + (uint32_t)((ch ^ ((rowA >> 1) & 3)) << 4);
                uint32_t ah[4], al[4];
                ldm_x4(sb + off, ah);
                ldm_x4(sb + 8192 + off, al);
#pragma unroll
                for (int nt = 0; nt < 4; nt++) {
                    mma16816(acc[mt][nt], ah, bh[nt]);
                    mma16816(acc[mt][nt], al, bh[nt]);
                }
            }
        }
    };

    load_stage(0);
    if (tiles > 1) load_stage(1);
    for (int t = 0; t < tiles; t++) {
        if (t + 1 < tiles) cp_wait<1>(); else cp_wait<0>();
        __syncthreads();
        if (t + 2 < tiles) load_stage(t + 2);
        compute_stage(t);
    }

    if (Cf) {
#pragma unroll
        for (int mt = 0; mt < 4; mt++) {
#pragma unroll
            for (int nt = 0; nt < 4; nt++) {
                int r = r0 + wm + mt * 16 + (lane >> 2);
                int c = c0 + wn + nt * 8 + ((lane & 3) << 1);
                float* p0 = Cf + (size_t)r * ldc + c;
                float* p1 = p0 + 8 * ldc;
                p0[0] = acc[mt][nt][0]; p0[1] = acc[mt][nt][1];
                p1[0] = acc[mt][nt][2]; p1[1] = acc[mt][nt][3];
            }
        }
    } else {
#pragma unroll
        for (int mt = 0; mt < 4; mt++) {
#pragma unroll
            for (int nt = 0; nt < 4; nt++) {
                int r = r0 + wm + mt * 16 + (lane >> 2);
                int c = c0 + wn + nt * 8 + ((lane & 3) << 1);
                size_t o0 = (size_t)r * ldc + c;
                size_t o1 = o0 + (size_t)8 * ldc;
                float v0 = acc[mt][nt][0], v1 = acc[mt][nt][1];
                float v2 = acc[mt][nt][2], v3 = acc[mt][nt][3];
                float h0 = __half2float(__float2half_rn(v0));
                float h1 = __half2float(__float2half_rn(v1));
                float h2 = __half2float(__float2half_rn(v2));
                float h3 = __half2float(__float2half_rn(v3));
                *(uint32_t*)(Ch + o0) = pack_h2(h0, h1);
                *(uint32_t*)(Ch + o1) = pack_h2(h2, h3);
                if (Cl) {
                    *(uint32_t*)(Cl + o0) = pack_h2(v0 - h0, v1 - h1);
                    *(uint32_t*)(Cl + o1) = pack_h2(v2 - h2, v3 - h3);
                }
            }
        }
    }
}

// ---------------- prep1: x split + W1 transposes ----------------
__global__ __launch_bounds__(256)
void prep1(const float* __restrict__ x,
           const float* __restrict__ W_dq, const float* __restrict__ W_dkv,
           const float* __restrict__ W_kr,
           h16* __restrict__ xhi, h16* __restrict__ xlo,
           h16* __restrict__ w1h)
{
    int i = blockIdx.x;
    if (i < 512) {
        split_chunk((const float4*)x, (__half2*)xhi, (__half2*)xlo,
                    (size_t)i * 4096, (size_t)BS * DMODEL / 4);
    } else if (i < 768) {
        tr_strip(W_dq, w1h, DMODEL, QPROJ, QPROJ, DMODEL, 0, i - 512, 4);
    } else if (i < 1152) {
        tr_strip(W_dkv, w1h, DMODEL, KVPROJ, KVPAD, DMODEL, QPROJ, i - 768, 6);
    } else {
        tr_strip(W_kr, w1h, DMODEL, 256, 256, DMODEL, QPROJ + KVPAD, i - 1152, 1);
    }
}

// ---------------- p1 GEMM fused with prep2 ----------------
__global__ __launch_bounds__(256, 2)
void gemm_p1_prep2(const h16* __restrict__ xhi, const h16* __restrict__ xlo,
                   const h16* __restrict__ w1h,
                   float* __restrict__ p1,
                   const float* __restrict__ W_uq, const float* __restrict__ W_qr,
                   const float* __restrict__ W_ukv, const float* __restrict__ W_o,
                   h16* __restrict__ w2h, h16* __restrict__ wukvh, h16* __restrict__ woh)
{
    extern __shared__ __align__(128) char smem[];
    int i = blockIdx.x;
    bool isGemm;
    int sub;
    if (i < 1344) { isGemm = !(i & 1); sub = i >> 1; }
    else          { isGemm = false;    sub = 672 + (i - 1344); }

    if (isGemm) {
        int cx = sub % 21, cy = sub / 21;
        gemm_core(xhi, xlo, w1h, p1, nullptr, nullptr,
                  N1, DMODEL, DMODEL, DMODEL, N1, cy * 128, cx * 128, smem);
    } else {
        if (sub < 224) {
            tr_strip(W_uq, w2h, QPROJ, KNOPE, KNOPE, QPROJ, 0, sub, 7);
        } else if (sub < 256) {
            tr_strip(W_qr, w2h, QPROJ, 256, 256, QPROJ, KNOPE, sub - 224, 1);
        } else if (sub < 916) {
            tr_strip(W_ukv, wukvh, KVPROJ, KVCOLS, KVCOLS, KVPAD, 0, sub - 256, 15);
        } else {
            split_chunk((const float4*)W_o, (__half2*)woh, nullptr,
                        (size_t)(sub - 916) * 4096, (size_t)DMODEL * DMODEL / 4);
        }
    }
}

__global__ __launch_bounds__(256, 2)
void hmma_gemm(const h16* __restrict__ Ahi, const h16* __restrict__ Alo,
               const h16* __restrict__ Bhi,
               float* __restrict__ Cf, h16* __restrict__ Ch, h16* __restrict__ Cl,
               int N, int Kpad, int lda, int ldb, int ldc)
{
    extern __shared__ __align__(128) char smem[];
    gemm_core(Ahi, Alo, Bhi, Cf, Ch, Cl, N, Kpad, lda, ldb, ldc,
              blockIdx.y * 128, blockIdx.x * 128, smem);
}

__global__ __launch_bounds__(256, 2)
void hmma_gemm_dual(
    const h16* A1h, const h16* A1l, const h16* B1h,
    h16* C1h, h16* C1l, int n1, int k1, int la1, int lb1, int lc1, int gx1,
    const h16* A2h, const h16* A2l, const h16* B2h,
    h16* C2h, h16* C2l, int n2, int k2, int la2, int lb2, int lc2, int gx2,
    int split)
{
    extern __shared__ __align__(128) char smem[];
    int idx = blockIdx.x;
    if (idx < split) {
        int cx = idx % gx1, cy = idx / gx1;
        gemm_core(A1h, A1l, B1h, nullptr, C1h, C1l, n1, k1, la1, lb1, lc1,
                  cy * 128, cx * 128, smem);
    } else {
        idx -= split;
        int cx = idx % gx2, cy = idx / gx2;
        gemm_core(A2h, A2l, B2h, nullptr, C2h, C2l, n2, k2, la2, lb2, lc2,
                  cy * 128, cx * 128, smem);
    }
}

// ---------------- fused flash attention (fp16 2-product) ----------------
// Q split hi/lo (A side); K, V fp16-rounded only.
#define FST 32768                       // stage: Kh 16K, Vh 16K
#define FQB 65536                       // Q hi 32K + lo 32K
#define SMEM_FLASH (FQB + 3*FST)        // 160 KB

__global__ __launch_bounds__(256, 1)
void flash_attn(const h16* __restrict__ q2h, const h16* __restrict__ q2l,
                const h16* __restrict__ kvh,
                h16* __restrict__ aoh, h16* __restrict__ aol)
{
    extern __shared__ __align__(128) char smem[];
    int tid = threadIdx.x, lane = tid & 31, wid = tid >> 5;
    int z = blockIdx.y, bb = z >> 4, hh = z & 15;
    int r0 = ((int)gridDim.x - 1 - (int)blockIdx.x) * 128;

    int kcol = (hh < NOPE) ? hh * DH : KVCOLS + (hh - NOPE) * DH;
    int vcol = KNOPE + hh * DH;

    const h16* qhz = q2h + ((size_t)(bb * S_ + r0)) * N2 + hh * DH;
    const h16* qlz = q2l + ((size_t)(bb * S_ + r0)) * N2 + hh * DH;
    const h16* khz = kvh + (size_t)(bb * S_) * KVLD + kcol;
    const h16* vhz = kvh + (size_t)(bb * S_) * KVLD + vcol;

    uint32_t sb = smem_u32(smem);

    // stage Q (128 x 128, hi+lo)
#pragma unroll
    for (int q = 0; q < 8; q++) {
        int idx = tid + q * 256;
        int row = idx >> 4, ch = idx & 15;
        uint32_t off = (uint32_t)row * 256 + (uint32_t)((ch ^ (row & 7)) << 4);
        cp16(sb + off,         qhz + (size_t)row * N2 + ch * 8);
        cp16(sb + 32768 + off, qlz + (size_t)row * N2 + ch * 8);
    }
    cp_commit();

    int ntiles = (r0 >> 6) + 2;
    int diag = r0 >> 6;

    auto load_stage = [&](int jt) {
        uint32_t st = sb + FQB + (uint32_t)(jt % 3) * FST;
        int s0 = jt * 64;
#pragma unroll
        for (int q = 0; q < 4; q++) {
            int idx = tid + q * 256;
            int row = idx >> 4, ch = idx & 15;
            uint32_t off = (uint32_t)row * 256 + (uint32_t)((ch ^ (row & 7)) << 4);
            size_t g = (size_t)(s0 + row) * KVLD + ch * 8;
            cp16(st + off,         khz + g);
            cp16(st + 16384 + off, vhz + g);
        }
        cp_commit();
    };

    load_stage(0);
    load_stage(1);
    cp_wait<2>();
    __syncthreads();

    int wrow = wid * 16;
    uint32_t qah[8][4], qal[8][4];
#pragma unroll
    for (int kf = 0; kf < 8; kf++) {
        int row = wrow + (lane & 15);
        int ch = kf * 2 + (lane >> 4);
        uint32_t off = (uint32_t)row * 256 + (uint32_t)((ch ^ (row & 7)) << 4);
        ldm_x4(sb + off, qah[kf]);
        ldm_x4(sb + 32768 + off, qal[kf]);
    }

    float of[16][4];
#pragma unroll
    for (int i = 0; i < 16; i++)
#pragma unroll
        for (int v = 0; v < 4; v++) of[i][v] = 0.f;
    float m0 = -1e30f, m1 = -1e30f, l0 = 0.f, l1 = 0.f;
    const float CEXP = 0.08838834764831845f * 1.4426950408889634f;

    int rowa = r0 + wrow + (lane >> 2);

    for (int jt = 0; jt < ntiles; jt++) {
        if (jt + 1 < ntiles) cp_wait<1>(); else cp_wait<0>();
        __syncthreads();
        if (jt + 2 < ntiles) load_stage(jt + 2);
        uint32_t st = sb + FQB + (uint32_t)(jt % 3) * FST;

        // ---- S = Q @ K^T ----
        float sf[8][4];
#pragma unroll
        for (int nf = 0; nf < 8; nf++)
#pragma unroll
            for (int v = 0; v < 4; v++) sf[nf][v] = 0.f;

#pragma unroll
        for (int kf = 0; kf < 8; kf++) {
            uint32_t bh[8][2];
#pragma unroll
            for (int p = 0; p < 4; p++) {
                int rowB = p * 16 + ((lane >> 4) << 3) + (lane & 7);
                int ch = kf * 2 + ((lane >> 3) & 1);
                uint32_t off = (uint32_t)rowB * 256 + (uint32_t)((ch ^ (rowB & 7)) << 4);
                uint32_t r4[4];
                ldm_x4(st + off, r4);
                bh[2 * p][0] = r4[0]; bh[2 * p][1] = r4[1];
                bh[2 * p + 1][0] = r4[2]; bh[2 * p + 1][1] = r4[3];
            }
#pragma unroll
            for (int nf = 0; nf < 8; nf++) {
                mma16816(sf[nf], qah[kf], bh[nf]);
                mma16816(sf[nf], qal[kf], bh[nf]);
            }
        }

        // ---- causal mask on diagonal tiles ----
        if (jt >= diag) {
            int colb = jt * 64 + 2 * (lane & 3);
#pragma unroll
            for (int nf = 0; nf < 8; nf++) {
                int c = colb + nf * 8;
                if (c > rowa)     sf[nf][0] = -1e30f;
                if (c + 1 > rowa) sf[nf][1] = -1e30f;
                if (c > rowa + 8)     sf[nf][2] = -1e30f;
                if (c + 1 > rowa + 8) sf[nf][3] = -1e30f;
            }
        }

        // ---- online softmax ----
        float tm0 = -1e30f, tm1 = -1e30f;
#pragma unroll
        for (int nf = 0; nf < 8; nf++) {
            tm0 = fmaxf(tm0, fmaxf(sf[nf][0], sf[nf][1]));
            tm1 = fmaxf(tm1, fmaxf(sf[nf][2], sf[nf][3]));
        }
        tm0 = fmaxf(tm0, __shfl_xor_sync(0xffffffffu, tm0, 1));
        tm0 = fmaxf(tm0, __shfl_xor_sync(0xffffffffu, tm0, 2));
        tm1 = fmaxf(tm1, __shfl_xor_sync(0xffffffffu, tm1, 1));
        tm1 = fmaxf(tm1, __shfl_xor_sync(0xffffffffu, tm1, 2));
        float mn0 = fmaxf(m0, tm0), mn1 = fmaxf(m1, tm1);
        float al0 = exp2f((m0 - mn0) * CEXP), al1 = exp2f((m1 - mn1) * CEXP);
        m0 = mn0; m1 = mn1;

        uint32_t pah[4][4], pal[4][4];
        float rs0 = 0.f, rs1 = 0.f;
#pragma unroll
        for (int nf = 0; nf < 8; nf++) {
            float e0 = exp2f((sf[nf][0] - m0) * CEXP);
            float e1 = exp2f((sf[nf][1] - m0) * CEXP);
            float e2 = exp2f((sf[nf][2] - m1) * CEXP);
            float e3 = exp2f((sf[nf][3] - m1) * CEXP);
            rs0 += e0 + e1; rs1 += e2 + e3;
            float h0 = __half2float(__float2half_rn(e0));
            float h1 = __half2float(__float2half_rn(e1));
            float h2 = __half2float(__float2half_rn(e2));
            float h3 = __half2float(__float2half_rn(e3));
            int kf2 = nf >> 1, s = (nf & 1) * 2;
            pah[kf2][s]     = pack_h2(h0, h1);
            pah[kf2][s + 1] = pack_h2(h2, h3);
            pal[kf2][s]     = pack_h2(e0 - h0, e1 - h1);
            pal[kf2][s + 1] = pack_h2(e2 - h2, e3 - h3);
        }
        l0 = l0 * al0 + rs0;
        l1 = l1 * al1 + rs1;

#pragma unroll
        for (int i = 0; i < 16; i++) {
            of[i][0] *= al0; of[i][1] *= al0;
            of[i][2] *= al1; of[i][3] *= al1;
        }

        // ---- O += P @ V  (V fp16-rounded, natural (s,d), ldmatrix.trans) ----
#pragma unroll
        for (int kf2 = 0; kf2 < 4; kf2++) {
#pragma unroll
            for (int nb = 0; nb < 8; nb++) {
                int row = kf2 * 16 + (lane & 15);
                int ch = nb * 2 + (lane >> 4);
                uint32_t off = (uint32_t)row * 256 + (uint32_t)((ch ^ (row & 7)) << 4);
                uint32_t rh[4];
                ldm_x4_t(st + 16384 + off, rh);
                uint32_t bh0[2] = {rh[0], rh[1]}, bh1[2] = {rh[2], rh[3]};
                mma16816(of[2 * nb],     pah[kf2], bh0);
                mma16816(of[2 * nb],     pal[kf2], bh0);
                mma16816(of[2 * nb + 1], pah[kf2], bh1);
                mma16816(of[2 * nb + 1], pal[kf2], bh1);
            }
        }
    }

    l0 += __shfl_xor_sync(0xffffffffu, l0, 1);
    l0 += __shfl_xor_sync(0xffffffffu, l0, 2);
    l1 += __shfl_xor_sync(0xffffffffu, l1, 1);
    l1 += __shfl_xor_sync(0xffffffffu, l1, 2);
    float inv0 = 1.f / l0, inv1 = 1.f / l1;

    size_t ga = ((size_t)(bb * S_) + rowa) * DMODEL + hh * DH;
    size_t gb = ga + (size_t)8 * DMODEL;
#pragma unroll
    for (int i = 0; i < 16; i++) {
        int d = i * 8 + 2 * (lane & 3);
        float v0 = of[i][0] * inv0, v1 = of[i][1] * inv0;
        float v2 = of[i][2] * inv1, v3 = of[i][3] * inv1;
        float h0 = __half2float(__float2half_rn(v0));
        float h1 = __half2float(__float2half_rn(v1));
        float h2 = __half2float(__float2half_rn(v2));
        float h3 = __half2float(__float2half_rn(v3));
        *(uint32_t*)(aoh + ga + d) = pack_h2(h0, h1);
        *(uint32_t*)(aoh + gb + d) = pack_h2(h2, h3);
        *(uint32_t*)(aol + ga + d) = pack_h2(v0 - h0, v1 - h1);
        *(uint32_t*)(aol + gb + d) = pack_h2(v2 - h2, v3 - h3);
    }
}

// ---------------- merged LayerNorm ----------------
__global__ __launch_bounds__(256)
void layernorm2(const float* __restrict__ p1,
                h16* __restrict__ cqh, h16* __restrict__ cql,
                float* __restrict__ ckv,
                h16* __restrict__ ckvh, h16* __restrict__ ckvl,
                const float* __restrict__ q_w, const float* __restrict__ q_b,
                const float* __restrict__ kv_w, const float* __restrict__ kv_b)
{
    bool isKV = blockIdx.y != 0;
    const float* p = p1 + (size_t)blockIdx.x * N1 + (isKV ? QPROJ : 0);
    int n = isKV ? KVPROJ : QPROJ;
    int npad = isKV ? KVPAD : QPROJ;
    const float* w = isKV ? kv_w : q_w;
    const float* b = isKV ? kv_b : q_b;
    h16* hh = (isKV ? ckvh : cqh) + (size_t)blockIdx.x * npad;
    h16* ll = (isKV ? ckvl : cql) + (size_t)blockIdx.x * npad;
    float* of = isKV ? ckv + (size_t)blockIdx.x * KVPROJ : nullptr;

    float s = 0.f, s2 = 0.f;
    for (int j = threadIdx.x; j < n; j += 256) {
        float v = p[j];
        s += v; s2 += v * v;
    }
    __shared__ float sh[20];
#pragma unroll
    for (int o = 16; o; o >>= 1) {
        s  += __shfl_down_sync(0xffffffffu, s,  o);
        s2 += __shfl_down_sync(0xffffffffu, s2, o);
    }
    int wd = threadIdx.x >> 5, ln = threadIdx.x & 31;
    if (!ln) { sh[wd] = s; sh[wd + 8] = s2; }
    __syncthreads();
    if (threadIdx.x == 0) {
        float ts = 0.f, ts2 = 0.f;
        for (int i = 0; i < 8; i++) { ts += sh[i]; ts2 += sh[i + 8]; }
        float mean = ts / n;
        float var = fmaxf(ts2 / n - mean * mean, 0.f);
        sh[16] = mean;
        sh[17] = rsqrtf(var + 1e-5f);
    }
    __syncthreads();
    float mean = sh[16], rstd = sh[17];
    for (int j = threadIdx.x; j < npad; j += 256) {
        float v = 0.f;
        if (j < n) {
            v = (p[j] - mean) * rstd * w[j] + b[j];
            if (of) of[j] = v;
        }
        split2(v, hh[j], ll[j]);
    }
}

// merged RoPE: first half -> Q (in-place on q2 hi/lo), second half -> K (p1 -> kvh)
__global__ __launch_bounds__(256)
void rope_qk(h16* __restrict__ q2h, h16* __restrict__ q2l,
             const float* __restrict__ p1,
             h16* __restrict__ kvh)
{
    int total = BS * 2 * 64;
    int idx = blockIdx.x * 256 + threadIdx.x;
    if (idx >= 2 * total) return;
    bool isK = idx >= total;
    if (isK) idx -= total;
    int dp = idx & 63;
    int h2 = (idx >> 6) & 1;
    int row = idx >> 7;
    int s = row & (S_ - 1);
    float freq = exp2f(-(float)dp * 0.20762050593046015f);
    float sn, cs;
    sincosf((float)s * freq, &sn, &cs);

    if (!isK) {
        size_t base = (size_t)row * N2 + KNOPE + h2 * DH;
        float x1 = __half2float(q2h[base + dp]) + __half2float(q2l[base + dp]);
        float x2 = __half2float(q2h[base + dp + 64]) + __half2float(q2l[base + dp + 64]);
        float v1 = x1 * cs - x2 * sn;
        float v2 = x2 * cs + x1 * sn;
        split2(v1, q2h[base + dp], q2l[base + dp]);
        split2(v2, q2h[base + dp + 64], q2l[base + dp + 64]);
    } else {
        const float* src = p1 + (size_t)row * N1 + 2432 + h2 * DH;
        float x1 = src[dp], x2 = src[dp + 64];
        float v1 = x1 * cs - x2 * sn;
        float v2 = x2 * cs + x1 * sn;
        size_t base = (size_t)row * KVLD + KVCOLS + h2 * DH;
        kvh[base + dp]      = __float2half_rn(v1);
        kvh[base + dp + 64] = __float2half_rn(v2);
    }
}

// ---------------- launch ----------------
static inline void* sym(const void* s) { void* p; cudaGetSymbolAddress(&p, s); return p; }

extern "C" void kernel_launch(void* const* d_in, const int* in_sizes, int n_in,
                              void* d_out, int out_size)
{
    const float* x     = (const float*)d_in[0];
    const float* W_dq  = (const float*)d_in[1];
    const float* W_uq  = (const float*)d_in[2];
    const float* W_qr  = (const float*)d_in[3];
    const float* W_dkv = (const float*)d_in[4];
    const float* W_ukv = (const float*)d_in[5];
    const float* W_kr  = (const float*)d_in[6];
    const float* W_o   = (const float*)d_in[7];
    const float* q_w   = (const float*)d_in[8];
    const float* q_b   = (const float*)d_in[9];
    const float* kv_w  = (const float*)d_in[10];
    const float* kv_b  = (const float*)d_in[11];

    float* out = (float*)d_out;
    float* ckv = out + (size_t)BS * DMODEL;

    h16 *xhi=(h16*)sym(g_xhi), *xlo=(h16*)sym(g_xlo);
    h16 *w1h=(h16*)sym(g_w1h);
    h16 *w2h=(h16*)sym(g_w2h);
    h16 *wukvh=(h16*)sym(g_wukvh);
    h16 *woh=(h16*)sym(g_woh);
    float *p1=(float*)sym(g_p1);
    h16 *cqh=(h16*)sym(g_cqh), *cql=(h16*)sym(g_cql);
    h16 *ckvh=(h16*)sym(g_ckvh), *ckvl=(h16*)sym(g_ckvl);
    h16 *q2h=(h16*)sym(g_q2h), *q2l=(h16*)sym(g_q2l);
    h16 *kvh=(h16*)sym(g_kvh);
    h16 *aoh=(h16*)sym(g_aoh), *aol=(h16*)sym(g_aol);

    cudaFuncSetAttribute(hmma_gemm, cudaFuncAttributeMaxDynamicSharedMemorySize, SMEM_GEMM);
    cudaFuncSetAttribute(hmma_gemm_dual, cudaFuncAttributeMaxDynamicSharedMemorySize, SMEM_GEMM);
    cudaFuncSetAttribute(gemm_p1_prep2, cudaFuncAttributeMaxDynamicSharedMemorySize, SMEM_GEMM);
    cudaFuncSetAttribute(flash_attn, cudaFuncAttributeMaxDynamicSharedMemorySize, SMEM_FLASH);

    // 1. x split + W1 transposes
    prep1<<<1216, 256>>>(x, W_dq, W_dkv, W_kr, xhi, xlo, w1h);

    // 2. p1 = x @ W1 (fp32) fused with prep2
    gemm_p1_prep2<<<1844, 256, SMEM_GEMM>>>(
        xhi, xlo, w1h, p1,
        W_uq, W_qr, W_ukv, W_o,
        w2h, wukvh, woh);

    // 3. LayerNorms (merged)
    layernorm2<<<dim3(BS, 2), 256>>>(p1, cqh, cql, ckv, ckvh, ckvl, q_w, q_b, kv_w, kv_b);

    // 4. q2 = cq @ W2 AND kv = ckv @ W_ukv in one launch
    {
        int gx_ukv = KVCOLS / 128;              // 30
        int gx_q2  = N2 / 128;                  // 16
        int blocks_ukv = gx_ukv * (BS / 128);   // 960
        int blocks_q2  = gx_q2  * (BS / 128);   // 512
        hmma_gemm_dual<<<blocks_ukv + blocks_q2, 256, SMEM_GEMM>>>(
            ckvh, ckvl, wukvh, kvh, nullptr,
            KVCOLS, KVPAD, KVPAD, KVPAD, KVLD, gx_ukv,
            cqh, cql, w2h, q2h, q2l,
            N2, QPROJ, QPROJ, QPROJ, N2, gx_q2,
            blocks_ukv);
    }

    // 5. RoPE
    rope_qk<<<(2*BS*2*64 + 255)/256, 256>>>(q2h, q2l, p1, kvh);

    // 6. flash attention
    flash_attn<<<dim3(S_/128, NZ), 256, SMEM_FLASH>>>(q2h, q2l, kvh, aoh, aol);

    // 7. final projection
    hmma_gemm<<<dim3(DMODEL/128, BS/128), 256, SMEM_GEMM>>>(
        aoh, aol, woh, out, nullptr, nullptr, DMODEL, DMODEL, DMODEL, DMODEL, DMODEL);
}

// round 11
// speedup vs baseline: 9.3321x; 1.2050x over previous
#include <cuda_runtime.h>
#include <cuda_fp16.h>
#include <cstdint>
#include <math.h>

// ---------------- problem constants ----------------
#define B_      2
#define S_      2048
#define DMODEL  2048
#define NH      16
#define DH      128
#define NOPE    14
#define QPROJ   1024
#define KVPROJ  1365
#define KVPAD   1408
#define KNOPE   1792
#define KVCOLS  3840
#define KVLD    4096
#define BS      (B_*S_)
#define NZ      (B_*NH)
#define N1      2688
#define N2      2048

typedef __half h16;

// ---------------- device scratch ----------------
__device__ h16 g_xhi[(size_t)BS*DMODEL],   g_xlo[(size_t)BS*DMODEL];
__device__ h16 g_w1h[(size_t)N1*DMODEL];
__device__ h16 g_w2h[(size_t)N2*QPROJ];
__device__ h16 g_wukvh[(size_t)KVCOLS*KVPAD];
__device__ h16 g_woh[(size_t)DMODEL*DMODEL];
__device__ float g_p1[(size_t)BS*N1];
__device__ h16 g_cqh[(size_t)BS*QPROJ],    g_cql[(size_t)BS*QPROJ];
__device__ h16 g_ckvh[(size_t)BS*KVPAD],   g_ckvl[(size_t)BS*KVPAD];
__device__ h16 g_q2h[(size_t)BS*N2];
__device__ h16 g_kvh[(size_t)BS*KVLD];
__device__ h16 g_aoh[(size_t)BS*DMODEL];

// ---------------- helpers ----------------
__device__ __forceinline__ uint32_t smem_u32(const void* p) {
    uint32_t a;
    asm("{ .reg .u64 t; cvta.to.shared.u64 t, %1; cvt.u32.u64 %0, t; }" : "=r"(a) : "l"(p));
    return a;
}
__device__ __forceinline__ void cp16(uint32_t saddr, const void* g) {
    asm volatile("cp.async.cg.shared.global [%0], [%1], 16;" :: "r"(saddr), "l"(g) : "memory");
}
__device__ __forceinline__ void cp_commit() {
    asm volatile("cp.async.commit_group;" ::: "memory");
}
template<int N> __device__ __forceinline__ void cp_wait() {
    asm volatile("cp.async.wait_group %0;" :: "n"(N) : "memory");
}
__device__ __forceinline__ void ldm_x4(uint32_t addr, uint32_t* r) {
    asm volatile("ldmatrix.sync.aligned.m8n8.x4.shared.b16 {%0,%1,%2,%3}, [%4];"
        : "=r"(r[0]), "=r"(r[1]), "=r"(r[2]), "=r"(r[3]) : "r"(addr));
}
__device__ __forceinline__ void ldm_x4_t(uint32_t addr, uint32_t* r) {
    asm volatile("ldmatrix.sync.aligned.m8n8.x4.trans.shared.b16 {%0,%1,%2,%3}, [%4];"
        : "=r"(r[0]), "=r"(r[1]), "=r"(r[2]), "=r"(r[3]) : "r"(addr));
}
__device__ __forceinline__ void mma16816(float* d, const uint32_t* a, const uint32_t* b) {
    asm volatile("mma.sync.aligned.m16n8k16.row.col.f32.f16.f16.f32 "
        "{%0,%1,%2,%3}, {%4,%5,%6,%7}, {%8,%9}, {%0,%1,%2,%3};"
        : "+f"(d[0]), "+f"(d[1]), "+f"(d[2]), "+f"(d[3])
        : "r"(a[0]), "r"(a[1]), "r"(a[2]), "r"(a[3]), "r"(b[0]), "r"(b[1]));
}
__device__ __forceinline__ void split2(float v, h16& h, h16& l) {
    h = __float2half_rn(v);
    l = __float2half_rn(v - __half2float(h));
}
__device__ __forceinline__ uint32_t pack_h2(float a, float b) {
    __half2 t = __floats2half2_rn(a, b);
    return *(uint32_t*)&t;
}

// ---------------- prep device functions ----------------
__device__ __forceinline__ void split_chunk(const float4* __restrict__ in,
                                            __half2* __restrict__ hi,
                                            __half2* __restrict__ lo,
                                            size_t base4, size_t n4)
{
#pragma unroll
    for (int q = 0; q < 16; q++) {
        size_t i = base4 + (size_t)q * 256 + threadIdx.x;
        if (i >= n4) return;
        float4 v = in[i];
        h16 h0, l0_, h1, l1_, h2, l2_, h3, l3_;
        split2(v.x, h0, l0_); split2(v.y, h1, l1_);
        split2(v.z, h2, l2_); split2(v.w, h3, l3_);
        hi[i * 2]     = __halves2half2(h0, h1);
        hi[i * 2 + 1] = __halves2half2(h2, h3);
        if (lo) {
            lo[i * 2]     = __halves2half2(l0_, l1_);
            lo[i * 2 + 1] = __halves2half2(l2_, l3_);
        }
    }
}

__device__ __forceinline__ void tr_strip(const float* __restrict__ in,
                                         h16* __restrict__ hi,
                                         int K, int N, int Npad, int Kpad, int rowOff,
                                         int strip, int nStrips)
{
    __shared__ float t[32][33];
    int kTile = strip / nStrips;
    int nT0 = (strip % nStrips) * 8;
    int k0 = kTile * 32;
    int tx = threadIdx.x & 31, ty = threadIdx.x >> 5;
    for (int sub = 0; sub < 8; sub++) {
        int n0 = (nT0 + sub) * 32;
        if (n0 >= Npad) break;
        __syncthreads();
#pragma unroll
        for (int i = 0; i < 4; i++) {
            int k = k0 + ty + i * 8;
            float v = (k < K && n0 + tx < N) ? in[(size_t)k * N + n0 + tx] : 0.f;
            t[ty + i * 8][tx] = v;
        }
        __syncthreads();
#pragma unroll
        for (int i = 0; i < 4; i++) {
            int n = n0 + ty + i * 8, k = k0 + tx;
            if (n < Npad && k < Kpad)
                hi[(size_t)(n + rowOff) * Kpad + k] = __float2half_rn(t[tx][ty + i * 8]);
        }
    }
}

// ---------------- GEMM core: C = (Ah[+Al]) @ Bh^T, BK=32, 3-stage ----------------
// TWO: A supplied as hi/lo pair (2 MMA products); else single fp16 A.
#define STAGE2 24576
#define STAGE1 16384
#define SMEM_GEMM2 (3*STAGE2)
#define SMEM_GEMM1 (3*STAGE1)

template<bool TWO>
__device__ __forceinline__ void gemm_core(
    const h16* __restrict__ Ahi, const h16* __restrict__ Alo,
    const h16* __restrict__ Bhi,
    float* __restrict__ Cf, h16* __restrict__ Ch, h16* __restrict__ Cl,
    int N, int Kpad, int lda, int ldb, int ldc,
    int r0, int c0, char* smem)
{
    constexpr uint32_t STG  = TWO ? STAGE2 : STAGE1;
    constexpr uint32_t BOFF = TWO ? 16384 : 8192;
    int tid = threadIdx.x, lane = tid & 31, wid = tid >> 5;
    int tiles = Kpad >> 5;

    const h16* Ah = Ahi + (size_t)r0 * lda;
    const h16* Al = TWO ? Alo + (size_t)r0 * lda : nullptr;
    const h16* Bh = Bhi + (size_t)c0 * ldb;

    uint32_t sbase = smem_u32(smem);
    int wm = (wid >> 2) * 64, wn = (wid & 3) * 32;

    float acc[4][4][4];
#pragma unroll
    for (int i = 0; i < 4; i++)
#pragma unroll
        for (int j = 0; j < 4; j++)
#pragma unroll
            for (int v = 0; v < 4; v++) acc[i][j][v] = 0.f;

    auto load_stage = [&](int t) {
        int k0 = t << 5;
        uint32_t sb = sbase + (uint32_t)(t % 3) * STG;
#pragma unroll
        for (int q = 0; q < 2; q++) {
            int c = tid + q * 256;
            int row = c >> 2, ch = c & 3;
            uint32_t off = (uint32_t)row * 64 + (uint32_t)((ch ^ ((row >> 1) & 3)) << 4);
            size_t ga = (size_t)row * lda + k0 + ch * 8;
            size_t gb = (size_t)row * ldb + k0 + ch * 8;
            cp16(sb + off, Ah + ga);
            if (TWO) cp16(sb + 8192 + off, Al + ga);
            cp16(sb + BOFF + off, Bh + gb);
        }
        cp_commit();
    };

    auto compute_stage = [&](int t) {
        uint32_t sb = sbase + (uint32_t)(t % 3) * STG;
#pragma unroll
        for (int kk = 0; kk < 32; kk += 16) {
            uint32_t bh[4][2];
#pragma unroll
            for (int p = 0; p < 2; p++) {
                int rowB = wn + p * 16 + ((lane >> 4) << 3) + (lane & 7);
                int ch = (kk >> 3) + ((lane >> 3) & 1);
                uint32_t off = (uint32_t)rowB * 64 + (uint32_t)((ch ^ ((rowB >> 1) & 3)) << 4);
                uint32_t r[4];
                ldm_x4(sb + BOFF + off, r);
                bh[2 * p][0] = r[0]; bh[2 * p][1] = r[1];
                bh[2 * p + 1][0] = r[2]; bh[2 * p + 1][1] = r[3];
            }
#pragma unroll
            for (int mt = 0; mt < 4; mt++) {
                int rowA = wm + mt * 16 + (lane & 15);
                int ch = (kk >> 3) + (lane >> 4);
                uint32_t off = (uint32_t)rowA * 64 + (uint32_t)((ch ^ ((rowA >> 1) & 3)) << 4);
                uint32_t ah[4], al[4];
                ldm_x4(sb + off, ah);
                if (TWO) ldm_x4(sb + 8192 + off, al);
#pragma unroll
                for (int nt = 0; nt < 4; nt++) {
                    mma16816(acc[mt][nt], ah, bh[nt]);
                    if (TWO) mma16816(acc[mt][nt], al, bh[nt]);
                }
            }
        }
    };

    load_stage(0);
    if (tiles > 1) load_stage(1);
    for (int t = 0; t < tiles; t++) {
        if (t + 1 < tiles) cp_wait<1>(); else cp_wait<0>();
        __syncthreads();
        if (t + 2 < tiles) load_stage(t + 2);
        compute_stage(t);
    }

    if (Cf) {
#pragma unroll
        for (int mt = 0; mt < 4; mt++) {
#pragma unroll
            for (int nt = 0; nt < 4; nt++) {
                int r = r0 + wm + mt * 16 + (lane >> 2);
                int c = c0 + wn + nt * 8 + ((lane & 3) << 1);
                float* p0 = Cf + (size_t)r * ldc + c;
                float* p1 = p0 + 8 * ldc;
                p0[0] = acc[mt][nt][0]; p0[1] = acc[mt][nt][1];
                p1[0] = acc[mt][nt][2]; p1[1] = acc[mt][nt][3];
            }
        }
    } else {
#pragma unroll
        for (int mt = 0; mt < 4; mt++) {
#pragma unroll
            for (int nt = 0; nt < 4; nt++) {
                int r = r0 + wm + mt * 16 + (lane >> 2);
                int c = c0 + wn + nt * 8 + ((lane & 3) << 1);
                size_t o0 = (size_t)r * ldc + c;
                size_t o1 = o0 + (size_t)8 * ldc;
                float v0 = acc[mt][nt][0], v1 = acc[mt][nt][1];
                float v2 = acc[mt][nt][2], v3 = acc[mt][nt][3];
                float h0 = __half2float(__float2half_rn(v0));
                float h1 = __half2float(__float2half_rn(v1));
                float h2 = __half2float(__float2half_rn(v2));
                float h3 = __half2float(__float2half_rn(v3));
                *(uint32_t*)(Ch + o0) = pack_h2(h0, h1);
                *(uint32_t*)(Ch + o1) = pack_h2(h2, h3);
                if (Cl) {
                    *(uint32_t*)(Cl + o0) = pack_h2(v0 - h0, v1 - h1);
                    *(uint32_t*)(Cl + o1) = pack_h2(v2 - h2, v3 - h3);
                }
            }
        }
    }
}

// ---------------- prep1: x split + W1 transposes ----------------
__global__ __launch_bounds__(256)
void prep1(const float* __restrict__ x,
           const float* __restrict__ W_dq, const float* __restrict__ W_dkv,
           const float* __restrict__ W_kr,
           h16* __restrict__ xhi, h16* __restrict__ xlo,
           h16* __restrict__ w1h)
{
    int i = blockIdx.x;
    if (i < 512) {
        split_chunk((const float4*)x, (__half2*)xhi, (__half2*)xlo,
                    (size_t)i * 4096, (size_t)BS * DMODEL / 4);
    } else if (i < 768) {
        tr_strip(W_dq, w1h, DMODEL, QPROJ, QPROJ, DMODEL, 0, i - 512, 4);
    } else if (i < 1152) {
        tr_strip(W_dkv, w1h, DMODEL, KVPROJ, KVPAD, DMODEL, QPROJ, i - 768, 6);
    } else {
        tr_strip(W_kr, w1h, DMODEL, 256, 256, DMODEL, QPROJ + KVPAD, i - 1152, 1);
    }
}

// ---------------- p1 GEMM fused with prep2 ----------------
__global__ __launch_bounds__(256, 2)
void gemm_p1_prep2(const h16* __restrict__ xhi, const h16* __restrict__ xlo,
                   const h16* __restrict__ w1h,
                   float* __restrict__ p1,
                   const float* __restrict__ W_uq, const float* __restrict__ W_qr,
                   const float* __restrict__ W_ukv, const float* __restrict__ W_o,
                   h16* __restrict__ w2h, h16* __restrict__ wukvh, h16* __restrict__ woh)
{
    extern __shared__ __align__(128) char smem[];
    int i = blockIdx.x;
    bool isGemm;
    int sub;
    if (i < 1344) { isGemm = !(i & 1); sub = i >> 1; }
    else          { isGemm = false;    sub = 672 + (i - 1344); }

    if (isGemm) {
        int cx = sub % 21, cy = sub / 21;
        gemm_core<true>(xhi, xlo, w1h, p1, nullptr, nullptr,
                        N1, DMODEL, DMODEL, DMODEL, N1, cy * 128, cx * 128, smem);
    } else {
        if (sub < 224) {
            tr_strip(W_uq, w2h, QPROJ, KNOPE, KNOPE, QPROJ, 0, sub, 7);
        } else if (sub < 256) {
            tr_strip(W_qr, w2h, QPROJ, 256, 256, QPROJ, KNOPE, sub - 224, 1);
        } else if (sub < 916) {
            tr_strip(W_ukv, wukvh, KVPROJ, KVCOLS, KVCOLS, KVPAD, 0, sub - 256, 15);
        } else {
            split_chunk((const float4*)W_o, (__half2*)woh, nullptr,
                        (size_t)(sub - 916) * 4096, (size_t)DMODEL * DMODEL / 4);
        }
    }
}

// single-product GEMM (Wo): fp32 out
__global__ __launch_bounds__(256, 2)
void hmma_gemm1(const h16* __restrict__ Ahi, const h16* __restrict__ Bhi,
                float* __restrict__ Cf, int N, int Kpad, int lda, int ldb, int ldc)
{
    extern __shared__ __align__(128) char smem[];
    gemm_core<false>(Ahi, nullptr, Bhi, Cf, nullptr, nullptr, N, Kpad, lda, ldb, ldc,
                     blockIdx.y * 128, blockIdx.x * 128, smem);
}

__global__ __launch_bounds__(256, 2)
void hmma_gemm_dual(
    const h16* A1h, const h16* A1l, const h16* B1h,
    h16* C1h, h16* C1l, int n1, int k1, int la1, int lb1, int lc1, int gx1,
    const h16* A2h, const h16* A2l, const h16* B2h,
    h16* C2h, h16* C2l, int n2, int k2, int la2, int lb2, int lc2, int gx2,
    int split)
{
    extern __shared__ __align__(128) char smem[];
    int idx = blockIdx.x;
    if (idx < split) {
        int cx = idx % gx1, cy = idx / gx1;
        gemm_core<true>(A1h, A1l, B1h, nullptr, C1h, C1l, n1, k1, la1, lb1, lc1,
                        cy * 128, cx * 128, smem);
    } else {
        idx -= split;
        int cx = idx % gx2, cy = idx / gx2;
        gemm_core<true>(A2h, A2l, B2h, nullptr, C2h, C2l, n2, k2, la2, lb2, lc2,
                        cy * 128, cx * 128, smem);
    }
}

// ---------------- fused flash attention (single-product QK and PV) ----------------
#define FST 32768                       // stage: Kh 16K, Vh 16K
#define FQB 32768                       // Q hi only
#define SMEM_FLASH (FQB + 3*FST)        // 128 KB

__global__ __launch_bounds__(256, 1)
void flash_attn(const h16* __restrict__ q2h,
                const h16* __restrict__ kvh,
                h16* __restrict__ aoh)
{
    extern __shared__ __align__(128) char smem[];
    int tid = threadIdx.x, lane = tid & 31, wid = tid >> 5;
    int z = blockIdx.y, bb = z >> 4, hh = z & 15;
    int r0 = ((int)gridDim.x - 1 - (int)blockIdx.x) * 128;

    int kcol = (hh < NOPE) ? hh * DH : KVCOLS + (hh - NOPE) * DH;
    int vcol = KNOPE + hh * DH;

    const h16* qhz = q2h + ((size_t)(bb * S_ + r0)) * N2 + hh * DH;
    const h16* khz = kvh + (size_t)(bb * S_) * KVLD + kcol;
    const h16* vhz = kvh + (size_t)(bb * S_) * KVLD + vcol;

    uint32_t sb = smem_u32(smem);

    // stage Q (128 x 128 fp16)
#pragma unroll
    for (int q = 0; q < 8; q++) {
        int idx = tid + q * 256;
        int row = idx >> 4, ch = idx & 15;
        uint32_t off = (uint32_t)row * 256 + (uint32_t)((ch ^ (row & 7)) << 4);
        cp16(sb + off, qhz + (size_t)row * N2 + ch * 8);
    }
    cp_commit();

    int ntiles = (r0 >> 6) + 2;
    int diag = r0 >> 6;

    auto load_stage = [&](int jt) {
        uint32_t st = sb + FQB + (uint32_t)(jt % 3) * FST;
        int s0 = jt * 64;
#pragma unroll
        for (int q = 0; q < 4; q++) {
            int idx = tid + q * 256;
            int row = idx >> 4, ch = idx & 15;
            uint32_t off = (uint32_t)row * 256 + (uint32_t)((ch ^ (row & 7)) << 4);
            size_t g = (size_t)(s0 + row) * KVLD + ch * 8;
            cp16(st + off,         khz + g);
            cp16(st + 16384 + off, vhz + g);
        }
        cp_commit();
    };

    load_stage(0);
    load_stage(1);
    cp_wait<2>();
    __syncthreads();

    int wrow = wid * 16;
    uint32_t qah[8][4];
#pragma unroll
    for (int kf = 0; kf < 8; kf++) {
        int row = wrow + (lane & 15);
        int ch = kf * 2 + (lane >> 4);
        uint32_t off = (uint32_t)row * 256 + (uint32_t)((ch ^ (row & 7)) << 4);
        ldm_x4(sb + off, qah[kf]);
    }

    float of[16][4];
#pragma unroll
    for (int i = 0; i < 16; i++)
#pragma unroll
        for (int v = 0; v < 4; v++) of[i][v] = 0.f;
    float m0 = -1e30f, m1 = -1e30f, l0 = 0.f, l1 = 0.f;
    const float CEXP = 0.08838834764831845f * 1.4426950408889634f;

    int rowa = r0 + wrow + (lane >> 2);

    for (int jt = 0; jt < ntiles; jt++) {
        if (jt + 1 < ntiles) cp_wait<1>(); else cp_wait<0>();
        __syncthreads();
        if (jt + 2 < ntiles) load_stage(jt + 2);
        uint32_t st = sb + FQB + (uint32_t)(jt % 3) * FST;

        // ---- S = Q @ K^T ----
        float sf[8][4];
#pragma unroll
        for (int nf = 0; nf < 8; nf++)
#pragma unroll
            for (int v = 0; v < 4; v++) sf[nf][v] = 0.f;

#pragma unroll
        for (int kf = 0; kf < 8; kf++) {
            uint32_t bh[8][2];
#pragma unroll
            for (int p = 0; p < 4; p++) {
                int rowB = p * 16 + ((lane >> 4) << 3) + (lane & 7);
                int ch = kf * 2 + ((lane >> 3) & 1);
                uint32_t off = (uint32_t)rowB * 256 + (uint32_t)((ch ^ (rowB & 7)) << 4);
                uint32_t r4[4];
                ldm_x4(st + off, r4);
                bh[2 * p][0] = r4[0]; bh[2 * p][1] = r4[1];
                bh[2 * p + 1][0] = r4[2]; bh[2 * p + 1][1] = r4[3];
            }
#pragma unroll
            for (int nf = 0; nf < 8; nf++)
                mma16816(sf[nf], qah[kf], bh[nf]);
        }

        // ---- causal mask on diagonal tiles ----
        if (jt >= diag) {
            int colb = jt * 64 + 2 * (lane & 3);
#pragma unroll
            for (int nf = 0; nf < 8; nf++) {
                int c = colb + nf * 8;
                if (c > rowa)     sf[nf][0] = -1e30f;
                if (c + 1 > rowa) sf[nf][1] = -1e30f;
                if (c > rowa + 8)     sf[nf][2] = -1e30f;
                if (c + 1 > rowa + 8) sf[nf][3] = -1e30f;
            }
        }

        // ---- online softmax ----
        float tm0 = -1e30f, tm1 = -1e30f;
#pragma unroll
        for (int nf = 0; nf < 8; nf++) {
            tm0 = fmaxf(tm0, fmaxf(sf[nf][0], sf[nf][1]));
            tm1 = fmaxf(tm1, fmaxf(sf[nf][2], sf[nf][3]));
        }
        tm0 = fmaxf(tm0, __shfl_xor_sync(0xffffffffu, tm0, 1));
        tm0 = fmaxf(tm0, __shfl_xor_sync(0xffffffffu, tm0, 2));
        tm1 = fmaxf(tm1, __shfl_xor_sync(0xffffffffu, tm1, 1));
        tm1 = fmaxf(tm1, __shfl_xor_sync(0xffffffffu, tm1, 2));
        float mn0 = fmaxf(m0, tm0), mn1 = fmaxf(m1, tm1);
        float al0 = exp2f((m0 - mn0) * CEXP), al1 = exp2f((m1 - mn1) * CEXP);
        m0 = mn0; m1 = mn1;

        uint32_t pah[4][4];
        float rs0 = 0.f, rs1 = 0.f;
#pragma unroll
        for (int nf = 0; nf < 8; nf++) {
            float e0 = exp2f((sf[nf][0] - m0) * CEXP);
            float e1 = exp2f((sf[nf][1] - m0) * CEXP);
            float e2 = exp2f((sf[nf][2] - m1) * CEXP);
            float e3 = exp2f((sf[nf][3] - m1) * CEXP);
            rs0 += e0 + e1; rs1 += e2 + e3;
            int kf2 = nf >> 1, s = (nf & 1) * 2;
            pah[kf2][s]     = pack_h2(e0, e1);
            pah[kf2][s + 1] = pack_h2(e2, e3);
        }
        l0 = l0 * al0 + rs0;
        l1 = l1 * al1 + rs1;

#pragma unroll
        for (int i = 0; i < 16; i++) {
            of[i][0] *= al0; of[i][1] *= al0;
            of[i][2] *= al1; of[i][3] *= al1;
        }

        // ---- O += P @ V ----
#pragma unroll
        for (int kf2 = 0; kf2 < 4; kf2++) {
#pragma unroll
            for (int nb = 0; nb < 8; nb++) {
                int row = kf2 * 16 + (lane & 15);
                int ch = nb * 2 + (lane >> 4);
                uint32_t off = (uint32_t)row * 256 + (uint32_t)((ch ^ (row & 7)) << 4);
                uint32_t rh[4];
                ldm_x4_t(st + 16384 + off, rh);
                uint32_t bh0[2] = {rh[0], rh[1]}, bh1[2] = {rh[2], rh[3]};
                mma16816(of[2 * nb],     pah[kf2], bh0);
                mma16816(of[2 * nb + 1], pah[kf2], bh1);
            }
        }
    }

    l0 += __shfl_xor_sync(0xffffffffu, l0, 1);
    l0 += __shfl_xor_sync(0xffffffffu, l0, 2);
    l1 += __shfl_xor_sync(0xffffffffu, l1, 1);
    l1 += __shfl_xor_sync(0xffffffffu, l1, 2);
    float inv0 = 1.f / l0, inv1 = 1.f / l1;

    size_t ga = ((size_t)(bb * S_) + rowa) * DMODEL + hh * DH;
    size_t gb = ga + (size_t)8 * DMODEL;
#pragma unroll
    for (int i = 0; i < 16; i++) {
        int d = i * 8 + 2 * (lane & 3);
        *(uint32_t*)(aoh + ga + d) = pack_h2(of[i][0] * inv0, of[i][1] * inv0);
        *(uint32_t*)(aoh + gb + d) = pack_h2(of[i][2] * inv1, of[i][3] * inv1);
    }
}

// ---------------- merged LayerNorm ----------------
__global__ __launch_bounds__(256)
void layernorm2(const float* __restrict__ p1,
                h16* __restrict__ cqh, h16* __restrict__ cql,
                float* __restrict__ ckv,
                h16* __restrict__ ckvh, h16* __restrict__ ckvl,
                const float* __restrict__ q_w, const float* __restrict__ q_b,
                const float* __restrict__ kv_w, const float* __restrict__ kv_b)
{
    bool isKV = blockIdx.y != 0;
    const float* p = p1 + (size_t)blockIdx.x * N1 + (isKV ? QPROJ : 0);
    int n = isKV ? KVPROJ : QPROJ;
    int npad = isKV ? KVPAD : QPROJ;
    const float* w = isKV ? kv_w : q_w;
    const float* b = isKV ? kv_b : q_b;
    h16* hh = (isKV ? ckvh : cqh) + (size_t)blockIdx.x * npad;
    h16* ll = (isKV ? ckvl : cql) + (size_t)blockIdx.x * npad;
    float* of = isKV ? ckv + (size_t)blockIdx.x * KVPROJ : nullptr;

    float s = 0.f, s2 = 0.f;
    for (int j = threadIdx.x; j < n; j += 256) {
        float v = p[j];
        s += v; s2 += v * v;
    }
    __shared__ float sh[20];
#pragma unroll
    for (int o = 16; o; o >>= 1) {
        s  += __shfl_down_sync(0xffffffffu, s,  o);
        s2 += __shfl_down_sync(0xffffffffu, s2, o);
    }
    int wd = threadIdx.x >> 5, ln = threadIdx.x & 31;
    if (!ln) { sh[wd] = s; sh[wd + 8] = s2; }
    __syncthreads();
    if (threadIdx.x == 0) {
        float ts = 0.f, ts2 = 0.f;
        for (int i = 0; i < 8; i++) { ts += sh[i]; ts2 += sh[i + 8]; }
        float mean = ts / n;
        float var = fmaxf(ts2 / n - mean * mean, 0.f);
        sh[16] = mean;
        sh[17] = rsqrtf(var + 1e-5f);
    }
    __syncthreads();
    float mean = sh[16], rstd = sh[17];
    for (int j = threadIdx.x; j < npad; j += 256) {
        float v = 0.f;
        if (j < n) {
            v = (p[j] - mean) * rstd * w[j] + b[j];
            if (of) of[j] = v;
        }
        split2(v, hh[j], ll[j]);
    }
}

// merged RoPE: first half -> Q (in-place on q2h), second half -> K (p1 -> kvh)
__global__ __launch_bounds__(256)
void rope_qk(h16* __restrict__ q2h,
             const float* __restrict__ p1,
             h16* __restrict__ kvh)
{
    int total = BS * 2 * 64;
    int idx = blockIdx.x * 256 + threadIdx.x;
    if (idx >= 2 * total) return;
    bool isK = idx >= total;
    if (isK) idx -= total;
    int dp = idx & 63;
    int h2 = (idx >> 6) & 1;
    int row = idx >> 7;
    int s = row & (S_ - 1);
    float freq = exp2f(-(float)dp * 0.20762050593046015f);
    float sn, cs;
    sincosf((float)s * freq, &sn, &cs);

    if (!isK) {
        size_t base = (size_t)row * N2 + KNOPE + h2 * DH;
        float x1 = __half2float(q2h[base + dp]);
        float x2 = __half2float(q2h[base + dp + 64]);
        q2h[base + dp]      = __float2half_rn(x1 * cs - x2 * sn);
        q2h[base + dp + 64] = __float2half_rn(x2 * cs + x1 * sn);
    } else {
        const float* src = p1 + (size_t)row * N1 + 2432 + h2 * DH;
        float x1 = src[dp], x2 = src[dp + 64];
        size_t base = (size_t)row * KVLD + KVCOLS + h2 * DH;
        kvh[base + dp]      = __float2half_rn(x1 * cs - x2 * sn);
        kvh[base + dp + 64] = __float2half_rn(x2 * cs + x1 * sn);
    }
}

// ---------------- launch ----------------
static inline void* sym(const void* s) { void* p; cudaGetSymbolAddress(&p, s); return p; }

extern "C" void kernel_launch(void* const* d_in, const int* in_sizes, int n_in,
                              void* d_out, int out_size)
{
    const float* x     = (const float*)d_in[0];
    const float* W_dq  = (const float*)d_in[1];
    const float* W_uq  = (const float*)d_in[2];
    const float* W_qr  = (const float*)d_in[3];
    const float* W_dkv = (const float*)d_in[4];
    const float* W_ukv = (const float*)d_in[5];
    const float* W_kr  = (const float*)d_in[6];
    const float* W_o   = (const float*)d_in[7];
    const float* q_w   = (const float*)d_in[8];
    const float* q_b   = (const float*)d_in[9];
    const float* kv_w  = (const float*)d_in[10];
    const float* kv_b  = (const float*)d_in[11];

    float* out = (float*)d_out;
    float* ckv = out + (size_t)BS * DMODEL;

    h16 *xhi=(h16*)sym(g_xhi), *xlo=(h16*)sym(g_xlo);
    h16 *w1h=(h16*)sym(g_w1h);
    h16 *w2h=(h16*)sym(g_w2h);
    h16 *wukvh=(h16*)sym(g_wukvh);
    h16 *woh=(h16*)sym(g_woh);
    float *p1=(float*)sym(g_p1);
    h16 *cqh=(h16*)sym(g_cqh), *cql=(h16*)sym(g_cql);
    h16 *ckvh=(h16*)sym(g_ckvh), *ckvl=(h16*)sym(g_ckvl);
    h16 *q2h=(h16*)sym(g_q2h);
    h16 *kvh=(h16*)sym(g_kvh);
    h16 *aoh=(h16*)sym(g_aoh);

    cudaFuncSetAttribute(hmma_gemm1, cudaFuncAttributeMaxDynamicSharedMemorySize, SMEM_GEMM1);
    cudaFuncSetAttribute(hmma_gemm_dual, cudaFuncAttributeMaxDynamicSharedMemorySize, SMEM_GEMM2);
    cudaFuncSetAttribute(gemm_p1_prep2, cudaFuncAttributeMaxDynamicSharedMemorySize, SMEM_GEMM2);
    cudaFuncSetAttribute(flash_attn, cudaFuncAttributeMaxDynamicSharedMemorySize, SMEM_FLASH);

    // 1. x split + W1 transposes
    prep1<<<1216, 256>>>(x, W_dq, W_dkv, W_kr, xhi, xlo, w1h);

    // 2. p1 = x @ W1 (fp32) fused with prep2
    gemm_p1_prep2<<<1844, 256, SMEM_GEMM2>>>(
        xhi, xlo, w1h, p1,
        W_uq, W_qr, W_ukv, W_o,
        w2h, wukvh, woh);

    // 3. LayerNorms (merged)
    layernorm2<<<dim3(BS, 2), 256>>>(p1, cqh, cql, ckv, ckvh, ckvl, q_w, q_b, kv_w, kv_b);

    // 4. q2 = cq @ W2 AND kv = ckv @ W_ukv in one launch
    {
        int gx_ukv = KVCOLS / 128;              // 30
        int gx_q2  = N2 / 128;                  // 16
        int blocks_ukv = gx_ukv * (BS / 128);   // 960
        int blocks_q2  = gx_q2  * (BS / 128);   // 512
        hmma_gemm_dual<<<blocks_ukv + blocks_q2, 256, SMEM_GEMM2>>>(
            ckvh, ckvl, wukvh, kvh, nullptr,
            KVCOLS, KVPAD, KVPAD, KVPAD, KVLD, gx_ukv,
            cqh, cql, w2h, q2h, nullptr,
            N2, QPROJ, QPROJ, QPROJ, N2, gx_q2,
            blocks_ukv);
    }

    // 5. RoPE
    rope_qk<<<(2*BS*2*64 + 255)/256, 256>>>(q2h, p1, kvh);

    // 6. flash attention (single-product)
    flash_attn<<<dim3(S_/128, NZ), 256, SMEM_FLASH>>>(q2h, kvh, aoh);

    // 7. final projection (single-product)
    hmma_gemm1<<<dim3(DMODEL/128, BS/128), 256, SMEM_GEMM1>>>(
        aoh, woh, out, DMODEL, DMODEL, DMODEL, DMODEL, DMODEL);
}

// round 12
// speedup vs baseline: 10.8641x; 1.1642x over previous
#include <cuda_runtime.h>
#include <cuda_fp16.h>
#include <cstdint>
#include <math.h>

// ---------------- problem constants ----------------
#define B_      2
#define S_      2048
#define DMODEL  2048
#define NH      16
#define DH      128
#define NOPE    14
#define QPROJ   1024
#define KVPROJ  1365
#define KVPAD   1408
#define KNOPE   1792
#define KVCOLS  3840
#define KVLD    4096
#define BS      (B_*S_)
#define NZ      (B_*NH)
#define N1      2688
#define N2      2048

typedef __half h16;

// ---------------- device scratch ----------------
__device__ h16 g_xhi[(size_t)BS*DMODEL],   g_xlo[(size_t)BS*DMODEL];
__device__ h16 g_w1h[(size_t)N1*DMODEL];
__device__ h16 g_w2h[(size_t)N2*QPROJ];
__device__ h16 g_wukvh[(size_t)KVCOLS*KVPAD];
__device__ h16 g_woh[(size_t)DMODEL*DMODEL];
__device__ float g_p1[(size_t)BS*N1];
__device__ h16 g_cqh[(size_t)BS*QPROJ];
__device__ h16 g_ckvh[(size_t)BS*KVPAD];
__device__ h16 g_q2h[(size_t)BS*N2];
__device__ h16 g_kvh[(size_t)BS*KVLD];
__device__ h16 g_aoh[(size_t)BS*DMODEL];

// ---------------- helpers ----------------
__device__ __forceinline__ uint32_t smem_u32(const void* p) {
    uint32_t a;
    asm("{ .reg .u64 t; cvta.to.shared.u64 t, %1; cvt.u32.u64 %0, t; }" : "=r"(a) : "l"(p));
    return a;
}
__device__ __forceinline__ void cp16(uint32_t saddr, const void* g) {
    asm volatile("cp.async.cg.shared.global [%0], [%1], 16;" :: "r"(saddr), "l"(g) : "memory");
}
__device__ __forceinline__ void cp_commit() {
    asm volatile("cp.async.commit_group;" ::: "memory");
}
template<int N> __device__ __forceinline__ void cp_wait() {
    asm volatile("cp.async.wait_group %0;" :: "n"(N) : "memory");
}
__device__ __forceinline__ void ldm_x4(uint32_t addr, uint32_t* r) {
    asm volatile("ldmatrix.sync.aligned.m8n8.x4.shared.b16 {%0,%1,%2,%3}, [%4];"
        : "=r"(r[0]), "=r"(r[1]), "=r"(r[2]), "=r"(r[3]) : "r"(addr));
}
__device__ __forceinline__ void ldm_x4_t(uint32_t addr, uint32_t* r) {
    asm volatile("ldmatrix.sync.aligned.m8n8.x4.trans.shared.b16 {%0,%1,%2,%3}, [%4];"
        : "=r"(r[0]), "=r"(r[1]), "=r"(r[2]), "=r"(r[3]) : "r"(addr));
}
__device__ __forceinline__ void mma16816(float* d, const uint32_t* a, const uint32_t* b) {
    asm volatile("mma.sync.aligned.m16n8k16.row.col.f32.f16.f16.f32 "
        "{%0,%1,%2,%3}, {%4,%5,%6,%7}, {%8,%9}, {%0,%1,%2,%3};"
        : "+f"(d[0]), "+f"(d[1]), "+f"(d[2]), "+f"(d[3])
        : "r"(a[0]), "r"(a[1]), "r"(a[2]), "r"(a[3]), "r"(b[0]), "r"(b[1]));
}
__device__ __forceinline__ void split2(float v, h16& h, h16& l) {
    h = __float2half_rn(v);
    l = __float2half_rn(v - __half2float(h));
}
__device__ __forceinline__ uint32_t pack_h2(float a, float b) {
    __half2 t = __floats2half2_rn(a, b);
    return *(uint32_t*)&t;
}

// ---------------- prep device functions ----------------
__device__ __forceinline__ void split_chunk(const float4* __restrict__ in,
                                            __half2* __restrict__ hi,
                                            __half2* __restrict__ lo,
                                            size_t base4, size_t n4)
{
#pragma unroll
    for (int q = 0; q < 16; q++) {
        size_t i = base4 + (size_t)q * 256 + threadIdx.x;
        if (i >= n4) return;
        float4 v = in[i];
        h16 h0, l0_, h1, l1_, h2, l2_, h3, l3_;
        split2(v.x, h0, l0_); split2(v.y, h1, l1_);
        split2(v.z, h2, l2_); split2(v.w, h3, l3_);
        hi[i * 2]     = __halves2half2(h0, h1);
        hi[i * 2 + 1] = __halves2half2(h2, h3);
        if (lo) {
            lo[i * 2]     = __halves2half2(l0_, l1_);
            lo[i * 2 + 1] = __halves2half2(l2_, l3_);
        }
    }
}

__device__ __forceinline__ void tr_strip(const float* __restrict__ in,
                                         h16* __restrict__ hi,
                                         int K, int N, int Npad, int Kpad, int rowOff,
                                         int strip, int nStrips)
{
    __shared__ float t[32][33];
    int kTile = strip / nStrips;
    int nT0 = (strip % nStrips) * 8;
    int k0 = kTile * 32;
    int tx = threadIdx.x & 31, ty = threadIdx.x >> 5;
    for (int sub = 0; sub < 8; sub++) {
        int n0 = (nT0 + sub) * 32;
        if (n0 >= Npad) break;
        __syncthreads();
#pragma unroll
        for (int i = 0; i < 4; i++) {
            int k = k0 + ty + i * 8;
            float v = (k < K && n0 + tx < N) ? in[(size_t)k * N + n0 + tx] : 0.f;
            t[ty + i * 8][tx] = v;
        }
        __syncthreads();
#pragma unroll
        for (int i = 0; i < 4; i++) {
            int n = n0 + ty + i * 8, k = k0 + tx;
            if (n < Npad && k < Kpad)
                hi[(size_t)(n + rowOff) * Kpad + k] = __float2half_rn(t[tx][ty + i * 8]);
        }
    }
}

// ---------------- GEMM core: C = (Ah[+Al]) @ Bh^T, BK=32, 3-stage ----------------
#define STAGE2 24576
#define STAGE1 16384
#define SMEM_GEMM2 (3*STAGE2)
#define SMEM_GEMM1 (3*STAGE1)

template<bool TWO>
__device__ __forceinline__ void gemm_core(
    const h16* __restrict__ Ahi, const h16* __restrict__ Alo,
    const h16* __restrict__ Bhi,
    float* __restrict__ Cf, h16* __restrict__ Ch,
    int N, int Kpad, int lda, int ldb, int ldc,
    int r0, int c0, char* smem)
{
    constexpr uint32_t STG  = TWO ? STAGE2 : STAGE1;
    constexpr uint32_t BOFF = TWO ? 16384 : 8192;
    int tid = threadIdx.x, lane = tid & 31, wid = tid >> 5;
    int tiles = Kpad >> 5;

    const h16* Ah = Ahi + (size_t)r0 * lda;
    const h16* Al = TWO ? Alo + (size_t)r0 * lda : nullptr;
    const h16* Bh = Bhi + (size_t)c0 * ldb;

    uint32_t sbase = smem_u32(smem);
    int wm = (wid >> 2) * 64, wn = (wid & 3) * 32;

    float acc[4][4][4];
#pragma unroll
    for (int i = 0; i < 4; i++)
#pragma unroll
        for (int j = 0; j < 4; j++)
#pragma unroll
            for (int v = 0; v < 4; v++) acc[i][j][v] = 0.f;

    auto load_stage = [&](int t) {
        int k0 = t << 5;
        uint32_t sb = sbase + (uint32_t)(t % 3) * STG;
#pragma unroll
        for (int q = 0; q < 2; q++) {
            int c = tid + q * 256;
            int row = c >> 2, ch = c & 3;
            uint32_t off = (uint32_t)row * 64 + (uint32_t)((ch ^ ((row >> 1) & 3)) << 4);
            size_t ga = (size_t)row * lda + k0 + ch * 8;
            size_t gb = (size_t)row * ldb + k0 + ch * 8;
            cp16(sb + off, Ah + ga);
            if (TWO) cp16(sb + 8192 + off, Al + ga);
            cp16(sb + BOFF + off, Bh + gb);
        }
        cp_commit();
    };

    auto compute_stage = [&](int t) {
        uint32_t sb = sbase + (uint32_t)(t % 3) * STG;
#pragma unroll
        for (int kk = 0; kk < 32; kk += 16) {
            uint32_t bh[4][2];
#pragma unroll
            for (int p = 0; p < 2; p++) {
                int rowB = wn + p * 16 + ((lane >> 4) << 3) + (lane & 7);
                int ch = (kk >> 3) + ((lane >> 3) & 1);
                uint32_t off = (uint32_t)rowB * 64 + (uint32_t)((ch ^ ((rowB >> 1) & 3)) << 4);
                uint32_t r[4];
                ldm_x4(sb + BOFF + off, r);
                bh[2 * p][0] = r[0]; bh[2 * p][1] = r[1];
                bh[2 * p + 1][0] = r[2]; bh[2 * p + 1][1] = r[3];
            }
#pragma unroll
            for (int mt = 0; mt < 4; mt++) {
                int rowA = wm + mt * 16 + (lane & 15);
                int ch = (kk >> 3) + (lane >> 4);
                uint32_t off = (uint32_t)rowA * 64 + (uint32_t)((ch ^ ((rowA >> 1) & 3)) << 4);
                uint32_t ah[4], al[4];
                ldm_x4(sb + off, ah);
                if (TWO) ldm_x4(sb + 8192 + off, al);
#pragma unroll
                for (int nt = 0; nt < 4; nt++) {
                    mma16816(acc[mt][nt], ah, bh[nt]);
                    if (TWO) mma16816(acc[mt][nt], al, bh[nt]);
                }
            }
        }
    };

    load_stage(0);
    if (tiles > 1) load_stage(1);
    for (int t = 0; t < tiles; t++) {
        if (t + 1 < tiles) cp_wait<1>(); else cp_wait<0>();
        __syncthreads();
        if (t + 2 < tiles) load_stage(t + 2);
        compute_stage(t);
    }

    if (Cf) {
#pragma unroll
        for (int mt = 0; mt < 4; mt++) {
#pragma unroll
            for (int nt = 0; nt < 4; nt++) {
                int r = r0 + wm + mt * 16 + (lane >> 2);
                int c = c0 + wn + nt * 8 + ((lane & 3) << 1);
                float* p0 = Cf + (size_t)r * ldc + c;
                float* p1 = p0 + 8 * ldc;
                p0[0] = acc[mt][nt][0]; p0[1] = acc[mt][nt][1];
                p1[0] = acc[mt][nt][2]; p1[1] = acc[mt][nt][3];
            }
        }
    } else {
#pragma unroll
        for (int mt = 0; mt < 4; mt++) {
#pragma unroll
            for (int nt = 0; nt < 4; nt++) {
                int r = r0 + wm + mt * 16 + (lane >> 2);
                int c = c0 + wn + nt * 8 + ((lane & 3) << 1);
                size_t o0 = (size_t)r * ldc + c;
                size_t o1 = o0 + (size_t)8 * ldc;
                *(uint32_t*)(Ch + o0) = pack_h2(acc[mt][nt][0], acc[mt][nt][1]);
                *(uint32_t*)(Ch + o1) = pack_h2(acc[mt][nt][2], acc[mt][nt][3]);
            }
        }
    }
}

// ---------------- prep1: x split + W1 transposes ----------------
__global__ __launch_bounds__(256)
void prep1(const float* __restrict__ x,
           const float* __restrict__ W_dq, const float* __restrict__ W_dkv,
           const float* __restrict__ W_kr,
           h16* __restrict__ xhi, h16* __restrict__ xlo,
           h16* __restrict__ w1h)
{
    int i = blockIdx.x;
    if (i < 512) {
        split_chunk((const float4*)x, (__half2*)xhi, (__half2*)xlo,
                    (size_t)i * 4096, (size_t)BS * DMODEL / 4);
    } else if (i < 768) {
        tr_strip(W_dq, w1h, DMODEL, QPROJ, QPROJ, DMODEL, 0, i - 512, 4);
    } else if (i < 1152) {
        tr_strip(W_dkv, w1h, DMODEL, KVPROJ, KVPAD, DMODEL, QPROJ, i - 768, 6);
    } else {
        tr_strip(W_kr, w1h, DMODEL, 256, 256, DMODEL, QPROJ + KVPAD, i - 1152, 1);
    }
}

// ---------------- p1 GEMM fused with prep2 (p1 stays 2-product: protects ckv) ---
__global__ __launch_bounds__(256, 2)
void gemm_p1_prep2(const h16* __restrict__ xhi, const h16* __restrict__ xlo,
                   const h16* __restrict__ w1h,
                   float* __restrict__ p1,
                   const float* __restrict__ W_uq, const float* __restrict__ W_qr,
                   const float* __restrict__ W_ukv, const float* __restrict__ W_o,
                   h16* __restrict__ w2h, h16* __restrict__ wukvh, h16* __restrict__ woh)
{
    extern __shared__ __align__(128) char smem[];
    int i = blockIdx.x;
    bool isGemm;
    int sub;
    if (i < 1344) { isGemm = !(i & 1); sub = i >> 1; }
    else          { isGemm = false;    sub = 672 + (i - 1344); }

    if (isGemm) {
        int cx = sub % 21, cy = sub / 21;
        gemm_core<true>(xhi, xlo, w1h, p1, nullptr,
                        N1, DMODEL, DMODEL, DMODEL, N1, cy * 128, cx * 128, smem);
    } else {
        if (sub < 224) {
            tr_strip(W_uq, w2h, QPROJ, KNOPE, KNOPE, QPROJ, 0, sub, 7);
        } else if (sub < 256) {
            tr_strip(W_qr, w2h, QPROJ, 256, 256, QPROJ, KNOPE, sub - 224, 1);
        } else if (sub < 916) {
            tr_strip(W_ukv, wukvh, KVPROJ, KVCOLS, KVCOLS, KVPAD, 0, sub - 256, 15);
        } else {
            split_chunk((const float4*)W_o, (__half2*)woh, nullptr,
                        (size_t)(sub - 916) * 4096, (size_t)DMODEL * DMODEL / 4);
        }
    }
}

// single-product GEMM (Wo): fp32 out
__global__ __launch_bounds__(256, 2)
void hmma_gemm1(const h16* __restrict__ Ahi, const h16* __restrict__ Bhi,
                float* __restrict__ Cf, int N, int Kpad, int lda, int ldb, int ldc)
{
    extern __shared__ __align__(128) char smem[];
    gemm_core<false>(Ahi, nullptr, Bhi, Cf, nullptr, N, Kpad, lda, ldb, ldc,
                     blockIdx.y * 128, blockIdx.x * 128, smem);
}

// dual single-product GEMM: q2 + ukv in one launch
__global__ __launch_bounds__(256, 2)
void hmma_gemm_dual(
    const h16* A1h, const h16* B1h, h16* C1h,
    int n1, int k1, int la1, int lb1, int lc1, int gx1,
    const h16* A2h, const h16* B2h, h16* C2h,
    int n2, int k2, int la2, int lb2, int lc2, int gx2,
    int split)
{
    extern __shared__ __align__(128) char smem[];
    int idx = blockIdx.x;
    if (idx < split) {
        int cx = idx % gx1, cy = idx / gx1;
        gemm_core<false>(A1h, nullptr, B1h, nullptr, C1h, n1, k1, la1, lb1, lc1,
                         cy * 128, cx * 128, smem);
    } else {
        idx -= split;
        int cx = idx % gx2, cy = idx / gx2;
        gemm_core<false>(A2h, nullptr, B2h, nullptr, C2h, n2, k2, la2, lb2, lc2,
                         cy * 128, cx * 128, smem);
    }
}

// ---------------- fused flash attention (single-product) ----------------
#define FST 32768
#define FQB 32768
#define SMEM_FLASH (FQB + 3*FST)

__global__ __launch_bounds__(256, 1)
void flash_attn(const h16* __restrict__ q2h,
                const h16* __restrict__ kvh,
                h16* __restrict__ aoh)
{
    extern __shared__ __align__(128) char smem[];
    int tid = threadIdx.x, lane = tid & 31, wid = tid >> 5;
    int z = blockIdx.y, bb = z >> 4, hh = z & 15;
    int r0 = ((int)gridDim.x - 1 - (int)blockIdx.x) * 128;

    int kcol = (hh < NOPE) ? hh * DH : KVCOLS + (hh - NOPE) * DH;
    int vcol = KNOPE + hh * DH;

    const h16* qhz = q2h + ((size_t)(bb * S_ + r0)) * N2 + hh * DH;
    const h16* khz = kvh + (size_t)(bb * S_) * KVLD + kcol;
    const h16* vhz = kvh + (size_t)(bb * S_) * KVLD + vcol;

    uint32_t sb = smem_u32(smem);

#pragma unroll
    for (int q = 0; q < 8; q++) {
        int idx = tid + q * 256;
        int row = idx >> 4, ch = idx & 15;
        uint32_t off = (uint32_t)row * 256 + (uint32_t)((ch ^ (row & 7)) << 4);
        cp16(sb + off, qhz + (size_t)row * N2 + ch * 8);
    }
    cp_commit();

    int ntiles = (r0 >> 6) + 2;
    int diag = r0 >> 6;

    auto load_stage = [&](int jt) {
        uint32_t st = sb + FQB + (uint32_t)(jt % 3) * FST;
        int s0 = jt * 64;
#pragma unroll
        for (int q = 0; q < 4; q++) {
            int idx = tid + q * 256;
            int row = idx >> 4, ch = idx & 15;
            uint32_t off = (uint32_t)row * 256 + (uint32_t)((ch ^ (row & 7)) << 4);
            size_t g = (size_t)(s0 + row) * KVLD + ch * 8;
            cp16(st + off,         khz + g);
            cp16(st + 16384 + off, vhz + g);
        }
        cp_commit();
    };

    load_stage(0);
    load_stage(1);
    cp_wait<2>();
    __syncthreads();

    int wrow = wid * 16;
    uint32_t qah[8][4];
#pragma unroll
    for (int kf = 0; kf < 8; kf++) {
        int row = wrow + (lane & 15);
        int ch = kf * 2 + (lane >> 4);
        uint32_t off = (uint32_t)row * 256 + (uint32_t)((ch ^ (row & 7)) << 4);
        ldm_x4(sb + off, qah[kf]);
    }

    float of[16][4];
#pragma unroll
    for (int i = 0; i < 16; i++)
#pragma unroll
        for (int v = 0; v < 4; v++) of[i][v] = 0.f;
    float m0 = -1e30f, m1 = -1e30f, l0 = 0.f, l1 = 0.f;
    const float CEXP = 0.08838834764831845f * 1.4426950408889634f;

    int rowa = r0 + wrow + (lane >> 2);

    for (int jt = 0; jt < ntiles; jt++) {
        if (jt + 1 < ntiles) cp_wait<1>(); else cp_wait<0>();
        __syncthreads();
        if (jt + 2 < ntiles) load_stage(jt + 2);
        uint32_t st = sb + FQB + (uint32_t)(jt % 3) * FST;

        float sf[8][4];
#pragma unroll
        for (int nf = 0; nf < 8; nf++)
#pragma unroll
            for (int v = 0; v < 4; v++) sf[nf][v] = 0.f;

#pragma unroll
        for (int kf = 0; kf < 8; kf++) {
            uint32_t bh[8][2];
#pragma unroll
            for (int p = 0; p < 4; p++) {
                int rowB = p * 16 + ((lane >> 4) << 3) + (lane & 7);
                int ch = kf * 2 + ((lane >> 3) & 1);
                uint32_t off = (uint32_t)rowB * 256 + (uint32_t)((ch ^ (rowB & 7)) << 4);
                uint32_t r4[4];
                ldm_x4(st + off, r4);
                bh[2 * p][0] = r4[0]; bh[2 * p][1] = r4[1];
                bh[2 * p + 1][0] = r4[2]; bh[2 * p + 1][1] = r4[3];
            }
#pragma unroll
            for (int nf = 0; nf < 8; nf++)
                mma16816(sf[nf], qah[kf], bh[nf]);
        }

        if (jt >= diag) {
            int colb = jt * 64 + 2 * (lane & 3);
#pragma unroll
            for (int nf = 0; nf < 8; nf++) {
                int c = colb + nf * 8;
                if (c > rowa)     sf[nf][0] = -1e30f;
                if (c + 1 > rowa) sf[nf][1] = -1e30f;
                if (c > rowa + 8)     sf[nf][2] = -1e30f;
                if (c + 1 > rowa + 8) sf[nf][3] = -1e30f;
            }
        }

        float tm0 = -1e30f, tm1 = -1e30f;
#pragma unroll
        for (int nf = 0; nf < 8; nf++) {
            tm0 = fmaxf(tm0, fmaxf(sf[nf][0], sf[nf][1]));
            tm1 = fmaxf(tm1, fmaxf(sf[nf][2], sf[nf][3]));
        }
        tm0 = fmaxf(tm0, __shfl_xor_sync(0xffffffffu, tm0, 1));
        tm0 = fmaxf(tm0, __shfl_xor_sync(0xffffffffu, tm0, 2));
        tm1 = fmaxf(tm1, __shfl_xor_sync(0xffffffffu, tm1, 1));
        tm1 = fmaxf(tm1, __shfl_xor_sync(0xffffffffu, tm1, 2));
        float mn0 = fmaxf(m0, tm0), mn1 = fmaxf(m1, tm1);
        float al0 = exp2f((m0 - mn0) * CEXP), al1 = exp2f((m1 - mn1) * CEXP);
        m0 = mn0; m1 = mn1;

        uint32_t pah[4][4];
        float rs0 = 0.f, rs1 = 0.f;
#pragma unroll
        for (int nf = 0; nf < 8; nf++) {
            float e0 = exp2f((sf[nf][0] - m0) * CEXP);
            float e1 = exp2f((sf[nf][1] - m0) * CEXP);
            float e2 = exp2f((sf[nf][2] - m1) * CEXP);
            float e3 = exp2f((sf[nf][3] - m1) * CEXP);
            rs0 += e0 + e1; rs1 += e2 + e3;
            int kf2 = nf >> 1, s = (nf & 1) * 2;
            pah[kf2][s]     = pack_h2(e0, e1);
            pah[kf2][s + 1] = pack_h2(e2, e3);
        }
        l0 = l0 * al0 + rs0;
        l1 = l1 * al1 + rs1;

#pragma unroll
        for (int i = 0; i < 16; i++) {
            of[i][0] *= al0; of[i][1] *= al0;
            of[i][2] *= al1; of[i][3] *= al1;
        }

#pragma unroll
        for (int kf2 = 0; kf2 < 4; kf2++) {
#pragma unroll
            for (int nb = 0; nb < 8; nb++) {
                int row = kf2 * 16 + (lane & 15);
                int ch = nb * 2 + (lane >> 4);
                uint32_t off = (uint32_t)row * 256 + (uint32_t)((ch ^ (row & 7)) << 4);
                uint32_t rh[4];
                ldm_x4_t(st + 16384 + off, rh);
                uint32_t bh0[2] = {rh[0], rh[1]}, bh1[2] = {rh[2], rh[3]};
                mma16816(of[2 * nb],     pah[kf2], bh0);
                mma16816(of[2 * nb + 1], pah[kf2], bh1);
            }
        }
    }

    l0 += __shfl_xor_sync(0xffffffffu, l0, 1);
    l0 += __shfl_xor_sync(0xffffffffu, l0, 2);
    l1 += __shfl_xor_sync(0xffffffffu, l1, 1);
    l1 += __shfl_xor_sync(0xffffffffu, l1, 2);
    float inv0 = 1.f / l0, inv1 = 1.f / l1;

    size_t ga = ((size_t)(bb * S_) + rowa) * DMODEL + hh * DH;
    size_t gb = ga + (size_t)8 * DMODEL;
#pragma unroll
    for (int i = 0; i < 16; i++) {
        int d = i * 8 + 2 * (lane & 3);
        *(uint32_t*)(aoh + ga + d) = pack_h2(of[i][0] * inv0, of[i][1] * inv0);
        *(uint32_t*)(aoh + gb + d) = pack_h2(of[i][2] * inv1, of[i][3] * inv1);
    }
}

// ---------------- merged LayerNorm (hi outputs only) ----------------
__global__ __launch_bounds__(256)
void layernorm2(const float* __restrict__ p1,
                h16* __restrict__ cqh,
                float* __restrict__ ckv,
                h16* __restrict__ ckvh,
                const float* __restrict__ q_w, const float* __restrict__ q_b,
                const float* __restrict__ kv_w, const float* __restrict__ kv_b)
{
    bool isKV = blockIdx.y != 0;
    const float* p = p1 + (size_t)blockIdx.x * N1 + (isKV ? QPROJ : 0);
    int n = isKV ? KVPROJ : QPROJ;
    int npad = isKV ? KVPAD : QPROJ;
    const float* w = isKV ? kv_w : q_w;
    const float* b = isKV ? kv_b : q_b;
    h16* hh = (isKV ? ckvh : cqh) + (size_t)blockIdx.x * npad;
    float* of = isKV ? ckv + (size_t)blockIdx.x * KVPROJ : nullptr;

    float s = 0.f, s2 = 0.f;
    for (int j = threadIdx.x; j < n; j += 256) {
        float v = p[j];
        s += v; s2 += v * v;
    }
    __shared__ float sh[20];
#pragma unroll
    for (int o = 16; o; o >>= 1) {
        s  += __shfl_down_sync(0xffffffffu, s,  o);
        s2 += __shfl_down_sync(0xffffffffu, s2, o);
    }
    int wd = threadIdx.x >> 5, ln = threadIdx.x & 31;
    if (!ln) { sh[wd] = s; sh[wd + 8] = s2; }
    __syncthreads();
    if (threadIdx.x == 0) {
        float ts = 0.f, ts2 = 0.f;
        for (int i = 0; i < 8; i++) { ts += sh[i]; ts2 += sh[i + 8]; }
        float mean = ts / n;
        float var = fmaxf(ts2 / n - mean * mean, 0.f);
        sh[16] = mean;
        sh[17] = rsqrtf(var + 1e-5f);
    }
    __syncthreads();
    float mean = sh[16], rstd = sh[17];
    for (int j = threadIdx.x; j < npad; j += 256) {
        float v = 0.f;
        if (j < n) {
            v = (p[j] - mean) * rstd * w[j] + b[j];
            if (of) of[j] = v;
        }
        hh[j] = __float2half_rn(v);
    }
}

// merged RoPE: first half -> Q (in-place on q2h), second half -> K (p1 -> kvh)
__global__ __launch_bounds__(256)
void rope_qk(h16* __restrict__ q2h,
             const float* __restrict__ p1,
             h16* __restrict__ kvh)
{
    int total = BS * 2 * 64;
    int idx = blockIdx.x * 256 + threadIdx.x;
    if (idx >= 2 * total) return;
    bool isK = idx >= total;
    if (isK) idx -= total;
    int dp = idx & 63;
    int h2 = (idx >> 6) & 1;
    int row = idx >> 7;
    int s = row & (S_ - 1);
    float freq = exp2f(-(float)dp * 0.20762050593046015f);
    float sn, cs;
    sincosf((float)s * freq, &sn, &cs);

    if (!isK) {
        size_t base = (size_t)row * N2 + KNOPE + h2 * DH;
        float x1 = __half2float(q2h[base + dp]);
        float x2 = __half2float(q2h[base + dp + 64]);
        q2h[base + dp]      = __float2half_rn(x1 * cs - x2 * sn);
        q2h[base + dp + 64] = __float2half_rn(x2 * cs + x1 * sn);
    } else {
        const float* src = p1 + (size_t)row * N1 + 2432 + h2 * DH;
        float x1 = src[dp], x2 = src[dp + 64];
        size_t base = (size_t)row * KVLD + KVCOLS + h2 * DH;
        kvh[base + dp]      = __float2half_rn(x1 * cs - x2 * sn);
        kvh[base + dp + 64] = __float2half_rn(x2 * cs + x1 * sn);
    }
}

// ---------------- launch ----------------
static inline void* sym(const void* s) { void* p; cudaGetSymbolAddress(&p, s); return p; }

extern "C" void kernel_launch(void* const* d_in, const int* in_sizes, int n_in,
                              void* d_out, int out_size)
{
    const float* x     = (const float*)d_in[0];
    const float* W_dq  = (const float*)d_in[1];
    const float* W_uq  = (const float*)d_in[2];
    const float* W_qr  = (const float*)d_in[3];
    const float* W_dkv = (const float*)d_in[4];
    const float* W_ukv = (const float*)d_in[5];
    const float* W_kr  = (const float*)d_in[6];
    const float* W_o   = (const float*)d_in[7];
    const float* q_w   = (const float*)d_in[8];
    const float* q_b   = (const float*)d_in[9];
    const float* kv_w  = (const float*)d_in[10];
    const float* kv_b  = (const float*)d_in[11];

    float* out = (float*)d_out;
    float* ckv = out + (size_t)BS * DMODEL;

    h16 *xhi=(h16*)sym(g_xhi), *xlo=(h16*)sym(g_xlo);
    h16 *w1h=(h16*)sym(g_w1h);
    h16 *w2h=(h16*)sym(g_w2h);
    h16 *wukvh=(h16*)sym(g_wukvh);
    h16 *woh=(h16*)sym(g_woh);
    float *p1=(float*)sym(g_p1);
    h16 *cqh=(h16*)sym(g_cqh);
    h16 *ckvh=(h16*)sym(g_ckvh);
    h16 *q2h=(h16*)sym(g_q2h);
    h16 *kvh=(h16*)sym(g_kvh);
    h16 *aoh=(h16*)sym(g_aoh);

    cudaFuncSetAttribute(hmma_gemm1, cudaFuncAttributeMaxDynamicSharedMemorySize, SMEM_GEMM1);
    cudaFuncSetAttribute(hmma_gemm_dual, cudaFuncAttributeMaxDynamicSharedMemorySize, SMEM_GEMM1);
    cudaFuncSetAttribute(gemm_p1_prep2, cudaFuncAttributeMaxDynamicSharedMemorySize, SMEM_GEMM2);
    cudaFuncSetAttribute(flash_attn, cudaFuncAttributeMaxDynamicSharedMemorySize, SMEM_FLASH);

    // 1. x split + W1 transposes
    prep1<<<1216, 256>>>(x, W_dq, W_dkv, W_kr, xhi, xlo, w1h);

    // 2. p1 = x @ W1 (fp32, 2-product) fused with prep2
    gemm_p1_prep2<<<1844, 256, SMEM_GEMM2>>>(
        xhi, xlo, w1h, p1,
        W_uq, W_qr, W_ukv, W_o,
        w2h, wukvh, woh);

    // 3. LayerNorms (merged, hi only)
    layernorm2<<<dim3(BS, 2), 256>>>(p1, cqh, ckv, ckvh, q_w, q_b, kv_w, kv_b);

    // 4. q2 = cq @ W2 AND kv = ckv @ W_ukv in one launch (single-product)
    {
        int gx_ukv = KVCOLS / 128;              // 30
        int gx_q2  = N2 / 128;                  // 16
        int blocks_ukv = gx_ukv * (BS / 128);   // 960
        int blocks_q2  = gx_q2  * (BS / 128);   // 512
        hmma_gemm_dual<<<blocks_ukv + blocks_q2, 256, SMEM_GEMM1>>>(
            ckvh, wukvh, kvh,
            KVCOLS, KVPAD, KVPAD, KVPAD, KVLD, gx_ukv,
            cqh, w2h, q2h,
            N2, QPROJ, QPROJ, QPROJ, N2, gx_q2,
            blocks_ukv);
    }

    // 5. RoPE
    rope_qk<<<(2*BS*2*64 + 255)/256, 256>>>(q2h, p1, kvh);

    // 6. flash attention
    flash_attn<<<dim3(S_/128, NZ), 256, SMEM_FLASH>>>(q2h, kvh, aoh);

    // 7. final projection
    hmma_gemm1<<<dim3(DMODEL/128, BS/128), 256, SMEM_GEMM1>>>(
        aoh, woh, out, DMODEL, DMODEL, DMODEL, DMODEL, DMODEL);
}

// round 13
// speedup vs baseline: 13.8757x; 1.2772x over previous
#include <cuda_runtime.h>
#include <cuda_fp16.h>
#include <cstdint>
#include <math.h>

// ---------------- problem constants ----------------
#define B_      2
#define S_      2048
#define DMODEL  2048
#define NH      16
#define DH      128
#define NOPE    14
#define QPROJ   1024
#define KVPROJ  1365
#define KVPAD   1408
#define KNOPE   1792
#define KVCOLS  3840
#define KVLD    4096
#define BS      (B_*S_)
#define NZ      (B_*NH)
#define N1      2688
#define N2      2048

typedef __half h16;

// ---------------- device scratch ----------------
__device__ h16 g_xhi[(size_t)BS*DMODEL];
__device__ h16 g_w1h[(size_t)N1*DMODEL];
__device__ h16 g_w2h[(size_t)N2*QPROJ];
__device__ h16 g_wukvh[(size_t)KVCOLS*KVPAD];
__device__ h16 g_woh[(size_t)DMODEL*DMODEL];
__device__ float g_p1[(size_t)BS*N1];
__device__ h16 g_cqh[(size_t)BS*QPROJ];
__device__ h16 g_ckvh[(size_t)BS*KVPAD];
__device__ h16 g_q2h[(size_t)BS*N2];
__device__ h16 g_kvh[(size_t)BS*KVLD];
__device__ h16 g_aoh[(size_t)BS*DMODEL];

// ---------------- helpers ----------------
__device__ __forceinline__ uint32_t smem_u32(const void* p) {
    uint32_t a;
    asm("{ .reg .u64 t; cvta.to.shared.u64 t, %1; cvt.u32.u64 %0, t; }" : "=r"(a) : "l"(p));
    return a;
}
__device__ __forceinline__ void cp16(uint32_t saddr, const void* g) {
    asm volatile("cp.async.cg.shared.global [%0], [%1], 16;" :: "r"(saddr), "l"(g) : "memory");
}
__device__ __forceinline__ void cp_commit() {
    asm volatile("cp.async.commit_group;" ::: "memory");
}
template<int N> __device__ __forceinline__ void cp_wait() {
    asm volatile("cp.async.wait_group %0;" :: "n"(N) : "memory");
}
__device__ __forceinline__ void ldm_x4(uint32_t addr, uint32_t* r) {
    asm volatile("ldmatrix.sync.aligned.m8n8.x4.shared.b16 {%0,%1,%2,%3}, [%4];"
        : "=r"(r[0]), "=r"(r[1]), "=r"(r[2]), "=r"(r[3]) : "r"(addr));
}
__device__ __forceinline__ void ldm_x4_t(uint32_t addr, uint32_t* r) {
    asm volatile("ldmatrix.sync.aligned.m8n8.x4.trans.shared.b16 {%0,%1,%2,%3}, [%4];"
        : "=r"(r[0]), "=r"(r[1]), "=r"(r[2]), "=r"(r[3]) : "r"(addr));
}
__device__ __forceinline__ void mma16816(float* d, const uint32_t* a, const uint32_t* b) {
    asm volatile("mma.sync.aligned.m16n8k16.row.col.f32.f16.f16.f32 "
        "{%0,%1,%2,%3}, {%4,%5,%6,%7}, {%8,%9}, {%0,%1,%2,%3};"
        : "+f"(d[0]), "+f"(d[1]), "+f"(d[2]), "+f"(d[3])
        : "r"(a[0]), "r"(a[1]), "r"(a[2]), "r"(a[3]), "r"(b[0]), "r"(b[1]));
}
__device__ __forceinline__ uint32_t pack_h2(float a, float b) {
    __half2 t = __floats2half2_rn(a, b);
    return *(uint32_t*)&t;
}

// ---------------- prep device functions ----------------
__device__ __forceinline__ void split_chunk(const float4* __restrict__ in,
                                            __half2* __restrict__ hi,
                                            size_t base4, size_t n4)
{
#pragma unroll
    for (int q = 0; q < 16; q++) {
        size_t i = base4 + (size_t)q * 256 + threadIdx.x;
        if (i >= n4) return;
        float4 v = in[i];
        hi[i * 2]     = __floats2half2_rn(v.x, v.y);
        hi[i * 2 + 1] = __floats2half2_rn(v.z, v.w);
    }
}

__device__ __forceinline__ void tr_strip(const float* __restrict__ in,
                                         h16* __restrict__ hi,
                                         int K, int N, int Npad, int Kpad, int rowOff,
                                         int strip, int nStrips)
{
    __shared__ float t[32][33];
    int kTile = strip / nStrips;
    int nT0 = (strip % nStrips) * 8;
    int k0 = kTile * 32;
    int tx = threadIdx.x & 31, ty = threadIdx.x >> 5;
    for (int sub = 0; sub < 8; sub++) {
        int n0 = (nT0 + sub) * 32;
        if (n0 >= Npad) break;
        __syncthreads();
#pragma unroll
        for (int i = 0; i < 4; i++) {
            int k = k0 + ty + i * 8;
            float v = (k < K && n0 + tx < N) ? in[(size_t)k * N + n0 + tx] : 0.f;
            t[ty + i * 8][tx] = v;
        }
        __syncthreads();
#pragma unroll
        for (int i = 0; i < 4; i++) {
            int n = n0 + ty + i * 8, k = k0 + tx;
            if (n < Npad && k < Kpad)
                hi[(size_t)(n + rowOff) * Kpad + k] = __float2half_rn(t[tx][ty + i * 8]);
        }
    }
}

// ---------------- GEMM core: C = Ah @ Bh^T, fp16 single-product, BK=64, 3-stage ---
#define STAGE 32768
#define SMEM_GEMM (3*STAGE)

__device__ __forceinline__ void gemm_core(
    const h16* __restrict__ Ahi, const h16* __restrict__ Bhi,
    float* __restrict__ Cf, h16* __restrict__ Ch,
    int N, int Kpad, int lda, int ldb, int ldc,
    int r0, int c0, char* smem)
{
    int tid = threadIdx.x, lane = tid & 31, wid = tid >> 5;
    int tiles = Kpad >> 6;

    const h16* Ah = Ahi + (size_t)r0 * lda;
    const h16* Bh = Bhi + (size_t)c0 * ldb;

    uint32_t sbase = smem_u32(smem);
    int wm = (wid >> 2) * 64, wn = (wid & 3) * 32;

    float acc[4][4][4];
#pragma unroll
    for (int i = 0; i < 4; i++)
#pragma unroll
        for (int j = 0; j < 4; j++)
#pragma unroll
            for (int v = 0; v < 4; v++) acc[i][j][v] = 0.f;

    // stage: A 0..16K, B 16K..32K; 128 rows x 128B, 8 chunks, xor-swizzle
    auto load_stage = [&](int t) {
        int k0 = t << 6;
        uint32_t sb = sbase + (uint32_t)(t % 3) * STAGE;
#pragma unroll
        for (int q = 0; q < 4; q++) {
            int idx = tid + q * 256;
            int row = idx >> 3, ch = idx & 7;
            uint32_t off = (uint32_t)row * 128 + (uint32_t)((ch ^ (row & 7)) << 4);
            cp16(sb + off,         Ah + (size_t)row * lda + k0 + ch * 8);
            cp16(sb + 16384 + off, Bh + (size_t)row * ldb + k0 + ch * 8);
        }
        cp_commit();
    };

    auto compute_stage = [&](int t) {
        uint32_t sb = sbase + (uint32_t)(t % 3) * STAGE;
#pragma unroll
        for (int kk = 0; kk < 64; kk += 16) {
            uint32_t bh[4][2];
#pragma unroll
            for (int p = 0; p < 2; p++) {
                int rowB = wn + p * 16 + ((lane >> 4) << 3) + (lane & 7);
                int ch = (kk >> 3) + ((lane >> 3) & 1);
                uint32_t off = (uint32_t)rowB * 128 + (uint32_t)((ch ^ (rowB & 7)) << 4);
                uint32_t r[4];
                ldm_x4(sb + 16384 + off, r);
                bh[2 * p][0] = r[0]; bh[2 * p][1] = r[1];
                bh[2 * p + 1][0] = r[2]; bh[2 * p + 1][1] = r[3];
            }
#pragma unroll
            for (int mt = 0; mt < 4; mt++) {
                int rowA = wm + mt * 16 + (lane & 15);
                int ch = (kk >> 3) + (lane >> 4);
                uint32_t off = (uint32_t)rowA * 128 + (uint32_t)((ch ^ (rowA & 7)) << 4);
                uint32_t ah[4];
                ldm_x4(sb + off, ah);
#pragma unroll
                for (int nt = 0; nt < 4; nt++)
                    mma16816(acc[mt][nt], ah, bh[nt]);
            }
        }
    };

    load_stage(0);
    if (tiles > 1) load_stage(1);
    for (int t = 0; t < tiles; t++) {
        if (t + 1 < tiles) cp_wait<1>(); else cp_wait<0>();
        __syncthreads();
        if (t + 2 < tiles) load_stage(t + 2);
        compute_stage(t);
    }

    if (Cf) {
#pragma unroll
        for (int mt = 0; mt < 4; mt++) {
#pragma unroll
            for (int nt = 0; nt < 4; nt++) {
                int r = r0 + wm + mt * 16 + (lane >> 2);
                int c = c0 + wn + nt * 8 + ((lane & 3) << 1);
                float* p0 = Cf + (size_t)r * ldc + c;
                float* p1 = p0 + 8 * ldc;
                p0[0] = acc[mt][nt][0]; p0[1] = acc[mt][nt][1];
                p1[0] = acc[mt][nt][2]; p1[1] = acc[mt][nt][3];
            }
        }
    } else {
#pragma unroll
        for (int mt = 0; mt < 4; mt++) {
#pragma unroll
            for (int nt = 0; nt < 4; nt++) {
                int r = r0 + wm + mt * 16 + (lane >> 2);
                int c = c0 + wn + nt * 8 + ((lane & 3) << 1);
                size_t o0 = (size_t)r * ldc + c;
                size_t o1 = o0 + (size_t)8 * ldc;
                *(uint32_t*)(Ch + o0) = pack_h2(acc[mt][nt][0], acc[mt][nt][1]);
                *(uint32_t*)(Ch + o1) = pack_h2(acc[mt][nt][2], acc[mt][nt][3]);
            }
        }
    }
}

// ---------------- prep1: x convert + W1 transposes ----------------
__global__ __launch_bounds__(256)
void prep1(const float* __restrict__ x,
           const float* __restrict__ W_dq, const float* __restrict__ W_dkv,
           const float* __restrict__ W_kr,
           h16* __restrict__ xhi, h16* __restrict__ w1h)
{
    int i = blockIdx.x;
    if (i < 512) {
        split_chunk((const float4*)x, (__half2*)xhi,
                    (size_t)i * 4096, (size_t)BS * DMODEL / 4);
    } else if (i < 768) {
        tr_strip(W_dq, w1h, DMODEL, QPROJ, QPROJ, DMODEL, 0, i - 512, 4);
    } else if (i < 1152) {
        tr_strip(W_dkv, w1h, DMODEL, KVPROJ, KVPAD, DMODEL, QPROJ, i - 768, 6);
    } else {
        tr_strip(W_kr, w1h, DMODEL, 256, 256, DMODEL, QPROJ + KVPAD, i - 1152, 1);
    }
}

// ---------------- p1 GEMM fused with prep2 ----------------
__global__ __launch_bounds__(256, 2)
void gemm_p1_prep2(const h16* __restrict__ xhi,
                   const h16* __restrict__ w1h,
                   float* __restrict__ p1,
                   const float* __restrict__ W_uq, const float* __restrict__ W_qr,
                   const float* __restrict__ W_ukv, const float* __restrict__ W_o,
                   h16* __restrict__ w2h, h16* __restrict__ wukvh, h16* __restrict__ woh)
{
    extern __shared__ __align__(128) char smem[];
    int i = blockIdx.x;
    bool isGemm;
    int sub;
    if (i < 1344) { isGemm = !(i & 1); sub = i >> 1; }
    else          { isGemm = false;    sub = 672 + (i - 1344); }

    if (isGemm) {
        int cx = sub % 21, cy = sub / 21;
        gemm_core(xhi, w1h, p1, nullptr,
                  N1, DMODEL, DMODEL, DMODEL, N1, cy * 128, cx * 128, smem);
    } else {
        if (sub < 224) {
            tr_strip(W_uq, w2h, QPROJ, KNOPE, KNOPE, QPROJ, 0, sub, 7);
        } else if (sub < 256) {
            tr_strip(W_qr, w2h, QPROJ, 256, 256, QPROJ, KNOPE, sub - 224, 1);
        } else if (sub < 916) {
            tr_strip(W_ukv, wukvh, KVPROJ, KVCOLS, KVCOLS, KVPAD, 0, sub - 256, 15);
        } else {
            split_chunk((const float4*)W_o, (__half2*)woh,
                        (size_t)(sub - 916) * 4096, (size_t)DMODEL * DMODEL / 4);
        }
    }
}

// single GEMM (Wo): fp32 out
__global__ __launch_bounds__(256, 2)
void hmma_gemm1(const h16* __restrict__ Ahi, const h16* __restrict__ Bhi,
                float* __restrict__ Cf, int N, int Kpad, int lda, int ldb, int ldc)
{
    extern __shared__ __align__(128) char smem[];
    gemm_core(Ahi, Bhi, Cf, nullptr, N, Kpad, lda, ldb, ldc,
              blockIdx.y * 128, blockIdx.x * 128, smem);
}

// dual GEMM: q2 + ukv in one launch
__global__ __launch_bounds__(256, 2)
void hmma_gemm_dual(
    const h16* A1h, const h16* B1h, h16* C1h,
    int n1, int k1, int la1, int lb1, int lc1, int gx1,
    const h16* A2h, const h16* B2h, h16* C2h,
    int n2, int k2, int la2, int lb2, int lc2, int gx2,
    int split)
{
    extern __shared__ __align__(128) char smem[];
    int idx = blockIdx.x;
    if (idx < split) {
        int cx = idx % gx1, cy = idx / gx1;
        gemm_core(A1h, B1h, nullptr, C1h, n1, k1, la1, lb1, lc1,
                  cy * 128, cx * 128, smem);
    } else {
        idx -= split;
        int cx = idx % gx2, cy = idx / gx2;
        gemm_core(A2h, B2h, nullptr, C2h, n2, k2, la2, lb2, lc2,
                  cy * 128, cx * 128, smem);
    }
}

// ---------------- fused flash attention (single-product) ----------------
#define FST 32768
#define FQB 32768
#define SMEM_FLASH (FQB + 3*FST)

__global__ __launch_bounds__(256, 1)
void flash_attn(const h16* __restrict__ q2h,
                const h16* __restrict__ kvh,
                h16* __restrict__ aoh)
{
    extern __shared__ __align__(128) char smem[];
    int tid = threadIdx.x, lane = tid & 31, wid = tid >> 5;
    int z = blockIdx.y, bb = z >> 4, hh = z & 15;
    int r0 = ((int)gridDim.x - 1 - (int)blockIdx.x) * 128;

    int kcol = (hh < NOPE) ? hh * DH : KVCOLS + (hh - NOPE) * DH;
    int vcol = KNOPE + hh * DH;

    const h16* qhz = q2h + ((size_t)(bb * S_ + r0)) * N2 + hh * DH;
    const h16* khz = kvh + (size_t)(bb * S_) * KVLD + kcol;
    const h16* vhz = kvh + (size_t)(bb * S_) * KVLD + vcol;

    uint32_t sb = smem_u32(smem);

#pragma unroll
    for (int q = 0; q < 8; q++) {
        int idx = tid + q * 256;
        int row = idx >> 4, ch = idx & 15;
        uint32_t off = (uint32_t)row * 256 + (uint32_t)((ch ^ (row & 7)) << 4);
        cp16(sb + off, qhz + (size_t)row * N2 + ch * 8);
    }
    cp_commit();

    int ntiles = (r0 >> 6) + 2;
    int diag = r0 >> 6;

    auto load_stage = [&](int jt) {
        uint32_t st = sb + FQB + (uint32_t)(jt % 3) * FST;
        int s0 = jt * 64;
#pragma unroll
        for (int q = 0; q < 4; q++) {
            int idx = tid + q * 256;
            int row = idx >> 4, ch = idx & 15;
            uint32_t off = (uint32_t)row * 256 + (uint32_t)((ch ^ (row & 7)) << 4);
            size_t g = (size_t)(s0 + row) * KVLD + ch * 8;
            cp16(st + off,         khz + g);
            cp16(st + 16384 + off, vhz + g);
        }
        cp_commit();
    };

    load_stage(0);
    load_stage(1);
    cp_wait<2>();
    __syncthreads();

    int wrow = wid * 16;
    uint32_t qah[8][4];
#pragma unroll
    for (int kf = 0; kf < 8; kf++) {
        int row = wrow + (lane & 15);
        int ch = kf * 2 + (lane >> 4);
        uint32_t off = (uint32_t)row * 256 + (uint32_t)((ch ^ (row & 7)) << 4);
        ldm_x4(sb + off, qah[kf]);
    }

    float of[16][4];
#pragma unroll
    for (int i = 0; i < 16; i++)
#pragma unroll
        for (int v = 0; v < 4; v++) of[i][v] = 0.f;
    float m0 = -1e30f, m1 = -1e30f, l0 = 0.f, l1 = 0.f;
    const float CEXP = 0.08838834764831845f * 1.4426950408889634f;

    int rowa = r0 + wrow + (lane >> 2);

    for (int jt = 0; jt < ntiles; jt++) {
        if (jt + 1 < ntiles) cp_wait<1>(); else cp_wait<0>();
        __syncthreads();
        if (jt + 2 < ntiles) load_stage(jt + 2);
        uint32_t st = sb + FQB + (uint32_t)(jt % 3) * FST;

        float sf[8][4];
#pragma unroll
        for (int nf = 0; nf < 8; nf++)
#pragma unroll
            for (int v = 0; v < 4; v++) sf[nf][v] = 0.f;

#pragma unroll
        for (int kf = 0; kf < 8; kf++) {
            uint32_t bh[8][2];
#pragma unroll
            for (int p = 0; p < 4; p++) {
                int rowB = p * 16 + ((lane >> 4) << 3) + (lane & 7);
                int ch = kf * 2 + ((lane >> 3) & 1);
                uint32_t off = (uint32_t)rowB * 256 + (uint32_t)((ch ^ (rowB & 7)) << 4);
                uint32_t r4[4];
                ldm_x4(st + off, r4);
                bh[2 * p][0] = r4[0]; bh[2 * p][1] = r4[1];
                bh[2 * p + 1][0] = r4[2]; bh[2 * p + 1][1] = r4[3];
            }
#pragma unroll
            for (int nf = 0; nf < 8; nf++)
                mma16816(sf[nf], qah[kf], bh[nf]);
        }

        if (jt >= diag) {
            int colb = jt * 64 + 2 * (lane & 3);
#pragma unroll
            for (int nf = 0; nf < 8; nf++) {
                int c = colb + nf * 8;
                if (c > rowa)     sf[nf][0] = -1e30f;
                if (c + 1 > rowa) sf[nf][1] = -1e30f;
                if (c > rowa + 8)     sf[nf][2] = -1e30f;
                if (c + 1 > rowa + 8) sf[nf][3] = -1e30f;
            }
        }

        float tm0 = -1e30f, tm1 = -1e30f;
#pragma unroll
        for (int nf = 0; nf < 8; nf++) {
            tm0 = fmaxf(tm0, fmaxf(sf[nf][0], sf[nf][1]));
            tm1 = fmaxf(tm1, fmaxf(sf[nf][2], sf[nf][3]));
        }
        tm0 = fmaxf(tm0, __shfl_xor_sync(0xffffffffu, tm0, 1));
        tm0 = fmaxf(tm0, __shfl_xor_sync(0xffffffffu, tm0, 2));
        tm1 = fmaxf(tm1, __shfl_xor_sync(0xffffffffu, tm1, 1));
        tm1 = fmaxf(tm1, __shfl_xor_sync(0xffffffffu, tm1, 2));
        float mn0 = fmaxf(m0, tm0), mn1 = fmaxf(m1, tm1);
        float al0 = exp2f((m0 - mn0) * CEXP), al1 = exp2f((m1 - mn1) * CEXP);
        m0 = mn0; m1 = mn1;

        uint32_t pah[4][4];
        float rs0 = 0.f, rs1 = 0.f;
#pragma unroll
        for (int nf = 0; nf < 8; nf++) {
            float e0 = exp2f((sf[nf][0] - m0) * CEXP);
            float e1 = exp2f((sf[nf][1] - m0) * CEXP);
            float e2 = exp2f((sf[nf][2] - m1) * CEXP);
            float e3 = exp2f((sf[nf][3] - m1) * CEXP);
            rs0 += e0 + e1; rs1 += e2 + e3;
            int kf2 = nf >> 1, s = (nf & 1) * 2;
            pah[kf2][s]     = pack_h2(e0, e1);
            pah[kf2][s + 1] = pack_h2(e2, e3);
        }
        l0 = l0 * al0 + rs0;
        l1 = l1 * al1 + rs1;

#pragma unroll
        for (int i = 0; i < 16; i++) {
            of[i][0] *= al0; of[i][1] *= al0;
            of[i][2] *= al1; of[i][3] *= al1;
        }

#pragma unroll
        for (int kf2 = 0; kf2 < 4; kf2++) {
#pragma unroll
            for (int nb = 0; nb < 8; nb++) {
                int row = kf2 * 16 + (lane & 15);
                int ch = nb * 2 + (lane >> 4);
                uint32_t off = (uint32_t)row * 256 + (uint32_t)((ch ^ (row & 7)) << 4);
                uint32_t rh[4];
                ldm_x4_t(st + 16384 + off, rh);
                uint32_t bh0[2] = {rh[0], rh[1]}, bh1[2] = {rh[2], rh[3]};
                mma16816(of[2 * nb],     pah[kf2], bh0);
                mma16816(of[2 * nb + 1], pah[kf2], bh1);
            }
        }
    }

    l0 += __shfl_xor_sync(0xffffffffu, l0, 1);
    l0 += __shfl_xor_sync(0xffffffffu, l0, 2);
    l1 += __shfl_xor_sync(0xffffffffu, l1, 1);
    l1 += __shfl_xor_sync(0xffffffffu, l1, 2);
    float inv0 = 1.f / l0, inv1 = 1.f / l1;

    size_t ga = ((size_t)(bb * S_) + rowa) * DMODEL + hh * DH;
    size_t gb = ga + (size_t)8 * DMODEL;
#pragma unroll
    for (int i = 0; i < 16; i++) {
        int d = i * 8 + 2 * (lane & 3);
        *(uint32_t*)(aoh + ga + d) = pack_h2(of[i][0] * inv0, of[i][1] * inv0);
        *(uint32_t*)(aoh + gb + d) = pack_h2(of[i][2] * inv1, of[i][3] * inv1);
    }
}

// ---------------- merged LayerNorm ----------------
__global__ __launch_bounds__(256)
void layernorm2(const float* __restrict__ p1,
                h16* __restrict__ cqh,
                float* __restrict__ ckv,
                h16* __restrict__ ckvh,
                const float* __restrict__ q_w, const float* __restrict__ q_b,
                const float* __restrict__ kv_w, const float* __restrict__ kv_b)
{
    bool isKV = blockIdx.y != 0;
    const float* p = p1 + (size_t)blockIdx.x * N1 + (isKV ? QPROJ : 0);
    int n = isKV ? KVPROJ : QPROJ;
    int npad = isKV ? KVPAD : QPROJ;
    const float* w = isKV ? kv_w : q_w;
    const float* b = isKV ? kv_b : q_b;
    h16* hh = (isKV ? ckvh : cqh) + (size_t)blockIdx.x * npad;
    float* of = isKV ? ckv + (size_t)blockIdx.x * KVPROJ : nullptr;

    float s = 0.f, s2 = 0.f;
    for (int j = threadIdx.x; j < n; j += 256) {
        float v = p[j];
        s += v; s2 += v * v;
    }
    __shared__ float sh[20];
#pragma unroll
    for (int o = 16; o; o >>= 1) {
        s  += __shfl_down_sync(0xffffffffu, s,  o);
        s2 += __shfl_down_sync(0xffffffffu, s2, o);
    }
    int wd = threadIdx.x >> 5, ln = threadIdx.x & 31;
    if (!ln) { sh[wd] = s; sh[wd + 8] = s2; }
    __syncthreads();
    if (threadIdx.x == 0) {
        float ts = 0.f, ts2 = 0.f;
        for (int i = 0; i < 8; i++) { ts += sh[i]; ts2 += sh[i + 8]; }
        float mean = ts / n;
        float var = fmaxf(ts2 / n - mean * mean, 0.f);
        sh[16] = mean;
        sh[17] = rsqrtf(var + 1e-5f);
    }
    __syncthreads();
    float mean = sh[16], rstd = sh[17];
    for (int j = threadIdx.x; j < npad; j += 256) {
        float v = 0.f;
        if (j < n) {
            v = (p[j] - mean) * rstd * w[j] + b[j];
            if (of) of[j] = v;
        }
        hh[j] = __float2half_rn(v);
    }
}

// merged RoPE
__global__ __launch_bounds__(256)
void rope_qk(h16* __restrict__ q2h,
             const float* __restrict__ p1,
             h16* __restrict__ kvh)
{
    int total = BS * 2 * 64;
    int idx = blockIdx.x * 256 + threadIdx.x;
    if (idx >= 2 * total) return;
    bool isK = idx >= total;
    if (isK) idx -= total;
    int dp = idx & 63;
    int h2 = (idx >> 6) & 1;
    int row = idx >> 7;
    int s = row & (S_ - 1);
    float freq = exp2f(-(float)dp * 0.20762050593046015f);
    float sn, cs;
    sincosf((float)s * freq, &sn, &cs);

    if (!isK) {
        size_t base = (size_t)row * N2 + KNOPE + h2 * DH;
        float x1 = __half2float(q2h[base + dp]);
        float x2 = __half2float(q2h[base + dp + 64]);
        q2h[base + dp]      = __float2half_rn(x1 * cs - x2 * sn);
        q2h[base + dp + 64] = __float2half_rn(x2 * cs + x1 * sn);
    } else {
        const float* src = p1 + (size_t)row * N1 + 2432 + h2 * DH;
        float x1 = src[dp], x2 = src[dp + 64];
        size_t base = (size_t)row * KVLD + KVCOLS + h2 * DH;
        kvh[base + dp]      = __float2half_rn(x1 * cs - x2 * sn);
        kvh[base + dp + 64] = __float2half_rn(x2 * cs + x1 * sn);
    }
}

// ---------------- launch ----------------
static inline void* sym(const void* s) { void* p; cudaGetSymbolAddress(&p, s); return p; }

extern "C" void kernel_launch(void* const* d_in, const int* in_sizes, int n_in,
                              void* d_out, int out_size)
{
    const float* x     = (const float*)d_in[0];
    const float* W_dq  = (const float*)d_in[1];
    const float* W_uq  = (const float*)d_in[2];
    const float* W_qr  = (const float*)d_in[3];
    const float* W_dkv = (const float*)d_in[4];
    const float* W_ukv = (const float*)d_in[5];
    const float* W_kr  = (const float*)d_in[6];
    const float* W_o   = (const float*)d_in[7];
    const float* q_w   = (const float*)d_in[8];
    const float* q_b   = (const float*)d_in[9];
    const float* kv_w  = (const float*)d_in[10];
    const float* kv_b  = (const float*)d_in[11];

    float* out = (float*)d_out;
    float* ckv = out + (size_t)BS * DMODEL;

    h16 *xhi=(h16*)sym(g_xhi);
    h16 *w1h=(h16*)sym(g_w1h);
    h16 *w2h=(h16*)sym(g_w2h);
    h16 *wukvh=(h16*)sym(g_wukvh);
    h16 *woh=(h16*)sym(g_woh);
    float *p1=(float*)sym(g_p1);
    h16 *cqh=(h16*)sym(g_cqh);
    h16 *ckvh=(h16*)sym(g_ckvh);
    h16 *q2h=(h16*)sym(g_q2h);
    h16 *kvh=(h16*)sym(g_kvh);
    h16 *aoh=(h16*)sym(g_aoh);

    cudaFuncSetAttribute(hmma_gemm1, cudaFuncAttributeMaxDynamicSharedMemorySize, SMEM_GEMM);
    cudaFuncSetAttribute(hmma_gemm_dual, cudaFuncAttributeMaxDynamicSharedMemorySize, SMEM_GEMM);
    cudaFuncSetAttribute(gemm_p1_prep2, cudaFuncAttributeMaxDynamicSharedMemorySize, SMEM_GEMM);
    cudaFuncSetAttribute(flash_attn, cudaFuncAttributeMaxDynamicSharedMemorySize, SMEM_FLASH);

    // 1. x convert + W1 transposes
    prep1<<<1216, 256>>>(x, W_dq, W_dkv, W_kr, xhi, w1h);

    // 2. p1 = x @ W1 (fp32) fused with prep2
    gemm_p1_prep2<<<1844, 256, SMEM_GEMM>>>(
        xhi, w1h, p1,
        W_uq, W_qr, W_ukv, W_o,
        w2h, wukvh, woh);

    // 3. LayerNorms (merged)
    layernorm2<<<dim3(BS, 2), 256>>>(p1, cqh, ckv, ckvh, q_w, q_b, kv_w, kv_b);

    // 4. q2 = cq @ W2 AND kv = ckv @ W_ukv in one launch
    {
        int gx_ukv = KVCOLS / 128;              // 30
        int gx_q2  = N2 / 128;                  // 16
        int blocks_ukv = gx_ukv * (BS / 128);   // 960
        int blocks_q2  = gx_q2  * (BS / 128);   // 512
        hmma_gemm_dual<<<blocks_ukv + blocks_q2, 256, SMEM_GEMM>>>(
            ckvh, wukvh, kvh,
            KVCOLS, KVPAD, KVPAD, KVPAD, KVLD, gx_ukv,
            cqh, w2h, q2h,
            N2, QPROJ, QPROJ, QPROJ, N2, gx_q2,
            blocks_ukv);
    }

    // 5. RoPE
    rope_qk<<<(2*BS*2*64 + 255)/256, 256>>>(q2h, p1, kvh);

    // 6. flash attention
    flash_attn<<<dim3(S_/128, NZ), 256, SMEM_FLASH>>>(q2h, kvh, aoh);

    // 7. final projection
    hmma_gemm1<<<dim3(DMODEL/128, BS/128), 256, SMEM_GEMM>>>(
        aoh, woh, out, DMODEL, DMODEL, DMODEL, DMODEL, DMODEL);
}

// round 14
// speedup vs baseline: 14.1283x; 1.0182x over previous
#include <cuda_runtime.h>
#include <cuda_fp16.h>
#include <cstdint>
#include <math.h>

// ---------------- problem constants ----------------
#define B_      2
#define S_      2048
#define DMODEL  2048
#define NH      16
#define DH      128
#define NOPE    14
#define QPROJ   1024
#define KVPROJ  1365
#define KVPAD   1408
#define KNOPE   1792
#define KVCOLS  3840
#define KVLD    4096
#define BS      (B_*S_)
#define NZ      (B_*NH)
#define N1      2688
#define N2      2048

typedef __half h16;

// ---------------- device scratch ----------------
__device__ h16 g_xhi[(size_t)BS*DMODEL];
__device__ h16 g_w1h[(size_t)N1*DMODEL];
__device__ h16 g_w2h[(size_t)N2*QPROJ];
__device__ h16 g_wukvh[(size_t)KVCOLS*KVPAD];
__device__ h16 g_woh[(size_t)DMODEL*DMODEL];
__device__ float g_p1[(size_t)BS*N1];
__device__ h16 g_cqh[(size_t)BS*QPROJ];
__device__ h16 g_ckvh[(size_t)BS*KVPAD];
__device__ h16 g_q2h[(size_t)BS*N2];
__device__ h16 g_kvh[(size_t)BS*KVLD];
__device__ h16 g_aoh[(size_t)BS*DMODEL];

// ---------------- helpers ----------------
__device__ __forceinline__ uint32_t smem_u32(const void* p) {
    uint32_t a;
    asm("{ .reg .u64 t; cvta.to.shared.u64 t, %1; cvt.u32.u64 %0, t; }" : "=r"(a) : "l"(p));
    return a;
}
__device__ __forceinline__ void cp16(uint32_t saddr, const void* g) {
    asm volatile("cp.async.cg.shared.global [%0], [%1], 16;" :: "r"(saddr), "l"(g) : "memory");
}
__device__ __forceinline__ void cp_commit() {
    asm volatile("cp.async.commit_group;" ::: "memory");
}
template<int N> __device__ __forceinline__ void cp_wait() {
    asm volatile("cp.async.wait_group %0;" :: "n"(N) : "memory");
}
__device__ __forceinline__ void ldm_x4(uint32_t addr, uint32_t* r) {
    asm volatile("ldmatrix.sync.aligned.m8n8.x4.shared.b16 {%0,%1,%2,%3}, [%4];"
        : "=r"(r[0]), "=r"(r[1]), "=r"(r[2]), "=r"(r[3]) : "r"(addr));
}
__device__ __forceinline__ void ldm_x4_t(uint32_t addr, uint32_t* r) {
    asm volatile("ldmatrix.sync.aligned.m8n8.x4.trans.shared.b16 {%0,%1,%2,%3}, [%4];"
        : "=r"(r[0]), "=r"(r[1]), "=r"(r[2]), "=r"(r[3]) : "r"(addr));
}
__device__ __forceinline__ void mma16816(float* d, const uint32_t* a, const uint32_t* b) {
    asm volatile("mma.sync.aligned.m16n8k16.row.col.f32.f16.f16.f32 "
        "{%0,%1,%2,%3}, {%4,%5,%6,%7}, {%8,%9}, {%0,%1,%2,%3};"
        : "+f"(d[0]), "+f"(d[1]), "+f"(d[2]), "+f"(d[3])
        : "r"(a[0]), "r"(a[1]), "r"(a[2]), "r"(a[3]), "r"(b[0]), "r"(b[1]));
}
__device__ __forceinline__ uint32_t pack_h2(float a, float b) {
    __half2 t = __floats2half2_rn(a, b);
    return *(uint32_t*)&t;
}

// ---------------- prep device functions ----------------
__device__ __forceinline__ void split_chunk(const float4* __restrict__ in,
                                            __half2* __restrict__ hi,
                                            size_t base4, size_t n4)
{
#pragma unroll
    for (int q = 0; q < 16; q++) {
        size_t i = base4 + (size_t)q * 256 + threadIdx.x;
        if (i >= n4) return;
        float4 v = in[i];
        hi[i * 2]     = __floats2half2_rn(v.x, v.y);
        hi[i * 2 + 1] = __floats2half2_rn(v.z, v.w);
    }
}

__device__ __forceinline__ void tr_strip(const float* __restrict__ in,
                                         h16* __restrict__ hi,
                                         int K, int N, int Npad, int Kpad, int rowOff,
                                         int strip, int nStrips)
{
    __shared__ float t[32][33];
    int kTile = strip / nStrips;
    int nT0 = (strip % nStrips) * 8;
    int k0 = kTile * 32;
    int tx = threadIdx.x & 31, ty = threadIdx.x >> 5;
    for (int sub = 0; sub < 8; sub++) {
        int n0 = (nT0 + sub) * 32;
        if (n0 >= Npad) break;
        __syncthreads();
#pragma unroll
        for (int i = 0; i < 4; i++) {
            int k = k0 + ty + i * 8;
            float v = (k < K && n0 + tx < N) ? in[(size_t)k * N + n0 + tx] : 0.f;
            t[ty + i * 8][tx] = v;
        }
        __syncthreads();
#pragma unroll
        for (int i = 0; i < 4; i++) {
            int n = n0 + ty + i * 8, k = k0 + tx;
            if (n < Npad && k < Kpad)
                hi[(size_t)(n + rowOff) * Kpad + k] = __float2half_rn(t[tx][ty + i * 8]);
        }
    }
}

// rope-K chunk: 2048 elements per block (reads p1, writes kvh cols 3840+)
__device__ __forceinline__ void ropek_chunk(const float* __restrict__ p1,
                                            h16* __restrict__ kvh, int blk)
{
#pragma unroll
    for (int k = 0; k < 8; k++) {
        int e = blk * 2048 + k * 256 + threadIdx.x;
        int dp = e & 63;
        int h2 = (e >> 6) & 1;
        int row = e >> 7;
        int s = row & (S_ - 1);
        float freq = exp2f(-(float)dp * 0.20762050593046015f);
        float sn, cs;
        sincosf((float)s * freq, &sn, &cs);
        const float* src = p1 + (size_t)row * N1 + 2432 + h2 * DH;
        float x1 = src[dp], x2 = src[dp + 64];
        size_t base = (size_t)row * KVLD + KVCOLS + h2 * DH;
        kvh[base + dp]      = __float2half_rn(x1 * cs - x2 * sn);
        kvh[base + dp + 64] = __float2half_rn(x2 * cs + x1 * sn);
    }
}

// ---------------- GEMM core: C = Ah @ Bh^T, fp16 single-product, BK=64, 3-stage ---
#define STAGE 32768
#define SMEM_GEMM (3*STAGE)

__device__ __forceinline__ void gemm_core(
    const h16* __restrict__ Ahi, const h16* __restrict__ Bhi,
    float* __restrict__ Cf, h16* __restrict__ Ch,
    int N, int Kpad, int lda, int ldb, int ldc,
    int r0, int c0, char* smem)
{
    int tid = threadIdx.x, lane = tid & 31, wid = tid >> 5;
    int tiles = Kpad >> 6;

    const h16* Ah = Ahi + (size_t)r0 * lda;
    const h16* Bh = Bhi + (size_t)c0 * ldb;

    uint32_t sbase = smem_u32(smem);
    int wm = (wid >> 2) * 64, wn = (wid & 3) * 32;

    float acc[4][4][4];
#pragma unroll
    for (int i = 0; i < 4; i++)
#pragma unroll
        for (int j = 0; j < 4; j++)
#pragma unroll
            for (int v = 0; v < 4; v++) acc[i][j][v] = 0.f;

    auto load_stage = [&](int t) {
        int k0 = t << 6;
        uint32_t sb = sbase + (uint32_t)(t % 3) * STAGE;
#pragma unroll
        for (int q = 0; q < 4; q++) {
            int idx = tid + q * 256;
            int row = idx >> 3, ch = idx & 7;
            uint32_t off = (uint32_t)row * 128 + (uint32_t)((ch ^ (row & 7)) << 4);
            cp16(sb + off,         Ah + (size_t)row * lda + k0 + ch * 8);
            cp16(sb + 16384 + off, Bh + (size_t)row * ldb + k0 + ch * 8);
        }
        cp_commit();
    };

    auto compute_stage = [&](int t) {
        uint32_t sb = sbase + (uint32_t)(t % 3) * STAGE;
#pragma unroll
        for (int kk = 0; kk < 64; kk += 16) {
            uint32_t bh[4][2];
#pragma unroll
            for (int p = 0; p < 2; p++) {
                int rowB = wn + p * 16 + ((lane >> 4) << 3) + (lane & 7);
                int ch = (kk >> 3) + ((lane >> 3) & 1);
                uint32_t off = (uint32_t)rowB * 128 + (uint32_t)((ch ^ (rowB & 7)) << 4);
                uint32_t r[4];
                ldm_x4(sb + 16384 + off, r);
                bh[2 * p][0] = r[0]; bh[2 * p][1] = r[1];
                bh[2 * p + 1][0] = r[2]; bh[2 * p + 1][1] = r[3];
            }
#pragma unroll
            for (int mt = 0; mt < 4; mt++) {
                int rowA = wm + mt * 16 + (lane & 15);
                int ch = (kk >> 3) + (lane >> 4);
                uint32_t off = (uint32_t)rowA * 128 + (uint32_t)((ch ^ (rowA & 7)) << 4);
                uint32_t ah[4];
                ldm_x4(sb + off, ah);
#pragma unroll
                for (int nt = 0; nt < 4; nt++)
                    mma16816(acc[mt][nt], ah, bh[nt]);
            }
        }
    };

    load_stage(0);
    if (tiles > 1) load_stage(1);
    for (int t = 0; t < tiles; t++) {
        if (t + 1 < tiles) cp_wait<1>(); else cp_wait<0>();
        __syncthreads();
        if (t + 2 < tiles) load_stage(t + 2);
        compute_stage(t);
    }

    if (Cf) {
#pragma unroll
        for (int mt = 0; mt < 4; mt++) {
#pragma unroll
            for (int nt = 0; nt < 4; nt++) {
                int r = r0 + wm + mt * 16 + (lane >> 2);
                int c = c0 + wn + nt * 8 + ((lane & 3) << 1);
                float* p0 = Cf + (size_t)r * ldc + c;
                float* p1 = p0 + 8 * ldc;
                p0[0] = acc[mt][nt][0]; p0[1] = acc[mt][nt][1];
                p1[0] = acc[mt][nt][2]; p1[1] = acc[mt][nt][3];
            }
        }
    } else {
#pragma unroll
        for (int mt = 0; mt < 4; mt++) {
#pragma unroll
            for (int nt = 0; nt < 4; nt++) {
                int r = r0 + wm + mt * 16 + (lane >> 2);
                int c = c0 + wn + nt * 8 + ((lane & 3) << 1);
                size_t o0 = (size_t)r * ldc + c;
                size_t o1 = o0 + (size_t)8 * ldc;
                *(uint32_t*)(Ch + o0) = pack_h2(acc[mt][nt][0], acc[mt][nt][1]);
                *(uint32_t*)(Ch + o1) = pack_h2(acc[mt][nt][2], acc[mt][nt][3]);
            }
        }
    }
}

// ---------------- prep1: x convert + W1 transposes ----------------
__global__ __launch_bounds__(256)
void prep1(const float* __restrict__ x,
           const float* __restrict__ W_dq, const float* __restrict__ W_dkv,
           const float* __restrict__ W_kr,
           h16* __restrict__ xhi, h16* __restrict__ w1h)
{
    int i = blockIdx.x;
    if (i < 512) {
        split_chunk((const float4*)x, (__half2*)xhi,
                    (size_t)i * 4096, (size_t)BS * DMODEL / 4);
    } else if (i < 768) {
        tr_strip(W_dq, w1h, DMODEL, QPROJ, QPROJ, DMODEL, 0, i - 512, 4);
    } else if (i < 1152) {
        tr_strip(W_dkv, w1h, DMODEL, KVPROJ, KVPAD, DMODEL, QPROJ, i - 768, 6);
    } else {
        tr_strip(W_kr, w1h, DMODEL, 256, 256, DMODEL, QPROJ + KVPAD, i - 1152, 1);
    }
}

// ---------------- p1 GEMM fused with prep2 ----------------
__global__ __launch_bounds__(256, 2)
void gemm_p1_prep2(const h16* __restrict__ xhi,
                   const h16* __restrict__ w1h,
                   float* __restrict__ p1,
                   const float* __restrict__ W_uq, const float* __restrict__ W_qr,
                   const float* __restrict__ W_ukv, const float* __restrict__ W_o,
                   h16* __restrict__ w2h, h16* __restrict__ wukvh, h16* __restrict__ woh)
{
    extern __shared__ __align__(128) char smem[];
    int i = blockIdx.x;
    bool isGemm;
    int sub;
    if (i < 1344) { isGemm = !(i & 1); sub = i >> 1; }
    else          { isGemm = false;    sub = 672 + (i - 1344); }

    if (isGemm) {
        int cx = sub % 21, cy = sub / 21;
        gemm_core(xhi, w1h, p1, nullptr,
                  N1, DMODEL, DMODEL, DMODEL, N1, cy * 128, cx * 128, smem);
    } else {
        if (sub < 224) {
            tr_strip(W_uq, w2h, QPROJ, KNOPE, KNOPE, QPROJ, 0, sub, 7);
        } else if (sub < 256) {
            tr_strip(W_qr, w2h, QPROJ, 256, 256, QPROJ, KNOPE, sub - 224, 1);
        } else if (sub < 916) {
            tr_strip(W_ukv, wukvh, KVPROJ, KVCOLS, KVCOLS, KVPAD, 0, sub - 256, 15);
        } else {
            split_chunk((const float4*)W_o, (__half2*)woh,
                        (size_t)(sub - 916) * 4096, (size_t)DMODEL * DMODEL / 4);
        }
    }
}

// single GEMM (Wo): fp32 out
__global__ __launch_bounds__(256, 2)
void hmma_gemm1(const h16* __restrict__ Ahi, const h16* __restrict__ Bhi,
                float* __restrict__ Cf, int N, int Kpad, int lda, int ldb, int ldc)
{
    extern __shared__ __align__(128) char smem[];
    gemm_core(Ahi, Bhi, Cf, nullptr, N, Kpad, lda, ldb, ldc,
              blockIdx.y * 128, blockIdx.x * 128, smem);
}

// dual GEMM (q2 + ukv) with rope-K blocks folded in
__global__ __launch_bounds__(256, 2)
void hmma_gemm_dual(
    const h16* A1h, const h16* B1h, h16* C1h,
    int n1, int k1, int la1, int lb1, int lc1, int gx1,
    const h16* A2h, const h16* B2h, h16* C2h,
    int n2, int k2, int la2, int lb2, int lc2, int gx2,
    int split, int total_gemm,
    const float* __restrict__ p1, h16* __restrict__ kvh)
{
    extern __shared__ __align__(128) char smem[];
    int idx = blockIdx.x;
    if (idx >= total_gemm) {
        ropek_chunk(p1, kvh, idx - total_gemm);
        return;
    }
    if (idx < split) {
        int cx = idx % gx1, cy = idx / gx1;
        gemm_core(A1h, B1h, nullptr, C1h, n1, k1, la1, lb1, lc1,
                  cy * 128, cx * 128, smem);
    } else {
        idx -= split;
        int cx = idx % gx2, cy = idx / gx2;
        gemm_core(A2h, B2h, nullptr, C2h, n2, k2, la2, lb2, lc2,
                  cy * 128, cx * 128, smem);
    }
}

// ---------------- fused flash attention (128-key stages, rope-Q fused) ----------
#define FST 65536                       // stage: Kh 32K (128 rows), Vh 32K
#define FQB 32768                       // Q
#define SMEM_FLASH (FQB + 3*FST)        // 224 KB

__global__ __launch_bounds__(256, 1)
void flash_attn(const h16* __restrict__ q2h,
                const h16* __restrict__ kvh,
                h16* __restrict__ aoh)
{
    extern __shared__ __align__(128) char smem[];
    int tid = threadIdx.x, lane = tid & 31, wid = tid >> 5;
    int z = blockIdx.y, bb = z >> 4, hh = z & 15;
    int r0 = ((int)gridDim.x - 1 - (int)blockIdx.x) * 128;

    int kcol = (hh < NOPE) ? hh * DH : KVCOLS + (hh - NOPE) * DH;
    int vcol = KNOPE + hh * DH;

    const h16* qhz = q2h + ((size_t)(bb * S_ + r0)) * N2 + hh * DH;
    const h16* khz = kvh + (size_t)(bb * S_) * KVLD + kcol;
    const h16* vhz = kvh + (size_t)(bb * S_) * KVLD + vcol;

    uint32_t sb = smem_u32(smem);

    // stage Q (128 x 128 fp16)
#pragma unroll
    for (int q = 0; q < 8; q++) {
        int idx = tid + q * 256;
        int row = idx >> 4, ch = idx & 15;
        uint32_t off = (uint32_t)row * 256 + (uint32_t)((ch ^ (row & 7)) << 4);
        cp16(sb + off, qhz + (size_t)row * N2 + ch * 8);
    }
    cp_commit();

    int ntiles = (r0 >> 7) + 1;          // 128-key stages
    int diag64 = r0 >> 6;                // 64-key granularity diagonal

    auto load_stage = [&](int jt) {
        uint32_t st = sb + FQB + (uint32_t)(jt % 3) * FST;
        int s0 = jt * 128;
#pragma unroll
        for (int q = 0; q < 8; q++) {
            int idx = tid + q * 256;
            int row = idx >> 4, ch = idx & 15;
            uint32_t off = (uint32_t)row * 256 + (uint32_t)((ch ^ (row & 7)) << 4);
            size_t g = (size_t)(s0 + row) * KVLD + ch * 8;
            cp16(st + off,         khz + g);
            cp16(st + 32768 + off, vhz + g);
        }
        cp_commit();
    };

    load_stage(0);
    if (ntiles > 1) { load_stage(1); cp_wait<2>(); }
    else            { cp_wait<1>(); }

    // rope-Q in smem for the 2 rope heads (Q tile is resident; d/d+64 same row)
    if (hh >= NOPE) {
#pragma unroll 4
        for (int k = 0; k < 32; k++) {
            int idx = tid + k * 256;
            int row = idx >> 6, dp = idx & 63;
            float freq = exp2f(-(float)dp * 0.20762050593046015f);
            float sn, cs;
            sincosf((float)(r0 + row) * freq, &sn, &cs);
            uint32_t bin = (uint32_t)(dp & 7) * 2;
            uint32_t ch1 = (uint32_t)(dp >> 3);
            uint32_t o1 = (uint32_t)row * 256 + (((ch1 ^ (row & 7)) << 4) | bin);
            uint32_t o2 = (uint32_t)row * 256 + ((((ch1 + 8) ^ (row & 7)) << 4) | bin);
            float x1 = __half2float(*(h16*)(smem + o1));
            float x2 = __half2float(*(h16*)(smem + o2));
            *(h16*)(smem + o1) = __float2half_rn(x1 * cs - x2 * sn);
            *(h16*)(smem + o2) = __float2half_rn(x2 * cs + x1 * sn);
        }
    }
    __syncthreads();

    int wrow = wid * 16;
    uint32_t qah[8][4];
#pragma unroll
    for (int kf = 0; kf < 8; kf++) {
        int row = wrow + (lane & 15);
        int ch = kf * 2 + (lane >> 4);
        uint32_t off = (uint32_t)row * 256 + (uint32_t)((ch ^ (row & 7)) << 4);
        ldm_x4(sb + off, qah[kf]);
    }

    float of[16][4];
#pragma unroll
    for (int i = 0; i < 16; i++)
#pragma unroll
        for (int v = 0; v < 4; v++) of[i][v] = 0.f;
    float m0 = -1e30f, m1 = -1e30f, l0 = 0.f, l1 = 0.f;
    const float CEXP = 0.08838834764831845f * 1.4426950408889634f;

    int rowa = r0 + wrow + (lane >> 2);

    for (int jt = 0; jt < ntiles; jt++) {
        if (jt + 1 < ntiles) cp_wait<1>(); else cp_wait<0>();
        __syncthreads();
        if (jt + 2 < ntiles) load_stage(jt + 2);
        uint32_t st = sb + FQB + (uint32_t)(jt % 3) * FST;

#pragma unroll
        for (int hf = 0; hf < 2; hf++) {          // two 64-key halves per stage
            int j64 = jt * 2 + hf;
            uint32_t kbase = st + (uint32_t)hf * 16384;
            uint32_t vbase = st + 32768 + (uint32_t)hf * 16384;

            // ---- S = Q @ K^T ----
            float sf[8][4];
#pragma unroll
            for (int nf = 0; nf < 8; nf++)
#pragma unroll
                for (int v = 0; v < 4; v++) sf[nf][v] = 0.f;

#pragma unroll
            for (int kf = 0; kf < 8; kf++) {
                uint32_t bh[8][2];
#pragma unroll
                for (int p = 0; p < 4; p++) {
                    int rowB = p * 16 + ((lane >> 4) << 3) + (lane & 7);
                    int ch = kf * 2 + ((lane >> 3) & 1);
                    uint32_t off = (uint32_t)rowB * 256 + (uint32_t)((ch ^ (rowB & 7)) << 4);
                    uint32_t r4[4];
                    ldm_x4(kbase + off, r4);
                    bh[2 * p][0] = r4[0]; bh[2 * p][1] = r4[1];
                    bh[2 * p + 1][0] = r4[2]; bh[2 * p + 1][1] = r4[3];
                }
#pragma unroll
                for (int nf = 0; nf < 8; nf++)
                    mma16816(sf[nf], qah[kf], bh[nf]);
            }

            // ---- causal mask ----
            if (j64 >= diag64) {
                int colb = j64 * 64 + 2 * (lane & 3);
#pragma unroll
                for (int nf = 0; nf < 8; nf++) {
                    int c = colb + nf * 8;
                    if (c > rowa)     sf[nf][0] = -1e30f;
                    if (c + 1 > rowa) sf[nf][1] = -1e30f;
                    if (c > rowa + 8)     sf[nf][2] = -1e30f;
                    if (c + 1 > rowa + 8) sf[nf][3] = -1e30f;
                }
            }

            // ---- online softmax ----
            float tm0 = -1e30f, tm1 = -1e30f;
#pragma unroll
            for (int nf = 0; nf < 8; nf++) {
                tm0 = fmaxf(tm0, fmaxf(sf[nf][0], sf[nf][1]));
                tm1 = fmaxf(tm1, fmaxf(sf[nf][2], sf[nf][3]));
            }
            tm0 = fmaxf(tm0, __shfl_xor_sync(0xffffffffu, tm0, 1));
            tm0 = fmaxf(tm0, __shfl_xor_sync(0xffffffffu, tm0, 2));
            tm1 = fmaxf(tm1, __shfl_xor_sync(0xffffffffu, tm1, 1));
            tm1 = fmaxf(tm1, __shfl_xor_sync(0xffffffffu, tm1, 2));
            float mn0 = fmaxf(m0, tm0), mn1 = fmaxf(m1, tm1);
            float al0 = exp2f((m0 - mn0) * CEXP), al1 = exp2f((m1 - mn1) * CEXP);
            m0 = mn0; m1 = mn1;

            uint32_t pah[4][4];
            float rs0 = 0.f, rs1 = 0.f;
#pragma unroll
            for (int nf = 0; nf < 8; nf++) {
                float e0 = exp2f((sf[nf][0] - m0) * CEXP);
                float e1 = exp2f((sf[nf][1] - m0) * CEXP);
                float e2 = exp2f((sf[nf][2] - m1) * CEXP);
                float e3 = exp2f((sf[nf][3] - m1) * CEXP);
                rs0 += e0 + e1; rs1 += e2 + e3;
                int kf2 = nf >> 1, s = (nf & 1) * 2;
                pah[kf2][s]     = pack_h2(e0, e1);
                pah[kf2][s + 1] = pack_h2(e2, e3);
            }
            l0 = l0 * al0 + rs0;
            l1 = l1 * al1 + rs1;

#pragma unroll
            for (int i = 0; i < 16; i++) {
                of[i][0] *= al0; of[i][1] *= al0;
                of[i][2] *= al1; of[i][3] *= al1;
            }

            // ---- O += P @ V ----
#pragma unroll
            for (int kf2 = 0; kf2 < 4; kf2++) {
#pragma unroll
                for (int nb = 0; nb < 8; nb++) {
                    int row = kf2 * 16 + (lane & 15);
                    int ch = nb * 2 + (lane >> 4);
                    uint32_t off = (uint32_t)row * 256 + (uint32_t)((ch ^ (row & 7)) << 4);
                    uint32_t rh[4];
                    ldm_x4_t(vbase + off, rh);
                    uint32_t bh0[2] = {rh[0], rh[1]}, bh1[2] = {rh[2], rh[3]};
                    mma16816(of[2 * nb],     pah[kf2], bh0);
                    mma16816(of[2 * nb + 1], pah[kf2], bh1);
                }
            }
        }
    }

    l0 += __shfl_xor_sync(0xffffffffu, l0, 1);
    l0 += __shfl_xor_sync(0xffffffffu, l0, 2);
    l1 += __shfl_xor_sync(0xffffffffu, l1, 1);
    l1 += __shfl_xor_sync(0xffffffffu, l1, 2);
    float inv0 = 1.f / l0, inv1 = 1.f / l1;

    size_t ga = ((size_t)(bb * S_) + rowa) * DMODEL + hh * DH;
    size_t gb = ga + (size_t)8 * DMODEL;
#pragma unroll
    for (int i = 0; i < 16; i++) {
        int d = i * 8 + 2 * (lane & 3);
        *(uint32_t*)(aoh + ga + d) = pack_h2(of[i][0] * inv0, of[i][1] * inv0);
        *(uint32_t*)(aoh + gb + d) = pack_h2(of[i][2] * inv1, of[i][3] * inv1);
    }
}

// ---------------- merged LayerNorm ----------------
__global__ __launch_bounds__(256)
void layernorm2(const float* __restrict__ p1,
                h16* __restrict__ cqh,
                float* __restrict__ ckv,
                h16* __restrict__ ckvh,
                const float* __restrict__ q_w, const float* __restrict__ q_b,
                const float* __restrict__ kv_w, const float* __restrict__ kv_b)
{
    bool isKV = blockIdx.y != 0;
    const float* p = p1 + (size_t)blockIdx.x * N1 + (isKV ? QPROJ : 0);
    int n = isKV ? KVPROJ : QPROJ;
    int npad = isKV ? KVPAD : QPROJ;
    const float* w = isKV ? kv_w : q_w;
    const float* b = isKV ? kv_b : q_b;
    h16* hh = (isKV ? ckvh : cqh) + (size_t)blockIdx.x * npad;
    float* of = isKV ? ckv + (size_t)blockIdx.x * KVPROJ : nullptr;

    float s = 0.f, s2 = 0.f;
    for (int j = threadIdx.x; j < n; j += 256) {
        float v = p[j];
        s += v; s2 += v * v;
    }
    __shared__ float sh[20];
#pragma unroll
    for (int o = 16; o; o >>= 1) {
        s  += __shfl_down_sync(0xffffffffu, s,  o);
        s2 += __shfl_down_sync(0xffffffffu, s2, o);
    }
    int wd = threadIdx.x >> 5, ln = threadIdx.x & 31;
    if (!ln) { sh[wd] = s; sh[wd + 8] = s2; }
    __syncthreads();
    if (threadIdx.x == 0) {
        float ts = 0.f, ts2 = 0.f;
        for (int i = 0; i < 8; i++) { ts += sh[i]; ts2 += sh[i + 8]; }
        float mean = ts / n;
        float var = fmaxf(ts2 / n - mean * mean, 0.f);
        sh[16] = mean;
        sh[17] = rsqrtf(var + 1e-5f);
    }
    __syncthreads();
    float mean = sh[16], rstd = sh[17];
    for (int j = threadIdx.x; j < npad; j += 256) {
        float v = 0.f;
        if (j < n) {
            v = (p[j] - mean) * rstd * w[j] + b[j];
            if (of) of[j] = v;
        }
        hh[j] = __float2half_rn(v);
    }
}

// ---------------- launch ----------------
static inline void* sym(const void* s) { void* p; cudaGetSymbolAddress(&p, s); return p; }

extern "C" void kernel_launch(void* const* d_in, const int* in_sizes, int n_in,
                              void* d_out, int out_size)
{
    const float* x     = (const float*)d_in[0];
    const float* W_dq  = (const float*)d_in[1];
    const float* W_uq  = (const float*)d_in[2];
    const float* W_qr  = (const float*)d_in[3];
    const float* W_dkv = (const float*)d_in[4];
    const float* W_ukv = (const float*)d_in[5];
    const float* W_kr  = (const float*)d_in[6];
    const float* W_o   = (const float*)d_in[7];
    const float* q_w   = (const float*)d_in[8];
    const float* q_b   = (const float*)d_in[9];
    const float* kv_w  = (const float*)d_in[10];
    const float* kv_b  = (const float*)d_in[11];

    float* out = (float*)d_out;
    float* ckv = out + (size_t)BS * DMODEL;

    h16 *xhi=(h16*)sym(g_xhi);
    h16 *w1h=(h16*)sym(g_w1h);
    h16 *w2h=(h16*)sym(g_w2h);
    h16 *wukvh=(h16*)sym(g_wukvh);
    h16 *woh=(h16*)sym(g_woh);
    float *p1=(float*)sym(g_p1);
    h16 *cqh=(h16*)sym(g_cqh);
    h16 *ckvh=(h16*)sym(g_ckvh);
    h16 *q2h=(h16*)sym(g_q2h);
    h16 *kvh=(h16*)sym(g_kvh);
    h16 *aoh=(h16*)sym(g_aoh);

    cudaFuncSetAttribute(hmma_gemm1, cudaFuncAttributeMaxDynamicSharedMemorySize, SMEM_GEMM);
    cudaFuncSetAttribute(hmma_gemm_dual, cudaFuncAttributeMaxDynamicSharedMemorySize, SMEM_GEMM);
    cudaFuncSetAttribute(gemm_p1_prep2, cudaFuncAttributeMaxDynamicSharedMemorySize, SMEM_GEMM);
    cudaFuncSetAttribute(flash_attn, cudaFuncAttributeMaxDynamicSharedMemorySize, SMEM_FLASH);

    // 1. x convert + W1 transposes
    prep1<<<1216, 256>>>(x, W_dq, W_dkv, W_kr, xhi, w1h);

    // 2. p1 = x @ W1 (fp32) fused with prep2
    gemm_p1_prep2<<<1844, 256, SMEM_GEMM>>>(
        xhi, w1h, p1,
        W_uq, W_qr, W_ukv, W_o,
        w2h, wukvh, woh);

    // 3. LayerNorms (merged)
    layernorm2<<<dim3(BS, 2), 256>>>(p1, cqh, ckv, ckvh, q_w, q_b, kv_w, kv_b);

    // 4. q2 + ukv GEMMs + rope-K in one launch
    {
        int gx_ukv = KVCOLS / 128;              // 30
        int gx_q2  = N2 / 128;                  // 16
        int blocks_ukv = gx_ukv * (BS / 128);   // 960
        int blocks_q2  = gx_q2  * (BS / 128);   // 512
        int total_gemm = blocks_ukv + blocks_q2;
        hmma_gemm_dual<<<total_gemm + 256, 256, SMEM_GEMM>>>(
            ckvh, wukvh, kvh,
            KVCOLS, KVPAD, KVPAD, KVPAD, KVLD, gx_ukv,
            cqh, w2h, q2h,
            N2, QPROJ, QPROJ, QPROJ, N2, gx_q2,
            blocks_ukv, total_gemm,
            p1, kvh);
    }

    // 5. flash attention (rope-Q fused in prologue)
    flash_attn<<<dim3(S_/128, NZ), 256, SMEM_FLASH>>>(q2h, kvh, aoh);

    // 6. final projection
    hmma_gemm1<<<dim3(DMODEL/128, BS/128), 256, SMEM_GEMM>>>(
        aoh, woh, out, DMODEL, DMODEL, DMODEL, DMODEL, DMODEL);
}